// round 1
// baseline (speedup 1.0000x reference)
#include <cuda_runtime.h>
#include <math.h>

// ---------------- problem constants ----------------
#define NNODES 50000
#define ECAP   1000000

// ---------------- device scratch (static; no allocations) ----------------
__device__ float g_z[NNODES * 256];     // GEMM output of current layer (stride 256 or 240)
__device__ float g_h0[NNODES * 256];    // layer-0 output
__device__ float g_r2[NNODES * 240];    // layer-2 residual projection
__device__ float g_el[NNODES * 6];
__device__ float g_er[NNODES * 6];
__device__ int   g_deg[NNODES];
__device__ int   g_rowstart[NNODES + 1];
__device__ int   g_cursor[NNODES];
__device__ int   g_srcs[ECAP];

// ---------------- CSR build ----------------
__global__ void k_zero_deg(int n) {
    int i = blockIdx.x * blockDim.x + threadIdx.x;
    if (i < n) g_deg[i] = 0;
}

__global__ void k_hist(const int* __restrict__ dst, int E) {
    int e = blockIdx.x * blockDim.x + threadIdx.x;
    if (e < E) atomicAdd(&g_deg[dst[e]], 1);
}

// single-block inclusive->exclusive scan over g_deg (n <= ~64K)
__global__ void k_scan(int n, int E) {
    __shared__ int s[1024];
    __shared__ int carry;
    if (threadIdx.x == 0) carry = 0;
    __syncthreads();
    for (int base = 0; base < n; base += 1024) {
        int i = base + threadIdx.x;
        int v = (i < n) ? g_deg[i] : 0;
        s[threadIdx.x] = v;
        __syncthreads();
        #pragma unroll
        for (int off = 1; off < 1024; off <<= 1) {
            int t = (threadIdx.x >= off) ? s[threadIdx.x - off] : 0;
            __syncthreads();
            s[threadIdx.x] += t;
            __syncthreads();
        }
        int incl = s[threadIdx.x];
        int excl = incl - v + carry;
        if (i < n) { g_rowstart[i] = excl; g_cursor[i] = excl; }
        __syncthreads();
        if (threadIdx.x == 1023) carry += s[1023];
        __syncthreads();
    }
    if (threadIdx.x == 0) g_rowstart[n] = E;
}

__global__ void k_scatter(const int* __restrict__ src, const int* __restrict__ dst, int E) {
    int e = blockIdx.x * blockDim.x + threadIdx.x;
    if (e < E) {
        int p = atomicAdd(&g_cursor[dst[e]], 1);
        g_srcs[p] = src[e];
    }
}

// ---------------- SGEMM: C[M,Nn] = A[M,K] * B[K,Nn] ----------------
// BM=128 BN=128 BK=8, 256 threads, 8x8 per thread.
__global__ __launch_bounds__(256) void k_sgemm(
    const float* __restrict__ A, const float* __restrict__ B,
    float* __restrict__ C, int M, int Nn, int K)
{
    __shared__ float As[8][128];
    __shared__ float Bs[8][128];
    int tid = threadIdx.x;
    int rowBase = blockIdx.y * 128;
    int colBase = blockIdx.x * 128;
    int trow = tid >> 4;          // 0..15
    int tcol = tid & 15;          // 0..15

    float acc[8][8];
    #pragma unroll
    for (int m = 0; m < 8; ++m)
        #pragma unroll
        for (int n2 = 0; n2 < 8; ++n2) acc[m][n2] = 0.f;

    int aRow = tid >> 1;           // 0..127
    int aK   = (tid & 1) * 4;      // 0 or 4
    int bK   = tid >> 5;           // 0..7
    int bCol = (tid & 31) * 4;     // 0..124
    bool aValid = (rowBase + aRow) < M;

    for (int k0 = 0; k0 < K; k0 += 8) {
        float4 av = make_float4(0.f, 0.f, 0.f, 0.f);
        if (aValid)
            av = *reinterpret_cast<const float4*>(A + (size_t)(rowBase + aRow) * K + k0 + aK);
        As[aK + 0][aRow] = av.x;
        As[aK + 1][aRow] = av.y;
        As[aK + 2][aRow] = av.z;
        As[aK + 3][aRow] = av.w;
        #pragma unroll
        for (int j = 0; j < 4; ++j) {
            int col = colBase + bCol + j;
            Bs[bK][bCol + j] = (col < Nn) ? B[(size_t)(k0 + bK) * Nn + col] : 0.f;
        }
        __syncthreads();
        #pragma unroll
        for (int kk = 0; kk < 8; ++kk) {
            float ra[8], rb[8];
            #pragma unroll
            for (int m = 0; m < 8; ++m) ra[m] = As[kk][trow * 8 + m];
            #pragma unroll
            for (int n2 = 0; n2 < 8; ++n2) rb[n2] = Bs[kk][tcol * 8 + n2];
            #pragma unroll
            for (int m = 0; m < 8; ++m)
                #pragma unroll
                for (int n2 = 0; n2 < 8; ++n2)
                    acc[m][n2] = fmaf(ra[m], rb[n2], acc[m][n2]);
        }
        __syncthreads();
    }
    #pragma unroll
    for (int m = 0; m < 8; ++m) {
        int r = rowBase + trow * 8 + m;
        if (r < M) {
            #pragma unroll
            for (int n2 = 0; n2 < 8; ++n2) {
                int c = colBase + tcol * 8 + n2;
                if (c < Nn) C[(size_t)r * Nn + c] = acc[m][n2];
            }
        }
    }
}

// ---------------- el/er projections: el[n,h] = sum_d z[n,h*D+d]*al[h,d] ----------------
__global__ void k_elr(const float* __restrict__ z, const float* __restrict__ al,
                      const float* __restrict__ ar, float* __restrict__ el,
                      float* __restrict__ er, int n, int H, int D)
{
    int t = blockIdx.x * blockDim.x + threadIdx.x;
    if (t >= n * H) return;
    int node = t / H, h = t - node * H;
    const float4* zr  = reinterpret_cast<const float4*>(z + (size_t)node * H * D + h * D);
    const float4* alr = reinterpret_cast<const float4*>(al + h * D);
    const float4* arr = reinterpret_cast<const float4*>(ar + h * D);
    float sl = 0.f, sr = 0.f;
    int d4 = D >> 2;
    for (int i = 0; i < d4; ++i) {
        float4 zv = __ldg(&zr[i]);
        float4 av = __ldg(&alr[i]);
        float4 bv = __ldg(&arr[i]);
        sl = fmaf(zv.x, av.x, sl); sl = fmaf(zv.y, av.y, sl);
        sl = fmaf(zv.z, av.z, sl); sl = fmaf(zv.w, av.w, sl);
        sr = fmaf(zv.x, bv.x, sr); sr = fmaf(zv.y, bv.y, sr);
        sr = fmaf(zv.z, bv.z, sr); sr = fmaf(zv.w, bv.w, sr);
    }
    el[t] = sl;
    er[t] = sr;
}

// ---------------- aggregation, layers 0/1 (H=4, D=64, C=256), warp per dst node ----------------
template <bool RES>
__global__ __launch_bounds__(256) void k_agg256(
    const float* __restrict__ z, const float* __restrict__ el,
    const float* __restrict__ er, const float* __restrict__ bias,
    const float* __restrict__ xres, float* __restrict__ out, int n)
{
    int gw = (blockIdx.x * blockDim.x + threadIdx.x) >> 5;
    if (gw >= n) return;
    int lane = threadIdx.x & 31;
    int beg = g_rowstart[gw], end = g_rowstart[gw + 1];
    float erh = (lane < 4) ? __ldg(&er[gw * 4 + lane]) : 0.f;
    int h = lane >> 3;
    int c0 = lane * 8;
    float4 acc0 = make_float4(0.f, 0.f, 0.f, 0.f), acc1 = acc0;
    float denom = 0.f;
    for (int i = beg; i < end; ++i) {
        int s = __ldg(&g_srcs[i]);
        float w = 0.f;
        if (lane < 4) {
            float e = __ldg(&el[s * 4 + lane]) + erh;
            e = (e > 0.f) ? e : 0.2f * e;
            w = __expf(e);
            denom += w;
        }
        float wh = __shfl_sync(0xffffffffu, w, h);
        const float4* zp = reinterpret_cast<const float4*>(z + (size_t)s * 256 + c0);
        float4 a = __ldg(zp), b = __ldg(zp + 1);
        acc0.x = fmaf(wh, a.x, acc0.x); acc0.y = fmaf(wh, a.y, acc0.y);
        acc0.z = fmaf(wh, a.z, acc0.z); acc0.w = fmaf(wh, a.w, acc0.w);
        acc1.x = fmaf(wh, b.x, acc1.x); acc1.y = fmaf(wh, b.y, acc1.y);
        acc1.z = fmaf(wh, b.z, acc1.z); acc1.w = fmaf(wh, b.w, acc1.w);
    }
    float dh = __shfl_sync(0xffffffffu, denom, h);
    float inv = 1.f / dh;
    const float4* bp = reinterpret_cast<const float4*>(bias + c0);
    float4 b0 = __ldg(bp), b1 = __ldg(bp + 1);
    float v[8];
    v[0] = fmaf(acc0.x, inv, b0.x); v[1] = fmaf(acc0.y, inv, b0.y);
    v[2] = fmaf(acc0.z, inv, b0.z); v[3] = fmaf(acc0.w, inv, b0.w);
    v[4] = fmaf(acc1.x, inv, b1.x); v[5] = fmaf(acc1.y, inv, b1.y);
    v[6] = fmaf(acc1.z, inv, b1.z); v[7] = fmaf(acc1.w, inv, b1.w);
    if (RES) {
        const float4* rp = reinterpret_cast<const float4*>(xres + (size_t)gw * 256 + c0);
        float4 r0 = __ldg(rp), r1 = __ldg(rp + 1);
        v[0] += r0.x; v[1] += r0.y; v[2] += r0.z; v[3] += r0.w;
        v[4] += r1.x; v[5] += r1.y; v[6] += r1.z; v[7] += r1.w;
    }
    #pragma unroll
    for (int j = 0; j < 8; ++j) v[j] = (v[j] > 0.f) ? v[j] : expm1f(v[j]);  // ELU
    float4 o0 = make_float4(v[0], v[1], v[2], v[3]);
    float4 o1 = make_float4(v[4], v[5], v[6], v[7]);
    float4* op = reinterpret_cast<float4*>(out + (size_t)gw * 256 + c0);
    op[0] = o0; op[1] = o1;
}

// ---------------- aggregation, layer 2 (H=6, D=40, C=240) + head-mean to logits ----------------
__global__ __launch_bounds__(256) void k_agg_l2(
    const float* __restrict__ z, const float* __restrict__ el,
    const float* __restrict__ er, const float* __restrict__ bias,
    const float* __restrict__ res, float* __restrict__ logits, int n)
{
    __shared__ float sout[8][240];
    int wInB = threadIdx.x >> 5;
    int gw = blockIdx.x * 8 + wInB;
    int lane = threadIdx.x & 31;
    bool act = (lane < 30);
    if (gw < n) {
        int beg = g_rowstart[gw], end = g_rowstart[gw + 1];
        float erh = (lane < 6) ? __ldg(&er[gw * 6 + lane]) : 0.f;
        int h = act ? (lane / 5) : 0;
        int c0 = lane * 8;
        float4 acc0 = make_float4(0.f, 0.f, 0.f, 0.f), acc1 = acc0;
        float denom = 0.f;
        for (int i = beg; i < end; ++i) {
            int s = __ldg(&g_srcs[i]);
            float w = 0.f;
            if (lane < 6) {
                float e = __ldg(&el[s * 6 + lane]) + erh;
                e = (e > 0.f) ? e : 0.2f * e;
                w = __expf(e);
                denom += w;
            }
            float wh = __shfl_sync(0xffffffffu, w, h);
            if (act) {
                const float4* zp = reinterpret_cast<const float4*>(z + (size_t)s * 240 + c0);
                float4 a = __ldg(zp), b = __ldg(zp + 1);
                acc0.x = fmaf(wh, a.x, acc0.x); acc0.y = fmaf(wh, a.y, acc0.y);
                acc0.z = fmaf(wh, a.z, acc0.z); acc0.w = fmaf(wh, a.w, acc0.w);
                acc1.x = fmaf(wh, b.x, acc1.x); acc1.y = fmaf(wh, b.y, acc1.y);
                acc1.z = fmaf(wh, b.z, acc1.z); acc1.w = fmaf(wh, b.w, acc1.w);
            }
        }
        float dh = __shfl_sync(0xffffffffu, denom, h);
        if (act) {
            float inv = 1.f / dh;
            const float4* bp = reinterpret_cast<const float4*>(bias + c0);
            const float4* rp = reinterpret_cast<const float4*>(res + (size_t)gw * 240 + c0);
            float4 b0 = __ldg(bp), b1 = __ldg(bp + 1);
            float4 r0 = __ldg(rp), r1 = __ldg(rp + 1);
            sout[wInB][c0 + 0] = fmaf(acc0.x, inv, b0.x) + r0.x;
            sout[wInB][c0 + 1] = fmaf(acc0.y, inv, b0.y) + r0.y;
            sout[wInB][c0 + 2] = fmaf(acc0.z, inv, b0.z) + r0.z;
            sout[wInB][c0 + 3] = fmaf(acc0.w, inv, b0.w) + r0.w;
            sout[wInB][c0 + 4] = fmaf(acc1.x, inv, b1.x) + r1.x;
            sout[wInB][c0 + 5] = fmaf(acc1.y, inv, b1.y) + r1.y;
            sout[wInB][c0 + 6] = fmaf(acc1.z, inv, b1.z) + r1.z;
            sout[wInB][c0 + 7] = fmaf(acc1.w, inv, b1.w) + r1.w;
        }
    }
    __syncwarp();
    if (gw < n) {
        for (int d = lane; d < 40; d += 32) {
            float s_ = 0.f;
            #pragma unroll
            for (int hh = 0; hh < 6; ++hh) s_ += sout[wInB][hh * 40 + d];
            logits[(size_t)gw * 40 + d] = s_ * (1.0f / 6.0f);
        }
    }
}

// ---------------- host ----------------
extern "C" void kernel_launch(void* const* d_in, const int* in_sizes, int n_in,
                              void* d_out, int out_size)
{
    const float* feat  = (const float*)d_in[0];
    const int*   src   = (const int*)d_in[1];
    const int*   dst   = (const int*)d_in[2];
    const float* W0    = (const float*)d_in[3];
    const float* al0   = (const float*)d_in[4];
    const float* ar0   = (const float*)d_in[5];
    const float* b0    = (const float*)d_in[6];
    const float* W1    = (const float*)d_in[7];
    const float* al1   = (const float*)d_in[8];
    const float* ar1   = (const float*)d_in[9];
    const float* b1    = (const float*)d_in[10];
    const float* W2    = (const float*)d_in[11];
    const float* al2   = (const float*)d_in[12];
    const float* ar2   = (const float*)d_in[13];
    const float* b2    = (const float*)d_in[14];
    const float* resW2 = (const float*)d_in[15];

    const int n = NNODES;
    const int E = in_sizes[1];

    float* logits = (float*)d_out;            // [N,40]
    float* h1     = (float*)d_out + n * 40;   // [N,256]

    float *pz, *ph0, *pr2, *pel, *per;
    cudaGetSymbolAddress((void**)&pz,  g_z);
    cudaGetSymbolAddress((void**)&ph0, g_h0);
    cudaGetSymbolAddress((void**)&pr2, g_r2);
    cudaGetSymbolAddress((void**)&pel, g_el);
    cudaGetSymbolAddress((void**)&per, g_er);

    // ---- CSR by destination (same graph for all layers) ----
    k_zero_deg<<<(n + 255) / 256, 256>>>(n);
    k_hist<<<(E + 255) / 256, 256>>>(dst, E);
    k_scan<<<1, 1024>>>(n, E);
    k_scatter<<<(E + 255) / 256, 256>>>(src, dst, E);

    dim3 g256(2, (n + 127) / 128);   // Nn=256
    dim3 g240(2, (n + 127) / 128);   // Nn=240
    int elrBlocks4 = (n * 4 + 255) / 256;
    int elrBlocks6 = (n * 6 + 255) / 256;
    int aggBlocks  = (n + 7) / 8;

    // ---- Layer 0: feat -> h0 (ELU, no residual) ----
    k_sgemm<<<g256, 256>>>(feat, W0, pz, n, 256, 256);
    k_elr<<<elrBlocks4, 256>>>(pz, al0, ar0, pel, per, n, 4, 64);
    k_agg256<false><<<aggBlocks, 256>>>(pz, pel, per, b0, nullptr, ph0, n);

    // ---- Layer 1: h0 -> h1 (ELU, identity residual), h1 lives in d_out ----
    k_sgemm<<<g256, 256>>>(ph0, W1, pz, n, 256, 256);
    k_elr<<<elrBlocks4, 256>>>(pz, al1, ar1, pel, per, n, 4, 64);
    k_agg256<true><<<aggBlocks, 256>>>(pz, pel, per, b1, ph0, h1, n);

    // ---- Layer 2: h1 -> logits (linear residual, head mean) ----
    k_sgemm<<<g240, 256>>>(h1, W2, pz, n, 240, 256);
    k_sgemm<<<g240, 256>>>(h1, resW2, pr2, n, 240, 256);
    k_elr<<<elrBlocks6, 256>>>(pz, al2, ar2, pel, per, n, 6, 40);
    k_agg_l2<<<aggBlocks, 256>>>(pz, pel, per, b2, pr2, logits, n);
}

// round 3
// speedup vs baseline: 1.7616x; 1.7616x over previous
#include <cuda_runtime.h>
#include <cuda_bf16.h>
#include <math.h>
#include <cstdint>

// ---------------- problem constants ----------------
#define NNODES 50000
#define ECAP   1000000

// ---------------- device scratch (static; no allocations) ----------------
__device__ float g_z[NNODES * 256];
__device__ float g_h0[NNODES * 256];
__device__ float g_r2[NNODES * 240];
__device__ float g_el[NNODES * 6];
__device__ float g_er[NNODES * 6];
__device__ int   g_deg[NNODES];
__device__ int   g_rowstart[NNODES + 1];
__device__ int   g_cursor[NNODES];
__device__ int   g_srcs[ECAP];
__device__ __align__(16) __nv_bfloat16 g_Ahi[NNODES * 256];
__device__ __align__(16) __nv_bfloat16 g_Alo[NNODES * 256];
__device__ __align__(16) __nv_bfloat16 g_Bth[256 * 256];   // [N(pad 256), K=256]
__device__ __align__(16) __nv_bfloat16 g_Btl[256 * 256];

// ================= PTX helpers =================
__device__ __forceinline__ uint32_t smem_u32(const void* p) {
    uint32_t a;
    asm("{ .reg .u64 t; cvta.to.shared.u64 t, %1; cvt.u32.u64 %0, t; }" : "=r"(a) : "l"(p));
    return a;
}
__device__ __forceinline__ void cp16(uint32_t dst, const void* src, uint32_t srcsize) {
    asm volatile("cp.async.cg.shared.global [%0], [%1], 16, %2;"
                 :: "r"(dst), "l"(src), "r"(srcsize));
}
#define CP_COMMIT() asm volatile("cp.async.commit_group;" ::: "memory")
#define CP_WAIT(n)  asm volatile("cp.async.wait_group %0;" :: "n"(n) : "memory")
#define LDSM_X4(r0, r1, r2, r3, addr) \
    asm volatile("ldmatrix.sync.aligned.m8n8.x4.shared.b16 {%0,%1,%2,%3}, [%4];" \
        : "=r"(r0), "=r"(r1), "=r"(r2), "=r"(r3) : "r"(addr))
#define MMA_BF16(acc, a, b) \
    asm volatile("mma.sync.aligned.m16n8k16.row.col.f32.bf16.bf16.f32 " \
        "{%0,%1,%2,%3}, {%4,%5,%6,%7}, {%8,%9}, {%0,%1,%2,%3};" \
        : "+f"((acc)[0]), "+f"((acc)[1]), "+f"((acc)[2]), "+f"((acc)[3]) \
        : "r"((a)[0]), "r"((a)[1]), "r"((a)[2]), "r"((a)[3]), "r"((b)[0]), "r"((b)[1]))

// ---------------- CSR build ----------------
__global__ void k_zero_deg(int n) {
    int i = blockIdx.x * blockDim.x + threadIdx.x;
    if (i < n) g_deg[i] = 0;
}
__global__ void k_hist(const int* __restrict__ dst, int E) {
    int e = blockIdx.x * blockDim.x + threadIdx.x;
    if (e < E) atomicAdd(&g_deg[dst[e]], 1);
}
__global__ void k_scan(int n, int E) {
    __shared__ int s[1024];
    __shared__ int carry;
    if (threadIdx.x == 0) carry = 0;
    __syncthreads();
    for (int base = 0; base < n; base += 1024) {
        int i = base + threadIdx.x;
        int v = (i < n) ? g_deg[i] : 0;
        s[threadIdx.x] = v;
        __syncthreads();
        #pragma unroll
        for (int off = 1; off < 1024; off <<= 1) {
            int t = (threadIdx.x >= off) ? s[threadIdx.x - off] : 0;
            __syncthreads();
            s[threadIdx.x] += t;
            __syncthreads();
        }
        int incl = s[threadIdx.x];
        int excl = incl - v + carry;
        if (i < n) { g_rowstart[i] = excl; g_cursor[i] = excl; }
        __syncthreads();
        if (threadIdx.x == 1023) carry += s[1023];
        __syncthreads();
    }
    if (threadIdx.x == 0) g_rowstart[n] = E;
}
__global__ void k_scatter(const int* __restrict__ src, const int* __restrict__ dst, int E) {
    int e = blockIdx.x * blockDim.x + threadIdx.x;
    if (e < E) {
        int p = atomicAdd(&g_cursor[dst[e]], 1);
        g_srcs[p] = src[e];
    }
}

// ---------------- fp32 -> bf16 hi/lo split ----------------
__global__ void k_splitA(const float* __restrict__ A, __nv_bfloat16* __restrict__ hi,
                         __nv_bfloat16* __restrict__ lo, int n4) {
    int i = blockIdx.x * blockDim.x + threadIdx.x;
    if (i >= n4) return;
    float4 v = reinterpret_cast<const float4*>(A)[i];
    __nv_bfloat16 h0 = __float2bfloat16_rn(v.x);
    __nv_bfloat16 h1 = __float2bfloat16_rn(v.y);
    __nv_bfloat16 h2 = __float2bfloat16_rn(v.z);
    __nv_bfloat16 h3 = __float2bfloat16_rn(v.w);
    __nv_bfloat16 l0 = __float2bfloat16_rn(v.x - __bfloat162float(h0));
    __nv_bfloat16 l1 = __float2bfloat16_rn(v.y - __bfloat162float(h1));
    __nv_bfloat16 l2 = __float2bfloat16_rn(v.z - __bfloat162float(h2));
    __nv_bfloat16 l3 = __float2bfloat16_rn(v.w - __bfloat162float(h3));
    reinterpret_cast<ushort4*>(hi)[i] = make_ushort4(
        __bfloat16_as_ushort(h0), __bfloat16_as_ushort(h1),
        __bfloat16_as_ushort(h2), __bfloat16_as_ushort(h3));
    reinterpret_cast<ushort4*>(lo)[i] = make_ushort4(
        __bfloat16_as_ushort(l0), __bfloat16_as_ushort(l1),
        __bfloat16_as_ushort(l2), __bfloat16_as_ushort(l3));
}

// B [K=256, Nn] fp32 -> Bt hi/lo [256(N, zero-padded), 256(K)] bf16
__global__ void k_splitBt(const float* __restrict__ B, __nv_bfloat16* __restrict__ th,
                          __nv_bfloat16* __restrict__ tl, int Nn) {
    int t = blockIdx.x * blockDim.x + threadIdx.x;
    if (t >= 256 * 256) return;
    int nrow = t >> 8, k = t & 255;
    float x = (nrow < Nn) ? B[(size_t)k * Nn + nrow] : 0.f;
    __nv_bfloat16 h = __float2bfloat16_rn(x);
    th[t] = h;
    tl[t] = __float2bfloat16_rn(x - __bfloat162float(h));
}

// ---------------- mma.sync split-bf16 GEMM: C[M,Nn] = A[M,256] * B[256,Nn] ----------------
// CTA tile 128(M) x 64(N), BK=64, 8 warps (warp_m 0..3, warp_n 0..1), warp tile 32x32.
// Smem per stage: Ahi 16K | Alo 16K | Bhi 8K | Blo 8K = 48K; double buffered = 96K.
#define STAGE_BYTES 49152
#define GEMM_SMEM   (2 * STAGE_BYTES)

__device__ __forceinline__ void gemm_load_stage(
    uint32_t sb, const __nv_bfloat16* __restrict__ Ahi, const __nv_bfloat16* __restrict__ Alo,
    const __nv_bfloat16* __restrict__ Bth, const __nv_bfloat16* __restrict__ Btl,
    int m0, int n0, int M, int kb, int tid)
{
    // A: 128 rows x 8 chunks(16B) x 2 precisions = 2048 chunks
    #pragma unroll
    for (int it = 0; it < 8; ++it) {
        int idx = tid + it * 256;
        int prec = idx >> 10, rem = idx & 1023;
        int row = rem >> 3, ch = rem & 7;
        uint32_t dst = sb + prec * 16384 + row * 128 + (((uint32_t)(ch ^ (row & 7))) << 4);
        const __nv_bfloat16* srcb = prec ? Alo : Ahi;
        const __nv_bfloat16* src = srcb + (size_t)(m0 + row) * 256 + kb * 64 + ch * 8;
        cp16(dst, src, (m0 + row) < M ? 16u : 0u);
    }
    // B: 64 rows x 8 chunks x 2 precisions = 1024 chunks
    #pragma unroll
    for (int it = 0; it < 4; ++it) {
        int idx = tid + it * 256;
        int prec = idx >> 9, rem = idx & 511;
        int row = rem >> 3, ch = rem & 7;
        uint32_t dst = sb + 32768 + prec * 8192 + row * 128 + (((uint32_t)(ch ^ (row & 7))) << 4);
        const __nv_bfloat16* srcb = prec ? Btl : Bth;
        const __nv_bfloat16* src = srcb + (size_t)(n0 + row) * 256 + kb * 64 + ch * 8;
        cp16(dst, src, 16u);
    }
}

__global__ __launch_bounds__(256, 1) void k_gemm_mma(
    const __nv_bfloat16* __restrict__ Ahi, const __nv_bfloat16* __restrict__ Alo,
    const __nv_bfloat16* __restrict__ Bth, const __nv_bfloat16* __restrict__ Btl,
    float* __restrict__ C, int M, int Nn)
{
    extern __shared__ char smem[];
    const uint32_t sbase = smem_u32(smem);
    const int tid = threadIdx.x, wid = tid >> 5, lane = tid & 31;
    const int warp_m = wid & 3, warp_n = wid >> 2;
    const int m0 = blockIdx.y * 128;
    const int n0 = blockIdx.x * 64;

    float acc[2][4][4];
    #pragma unroll
    for (int mt = 0; mt < 2; ++mt)
        #pragma unroll
        for (int nt = 0; nt < 4; ++nt)
            #pragma unroll
            for (int q = 0; q < 4; ++q) acc[mt][nt][q] = 0.f;

    // per-lane smem geometry for ldmatrix
    const int rowA = warp_m * 32 + (lane & 15);        // + mt*16
    const int rowB = warp_n * 32 + (lane & 7) + ((lane >> 4) << 3);  // + ntp*16
    const uint32_t rowAswz = (uint32_t)(rowA & 7);
    const uint32_t rowBswz = (uint32_t)(rowB & 7);
    const int halfA = lane >> 4;                        // chunk half for A
    const int halfB = (lane >> 3) & 1;                  // chunk half for B

    gemm_load_stage(sbase, Ahi, Alo, Bth, Btl, m0, n0, M, 0, tid);
    CP_COMMIT();

    #pragma unroll 1
    for (int kb = 0; kb < 4; ++kb) {
        if (kb < 3) {
            gemm_load_stage(sbase + ((kb + 1) & 1) * STAGE_BYTES,
                            Ahi, Alo, Bth, Btl, m0, n0, M, kb + 1, tid);
            CP_COMMIT();
            CP_WAIT(1);
        } else {
            CP_WAIT(0);
        }
        __syncthreads();

        const uint32_t sb = sbase + (kb & 1) * STAGE_BYTES;
        #pragma unroll
        for (int s = 0; s < 4; ++s) {
            uint32_t a[2][2][4];   // [prec][mt][4]
            uint32_t b[2][4][2];   // [prec][nt][2]
            const uint32_t chA = (uint32_t)(s * 2 + halfA);
            const uint32_t offA = ((chA ^ rowAswz) << 4);
            const uint32_t chB = (uint32_t)(s * 2 + halfB);
            const uint32_t offB = ((chB ^ rowBswz) << 4);
            #pragma unroll
            for (int prec = 0; prec < 2; ++prec) {
                uint32_t baseA = sb + prec * 16384;
                #pragma unroll
                for (int mt = 0; mt < 2; ++mt) {
                    uint32_t addr = baseA + (uint32_t)(rowA + mt * 16) * 128 + offA;
                    LDSM_X4(a[prec][mt][0], a[prec][mt][1], a[prec][mt][2], a[prec][mt][3], addr);
                }
                uint32_t baseB = sb + 32768 + prec * 8192;
                #pragma unroll
                for (int ntp = 0; ntp < 2; ++ntp) {
                    uint32_t addr = baseB + (uint32_t)(rowB + ntp * 16) * 128 + offB;
                    LDSM_X4(b[prec][2 * ntp][0], b[prec][2 * ntp][1],
                            b[prec][2 * ntp + 1][0], b[prec][2 * ntp + 1][1], addr);
                }
            }
            #pragma unroll
            for (int mt = 0; mt < 2; ++mt)
                #pragma unroll
                for (int nt = 0; nt < 4; ++nt) {
                    MMA_BF16(acc[mt][nt], a[0][mt], b[0][nt]);  // hi*hi
                    MMA_BF16(acc[mt][nt], a[0][mt], b[1][nt]);  // hi*lo
                    MMA_BF16(acc[mt][nt], a[1][mt], b[0][nt]);  // lo*hi
                }
        }
        __syncthreads();
    }

    // epilogue: direct reg -> global
    #pragma unroll
    for (int mt = 0; mt < 2; ++mt) {
        int row = m0 + warp_m * 32 + mt * 16 + (lane >> 2);
        #pragma unroll
        for (int nt = 0; nt < 4; ++nt) {
            int col = n0 + warp_n * 32 + nt * 8 + (lane & 3) * 2;
            if (col < Nn) {
                if (row < M)
                    *reinterpret_cast<float2*>(C + (size_t)row * Nn + col) =
                        make_float2(acc[mt][nt][0], acc[mt][nt][1]);
                if (row + 8 < M)
                    *reinterpret_cast<float2*>(C + (size_t)(row + 8) * Nn + col) =
                        make_float2(acc[mt][nt][2], acc[mt][nt][3]);
            }
        }
    }
}

// ---------------- el/er projections ----------------
__global__ void k_elr(const float* __restrict__ z, const float* __restrict__ al,
                      const float* __restrict__ ar, float* __restrict__ el,
                      float* __restrict__ er, int n, int H, int D)
{
    int t = blockIdx.x * blockDim.x + threadIdx.x;
    if (t >= n * H) return;
    int node = t / H, h = t - node * H;
    const float4* zr  = reinterpret_cast<const float4*>(z + (size_t)node * H * D + h * D);
    const float4* alr = reinterpret_cast<const float4*>(al + h * D);
    const float4* arr = reinterpret_cast<const float4*>(ar + h * D);
    float sl = 0.f, sr = 0.f;
    int d4 = D >> 2;
    for (int i = 0; i < d4; ++i) {
        float4 zv = __ldg(&zr[i]);
        float4 av = __ldg(&alr[i]);
        float4 bv = __ldg(&arr[i]);
        sl = fmaf(zv.x, av.x, sl); sl = fmaf(zv.y, av.y, sl);
        sl = fmaf(zv.z, av.z, sl); sl = fmaf(zv.w, av.w, sl);
        sr = fmaf(zv.x, bv.x, sr); sr = fmaf(zv.y, bv.y, sr);
        sr = fmaf(zv.z, bv.z, sr); sr = fmaf(zv.w, bv.w, sr);
    }
    el[t] = sl;
    er[t] = sr;
}

// ---------------- aggregation, layers 0/1 ----------------
template <bool RES>
__global__ __launch_bounds__(256) void k_agg256(
    const float* __restrict__ z, const float* __restrict__ el,
    const float* __restrict__ er, const float* __restrict__ bias,
    const float* __restrict__ xres, float* __restrict__ out, int n)
{
    int gw = (blockIdx.x * blockDim.x + threadIdx.x) >> 5;
    if (gw >= n) return;
    int lane = threadIdx.x & 31;
    int beg = g_rowstart[gw], end = g_rowstart[gw + 1];
    float erh = (lane < 4) ? __ldg(&er[gw * 4 + lane]) : 0.f;
    int h = lane >> 3;
    int c0 = lane * 8;
    float4 acc0 = make_float4(0.f, 0.f, 0.f, 0.f), acc1 = acc0;
    float denom = 0.f;
    for (int i = beg; i < end; ++i) {
        int s = __ldg(&g_srcs[i]);
        float w = 0.f;
        if (lane < 4) {
            float e = __ldg(&el[s * 4 + lane]) + erh;
            e = (e > 0.f) ? e : 0.2f * e;
            w = __expf(e);
            denom += w;
        }
        float wh = __shfl_sync(0xffffffffu, w, h);
        const float4* zp = reinterpret_cast<const float4*>(z + (size_t)s * 256 + c0);
        float4 a = __ldg(zp), b = __ldg(zp + 1);
        acc0.x = fmaf(wh, a.x, acc0.x); acc0.y = fmaf(wh, a.y, acc0.y);
        acc0.z = fmaf(wh, a.z, acc0.z); acc0.w = fmaf(wh, a.w, acc0.w);
        acc1.x = fmaf(wh, b.x, acc1.x); acc1.y = fmaf(wh, b.y, acc1.y);
        acc1.z = fmaf(wh, b.z, acc1.z); acc1.w = fmaf(wh, b.w, acc1.w);
    }
    float dh = __shfl_sync(0xffffffffu, denom, h);
    float inv = 1.f / dh;
    const float4* bp = reinterpret_cast<const float4*>(bias + c0);
    float4 b0 = __ldg(bp), b1 = __ldg(bp + 1);
    float v[8];
    v[0] = fmaf(acc0.x, inv, b0.x); v[1] = fmaf(acc0.y, inv, b0.y);
    v[2] = fmaf(acc0.z, inv, b0.z); v[3] = fmaf(acc0.w, inv, b0.w);
    v[4] = fmaf(acc1.x, inv, b1.x); v[5] = fmaf(acc1.y, inv, b1.y);
    v[6] = fmaf(acc1.z, inv, b1.z); v[7] = fmaf(acc1.w, inv, b1.w);
    if (RES) {
        const float4* rp = reinterpret_cast<const float4*>(xres + (size_t)gw * 256 + c0);
        float4 r0 = __ldg(rp), r1 = __ldg(rp + 1);
        v[0] += r0.x; v[1] += r0.y; v[2] += r0.z; v[3] += r0.w;
        v[4] += r1.x; v[5] += r1.y; v[6] += r1.z; v[7] += r1.w;
    }
    #pragma unroll
    for (int j = 0; j < 8; ++j) v[j] = (v[j] > 0.f) ? v[j] : expm1f(v[j]);
    float4 o0 = make_float4(v[0], v[1], v[2], v[3]);
    float4 o1 = make_float4(v[4], v[5], v[6], v[7]);
    float4* op = reinterpret_cast<float4*>(out + (size_t)gw * 256 + c0);
    op[0] = o0; op[1] = o1;
}

// ---------------- aggregation, layer 2 ----------------
__global__ __launch_bounds__(256) void k_agg_l2(
    const float* __restrict__ z, const float* __restrict__ el,
    const float* __restrict__ er, const float* __restrict__ bias,
    const float* __restrict__ res, float* __restrict__ logits, int n)
{
    __shared__ float sout[8][240];
    int wInB = threadIdx.x >> 5;
    int gw = blockIdx.x * 8 + wInB;
    int lane = threadIdx.x & 31;
    bool act = (lane < 30);
    if (gw < n) {
        int beg = g_rowstart[gw], end = g_rowstart[gw + 1];
        float erh = (lane < 6) ? __ldg(&er[gw * 6 + lane]) : 0.f;
        int h = act ? (lane / 5) : 0;
        int c0 = lane * 8;
        float4 acc0 = make_float4(0.f, 0.f, 0.f, 0.f), acc1 = acc0;
        float denom = 0.f;
        for (int i = beg; i < end; ++i) {
            int s = __ldg(&g_srcs[i]);
            float w = 0.f;
            if (lane < 6) {
                float e = __ldg(&el[s * 6 + lane]) + erh;
                e = (e > 0.f) ? e : 0.2f * e;
                w = __expf(e);
                denom += w;
            }
            float wh = __shfl_sync(0xffffffffu, w, h);
            if (act) {
                const float4* zp = reinterpret_cast<const float4*>(z + (size_t)s * 240 + c0);
                float4 a = __ldg(zp), b = __ldg(zp + 1);
                acc0.x = fmaf(wh, a.x, acc0.x); acc0.y = fmaf(wh, a.y, acc0.y);
                acc0.z = fmaf(wh, a.z, acc0.z); acc0.w = fmaf(wh, a.w, acc0.w);
                acc1.x = fmaf(wh, b.x, acc1.x); acc1.y = fmaf(wh, b.y, acc1.y);
                acc1.z = fmaf(wh, b.z, acc1.z); acc1.w = fmaf(wh, b.w, acc1.w);
            }
        }
        float dh = __shfl_sync(0xffffffffu, denom, h);
        if (act) {
            float inv = 1.f / dh;
            const float4* bp = reinterpret_cast<const float4*>(bias + c0);
            const float4* rp = reinterpret_cast<const float4*>(res + (size_t)gw * 240 + c0);
            float4 b0 = __ldg(bp), b1 = __ldg(bp + 1);
            float4 r0 = __ldg(rp), r1 = __ldg(rp + 1);
            sout[wInB][c0 + 0] = fmaf(acc0.x, inv, b0.x) + r0.x;
            sout[wInB][c0 + 1] = fmaf(acc0.y, inv, b0.y) + r0.y;
            sout[wInB][c0 + 2] = fmaf(acc0.z, inv, b0.z) + r0.z;
            sout[wInB][c0 + 3] = fmaf(acc0.w, inv, b0.w) + r0.w;
            sout[wInB][c0 + 4] = fmaf(acc1.x, inv, b1.x) + r1.x;
            sout[wInB][c0 + 5] = fmaf(acc1.y, inv, b1.y) + r1.y;
            sout[wInB][c0 + 6] = fmaf(acc1.z, inv, b1.z) + r1.z;
            sout[wInB][c0 + 7] = fmaf(acc1.w, inv, b1.w) + r1.w;
        }
    }
    __syncwarp();
    if (gw < n) {
        for (int d = lane; d < 40; d += 32) {
            float s_ = 0.f;
            #pragma unroll
            for (int hh = 0; hh < 6; ++hh) s_ += sout[wInB][hh * 40 + d];
            logits[(size_t)gw * 40 + d] = s_ * (1.0f / 6.0f);
        }
    }
}

// ---------------- host ----------------
extern "C" void kernel_launch(void* const* d_in, const int* in_sizes, int n_in,
                              void* d_out, int out_size)
{
    const float* feat  = (const float*)d_in[0];
    const int*   src   = (const int*)d_in[1];
    const int*   dst   = (const int*)d_in[2];
    const float* W0    = (const float*)d_in[3];
    const float* al0   = (const float*)d_in[4];
    const float* ar0   = (const float*)d_in[5];
    const float* b0    = (const float*)d_in[6];
    const float* W1    = (const float*)d_in[7];
    const float* al1   = (const float*)d_in[8];
    const float* ar1   = (const float*)d_in[9];
    const float* b1    = (const float*)d_in[10];
    const float* W2    = (const float*)d_in[11];
    const float* al2   = (const float*)d_in[12];
    const float* ar2   = (const float*)d_in[13];
    const float* b2    = (const float*)d_in[14];
    const float* resW2 = (const float*)d_in[15];

    const int n = NNODES;
    const int E = in_sizes[1];

    float* logits = (float*)d_out;
    float* h1     = (float*)d_out + n * 40;

    float *pz, *ph0, *pr2, *pel, *per;
    __nv_bfloat16 *pAh, *pAl, *pBh, *pBl;
    cudaGetSymbolAddress((void**)&pz,  g_z);
    cudaGetSymbolAddress((void**)&ph0, g_h0);
    cudaGetSymbolAddress((void**)&pr2, g_r2);
    cudaGetSymbolAddress((void**)&pel, g_el);
    cudaGetSymbolAddress((void**)&per, g_er);
    cudaGetSymbolAddress((void**)&pAh, g_Ahi);
    cudaGetSymbolAddress((void**)&pAl, g_Alo);
    cudaGetSymbolAddress((void**)&pBh, g_Bth);
    cudaGetSymbolAddress((void**)&pBl, g_Btl);

    cudaFuncSetAttribute(k_gemm_mma, cudaFuncAttributeMaxDynamicSharedMemorySize, GEMM_SMEM);

    // ---- CSR by destination ----
    k_zero_deg<<<(n + 255) / 256, 256>>>(n);
    k_hist<<<(E + 255) / 256, 256>>>(dst, E);
    k_scan<<<1, 1024>>>(n, E);
    k_scatter<<<(E + 255) / 256, 256>>>(src, dst, E);

    const int n4 = n * 64;
    const int splitBlocks = (n4 + 255) / 256;
    dim3 gemmGrid(4, (n + 127) / 128);
    const int elrBlocks4 = (n * 4 + 255) / 256;
    const int elrBlocks6 = (n * 6 + 255) / 256;
    const int aggBlocks  = (n + 7) / 8;

    // ---- Layer 0 ----
    k_splitA<<<splitBlocks, 256>>>(feat, pAh, pAl, n4);
    k_splitBt<<<256, 256>>>(W0, pBh, pBl, 256);
    k_gemm_mma<<<gemmGrid, 256, GEMM_SMEM>>>(pAh, pAl, pBh, pBl, pz, n, 256);
    k_elr<<<elrBlocks4, 256>>>(pz, al0, ar0, pel, per, n, 4, 64);
    k_agg256<false><<<aggBlocks, 256>>>(pz, pel, per, b0, nullptr, ph0, n);

    // ---- Layer 1 ----
    k_splitA<<<splitBlocks, 256>>>(ph0, pAh, pAl, n4);
    k_splitBt<<<256, 256>>>(W1, pBh, pBl, 256);
    k_gemm_mma<<<gemmGrid, 256, GEMM_SMEM>>>(pAh, pAl, pBh, pBl, pz, n, 256);
    k_elr<<<elrBlocks4, 256>>>(pz, al1, ar1, pel, per, n, 4, 64);
    k_agg256<true><<<aggBlocks, 256>>>(pz, pel, per, b1, ph0, h1, n);

    // ---- Layer 2 ----
    k_splitA<<<splitBlocks, 256>>>(h1, pAh, pAl, n4);
    k_splitBt<<<256, 256>>>(W2, pBh, pBl, 240);
    k_gemm_mma<<<gemmGrid, 256, GEMM_SMEM>>>(pAh, pAl, pBh, pBl, pz, n, 240);
    k_splitBt<<<256, 256>>>(resW2, pBh, pBl, 240);
    k_gemm_mma<<<gemmGrid, 256, GEMM_SMEM>>>(pAh, pAl, pBh, pBl, pr2, n, 240);
    k_elr<<<elrBlocks6, 256>>>(pz, al2, ar2, pel, per, n, 6, 40);
    k_agg_l2<<<aggBlocks, 256>>>(pz, pel, per, b2, pr2, logits, n);
}

// round 4
// speedup vs baseline: 1.9643x; 1.1150x over previous
#include <cuda_runtime.h>
#include <cuda_bf16.h>
#include <math.h>
#include <cstdint>

// ---------------- problem constants ----------------
#define NNODES 50000
#define ECAP   1000000

// ---------------- device scratch (static; no allocations) ----------------
__device__ float g_z[NNODES * 256];
__device__ float g_h0[NNODES * 256];
__device__ float g_r2[NNODES * 240];
__device__ float g_el[NNODES * 6];
__device__ float g_er[NNODES * 6];
__device__ int   g_deg[NNODES];
__device__ int   g_rowstart[NNODES + 1];
__device__ int   g_cursor[NNODES];
__device__ int   g_srcs[ECAP];
__device__ __align__(16) __nv_bfloat16 g_Ahi[NNODES * 256];
__device__ __align__(16) __nv_bfloat16 g_Alo[NNODES * 256];
__device__ __align__(16) __nv_bfloat16 g_Bth[256 * 256];   // [N(pad 256), K=256]
__device__ __align__(16) __nv_bfloat16 g_Btl[256 * 256];

// ================= PTX helpers =================
__device__ __forceinline__ uint32_t smem_u32(const void* p) {
    uint32_t a;
    asm("{ .reg .u64 t; cvta.to.shared.u64 t, %1; cvt.u32.u64 %0, t; }" : "=r"(a) : "l"(p));
    return a;
}
__device__ __forceinline__ void cp16(uint32_t dst, const void* src, uint32_t srcsize) {
    asm volatile("cp.async.cg.shared.global [%0], [%1], 16, %2;"
                 :: "r"(dst), "l"(src), "r"(srcsize));
}
#define CP_COMMIT() asm volatile("cp.async.commit_group;" ::: "memory")
#define CP_WAIT(n)  asm volatile("cp.async.wait_group %0;" :: "n"(n) : "memory")
#define LDSM_X4(r0, r1, r2, r3, addr) \
    asm volatile("ldmatrix.sync.aligned.m8n8.x4.shared.b16 {%0,%1,%2,%3}, [%4];" \
        : "=r"(r0), "=r"(r1), "=r"(r2), "=r"(r3) : "r"(addr))
#define MMA_BF16(acc, a, b) \
    asm volatile("mma.sync.aligned.m16n8k16.row.col.f32.bf16.bf16.f32 " \
        "{%0,%1,%2,%3}, {%4,%5,%6,%7}, {%8,%9}, {%0,%1,%2,%3};" \
        : "+f"((acc)[0]), "+f"((acc)[1]), "+f"((acc)[2]), "+f"((acc)[3]) \
        : "r"((a)[0]), "r"((a)[1]), "r"((a)[2]), "r"((a)[3]), "r"((b)[0]), "r"((b)[1]))

// ---------------- CSR build ----------------
__global__ void k_zero_deg(int n) {
    int i = blockIdx.x * blockDim.x + threadIdx.x;
    if (i < n) g_deg[i] = 0;
}
__global__ void k_hist(const int* __restrict__ dst, int E) {
    int e = blockIdx.x * blockDim.x + threadIdx.x;
    if (e < E) atomicAdd(&g_deg[dst[e]], 1);
}
// warp-shuffle blocked scan, single block of 1024
__global__ void k_scan(int n, int E) {
    __shared__ int wsum[32];
    __shared__ int carry;
    int lane = threadIdx.x & 31, w = threadIdx.x >> 5;
    if (threadIdx.x == 0) carry = 0;
    __syncthreads();
    for (int base = 0; base < n; base += 1024) {
        int i = base + threadIdx.x;
        int v = (i < n) ? g_deg[i] : 0;
        int x = v;
        #pragma unroll
        for (int off = 1; off < 32; off <<= 1) {
            int t = __shfl_up_sync(0xffffffffu, x, off);
            if (lane >= off) x += t;
        }
        if (lane == 31) wsum[w] = x;
        __syncthreads();
        if (w == 0) {
            int y = wsum[lane];
            #pragma unroll
            for (int off = 1; off < 32; off <<= 1) {
                int t = __shfl_up_sync(0xffffffffu, y, off);
                if (lane >= off) y += t;
            }
            wsum[lane] = y;
        }
        __syncthreads();
        int incl = x + (w ? wsum[w - 1] : 0) + carry;
        int excl = incl - v;
        if (i < n) { g_rowstart[i] = excl; g_cursor[i] = excl; }
        __syncthreads();
        if (threadIdx.x == 1023) carry = incl;
        __syncthreads();
    }
    if (threadIdx.x == 0) g_rowstart[n] = E;
}
__global__ void k_scatter(const int* __restrict__ src, const int* __restrict__ dst, int E) {
    int e = blockIdx.x * blockDim.x + threadIdx.x;
    if (e < E) {
        int p = atomicAdd(&g_cursor[dst[e]], 1);
        g_srcs[p] = src[e];
    }
}

// ---------------- fp32 -> bf16 hi/lo split (only needed for feat) ----------------
__global__ void k_splitA(const float* __restrict__ A, __nv_bfloat16* __restrict__ hi,
                         __nv_bfloat16* __restrict__ lo, int n4) {
    int i = blockIdx.x * blockDim.x + threadIdx.x;
    if (i >= n4) return;
    float4 v = reinterpret_cast<const float4*>(A)[i];
    __nv_bfloat16 h0 = __float2bfloat16_rn(v.x);
    __nv_bfloat16 h1 = __float2bfloat16_rn(v.y);
    __nv_bfloat16 h2 = __float2bfloat16_rn(v.z);
    __nv_bfloat16 h3 = __float2bfloat16_rn(v.w);
    __nv_bfloat16 l0 = __float2bfloat16_rn(v.x - __bfloat162float(h0));
    __nv_bfloat16 l1 = __float2bfloat16_rn(v.y - __bfloat162float(h1));
    __nv_bfloat16 l2 = __float2bfloat16_rn(v.z - __bfloat162float(h2));
    __nv_bfloat16 l3 = __float2bfloat16_rn(v.w - __bfloat162float(h3));
    reinterpret_cast<ushort4*>(hi)[i] = make_ushort4(
        __bfloat16_as_ushort(h0), __bfloat16_as_ushort(h1),
        __bfloat16_as_ushort(h2), __bfloat16_as_ushort(h3));
    reinterpret_cast<ushort4*>(lo)[i] = make_ushort4(
        __bfloat16_as_ushort(l0), __bfloat16_as_ushort(l1),
        __bfloat16_as_ushort(l2), __bfloat16_as_ushort(l3));
}

// B [K=256, Nn] fp32 -> Bt hi/lo [256(N, zero-padded), 256(K)] bf16
__global__ void k_splitBt(const float* __restrict__ B, __nv_bfloat16* __restrict__ th,
                          __nv_bfloat16* __restrict__ tl, int Nn) {
    int t = blockIdx.x * blockDim.x + threadIdx.x;
    if (t >= 256 * 256) return;
    int nrow = t >> 8, k = t & 255;
    float x = (nrow < Nn) ? B[(size_t)k * Nn + nrow] : 0.f;
    __nv_bfloat16 h = __float2bfloat16_rn(x);
    th[t] = h;
    tl[t] = __float2bfloat16_rn(x - __bfloat162float(h));
}

// ---------------- mma.sync split-bf16 GEMM: C[M,Nn] = A[M,256] * B[256,Nn] ----------------
// CTA tile 128(M) x 128(N), BK=64, 512 threads, 16 warps (4x4), warp tile 32x32.
// Smem per stage: Ahi 16K | Alo 16K | Bhi 16K | Blo 16K = 64K; double buffered = 128K.
#define STAGE_BYTES 65536
#define GEMM_SMEM   (2 * STAGE_BYTES)

__device__ __forceinline__ void gemm_load_stage(
    uint32_t sb, const __nv_bfloat16* __restrict__ Ahi, const __nv_bfloat16* __restrict__ Alo,
    const __nv_bfloat16* __restrict__ Bth, const __nv_bfloat16* __restrict__ Btl,
    int m0, int n0, int M, int kb, int tid)
{
    // A: 128 rows x 8 chunks(16B) x 2 precisions = 2048 chunks
    #pragma unroll
    for (int it = 0; it < 4; ++it) {
        int idx = tid + it * 512;
        int prec = idx >> 10, rem = idx & 1023;
        int row = rem >> 3, ch = rem & 7;
        uint32_t dst = sb + prec * 16384 + row * 128 + (((uint32_t)(ch ^ (row & 7))) << 4);
        const __nv_bfloat16* srcb = prec ? Alo : Ahi;
        const __nv_bfloat16* src = srcb + (size_t)(m0 + row) * 256 + kb * 64 + ch * 8;
        cp16(dst, src, (m0 + row) < M ? 16u : 0u);
    }
    // B: 128 rows x 8 chunks x 2 precisions = 2048 chunks
    #pragma unroll
    for (int it = 0; it < 4; ++it) {
        int idx = tid + it * 512;
        int prec = idx >> 10, rem = idx & 1023;
        int row = rem >> 3, ch = rem & 7;
        uint32_t dst = sb + 32768 + prec * 16384 + row * 128 + (((uint32_t)(ch ^ (row & 7))) << 4);
        const __nv_bfloat16* srcb = prec ? Btl : Bth;
        const __nv_bfloat16* src = srcb + (size_t)(n0 + row) * 256 + kb * 64 + ch * 8;
        cp16(dst, src, 16u);
    }
}

__global__ __launch_bounds__(512, 1) void k_gemm_mma(
    const __nv_bfloat16* __restrict__ Ahi, const __nv_bfloat16* __restrict__ Alo,
    const __nv_bfloat16* __restrict__ Bth, const __nv_bfloat16* __restrict__ Btl,
    float* __restrict__ C, int M, int Nn)
{
    extern __shared__ char smem[];
    const uint32_t sbase = smem_u32(smem);
    const int tid = threadIdx.x, wid = tid >> 5, lane = tid & 31;
    const int warp_m = wid & 3, warp_n = wid >> 2;
    const int m0 = blockIdx.y * 128;
    const int n0 = blockIdx.x * 128;

    float acc[2][4][4];
    #pragma unroll
    for (int mt = 0; mt < 2; ++mt)
        #pragma unroll
        for (int nt = 0; nt < 4; ++nt)
            #pragma unroll
            for (int q = 0; q < 4; ++q) acc[mt][nt][q] = 0.f;

    const int rowA = warp_m * 32 + (lane & 15);
    const int rowB = warp_n * 32 + (lane & 7) + ((lane >> 4) << 3);
    const uint32_t rowAswz = (uint32_t)(rowA & 7);
    const uint32_t rowBswz = (uint32_t)(rowB & 7);
    const int halfA = lane >> 4;
    const int halfB = (lane >> 3) & 1;

    gemm_load_stage(sbase, Ahi, Alo, Bth, Btl, m0, n0, M, 0, tid);
    CP_COMMIT();

    #pragma unroll 1
    for (int kb = 0; kb < 4; ++kb) {
        if (kb < 3) {
            gemm_load_stage(sbase + ((kb + 1) & 1) * STAGE_BYTES,
                            Ahi, Alo, Bth, Btl, m0, n0, M, kb + 1, tid);
            CP_COMMIT();
            CP_WAIT(1);
        } else {
            CP_WAIT(0);
        }
        __syncthreads();

        const uint32_t sb = sbase + (kb & 1) * STAGE_BYTES;
        #pragma unroll
        for (int s = 0; s < 4; ++s) {
            uint32_t a[2][2][4];
            uint32_t b[2][4][2];
            const uint32_t offA = (((uint32_t)(s * 2 + halfA) ^ rowAswz) << 4);
            const uint32_t offB = (((uint32_t)(s * 2 + halfB) ^ rowBswz) << 4);
            #pragma unroll
            for (int prec = 0; prec < 2; ++prec) {
                uint32_t baseA = sb + prec * 16384;
                #pragma unroll
                for (int mt = 0; mt < 2; ++mt) {
                    uint32_t addr = baseA + (uint32_t)(rowA + mt * 16) * 128 + offA;
                    LDSM_X4(a[prec][mt][0], a[prec][mt][1], a[prec][mt][2], a[prec][mt][3], addr);
                }
                uint32_t baseB = sb + 32768 + prec * 16384;
                #pragma unroll
                for (int ntp = 0; ntp < 2; ++ntp) {
                    uint32_t addr = baseB + (uint32_t)(rowB + ntp * 16) * 128 + offB;
                    LDSM_X4(b[prec][2 * ntp][0], b[prec][2 * ntp][1],
                            b[prec][2 * ntp + 1][0], b[prec][2 * ntp + 1][1], addr);
                }
            }
            #pragma unroll
            for (int mt = 0; mt < 2; ++mt)
                #pragma unroll
                for (int nt = 0; nt < 4; ++nt) {
                    MMA_BF16(acc[mt][nt], a[0][mt], b[0][nt]);  // hi*hi
                    MMA_BF16(acc[mt][nt], a[0][mt], b[1][nt]);  // hi*lo
                    MMA_BF16(acc[mt][nt], a[1][mt], b[0][nt]);  // lo*hi
                }
        }
        __syncthreads();
    }

    #pragma unroll
    for (int mt = 0; mt < 2; ++mt) {
        int row = m0 + warp_m * 32 + mt * 16 + (lane >> 2);
        #pragma unroll
        for (int nt = 0; nt < 4; ++nt) {
            int col = n0 + warp_n * 32 + nt * 8 + (lane & 3) * 2;
            if (col < Nn) {
                if (row < M)
                    *reinterpret_cast<float2*>(C + (size_t)row * Nn + col) =
                        make_float2(acc[mt][nt][0], acc[mt][nt][1]);
                if (row + 8 < M)
                    *reinterpret_cast<float2*>(C + (size_t)(row + 8) * Nn + col) =
                        make_float2(acc[mt][nt][2], acc[mt][nt][3]);
            }
        }
    }
}

// ---------------- el/er projections ----------------
__global__ void k_elr(const float* __restrict__ z, const float* __restrict__ al,
                      const float* __restrict__ ar, float* __restrict__ el,
                      float* __restrict__ er, int n, int H, int D)
{
    int t = blockIdx.x * blockDim.x + threadIdx.x;
    if (t >= n * H) return;
    int node = t / H, h = t - node * H;
    const float4* zr  = reinterpret_cast<const float4*>(z + (size_t)node * H * D + h * D);
    const float4* alr = reinterpret_cast<const float4*>(al + h * D);
    const float4* arr = reinterpret_cast<const float4*>(ar + h * D);
    float sl = 0.f, sr = 0.f;
    int d4 = D >> 2;
    for (int i = 0; i < d4; ++i) {
        float4 zv = __ldg(&zr[i]);
        float4 av = __ldg(&alr[i]);
        float4 bv = __ldg(&arr[i]);
        sl = fmaf(zv.x, av.x, sl); sl = fmaf(zv.y, av.y, sl);
        sl = fmaf(zv.z, av.z, sl); sl = fmaf(zv.w, av.w, sl);
        sr = fmaf(zv.x, bv.x, sr); sr = fmaf(zv.y, bv.y, sr);
        sr = fmaf(zv.z, bv.z, sr); sr = fmaf(zv.w, bv.w, sr);
    }
    el[t] = sl;
    er[t] = sr;
}

// ---------------- aggregation, layers 0/1 (fused bf16 hi/lo split on output) ----------------
template <bool RES>
__global__ __launch_bounds__(256) void k_agg256(
    const float* __restrict__ z, const float* __restrict__ el,
    const float* __restrict__ er, const float* __restrict__ bias,
    const float* __restrict__ xres, float* __restrict__ out,
    __nv_bfloat16* __restrict__ ohi, __nv_bfloat16* __restrict__ olo, int n)
{
    int gw = (blockIdx.x * blockDim.x + threadIdx.x) >> 5;
    if (gw >= n) return;
    int lane = threadIdx.x & 31;
    int beg = g_rowstart[gw], end = g_rowstart[gw + 1];
    float erh = (lane < 4) ? __ldg(&er[gw * 4 + lane]) : 0.f;
    int h = lane >> 3;
    int c0 = lane * 8;
    float4 acc0 = make_float4(0.f, 0.f, 0.f, 0.f), acc1 = acc0;
    float denom = 0.f;
    for (int i = beg; i < end; ++i) {
        int s = __ldg(&g_srcs[i]);
        float w = 0.f;
        if (lane < 4) {
            float e = __ldg(&el[s * 4 + lane]) + erh;
            e = (e > 0.f) ? e : 0.2f * e;
            w = __expf(e);
            denom += w;
        }
        float wh = __shfl_sync(0xffffffffu, w, h);
        const float4* zp = reinterpret_cast<const float4*>(z + (size_t)s * 256 + c0);
        float4 a = __ldg(zp), b = __ldg(zp + 1);
        acc0.x = fmaf(wh, a.x, acc0.x); acc0.y = fmaf(wh, a.y, acc0.y);
        acc0.z = fmaf(wh, a.z, acc0.z); acc0.w = fmaf(wh, a.w, acc0.w);
        acc1.x = fmaf(wh, b.x, acc1.x); acc1.y = fmaf(wh, b.y, acc1.y);
        acc1.z = fmaf(wh, b.z, acc1.z); acc1.w = fmaf(wh, b.w, acc1.w);
    }
    float dh = __shfl_sync(0xffffffffu, denom, h);
    float inv = 1.f / dh;
    const float4* bp = reinterpret_cast<const float4*>(bias + c0);
    float4 b0 = __ldg(bp), b1 = __ldg(bp + 1);
    float v[8];
    v[0] = fmaf(acc0.x, inv, b0.x); v[1] = fmaf(acc0.y, inv, b0.y);
    v[2] = fmaf(acc0.z, inv, b0.z); v[3] = fmaf(acc0.w, inv, b0.w);
    v[4] = fmaf(acc1.x, inv, b1.x); v[5] = fmaf(acc1.y, inv, b1.y);
    v[6] = fmaf(acc1.z, inv, b1.z); v[7] = fmaf(acc1.w, inv, b1.w);
    if (RES) {
        const float4* rp = reinterpret_cast<const float4*>(xres + (size_t)gw * 256 + c0);
        float4 r0 = __ldg(rp), r1 = __ldg(rp + 1);
        v[0] += r0.x; v[1] += r0.y; v[2] += r0.z; v[3] += r0.w;
        v[4] += r1.x; v[5] += r1.y; v[6] += r1.z; v[7] += r1.w;
    }
    #pragma unroll
    for (int j = 0; j < 8; ++j) v[j] = (v[j] > 0.f) ? v[j] : expm1f(v[j]);
    float4 o0 = make_float4(v[0], v[1], v[2], v[3]);
    float4 o1 = make_float4(v[4], v[5], v[6], v[7]);
    float4* op = reinterpret_cast<float4*>(out + (size_t)gw * 256 + c0);
    op[0] = o0; op[1] = o1;
    // fused hi/lo bf16 split (input for next layer's GEMM)
    ushort hi[8], lo[8];
    #pragma unroll
    for (int j = 0; j < 8; ++j) {
        __nv_bfloat16 hh = __float2bfloat16_rn(v[j]);
        hi[j] = __bfloat16_as_ushort(hh);
        lo[j] = __bfloat16_as_ushort(__float2bfloat16_rn(v[j] - __bfloat162float(hh)));
    }
    ushort4* hp = reinterpret_cast<ushort4*>(ohi + (size_t)gw * 256 + c0);
    ushort4* lp = reinterpret_cast<ushort4*>(olo + (size_t)gw * 256 + c0);
    hp[0] = make_ushort4(hi[0], hi[1], hi[2], hi[3]);
    hp[1] = make_ushort4(hi[4], hi[5], hi[6], hi[7]);
    lp[0] = make_ushort4(lo[0], lo[1], lo[2], lo[3]);
    lp[1] = make_ushort4(lo[4], lo[5], lo[6], lo[7]);
}

// ---------------- aggregation, layer 2 ----------------
__global__ __launch_bounds__(256) void k_agg_l2(
    const float* __restrict__ z, const float* __restrict__ el,
    const float* __restrict__ er, const float* __restrict__ bias,
    const float* __restrict__ res, float* __restrict__ logits, int n)
{
    __shared__ float sout[8][240];
    int wInB = threadIdx.x >> 5;
    int gw = blockIdx.x * 8 + wInB;
    int lane = threadIdx.x & 31;
    bool act = (lane < 30);
    if (gw < n) {
        int beg = g_rowstart[gw], end = g_rowstart[gw + 1];
        float erh = (lane < 6) ? __ldg(&er[gw * 6 + lane]) : 0.f;
        int h = act ? (lane / 5) : 0;
        int c0 = lane * 8;
        float4 acc0 = make_float4(0.f, 0.f, 0.f, 0.f), acc1 = acc0;
        float denom = 0.f;
        for (int i = beg; i < end; ++i) {
            int s = __ldg(&g_srcs[i]);
            float w = 0.f;
            if (lane < 6) {
                float e = __ldg(&el[s * 6 + lane]) + erh;
                e = (e > 0.f) ? e : 0.2f * e;
                w = __expf(e);
                denom += w;
            }
            float wh = __shfl_sync(0xffffffffu, w, h);
            if (act) {
                const float4* zp = reinterpret_cast<const float4*>(z + (size_t)s * 240 + c0);
                float4 a = __ldg(zp), b = __ldg(zp + 1);
                acc0.x = fmaf(wh, a.x, acc0.x); acc0.y = fmaf(wh, a.y, acc0.y);
                acc0.z = fmaf(wh, a.z, acc0.z); acc0.w = fmaf(wh, a.w, acc0.w);
                acc1.x = fmaf(wh, b.x, acc1.x); acc1.y = fmaf(wh, b.y, acc1.y);
                acc1.z = fmaf(wh, b.z, acc1.z); acc1.w = fmaf(wh, b.w, acc1.w);
            }
        }
        float dh = __shfl_sync(0xffffffffu, denom, h);
        if (act) {
            float inv = 1.f / dh;
            const float4* bp = reinterpret_cast<const float4*>(bias + c0);
            const float4* rp = reinterpret_cast<const float4*>(res + (size_t)gw * 240 + c0);
            float4 b0 = __ldg(bp), b1 = __ldg(bp + 1);
            float4 r0 = __ldg(rp), r1 = __ldg(rp + 1);
            sout[wInB][c0 + 0] = fmaf(acc0.x, inv, b0.x) + r0.x;
            sout[wInB][c0 + 1] = fmaf(acc0.y, inv, b0.y) + r0.y;
            sout[wInB][c0 + 2] = fmaf(acc0.z, inv, b0.z) + r0.z;
            sout[wInB][c0 + 3] = fmaf(acc0.w, inv, b0.w) + r0.w;
            sout[wInB][c0 + 4] = fmaf(acc1.x, inv, b1.x) + r1.x;
            sout[wInB][c0 + 5] = fmaf(acc1.y, inv, b1.y) + r1.y;
            sout[wInB][c0 + 6] = fmaf(acc1.z, inv, b1.z) + r1.z;
            sout[wInB][c0 + 7] = fmaf(acc1.w, inv, b1.w) + r1.w;
        }
    }
    __syncwarp();
    if (gw < n) {
        for (int d = lane; d < 40; d += 32) {
            float s_ = 0.f;
            #pragma unroll
            for (int hh = 0; hh < 6; ++hh) s_ += sout[wInB][hh * 40 + d];
            logits[(size_t)gw * 40 + d] = s_ * (1.0f / 6.0f);
        }
    }
}

// ---------------- host ----------------
extern "C" void kernel_launch(void* const* d_in, const int* in_sizes, int n_in,
                              void* d_out, int out_size)
{
    const float* feat  = (const float*)d_in[0];
    const int*   src   = (const int*)d_in[1];
    const int*   dst   = (const int*)d_in[2];
    const float* W0    = (const float*)d_in[3];
    const float* al0   = (const float*)d_in[4];
    const float* ar0   = (const float*)d_in[5];
    const float* b0    = (const float*)d_in[6];
    const float* W1    = (const float*)d_in[7];
    const float* al1   = (const float*)d_in[8];
    const float* ar1   = (const float*)d_in[9];
    const float* b1    = (const float*)d_in[10];
    const float* W2    = (const float*)d_in[11];
    const float* al2   = (const float*)d_in[12];
    const float* ar2   = (const float*)d_in[13];
    const float* b2    = (const float*)d_in[14];
    const float* resW2 = (const float*)d_in[15];

    const int n = NNODES;
    const int E = in_sizes[1];

    float* logits = (float*)d_out;
    float* h1     = (float*)d_out + n * 40;

    float *pz, *ph0, *pr2, *pel, *per;
    __nv_bfloat16 *pAh, *pAl, *pBh, *pBl;
    cudaGetSymbolAddress((void**)&pz,  g_z);
    cudaGetSymbolAddress((void**)&ph0, g_h0);
    cudaGetSymbolAddress((void**)&pr2, g_r2);
    cudaGetSymbolAddress((void**)&pel, g_el);
    cudaGetSymbolAddress((void**)&per, g_er);
    cudaGetSymbolAddress((void**)&pAh, g_Ahi);
    cudaGetSymbolAddress((void**)&pAl, g_Alo);
    cudaGetSymbolAddress((void**)&pBh, g_Bth);
    cudaGetSymbolAddress((void**)&pBl, g_Btl);

    cudaFuncSetAttribute(k_gemm_mma, cudaFuncAttributeMaxDynamicSharedMemorySize, GEMM_SMEM);

    // ---- CSR by destination ----
    k_zero_deg<<<(n + 255) / 256, 256>>>(n);
    k_hist<<<(E + 255) / 256, 256>>>(dst, E);
    k_scan<<<1, 1024>>>(n, E);
    k_scatter<<<(E + 255) / 256, 256>>>(src, dst, E);

    const int n4 = n * 64;
    const int splitBlocks = (n4 + 255) / 256;
    dim3 gemmGrid(2, (n + 127) / 128);
    const int elrBlocks4 = (n * 4 + 255) / 256;
    const int elrBlocks6 = (n * 6 + 255) / 256;
    const int aggBlocks  = (n + 7) / 8;

    // ---- Layer 0 ----
    k_splitA<<<splitBlocks, 256>>>(feat, pAh, pAl, n4);
    k_splitBt<<<256, 256>>>(W0, pBh, pBl, 256);
    k_gemm_mma<<<gemmGrid, 512, GEMM_SMEM>>>(pAh, pAl, pBh, pBl, pz, n, 256);
    k_elr<<<elrBlocks4, 256>>>(pz, al0, ar0, pel, per, n, 4, 64);
    k_agg256<false><<<aggBlocks, 256>>>(pz, pel, per, b0, nullptr, ph0, pAh, pAl, n);

    // ---- Layer 1 ----
    k_splitBt<<<256, 256>>>(W1, pBh, pBl, 256);
    k_gemm_mma<<<gemmGrid, 512, GEMM_SMEM>>>(pAh, pAl, pBh, pBl, pz, n, 256);
    k_elr<<<elrBlocks4, 256>>>(pz, al1, ar1, pel, per, n, 4, 64);
    k_agg256<true><<<aggBlocks, 256>>>(pz, pel, per, b1, ph0, h1, pAh, pAl, n);

    // ---- Layer 2 ----
    k_splitBt<<<256, 256>>>(W2, pBh, pBl, 240);
    k_gemm_mma<<<gemmGrid, 512, GEMM_SMEM>>>(pAh, pAl, pBh, pBl, pz, n, 240);
    k_splitBt<<<256, 256>>>(resW2, pBh, pBl, 240);
    k_gemm_mma<<<gemmGrid, 512, GEMM_SMEM>>>(pAh, pAl, pBh, pBl, pr2, n, 240);
    k_elr<<<elrBlocks6, 256>>>(pz, al2, ar2, pel, per, n, 6, 40);
    k_agg_l2<<<aggBlocks, 256>>>(pz, pel, per, b2, pr2, logits, n);
}

// round 5
// speedup vs baseline: 2.1071x; 1.0727x over previous
#include <cuda_runtime.h>
#include <cuda_bf16.h>
#include <cuda_fp16.h>
#include <math.h>
#include <cstdint>

// ---------------- problem constants ----------------
#define NNODES 50000
#define ECAP   1000000

// ---------------- device scratch (static; no allocations) ----------------
__device__ __align__(16) __half g_zh[NNODES * 256];   // fp16 z (GEMM out, agg in)
__device__ float g_h0[NNODES * 256];
__device__ float g_r2[NNODES * 240];
__device__ float g_el[NNODES * 6];
__device__ float g_er[NNODES * 6];
__device__ int   g_deg[NNODES];
__device__ int   g_rowstart[NNODES + 1];
__device__ int   g_cursor[NNODES];
__device__ int   g_srcs[ECAP];
__device__ __align__(16) __nv_bfloat16 g_Ahi[NNODES * 256];
__device__ __align__(16) __nv_bfloat16 g_Alo[NNODES * 256];
__device__ __align__(16) __nv_bfloat16 g_Bth[256 * 256];   // [N(pad 256), K=256]
__device__ __align__(16) __nv_bfloat16 g_Btl[256 * 256];

// ================= PTX helpers =================
__device__ __forceinline__ uint32_t smem_u32(const void* p) {
    uint32_t a;
    asm("{ .reg .u64 t; cvta.to.shared.u64 t, %1; cvt.u32.u64 %0, t; }" : "=r"(a) : "l"(p));
    return a;
}
__device__ __forceinline__ void cp16(uint32_t dst, const void* src, uint32_t srcsize) {
    asm volatile("cp.async.cg.shared.global [%0], [%1], 16, %2;"
                 :: "r"(dst), "l"(src), "r"(srcsize));
}
#define CP_COMMIT() asm volatile("cp.async.commit_group;" ::: "memory")
#define CP_WAIT(n)  asm volatile("cp.async.wait_group %0;" :: "n"(n) : "memory")
#define LDSM_X4(r0, r1, r2, r3, addr) \
    asm volatile("ldmatrix.sync.aligned.m8n8.x4.shared.b16 {%0,%1,%2,%3}, [%4];" \
        : "=r"(r0), "=r"(r1), "=r"(r2), "=r"(r3) : "r"(addr))
#define MMA_BF16(acc, a, b) \
    asm volatile("mma.sync.aligned.m16n8k16.row.col.f32.bf16.bf16.f32 " \
        "{%0,%1,%2,%3}, {%4,%5,%6,%7}, {%8,%9}, {%0,%1,%2,%3};" \
        : "+f"((acc)[0]), "+f"((acc)[1]), "+f"((acc)[2]), "+f"((acc)[3]) \
        : "r"((a)[0]), "r"((a)[1]), "r"((a)[2]), "r"((a)[3]), "r"((b)[0]), "r"((b)[1]))

// ---------------- CSR build ----------------
__global__ void k_zero_deg(int n) {
    int i = blockIdx.x * blockDim.x + threadIdx.x;
    if (i < n) g_deg[i] = 0;
}
__global__ void k_zero_elr(int n6) {
    int i = blockIdx.x * blockDim.x + threadIdx.x;
    if (i < n6) { g_el[i] = 0.f; g_er[i] = 0.f; }
}
__global__ void k_hist(const int* __restrict__ dst, int E) {
    int e = blockIdx.x * blockDim.x + threadIdx.x;
    if (e < E) atomicAdd(&g_deg[dst[e]], 1);
}
__global__ void k_scan(int n, int E) {
    __shared__ int wsum[32];
    __shared__ int carry;
    int lane = threadIdx.x & 31, w = threadIdx.x >> 5;
    if (threadIdx.x == 0) carry = 0;
    __syncthreads();
    for (int base = 0; base < n; base += 1024) {
        int i = base + threadIdx.x;
        int v = (i < n) ? g_deg[i] : 0;
        int x = v;
        #pragma unroll
        for (int off = 1; off < 32; off <<= 1) {
            int t = __shfl_up_sync(0xffffffffu, x, off);
            if (lane >= off) x += t;
        }
        if (lane == 31) wsum[w] = x;
        __syncthreads();
        if (w == 0) {
            int y = wsum[lane];
            #pragma unroll
            for (int off = 1; off < 32; off <<= 1) {
                int t = __shfl_up_sync(0xffffffffu, y, off);
                if (lane >= off) y += t;
            }
            wsum[lane] = y;
        }
        __syncthreads();
        int incl = x + (w ? wsum[w - 1] : 0) + carry;
        int excl = incl - v;
        if (i < n) { g_rowstart[i] = excl; g_cursor[i] = excl; }
        __syncthreads();
        if (threadIdx.x == 1023) carry = incl;
        __syncthreads();
    }
    if (threadIdx.x == 0) g_rowstart[n] = E;
}
__global__ void k_scatter(const int* __restrict__ src, const int* __restrict__ dst, int E) {
    int e = blockIdx.x * blockDim.x + threadIdx.x;
    if (e < E) {
        int p = atomicAdd(&g_cursor[dst[e]], 1);
        g_srcs[p] = src[e];
    }
}

// ---------------- fp32 -> bf16 hi/lo split (feat only) ----------------
__global__ void k_splitA(const float* __restrict__ A, __nv_bfloat16* __restrict__ hi,
                         __nv_bfloat16* __restrict__ lo, int n4) {
    int i = blockIdx.x * blockDim.x + threadIdx.x;
    if (i >= n4) return;
    float4 v = reinterpret_cast<const float4*>(A)[i];
    __nv_bfloat16 h0 = __float2bfloat16_rn(v.x);
    __nv_bfloat16 h1 = __float2bfloat16_rn(v.y);
    __nv_bfloat16 h2 = __float2bfloat16_rn(v.z);
    __nv_bfloat16 h3 = __float2bfloat16_rn(v.w);
    __nv_bfloat16 l0 = __float2bfloat16_rn(v.x - __bfloat162float(h0));
    __nv_bfloat16 l1 = __float2bfloat16_rn(v.y - __bfloat162float(h1));
    __nv_bfloat16 l2 = __float2bfloat16_rn(v.z - __bfloat162float(h2));
    __nv_bfloat16 l3 = __float2bfloat16_rn(v.w - __bfloat162float(h3));
    reinterpret_cast<ushort4*>(hi)[i] = make_ushort4(
        __bfloat16_as_ushort(h0), __bfloat16_as_ushort(h1),
        __bfloat16_as_ushort(h2), __bfloat16_as_ushort(h3));
    reinterpret_cast<ushort4*>(lo)[i] = make_ushort4(
        __bfloat16_as_ushort(l0), __bfloat16_as_ushort(l1),
        __bfloat16_as_ushort(l2), __bfloat16_as_ushort(l3));
}

// B [K=256, Nn] fp32 -> Bt hi/lo [256(N, zero-padded), 256(K)] bf16
__global__ void k_splitBt(const float* __restrict__ B, __nv_bfloat16* __restrict__ th,
                          __nv_bfloat16* __restrict__ tl, int Nn) {
    int t = blockIdx.x * blockDim.x + threadIdx.x;
    if (t >= 256 * 256) return;
    int nrow = t >> 8, k = t & 255;
    float x = (nrow < Nn) ? B[(size_t)k * Nn + nrow] : 0.f;
    __nv_bfloat16 h = __float2bfloat16_rn(x);
    th[t] = h;
    tl[t] = __float2bfloat16_rn(x - __bfloat162float(h));
}

// ---------------- mma.sync split-bf16 GEMM ----------------
// CTA tile 128x128, BK=64, 512 threads (4x4 warps), warp tile 32x32.
// ELR=true: writes fp16 C and fused el/er (fp32-exact from accumulators).
#define STAGE_BYTES 65536
#define GEMM_SMEM   (2 * STAGE_BYTES)

__device__ __forceinline__ void gemm_load_stage(
    uint32_t sb, const __nv_bfloat16* __restrict__ Ahi, const __nv_bfloat16* __restrict__ Alo,
    const __nv_bfloat16* __restrict__ Bth, const __nv_bfloat16* __restrict__ Btl,
    int m0, int n0, int M, int kb, int tid)
{
    #pragma unroll
    for (int it = 0; it < 4; ++it) {
        int idx = tid + it * 512;
        int prec = idx >> 10, rem = idx & 1023;
        int row = rem >> 3, ch = rem & 7;
        uint32_t dst = sb + prec * 16384 + row * 128 + (((uint32_t)(ch ^ (row & 7))) << 4);
        const __nv_bfloat16* srcb = prec ? Alo : Ahi;
        const __nv_bfloat16* src = srcb + (size_t)(m0 + row) * 256 + kb * 64 + ch * 8;
        cp16(dst, src, (m0 + row) < M ? 16u : 0u);
    }
    #pragma unroll
    for (int it = 0; it < 4; ++it) {
        int idx = tid + it * 512;
        int prec = idx >> 10, rem = idx & 1023;
        int row = rem >> 3, ch = rem & 7;
        uint32_t dst = sb + 32768 + prec * 16384 + row * 128 + (((uint32_t)(ch ^ (row & 7))) << 4);
        const __nv_bfloat16* srcb = prec ? Btl : Bth;
        const __nv_bfloat16* src = srcb + (size_t)(n0 + row) * 256 + kb * 64 + ch * 8;
        cp16(dst, src, 16u);
    }
}

template <bool ELR>
__global__ __launch_bounds__(512, 1) void k_gemm_mma(
    const __nv_bfloat16* __restrict__ Ahi, const __nv_bfloat16* __restrict__ Alo,
    const __nv_bfloat16* __restrict__ Bth, const __nv_bfloat16* __restrict__ Btl,
    __half* __restrict__ Ch, float* __restrict__ Cf,
    const float* __restrict__ al, const float* __restrict__ ar,
    float* __restrict__ el, float* __restrict__ er,
    int M, int Nn, int H, int D)
{
    extern __shared__ char smem[];
    const uint32_t sbase = smem_u32(smem);
    const int tid = threadIdx.x, wid = tid >> 5, lane = tid & 31;
    const int warp_m = wid & 3, warp_n = wid >> 2;
    const int m0 = blockIdx.y * 128;
    const int n0 = blockIdx.x * 128;

    float acc[2][4][4];
    #pragma unroll
    for (int mt = 0; mt < 2; ++mt)
        #pragma unroll
        for (int nt = 0; nt < 4; ++nt)
            #pragma unroll
            for (int q = 0; q < 4; ++q) acc[mt][nt][q] = 0.f;

    const int rowA = warp_m * 32 + (lane & 15);
    const int rowB = warp_n * 32 + (lane & 7) + ((lane >> 4) << 3);
    const uint32_t rowAswz = (uint32_t)(rowA & 7);
    const uint32_t rowBswz = (uint32_t)(rowB & 7);
    const int halfA = lane >> 4;
    const int halfB = (lane >> 3) & 1;

    gemm_load_stage(sbase, Ahi, Alo, Bth, Btl, m0, n0, M, 0, tid);
    CP_COMMIT();

    #pragma unroll 1
    for (int kb = 0; kb < 4; ++kb) {
        if (kb < 3) {
            gemm_load_stage(sbase + ((kb + 1) & 1) * STAGE_BYTES,
                            Ahi, Alo, Bth, Btl, m0, n0, M, kb + 1, tid);
            CP_COMMIT();
            CP_WAIT(1);
        } else {
            CP_WAIT(0);
        }
        __syncthreads();

        const uint32_t sb = sbase + (kb & 1) * STAGE_BYTES;
        #pragma unroll
        for (int s = 0; s < 4; ++s) {
            uint32_t a[2][2][4];
            uint32_t b[2][4][2];
            const uint32_t offA = (((uint32_t)(s * 2 + halfA) ^ rowAswz) << 4);
            const uint32_t offB = (((uint32_t)(s * 2 + halfB) ^ rowBswz) << 4);
            #pragma unroll
            for (int prec = 0; prec < 2; ++prec) {
                uint32_t baseA = sb + prec * 16384;
                #pragma unroll
                for (int mt = 0; mt < 2; ++mt) {
                    uint32_t addr = baseA + (uint32_t)(rowA + mt * 16) * 128 + offA;
                    LDSM_X4(a[prec][mt][0], a[prec][mt][1], a[prec][mt][2], a[prec][mt][3], addr);
                }
                uint32_t baseB = sb + 32768 + prec * 16384;
                #pragma unroll
                for (int ntp = 0; ntp < 2; ++ntp) {
                    uint32_t addr = baseB + (uint32_t)(rowB + ntp * 16) * 128 + offB;
                    LDSM_X4(b[prec][2 * ntp][0], b[prec][2 * ntp][1],
                            b[prec][2 * ntp + 1][0], b[prec][2 * ntp + 1][1], addr);
                }
            }
            #pragma unroll
            for (int mt = 0; mt < 2; ++mt)
                #pragma unroll
                for (int nt = 0; nt < 4; ++nt) {
                    MMA_BF16(acc[mt][nt], a[0][mt], b[0][nt]);
                    MMA_BF16(acc[mt][nt], a[0][mt], b[1][nt]);
                    MMA_BF16(acc[mt][nt], a[1][mt], b[0][nt]);
                }
        }
        __syncthreads();
    }

    // ---- C store ----
    #pragma unroll
    for (int mt = 0; mt < 2; ++mt) {
        int row = m0 + warp_m * 32 + mt * 16 + (lane >> 2);
        #pragma unroll
        for (int nt = 0; nt < 4; ++nt) {
            int col = n0 + warp_n * 32 + nt * 8 + (lane & 3) * 2;
            if (col < Nn) {
                if (ELR) {
                    if (row < M)
                        *reinterpret_cast<__half2*>(Ch + (size_t)row * Nn + col) =
                            __floats2half2_rn(acc[mt][nt][0], acc[mt][nt][1]);
                    if (row + 8 < M)
                        *reinterpret_cast<__half2*>(Ch + (size_t)(row + 8) * Nn + col) =
                            __floats2half2_rn(acc[mt][nt][2], acc[mt][nt][3]);
                } else {
                    if (row < M)
                        *reinterpret_cast<float2*>(Cf + (size_t)row * Nn + col) =
                            make_float2(acc[mt][nt][0], acc[mt][nt][1]);
                    if (row + 8 < M)
                        *reinterpret_cast<float2*>(Cf + (size_t)(row + 8) * Nn + col) =
                            make_float2(acc[mt][nt][2], acc[mt][nt][3]);
                }
            }
        }
    }

    // ---- fused el/er: fp32-exact from accumulators ----
    if (ELR) {
        const int colbase = n0 + warp_n * 32;
        const int h0 = colbase / D;
        int nt_split = ((h0 + 1) * D - colbase) >> 3;        // nts in head h0
        if (nt_split > 4) nt_split = 4;
        // [mt][rowhalf][slot]
        float sl[2][2][2] = {}, sr[2][2][2] = {};
        #pragma unroll
        for (int nt = 0; nt < 4; ++nt) {
            int colg = colbase + nt * 8;
            float2 av = make_float2(0.f, 0.f), rv = av;
            if (colg < Nn) {
                int h = (nt < nt_split) ? h0 : (h0 + 1);
                int d = colg - h * D + (lane & 3) * 2;
                av = __ldg(reinterpret_cast<const float2*>(al + h * D + d));
                rv = __ldg(reinterpret_cast<const float2*>(ar + h * D + d));
            }
            int slot = (nt >= nt_split);
            #pragma unroll
            for (int mt = 0; mt < 2; ++mt) {
                sl[mt][0][slot] += acc[mt][nt][0] * av.x + acc[mt][nt][1] * av.y;
                sr[mt][0][slot] += acc[mt][nt][0] * rv.x + acc[mt][nt][1] * rv.y;
                sl[mt][1][slot] += acc[mt][nt][2] * av.x + acc[mt][nt][3] * av.y;
                sr[mt][1][slot] += acc[mt][nt][2] * rv.x + acc[mt][nt][3] * rv.y;
            }
        }
        // quad reduce (sum over lane&3)
        #pragma unroll
        for (int mt = 0; mt < 2; ++mt)
            #pragma unroll
            for (int rh = 0; rh < 2; ++rh)
                #pragma unroll
                for (int sidx = 0; sidx < 2; ++sidx) {
                    float vl = sl[mt][rh][sidx], vr = sr[mt][rh][sidx];
                    vl += __shfl_xor_sync(0xffffffffu, vl, 1);
                    vl += __shfl_xor_sync(0xffffffffu, vl, 2);
                    vr += __shfl_xor_sync(0xffffffffu, vr, 1);
                    vr += __shfl_xor_sync(0xffffffffu, vr, 2);
                    sl[mt][rh][sidx] = vl; sr[mt][rh][sidx] = vr;
                }
        if ((lane & 3) == 0) {
            bool slot1_valid = (nt_split < 4) && (colbase + nt_split * 8) < Nn;
            #pragma unroll
            for (int mt = 0; mt < 2; ++mt) {
                #pragma unroll
                for (int rh = 0; rh < 2; ++rh) {
                    int row = m0 + warp_m * 32 + mt * 16 + (lane >> 2) + rh * 8;
                    if (row < M) {
                        atomicAdd(&el[(size_t)row * H + h0], sl[mt][rh][0]);
                        atomicAdd(&er[(size_t)row * H + h0], sr[mt][rh][0]);
                        if (slot1_valid) {
                            atomicAdd(&el[(size_t)row * H + h0 + 1], sl[mt][rh][1]);
                            atomicAdd(&er[(size_t)row * H + h0 + 1], sr[mt][rh][1]);
                        }
                    }
                }
            }
        }
    }
}

// ---------------- aggregation, layers 0/1 (fp16 z, fused bf16 hi/lo split) ----------------
template <bool RES>
__global__ __launch_bounds__(256) void k_agg256(
    const __half* __restrict__ zh, const float* __restrict__ el,
    const float* __restrict__ er, const float* __restrict__ bias,
    const float* __restrict__ xres, float* __restrict__ out,
    __nv_bfloat16* __restrict__ ohi, __nv_bfloat16* __restrict__ olo, int n)
{
    int gw = (blockIdx.x * blockDim.x + threadIdx.x) >> 5;
    if (gw >= n) return;
    int lane = threadIdx.x & 31;
    int beg = g_rowstart[gw], end = g_rowstart[gw + 1];
    float erh = (lane < 4) ? __ldg(&er[gw * 4 + lane]) : 0.f;
    int h = lane >> 3;
    int c0 = lane * 8;
    float4 acc0 = make_float4(0.f, 0.f, 0.f, 0.f), acc1 = acc0;
    float denom = 0.f;
    int s = (beg < end) ? __ldg(&g_srcs[beg]) : 0;
    for (int i = beg; i < end; ++i) {
        int s_next = (i + 1 < end) ? __ldg(&g_srcs[i + 1]) : 0;
        float w = 0.f;
        if (lane < 4) {
            float e = __ldg(&el[s * 4 + lane]) + erh;
            e = (e > 0.f) ? e : 0.2f * e;
            w = __expf(e);
            denom += w;
        }
        float wh = __shfl_sync(0xffffffffu, w, h);
        uint4 q = __ldg(reinterpret_cast<const uint4*>(zh + (size_t)s * 256 + c0));
        float2 p0 = __half22float2(*reinterpret_cast<__half2*>(&q.x));
        float2 p1 = __half22float2(*reinterpret_cast<__half2*>(&q.y));
        float2 p2 = __half22float2(*reinterpret_cast<__half2*>(&q.z));
        float2 p3 = __half22float2(*reinterpret_cast<__half2*>(&q.w));
        acc0.x = fmaf(wh, p0.x, acc0.x); acc0.y = fmaf(wh, p0.y, acc0.y);
        acc0.z = fmaf(wh, p1.x, acc0.z); acc0.w = fmaf(wh, p1.y, acc0.w);
        acc1.x = fmaf(wh, p2.x, acc1.x); acc1.y = fmaf(wh, p2.y, acc1.y);
        acc1.z = fmaf(wh, p3.x, acc1.z); acc1.w = fmaf(wh, p3.y, acc1.w);
        s = s_next;
    }
    float dh = __shfl_sync(0xffffffffu, denom, h);
    float inv = 1.f / dh;
    const float4* bp = reinterpret_cast<const float4*>(bias + c0);
    float4 b0 = __ldg(bp), b1 = __ldg(bp + 1);
    float v[8];
    v[0] = fmaf(acc0.x, inv, b0.x); v[1] = fmaf(acc0.y, inv, b0.y);
    v[2] = fmaf(acc0.z, inv, b0.z); v[3] = fmaf(acc0.w, inv, b0.w);
    v[4] = fmaf(acc1.x, inv, b1.x); v[5] = fmaf(acc1.y, inv, b1.y);
    v[6] = fmaf(acc1.z, inv, b1.z); v[7] = fmaf(acc1.w, inv, b1.w);
    if (RES) {
        const float4* rp = reinterpret_cast<const float4*>(xres + (size_t)gw * 256 + c0);
        float4 r0 = __ldg(rp), r1 = __ldg(rp + 1);
        v[0] += r0.x; v[1] += r0.y; v[2] += r0.z; v[3] += r0.w;
        v[4] += r1.x; v[5] += r1.y; v[6] += r1.z; v[7] += r1.w;
    }
    #pragma unroll
    for (int j = 0; j < 8; ++j) v[j] = (v[j] > 0.f) ? v[j] : expm1f(v[j]);
    float4 o0 = make_float4(v[0], v[1], v[2], v[3]);
    float4 o1 = make_float4(v[4], v[5], v[6], v[7]);
    float4* op = reinterpret_cast<float4*>(out + (size_t)gw * 256 + c0);
    op[0] = o0; op[1] = o1;
    ushort hi[8], lo[8];
    #pragma unroll
    for (int j = 0; j < 8; ++j) {
        __nv_bfloat16 hh = __float2bfloat16_rn(v[j]);
        hi[j] = __bfloat16_as_ushort(hh);
        lo[j] = __bfloat16_as_ushort(__float2bfloat16_rn(v[j] - __bfloat162float(hh)));
    }
    ushort4* hp = reinterpret_cast<ushort4*>(ohi + (size_t)gw * 256 + c0);
    ushort4* lp = reinterpret_cast<ushort4*>(olo + (size_t)gw * 256 + c0);
    hp[0] = make_ushort4(hi[0], hi[1], hi[2], hi[3]);
    hp[1] = make_ushort4(hi[4], hi[5], hi[6], hi[7]);
    lp[0] = make_ushort4(lo[0], lo[1], lo[2], lo[3]);
    lp[1] = make_ushort4(lo[4], lo[5], lo[6], lo[7]);
}

// ---------------- aggregation, layer 2 (fp16 z) ----------------
__global__ __launch_bounds__(256) void k_agg_l2(
    const __half* __restrict__ zh, const float* __restrict__ el,
    const float* __restrict__ er, const float* __restrict__ bias,
    const float* __restrict__ res, float* __restrict__ logits, int n)
{
    __shared__ float sout[8][240];
    int wInB = threadIdx.x >> 5;
    int gw = blockIdx.x * 8 + wInB;
    int lane = threadIdx.x & 31;
    bool act = (lane < 30);
    if (gw < n) {
        int beg = g_rowstart[gw], end = g_rowstart[gw + 1];
        float erh = (lane < 6) ? __ldg(&er[gw * 6 + lane]) : 0.f;
        int h = act ? (lane / 5) : 0;
        int c0 = lane * 8;
        float4 acc0 = make_float4(0.f, 0.f, 0.f, 0.f), acc1 = acc0;
        float denom = 0.f;
        int s = (beg < end) ? __ldg(&g_srcs[beg]) : 0;
        for (int i = beg; i < end; ++i) {
            int s_next = (i + 1 < end) ? __ldg(&g_srcs[i + 1]) : 0;
            float w = 0.f;
            if (lane < 6) {
                float e = __ldg(&el[s * 6 + lane]) + erh;
                e = (e > 0.f) ? e : 0.2f * e;
                w = __expf(e);
                denom += w;
            }
            float wh = __shfl_sync(0xffffffffu, w, h);
            if (act) {
                uint4 q = __ldg(reinterpret_cast<const uint4*>(zh + (size_t)s * 240 + c0));
                float2 p0 = __half22float2(*reinterpret_cast<__half2*>(&q.x));
                float2 p1 = __half22float2(*reinterpret_cast<__half2*>(&q.y));
                float2 p2 = __half22float2(*reinterpret_cast<__half2*>(&q.z));
                float2 p3 = __half22float2(*reinterpret_cast<__half2*>(&q.w));
                acc0.x = fmaf(wh, p0.x, acc0.x); acc0.y = fmaf(wh, p0.y, acc0.y);
                acc0.z = fmaf(wh, p1.x, acc0.z); acc0.w = fmaf(wh, p1.y, acc0.w);
                acc1.x = fmaf(wh, p2.x, acc1.x); acc1.y = fmaf(wh, p2.y, acc1.y);
                acc1.z = fmaf(wh, p3.x, acc1.z); acc1.w = fmaf(wh, p3.y, acc1.w);
            }
            s = s_next;
        }
        float dh = __shfl_sync(0xffffffffu, denom, h);
        if (act) {
            float inv = 1.f / dh;
            const float4* bp = reinterpret_cast<const float4*>(bias + c0);
            const float4* rp = reinterpret_cast<const float4*>(res + (size_t)gw * 240 + c0);
            float4 b0 = __ldg(bp), b1 = __ldg(bp + 1);
            float4 r0 = __ldg(rp), r1 = __ldg(rp + 1);
            sout[wInB][c0 + 0] = fmaf(acc0.x, inv, b0.x) + r0.x;
            sout[wInB][c0 + 1] = fmaf(acc0.y, inv, b0.y) + r0.y;
            sout[wInB][c0 + 2] = fmaf(acc0.z, inv, b0.z) + r0.z;
            sout[wInB][c0 + 3] = fmaf(acc0.w, inv, b0.w) + r0.w;
            sout[wInB][c0 + 4] = fmaf(acc1.x, inv, b1.x) + r1.x;
            sout[wInB][c0 + 5] = fmaf(acc1.y, inv, b1.y) + r1.y;
            sout[wInB][c0 + 6] = fmaf(acc1.z, inv, b1.z) + r1.z;
            sout[wInB][c0 + 7] = fmaf(acc1.w, inv, b1.w) + r1.w;
        }
    }
    __syncwarp();
    if (gw < n) {
        for (int d = lane; d < 40; d += 32) {
            float s_ = 0.f;
            #pragma unroll
            for (int hh = 0; hh < 6; ++hh) s_ += sout[wInB][hh * 40 + d];
            logits[(size_t)gw * 40 + d] = s_ * (1.0f / 6.0f);
        }
    }
}

// ---------------- host ----------------
extern "C" void kernel_launch(void* const* d_in, const int* in_sizes, int n_in,
                              void* d_out, int out_size)
{
    const float* feat  = (const float*)d_in[0];
    const int*   src   = (const int*)d_in[1];
    const int*   dst   = (const int*)d_in[2];
    const float* W0    = (const float*)d_in[3];
    const float* al0   = (const float*)d_in[4];
    const float* ar0   = (const float*)d_in[5];
    const float* b0    = (const float*)d_in[6];
    const float* W1    = (const float*)d_in[7];
    const float* al1   = (const float*)d_in[8];
    const float* ar1   = (const float*)d_in[9];
    const float* b1    = (const float*)d_in[10];
    const float* W2    = (const float*)d_in[11];
    const float* al2   = (const float*)d_in[12];
    const float* ar2   = (const float*)d_in[13];
    const float* b2    = (const float*)d_in[14];
    const float* resW2 = (const float*)d_in[15];

    const int n = NNODES;
    const int E = in_sizes[1];

    float* logits = (float*)d_out;
    float* h1     = (float*)d_out + n * 40;

    float *ph0, *pr2, *pel, *per;
    __half* pzh;
    __nv_bfloat16 *pAh, *pAl, *pBh, *pBl;
    cudaGetSymbolAddress((void**)&pzh, g_zh);
    cudaGetSymbolAddress((void**)&ph0, g_h0);
    cudaGetSymbolAddress((void**)&pr2, g_r2);
    cudaGetSymbolAddress((void**)&pel, g_el);
    cudaGetSymbolAddress((void**)&per, g_er);
    cudaGetSymbolAddress((void**)&pAh, g_Ahi);
    cudaGetSymbolAddress((void**)&pAl, g_Alo);
    cudaGetSymbolAddress((void**)&pBh, g_Bth);
    cudaGetSymbolAddress((void**)&pBl, g_Btl);

    cudaFuncSetAttribute(k_gemm_mma<true>,  cudaFuncAttributeMaxDynamicSharedMemorySize, GEMM_SMEM);
    cudaFuncSetAttribute(k_gemm_mma<false>, cudaFuncAttributeMaxDynamicSharedMemorySize, GEMM_SMEM);

    // ---- CSR by destination ----
    k_zero_deg<<<(n + 255) / 256, 256>>>(n);
    k_hist<<<(E + 255) / 256, 256>>>(dst, E);
    k_scan<<<1, 1024>>>(n, E);
    k_scatter<<<(E + 255) / 256, 256>>>(src, dst, E);

    const int n4 = n * 64;
    const int splitBlocks = (n4 + 255) / 256;
    dim3 gemmGrid(2, (n + 127) / 128);
    const int zeroBlocks = (n * 6 + 255) / 256;
    const int aggBlocks  = (n + 7) / 8;

    // ---- Layer 0 ----
    k_splitA<<<splitBlocks, 256>>>(feat, pAh, pAl, n4);
    k_splitBt<<<256, 256>>>(W0, pBh, pBl, 256);
    k_zero_elr<<<zeroBlocks, 256>>>(n * 6);
    k_gemm_mma<true><<<gemmGrid, 512, GEMM_SMEM>>>(pAh, pAl, pBh, pBl, pzh, nullptr,
                                                   al0, ar0, pel, per, n, 256, 4, 64);
    k_agg256<false><<<aggBlocks, 256>>>(pzh, pel, per, b0, nullptr, ph0, pAh, pAl, n);

    // ---- Layer 1 ----
    k_splitBt<<<256, 256>>>(W1, pBh, pBl, 256);
    k_zero_elr<<<zeroBlocks, 256>>>(n * 6);
    k_gemm_mma<true><<<gemmGrid, 512, GEMM_SMEM>>>(pAh, pAl, pBh, pBl, pzh, nullptr,
                                                   al1, ar1, pel, per, n, 256, 4, 64);
    k_agg256<true><<<aggBlocks, 256>>>(pzh, pel, per, b1, ph0, h1, pAh, pAl, n);

    // ---- Layer 2 ----
    k_splitBt<<<256, 256>>>(W2, pBh, pBl, 240);
    k_zero_elr<<<zeroBlocks, 256>>>(n * 6);
    k_gemm_mma<true><<<gemmGrid, 512, GEMM_SMEM>>>(pAh, pAl, pBh, pBl, pzh, nullptr,
                                                   al2, ar2, pel, per, n, 240, 6, 40);
    k_splitBt<<<256, 256>>>(resW2, pBh, pBl, 240);
    k_gemm_mma<false><<<gemmGrid, 512, GEMM_SMEM>>>(pAh, pAl, pBh, pBl, nullptr, pr2,
                                                    nullptr, nullptr, nullptr, nullptr, n, 240, 1, 64);
    k_agg_l2<<<aggBlocks, 256>>>(pzh, pel, per, b2, pr2, logits, n);
}

// round 6
// speedup vs baseline: 2.5062x; 1.1894x over previous
#include <cuda_runtime.h>
#include <cuda_bf16.h>
#include <cuda_fp16.h>
#include <math.h>
#include <cstdint>

// ---------------- problem constants ----------------
#define NNODES 50000
#define ECAP   1000000
#define SPLITA_BLOCKS 12500   // (NNODES*256/4)/256

// ---------------- device scratch ----------------
__device__ __align__(16) __half g_zh[NNODES * 256];
__device__ float g_h0[NNODES * 256];
__device__ float g_r2[NNODES * 240];
__device__ float g_el[NNODES * 6];
__device__ float g_er[NNODES * 6];
__device__ int   g_deg[NNODES];
__device__ int   g_rowstart[NNODES + 1];
__device__ int   g_cursor[NNODES];
__device__ int   g_srcs[ECAP];
__device__ __align__(16) __nv_bfloat16 g_Ahi[NNODES * 256];
__device__ __align__(16) __nv_bfloat16 g_Alo[NNODES * 256];
__device__ __align__(16) __nv_bfloat16 g_Bth[256 * 256];
__device__ __align__(16) __nv_bfloat16 g_Btl[256 * 256];
__device__ __align__(16) __nv_bfloat16 g_Bth2[256 * 256];
__device__ __align__(16) __nv_bfloat16 g_Btl2[256 * 256];

// ================= PTX helpers =================
__device__ __forceinline__ uint32_t smem_u32(const void* p) {
    uint32_t a;
    asm("{ .reg .u64 t; cvta.to.shared.u64 t, %1; cvt.u32.u64 %0, t; }" : "=r"(a) : "l"(p));
    return a;
}
__device__ __forceinline__ void cp16(uint32_t dst, const void* src, uint32_t srcsize) {
    asm volatile("cp.async.cg.shared.global [%0], [%1], 16, %2;"
                 :: "r"(dst), "l"(src), "r"(srcsize));
}
#define CP_COMMIT() asm volatile("cp.async.commit_group;" ::: "memory")
#define CP_WAIT(n)  asm volatile("cp.async.wait_group %0;" :: "n"(n) : "memory")
#define LDSM_X4(r0, r1, r2, r3, addr) \
    asm volatile("ldmatrix.sync.aligned.m8n8.x4.shared.b16 {%0,%1,%2,%3}, [%4];" \
        : "=r"(r0), "=r"(r1), "=r"(r2), "=r"(r3) : "r"(addr))
#define MMA_BF16(acc, a, b) \
    asm volatile("mma.sync.aligned.m16n8k16.row.col.f32.bf16.bf16.f32 " \
        "{%0,%1,%2,%3}, {%4,%5,%6,%7}, {%8,%9}, {%0,%1,%2,%3};" \
        : "+f"((acc)[0]), "+f"((acc)[1]), "+f"((acc)[2]), "+f"((acc)[3]) \
        : "r"((a)[0]), "r"((a)[1]), "r"((a)[2]), "r"((a)[3]), "r"((b)[0]), "r"((b)[1]))

// ---------------- helper device funcs ----------------
__device__ __forceinline__ void splitBt_elem(const float* __restrict__ B,
                                             __nv_bfloat16* th, __nv_bfloat16* tl,
                                             int t, int Nn) {
    int nrow = t >> 8, k = t & 255;
    float x = (nrow < Nn) ? B[(size_t)k * Nn + nrow] : 0.f;
    __nv_bfloat16 h = __float2bfloat16_rn(x);
    th[t] = h;
    tl[t] = __float2bfloat16_rn(x - __bfloat162float(h));
}

// ---------------- kernel 1: zero deg + el/er ----------------
__global__ void k_zero0(int n, int n6) {
    int i = blockIdx.x * blockDim.x + threadIdx.x;
    if (i < n) g_deg[i] = 0;
    if (i < n6) { g_el[i] = 0.f; g_er[i] = 0.f; }
}

// ---------------- kernel 2: splitA(feat) + splitBt(W0) + hist ----------------
__global__ void k_prep0(const float* __restrict__ feat, const float* __restrict__ W0,
                        const int* __restrict__ dst, int E) {
    int bx = blockIdx.x;
    if (bx < SPLITA_BLOCKS) {
        int i = bx * 256 + threadIdx.x;
        float4 v = reinterpret_cast<const float4*>(feat)[i];
        __nv_bfloat16 h0 = __float2bfloat16_rn(v.x);
        __nv_bfloat16 h1 = __float2bfloat16_rn(v.y);
        __nv_bfloat16 h2 = __float2bfloat16_rn(v.z);
        __nv_bfloat16 h3 = __float2bfloat16_rn(v.w);
        reinterpret_cast<ushort4*>(g_Ahi)[i] = make_ushort4(
            __bfloat16_as_ushort(h0), __bfloat16_as_ushort(h1),
            __bfloat16_as_ushort(h2), __bfloat16_as_ushort(h3));
        reinterpret_cast<ushort4*>(g_Alo)[i] = make_ushort4(
            __bfloat16_as_ushort(__float2bfloat16_rn(v.x - __bfloat162float(h0))),
            __bfloat16_as_ushort(__float2bfloat16_rn(v.y - __bfloat162float(h1))),
            __bfloat16_as_ushort(__float2bfloat16_rn(v.z - __bfloat162float(h2))),
            __bfloat16_as_ushort(__float2bfloat16_rn(v.w - __bfloat162float(h3))));
    } else if (bx < SPLITA_BLOCKS + 256) {
        int t = (bx - SPLITA_BLOCKS) * 256 + threadIdx.x;
        splitBt_elem(W0, g_Bth, g_Btl, t, 256);
    } else {
        int e = (bx - SPLITA_BLOCKS - 256) * 256 + threadIdx.x;
        if (e < E) atomicAdd(&g_deg[dst[e]], 1);
    }
}

// ---------------- kernel: scan ----------------
__global__ void k_scan(int n, int E) {
    __shared__ int wsum[32];
    __shared__ int carry;
    int lane = threadIdx.x & 31, w = threadIdx.x >> 5;
    if (threadIdx.x == 0) carry = 0;
    __syncthreads();
    for (int base = 0; base < n; base += 1024) {
        int i = base + threadIdx.x;
        int v = (i < n) ? g_deg[i] : 0;
        int x = v;
        #pragma unroll
        for (int off = 1; off < 32; off <<= 1) {
            int t = __shfl_up_sync(0xffffffffu, x, off);
            if (lane >= off) x += t;
        }
        if (lane == 31) wsum[w] = x;
        __syncthreads();
        if (w == 0) {
            int y = wsum[lane];
            #pragma unroll
            for (int off = 1; off < 32; off <<= 1) {
                int t = __shfl_up_sync(0xffffffffu, y, off);
                if (lane >= off) y += t;
            }
            wsum[lane] = y;
        }
        __syncthreads();
        int incl = x + (w ? wsum[w - 1] : 0) + carry;
        int excl = incl - v;
        if (i < n) { g_rowstart[i] = excl; g_cursor[i] = excl; }
        __syncthreads();
        if (threadIdx.x == 1023) carry = incl;
        __syncthreads();
    }
    if (threadIdx.x == 0) g_rowstart[n] = E;
}

// ---------------- prep1 / prep2 ----------------
__global__ void k_prep1(const float* __restrict__ W1, int n6) {
    int bx = blockIdx.x;
    if (bx < 256) {
        splitBt_elem(W1, g_Bth, g_Btl, bx * 256 + threadIdx.x, 256);
    } else {
        int i = (bx - 256) * 256 + threadIdx.x;
        if (i < n6) { g_el[i] = 0.f; g_er[i] = 0.f; }
    }
}
__global__ void k_prep2(const float* __restrict__ W2, const float* __restrict__ resW2, int n6) {
    int bx = blockIdx.x;
    if (bx < 256) {
        splitBt_elem(W2, g_Bth, g_Btl, bx * 256 + threadIdx.x, 240);
    } else if (bx < 512) {
        splitBt_elem(resW2, g_Bth2, g_Btl2, (bx - 512 + 256) * 256 + threadIdx.x, 240);
    } else {
        int i = (bx - 512) * 256 + threadIdx.x;
        if (i < n6) { g_el[i] = 0.f; g_er[i] = 0.f; }
    }
}

// ---------------- GEMM body (mma.sync split-bf16) ----------------
#define STAGE_BYTES 65536
#define GEMM_SMEM   (2 * STAGE_BYTES)

__device__ __forceinline__ void gemm_load_stage(
    uint32_t sb, const __nv_bfloat16* __restrict__ Ahi, const __nv_bfloat16* __restrict__ Alo,
    const __nv_bfloat16* __restrict__ Bth, const __nv_bfloat16* __restrict__ Btl,
    int m0, int n0, int M, int kb, int tid)
{
    #pragma unroll
    for (int it = 0; it < 4; ++it) {
        int idx = tid + it * 512;
        int prec = idx >> 10, rem = idx & 1023;
        int row = rem >> 3, ch = rem & 7;
        uint32_t dst = sb + prec * 16384 + row * 128 + (((uint32_t)(ch ^ (row & 7))) << 4);
        const __nv_bfloat16* srcb = prec ? Alo : Ahi;
        const __nv_bfloat16* src = srcb + (size_t)(m0 + row) * 256 + kb * 64 + ch * 8;
        cp16(dst, src, (m0 + row) < M ? 16u : 0u);
    }
    #pragma unroll
    for (int it = 0; it < 4; ++it) {
        int idx = tid + it * 512;
        int prec = idx >> 10, rem = idx & 1023;
        int row = rem >> 3, ch = rem & 7;
        uint32_t dst = sb + 32768 + prec * 16384 + row * 128 + (((uint32_t)(ch ^ (row & 7))) << 4);
        const __nv_bfloat16* srcb = prec ? Btl : Bth;
        const __nv_bfloat16* src = srcb + (size_t)(n0 + row) * 256 + kb * 64 + ch * 8;
        cp16(dst, src, 16u);
    }
}

template <bool ELR>
__device__ __forceinline__ void gemm_body(
    const __nv_bfloat16* __restrict__ Ahi, const __nv_bfloat16* __restrict__ Alo,
    const __nv_bfloat16* __restrict__ Bth, const __nv_bfloat16* __restrict__ Btl,
    __half* __restrict__ Ch, float* __restrict__ Cf,
    const float* __restrict__ al, const float* __restrict__ ar,
    float* __restrict__ el, float* __restrict__ er,
    int M, int Nn, int H, int D, int m0, int n0)
{
    extern __shared__ char smem[];
    const uint32_t sbase = smem_u32(smem);
    const int tid = threadIdx.x, wid = tid >> 5, lane = tid & 31;
    const int warp_m = wid & 3, warp_n = wid >> 2;

    float acc[2][4][4];
    #pragma unroll
    for (int mt = 0; mt < 2; ++mt)
        #pragma unroll
        for (int nt = 0; nt < 4; ++nt)
            #pragma unroll
            for (int q = 0; q < 4; ++q) acc[mt][nt][q] = 0.f;

    const int rowA = warp_m * 32 + (lane & 15);
    const int rowB = warp_n * 32 + (lane & 7) + ((lane >> 4) << 3);
    const uint32_t rowAswz = (uint32_t)(rowA & 7);
    const uint32_t rowBswz = (uint32_t)(rowB & 7);
    const int halfA = lane >> 4;
    const int halfB = (lane >> 3) & 1;

    gemm_load_stage(sbase, Ahi, Alo, Bth, Btl, m0, n0, M, 0, tid);
    CP_COMMIT();

    #pragma unroll 1
    for (int kb = 0; kb < 4; ++kb) {
        if (kb < 3) {
            gemm_load_stage(sbase + ((kb + 1) & 1) * STAGE_BYTES,
                            Ahi, Alo, Bth, Btl, m0, n0, M, kb + 1, tid);
            CP_COMMIT();
            CP_WAIT(1);
        } else {
            CP_WAIT(0);
        }
        __syncthreads();

        const uint32_t sb = sbase + (kb & 1) * STAGE_BYTES;
        #pragma unroll
        for (int s = 0; s < 4; ++s) {
            uint32_t a[2][2][4];
            uint32_t b[2][4][2];
            const uint32_t offA = (((uint32_t)(s * 2 + halfA) ^ rowAswz) << 4);
            const uint32_t offB = (((uint32_t)(s * 2 + halfB) ^ rowBswz) << 4);
            #pragma unroll
            for (int prec = 0; prec < 2; ++prec) {
                uint32_t baseA = sb + prec * 16384;
                #pragma unroll
                for (int mt = 0; mt < 2; ++mt) {
                    uint32_t addr = baseA + (uint32_t)(rowA + mt * 16) * 128 + offA;
                    LDSM_X4(a[prec][mt][0], a[prec][mt][1], a[prec][mt][2], a[prec][mt][3], addr);
                }
                uint32_t baseB = sb + 32768 + prec * 16384;
                #pragma unroll
                for (int ntp = 0; ntp < 2; ++ntp) {
                    uint32_t addr = baseB + (uint32_t)(rowB + ntp * 16) * 128 + offB;
                    LDSM_X4(b[prec][2 * ntp][0], b[prec][2 * ntp][1],
                            b[prec][2 * ntp + 1][0], b[prec][2 * ntp + 1][1], addr);
                }
            }
            #pragma unroll
            for (int mt = 0; mt < 2; ++mt)
                #pragma unroll
                for (int nt = 0; nt < 4; ++nt) {
                    MMA_BF16(acc[mt][nt], a[0][mt], b[0][nt]);
                    MMA_BF16(acc[mt][nt], a[0][mt], b[1][nt]);
                    MMA_BF16(acc[mt][nt], a[1][mt], b[0][nt]);
                }
        }
        __syncthreads();
    }

    #pragma unroll
    for (int mt = 0; mt < 2; ++mt) {
        int row = m0 + warp_m * 32 + mt * 16 + (lane >> 2);
        #pragma unroll
        for (int nt = 0; nt < 4; ++nt) {
            int col = n0 + warp_n * 32 + nt * 8 + (lane & 3) * 2;
            if (col < Nn) {
                if (ELR) {
                    if (row < M)
                        *reinterpret_cast<__half2*>(Ch + (size_t)row * Nn + col) =
                            __floats2half2_rn(acc[mt][nt][0], acc[mt][nt][1]);
                    if (row + 8 < M)
                        *reinterpret_cast<__half2*>(Ch + (size_t)(row + 8) * Nn + col) =
                            __floats2half2_rn(acc[mt][nt][2], acc[mt][nt][3]);
                } else {
                    if (row < M)
                        *reinterpret_cast<float2*>(Cf + (size_t)row * Nn + col) =
                            make_float2(acc[mt][nt][0], acc[mt][nt][1]);
                    if (row + 8 < M)
                        *reinterpret_cast<float2*>(Cf + (size_t)(row + 8) * Nn + col) =
                            make_float2(acc[mt][nt][2], acc[mt][nt][3]);
                }
            }
        }
    }

    if (ELR) {
        const int colbase = n0 + warp_n * 32;
        const int h0 = colbase / D;
        int nt_split = ((h0 + 1) * D - colbase) >> 3;
        if (nt_split > 4) nt_split = 4;
        float sl[2][2][2] = {}, sr[2][2][2] = {};
        #pragma unroll
        for (int nt = 0; nt < 4; ++nt) {
            int colg = colbase + nt * 8;
            float2 av = make_float2(0.f, 0.f), rv = av;
            if (colg < Nn) {
                int h = (nt < nt_split) ? h0 : (h0 + 1);
                int d = colg - h * D + (lane & 3) * 2;
                av = __ldg(reinterpret_cast<const float2*>(al + h * D + d));
                rv = __ldg(reinterpret_cast<const float2*>(ar + h * D + d));
            }
            int slot = (nt >= nt_split);
            #pragma unroll
            for (int mt = 0; mt < 2; ++mt) {
                sl[mt][0][slot] += acc[mt][nt][0] * av.x + acc[mt][nt][1] * av.y;
                sr[mt][0][slot] += acc[mt][nt][0] * rv.x + acc[mt][nt][1] * rv.y;
                sl[mt][1][slot] += acc[mt][nt][2] * av.x + acc[mt][nt][3] * av.y;
                sr[mt][1][slot] += acc[mt][nt][2] * rv.x + acc[mt][nt][3] * rv.y;
            }
        }
        #pragma unroll
        for (int mt = 0; mt < 2; ++mt)
            #pragma unroll
            for (int rh = 0; rh < 2; ++rh)
                #pragma unroll
                for (int sidx = 0; sidx < 2; ++sidx) {
                    float vl = sl[mt][rh][sidx], vr = sr[mt][rh][sidx];
                    vl += __shfl_xor_sync(0xffffffffu, vl, 1);
                    vl += __shfl_xor_sync(0xffffffffu, vl, 2);
                    vr += __shfl_xor_sync(0xffffffffu, vr, 1);
                    vr += __shfl_xor_sync(0xffffffffu, vr, 2);
                    sl[mt][rh][sidx] = vl; sr[mt][rh][sidx] = vr;
                }
        if ((lane & 3) == 0) {
            bool slot1_valid = (nt_split < 4) && (colbase + nt_split * 8) < Nn;
            #pragma unroll
            for (int mt = 0; mt < 2; ++mt) {
                #pragma unroll
                for (int rh = 0; rh < 2; ++rh) {
                    int row = m0 + warp_m * 32 + mt * 16 + (lane >> 2) + rh * 8;
                    if (row < M) {
                        atomicAdd(&el[(size_t)row * H + h0], sl[mt][rh][0]);
                        atomicAdd(&er[(size_t)row * H + h0], sr[mt][rh][0]);
                        if (slot1_valid) {
                            atomicAdd(&el[(size_t)row * H + h0 + 1], sl[mt][rh][1]);
                            atomicAdd(&er[(size_t)row * H + h0 + 1], sr[mt][rh][1]);
                        }
                    }
                }
            }
        }
    }
}

// ---------------- GEMM launches ----------------
// L0: gemm (782 blocks) + scatter tail blocks
__global__ __launch_bounds__(512, 1) void k_gemm0(
    const __nv_bfloat16* __restrict__ Ahi, const __nv_bfloat16* __restrict__ Alo,
    __half* __restrict__ Ch, const float* __restrict__ al, const float* __restrict__ ar,
    float* __restrict__ el, float* __restrict__ er, int M, int nGemm,
    const int* __restrict__ src, const int* __restrict__ dst, int E)
{
    int bx = blockIdx.x;
    if (bx < nGemm) {
        gemm_body<true>(Ahi, Alo, g_Bth, g_Btl, Ch, nullptr, al, ar, el, er,
                        M, 256, 4, 64, (bx >> 1) * 128, (bx & 1) * 128);
    } else {
        int e = (bx - nGemm) * 512 + threadIdx.x;
        if (e < E) {
            int p = atomicAdd(&g_cursor[dst[e]], 1);
            g_srcs[p] = src[e];
        }
    }
}

__global__ __launch_bounds__(512, 1) void k_gemm1(
    const __nv_bfloat16* __restrict__ Ahi, const __nv_bfloat16* __restrict__ Alo,
    __half* __restrict__ Ch, const float* __restrict__ al, const float* __restrict__ ar,
    float* __restrict__ el, float* __restrict__ er, int M)
{
    int bx = blockIdx.x;
    gemm_body<true>(Ahi, Alo, g_Bth, g_Btl, Ch, nullptr, al, ar, el, er,
                    M, 256, 4, 64, (bx >> 1) * 128, (bx & 1) * 128);
}

// L2 dual: W2 (ELR, fp16) + resW2 (plain fp32)
__global__ __launch_bounds__(512, 1) void k_gemm2(
    const __nv_bfloat16* __restrict__ Ahi, const __nv_bfloat16* __restrict__ Alo,
    __half* __restrict__ Ch, float* __restrict__ Cf,
    const float* __restrict__ al, const float* __restrict__ ar,
    float* __restrict__ el, float* __restrict__ er, int M, int nGemm)
{
    int bx = blockIdx.x;
    if (bx < nGemm) {
        gemm_body<true>(Ahi, Alo, g_Bth, g_Btl, Ch, nullptr, al, ar, el, er,
                        M, 240, 6, 40, (bx >> 1) * 128, (bx & 1) * 128);
    } else {
        int b2 = bx - nGemm;
        gemm_body<false>(Ahi, Alo, g_Bth2, g_Btl2, nullptr, Cf, nullptr, nullptr,
                         nullptr, nullptr, M, 240, 1, 64, (b2 >> 1) * 128, (b2 & 1) * 128);
    }
}

// ---------------- aggregation helpers ----------------
__device__ __forceinline__ void fma_row(float4& a0, float4& a1, float wh, uint4 q) {
    float2 p0 = __half22float2(*reinterpret_cast<__half2*>(&q.x));
    float2 p1 = __half22float2(*reinterpret_cast<__half2*>(&q.y));
    float2 p2 = __half22float2(*reinterpret_cast<__half2*>(&q.z));
    float2 p3 = __half22float2(*reinterpret_cast<__half2*>(&q.w));
    a0.x = fmaf(wh, p0.x, a0.x); a0.y = fmaf(wh, p0.y, a0.y);
    a0.z = fmaf(wh, p1.x, a0.z); a0.w = fmaf(wh, p1.y, a0.w);
    a1.x = fmaf(wh, p2.x, a1.x); a1.y = fmaf(wh, p2.y, a1.y);
    a1.z = fmaf(wh, p3.x, a1.z); a1.w = fmaf(wh, p3.y, a1.w);
}

// ---------------- aggregation, layers 0/1 ----------------
template <bool RES>
__global__ __launch_bounds__(256) void k_agg256(
    const __half* __restrict__ zh, const float* __restrict__ el,
    const float* __restrict__ er, const float* __restrict__ bias,
    const float* __restrict__ xres, float* __restrict__ out,
    __nv_bfloat16* __restrict__ ohi, __nv_bfloat16* __restrict__ olo, int n)
{
    int gw = (blockIdx.x * blockDim.x + threadIdx.x) >> 5;
    if (gw >= n) return;
    int lane = threadIdx.x & 31;
    int beg = g_rowstart[gw], end = g_rowstart[gw + 1];
    float erh = (lane < 4) ? __ldg(&er[gw * 4 + lane]) : 0.f;
    int h = lane >> 3;
    int c0 = lane * 8;
    float4 acc0 = make_float4(0.f, 0.f, 0.f, 0.f), acc1 = acc0;
    float denom = 0.f;
    int i = beg;
    #pragma unroll 1
    for (; i + 2 <= end; i += 2) {
        int s0 = __ldg(&g_srcs[i]);
        int s1 = __ldg(&g_srcs[i + 1]);
        uint4 q0 = __ldg(reinterpret_cast<const uint4*>(zh + (size_t)s0 * 256 + c0));
        uint4 q1 = __ldg(reinterpret_cast<const uint4*>(zh + (size_t)s1 * 256 + c0));
        float w0 = 0.f, w1 = 0.f;
        if (lane < 4) {
            float e0 = __ldg(&el[s0 * 4 + lane]) + erh;
            float e1 = __ldg(&el[s1 * 4 + lane]) + erh;
            e0 = (e0 > 0.f) ? e0 : 0.2f * e0;
            e1 = (e1 > 0.f) ? e1 : 0.2f * e1;
            w0 = __expf(e0); w1 = __expf(e1);
            denom += w0 + w1;
        }
        float wh0 = __shfl_sync(0xffffffffu, w0, h);
        float wh1 = __shfl_sync(0xffffffffu, w1, h);
        fma_row(acc0, acc1, wh0, q0);
        fma_row(acc0, acc1, wh1, q1);
    }
    if (i < end) {
        int s0 = __ldg(&g_srcs[i]);
        uint4 q0 = __ldg(reinterpret_cast<const uint4*>(zh + (size_t)s0 * 256 + c0));
        float w0 = 0.f;
        if (lane < 4) {
            float e0 = __ldg(&el[s0 * 4 + lane]) + erh;
            e0 = (e0 > 0.f) ? e0 : 0.2f * e0;
            w0 = __expf(e0);
            denom += w0;
        }
        float wh0 = __shfl_sync(0xffffffffu, w0, h);
        fma_row(acc0, acc1, wh0, q0);
    }
    float dh = __shfl_sync(0xffffffffu, denom, h);
    float inv = 1.f / dh;
    const float4* bp = reinterpret_cast<const float4*>(bias + c0);
    float4 b0 = __ldg(bp), b1 = __ldg(bp + 1);
    float v[8];
    v[0] = fmaf(acc0.x, inv, b0.x); v[1] = fmaf(acc0.y, inv, b0.y);
    v[2] = fmaf(acc0.z, inv, b0.z); v[3] = fmaf(acc0.w, inv, b0.w);
    v[4] = fmaf(acc1.x, inv, b1.x); v[5] = fmaf(acc1.y, inv, b1.y);
    v[6] = fmaf(acc1.z, inv, b1.z); v[7] = fmaf(acc1.w, inv, b1.w);
    if (RES) {
        const float4* rp = reinterpret_cast<const float4*>(xres + (size_t)gw * 256 + c0);
        float4 r0 = __ldg(rp), r1 = __ldg(rp + 1);
        v[0] += r0.x; v[1] += r0.y; v[2] += r0.z; v[3] += r0.w;
        v[4] += r1.x; v[5] += r1.y; v[6] += r1.z; v[7] += r1.w;
    }
    #pragma unroll
    for (int j = 0; j < 8; ++j) v[j] = (v[j] > 0.f) ? v[j] : expm1f(v[j]);
    float4* op = reinterpret_cast<float4*>(out + (size_t)gw * 256 + c0);
    op[0] = make_float4(v[0], v[1], v[2], v[3]);
    op[1] = make_float4(v[4], v[5], v[6], v[7]);
    ushort hi[8], lo[8];
    #pragma unroll
    for (int j = 0; j < 8; ++j) {
        __nv_bfloat16 hh = __float2bfloat16_rn(v[j]);
        hi[j] = __bfloat16_as_ushort(hh);
        lo[j] = __bfloat16_as_ushort(__float2bfloat16_rn(v[j] - __bfloat162float(hh)));
    }
    ushort4* hp = reinterpret_cast<ushort4*>(ohi + (size_t)gw * 256 + c0);
    ushort4* lp = reinterpret_cast<ushort4*>(olo + (size_t)gw * 256 + c0);
    hp[0] = make_ushort4(hi[0], hi[1], hi[2], hi[3]);
    hp[1] = make_ushort4(hi[4], hi[5], hi[6], hi[7]);
    lp[0] = make_ushort4(lo[0], lo[1], lo[2], lo[3]);
    lp[1] = make_ushort4(lo[4], lo[5], lo[6], lo[7]);
}

// ---------------- aggregation, layer 2 ----------------
__global__ __launch_bounds__(256) void k_agg_l2(
    const __half* __restrict__ zh, const float* __restrict__ el,
    const float* __restrict__ er, const float* __restrict__ bias,
    const float* __restrict__ res, float* __restrict__ logits, int n)
{
    __shared__ float sout[8][240];
    int wInB = threadIdx.x >> 5;
    int gw = blockIdx.x * 8 + wInB;
    int lane = threadIdx.x & 31;
    bool act = (lane < 30);
    if (gw < n) {
        int beg = g_rowstart[gw], end = g_rowstart[gw + 1];
        float erh = (lane < 6) ? __ldg(&er[gw * 6 + lane]) : 0.f;
        int h = act ? (lane / 5) : 0;
        int c0 = lane * 8;
        float4 acc0 = make_float4(0.f, 0.f, 0.f, 0.f), acc1 = acc0;
        float denom = 0.f;
        int i = beg;
        #pragma unroll 1
        for (; i + 2 <= end; i += 2) {
            int s0 = __ldg(&g_srcs[i]);
            int s1 = __ldg(&g_srcs[i + 1]);
            uint4 q0 = make_uint4(0, 0, 0, 0), q1 = q0;
            if (act) {
                q0 = __ldg(reinterpret_cast<const uint4*>(zh + (size_t)s0 * 240 + c0));
                q1 = __ldg(reinterpret_cast<const uint4*>(zh + (size_t)s1 * 240 + c0));
            }
            float w0 = 0.f, w1 = 0.f;
            if (lane < 6) {
                float e0 = __ldg(&el[s0 * 6 + lane]) + erh;
                float e1 = __ldg(&el[s1 * 6 + lane]) + erh;
                e0 = (e0 > 0.f) ? e0 : 0.2f * e0;
                e1 = (e1 > 0.f) ? e1 : 0.2f * e1;
                w0 = __expf(e0); w1 = __expf(e1);
                denom += w0 + w1;
            }
            float wh0 = __shfl_sync(0xffffffffu, w0, h);
            float wh1 = __shfl_sync(0xffffffffu, w1, h);
            if (act) {
                fma_row(acc0, acc1, wh0, q0);
                fma_row(acc0, acc1, wh1, q1);
            }
        }
        if (i < end) {
            int s0 = __ldg(&g_srcs[i]);
            uint4 q0 = make_uint4(0, 0, 0, 0);
            if (act) q0 = __ldg(reinterpret_cast<const uint4*>(zh + (size_t)s0 * 240 + c0));
            float w0 = 0.f;
            if (lane < 6) {
                float e0 = __ldg(&el[s0 * 6 + lane]) + erh;
                e0 = (e0 > 0.f) ? e0 : 0.2f * e0;
                w0 = __expf(e0);
                denom += w0;
            }
            float wh0 = __shfl_sync(0xffffffffu, w0, h);
            if (act) fma_row(acc0, acc1, wh0, q0);
        }
        float dh = __shfl_sync(0xffffffffu, denom, h);
        if (act) {
            float inv = 1.f / dh;
            const float4* bp = reinterpret_cast<const float4*>(bias + c0);
            const float4* rp = reinterpret_cast<const float4*>(res + (size_t)gw * 240 + c0);
            float4 b0 = __ldg(bp), b1 = __ldg(bp + 1);
            float4 r0 = __ldg(rp), r1 = __ldg(rp + 1);
            sout[wInB][c0 + 0] = fmaf(acc0.x, inv, b0.x) + r0.x;
            sout[wInB][c0 + 1] = fmaf(acc0.y, inv, b0.y) + r0.y;
            sout[wInB][c0 + 2] = fmaf(acc0.z, inv, b0.z) + r0.z;
            sout[wInB][c0 + 3] = fmaf(acc0.w, inv, b0.w) + r0.w;
            sout[wInB][c0 + 4] = fmaf(acc1.x, inv, b1.x) + r1.x;
            sout[wInB][c0 + 5] = fmaf(acc1.y, inv, b1.y) + r1.y;
            sout[wInB][c0 + 6] = fmaf(acc1.z, inv, b1.z) + r1.z;
            sout[wInB][c0 + 7] = fmaf(acc1.w, inv, b1.w) + r1.w;
        }
    }
    __syncwarp();
    if (gw < n) {
        for (int d = lane; d < 40; d += 32) {
            float s_ = 0.f;
            #pragma unroll
            for (int hh = 0; hh < 6; ++hh) s_ += sout[wInB][hh * 40 + d];
            logits[(size_t)gw * 40 + d] = s_ * (1.0f / 6.0f);
        }
    }
}

// ---------------- host ----------------
extern "C" void kernel_launch(void* const* d_in, const int* in_sizes, int n_in,
                              void* d_out, int out_size)
{
    const float* feat  = (const float*)d_in[0];
    const int*   src   = (const int*)d_in[1];
    const int*   dst   = (const int*)d_in[2];
    const float* al0   = (const float*)d_in[4];
    const float* ar0   = (const float*)d_in[5];
    const float* b0    = (const float*)d_in[6];
    const float* W1    = (const float*)d_in[7];
    const float* al1   = (const float*)d_in[8];
    const float* ar1   = (const float*)d_in[9];
    const float* b1    = (const float*)d_in[10];
    const float* W2    = (const float*)d_in[11];
    const float* al2   = (const float*)d_in[12];
    const float* ar2   = (const float*)d_in[13];
    const float* b2    = (const float*)d_in[14];
    const float* resW2 = (const float*)d_in[15];
    const float* W0    = (const float*)d_in[3];

    const int n = NNODES;
    const int E = in_sizes[1];

    float* logits = (float*)d_out;
    float* h1     = (float*)d_out + n * 40;

    float *ph0, *pr2, *pel, *per;
    __half* pzh;
    __nv_bfloat16 *pAh, *pAl;
    cudaGetSymbolAddress((void**)&pzh, g_zh);
    cudaGetSymbolAddress((void**)&ph0, g_h0);
    cudaGetSymbolAddress((void**)&pr2, g_r2);
    cudaGetSymbolAddress((void**)&pel, g_el);
    cudaGetSymbolAddress((void**)&per, g_er);
    cudaGetSymbolAddress((void**)&pAh, g_Ahi);
    cudaGetSymbolAddress((void**)&pAl, g_Alo);

    cudaFuncSetAttribute(k_gemm0, cudaFuncAttributeMaxDynamicSharedMemorySize, GEMM_SMEM);
    cudaFuncSetAttribute(k_gemm1, cudaFuncAttributeMaxDynamicSharedMemorySize, GEMM_SMEM);
    cudaFuncSetAttribute(k_gemm2, cudaFuncAttributeMaxDynamicSharedMemorySize, GEMM_SMEM);

    const int nGemm = ((n + 127) / 128) * 2;          // 782
    const int histBlocks = (E + 255) / 256;
    const int scatBlocks = (E + 511) / 512;
    const int zeroBlocks = (n * 6 + 255) / 256;       // 1172
    const int aggBlocks  = (n + 7) / 8;

    // 1. zero deg + el/er(L0)
    k_zero0<<<zeroBlocks, 256>>>(n, n * 6);
    // 2. splitA(feat) + splitBt(W0) + hist
    k_prep0<<<SPLITA_BLOCKS + 256 + histBlocks, 256>>>(feat, W0, dst, E);
    // 3. scan
    k_scan<<<1, 1024>>>(n, E);
    // 4. gemm L0 + scatter
    k_gemm0<<<nGemm + scatBlocks, 512, GEMM_SMEM>>>(pAh, pAl, pzh, al0, ar0, pel, per,
                                                    n, nGemm, src, dst, E);
    // 5. agg L0
    k_agg256<false><<<aggBlocks, 256>>>(pzh, pel, per, b0, nullptr, ph0, pAh, pAl, n);
    // 6. prep L1
    k_prep1<<<256 + zeroBlocks, 256>>>(W1, n * 6);
    // 7. gemm L1
    k_gemm1<<<nGemm, 512, GEMM_SMEM>>>(pAh, pAl, pzh, al1, ar1, pel, per, n);
    // 8. agg L1 -> h1 (in d_out)
    k_agg256<true><<<aggBlocks, 256>>>(pzh, pel, per, b1, ph0, h1, pAh, pAl, n);
    // 9. prep L2
    k_prep2<<<512 + zeroBlocks, 256>>>(W2, resW2, n * 6);
    // 10. gemm L2 dual (W2 + resW2)
    k_gemm2<<<2 * nGemm, 512, GEMM_SMEM>>>(pAh, pAl, pzh, pr2, al2, ar2, pel, per, n, nGemm);
    // 11. agg L2 -> logits
    k_agg_l2<<<aggBlocks, 256>>>(pzh, pel, per, b2, pr2, logits, n);
}

// round 7
// speedup vs baseline: 2.5895x; 1.0333x over previous
#include <cuda_runtime.h>
#include <cuda_bf16.h>
#include <cuda_fp16.h>
#include <math.h>
#include <cstdint>

// ---------------- problem constants ----------------
#define NNODES 50000
#define ECAP   1000000
#define SPLITA_BLOCKS 12500   // (NNODES*256/4)/256

// ---------------- device scratch ----------------
__device__ __align__(16) __half g_zh[NNODES * 256];
__device__ float g_h0[NNODES * 256];
__device__ float g_r2[NNODES * 240];
__device__ float g_el[NNODES * 6];
__device__ float g_er[NNODES * 6];
__device__ int   g_deg[NNODES];
__device__ int   g_rowstart[NNODES + 1];
__device__ int   g_cursor[NNODES];
__device__ int   g_srcs[ECAP];
__device__ __align__(16) __nv_bfloat16 g_Ahi[NNODES * 256];
__device__ __align__(16) __nv_bfloat16 g_Alo[NNODES * 256];
__device__ __align__(16) __nv_bfloat16 g_Bth[256 * 256];
__device__ __align__(16) __nv_bfloat16 g_Btl[256 * 256];
__device__ __align__(16) __nv_bfloat16 g_Bth2[256 * 256];
__device__ __align__(16) __nv_bfloat16 g_Btl2[256 * 256];

// ================= PTX helpers =================
__device__ __forceinline__ uint32_t smem_u32(const void* p) {
    uint32_t a;
    asm("{ .reg .u64 t; cvta.to.shared.u64 t, %1; cvt.u32.u64 %0, t; }" : "=r"(a) : "l"(p));
    return a;
}
__device__ __forceinline__ void cp16(uint32_t dst, const void* src, uint32_t srcsize) {
    asm volatile("cp.async.cg.shared.global [%0], [%1], 16, %2;"
                 :: "r"(dst), "l"(src), "r"(srcsize));
}
#define CP_COMMIT() asm volatile("cp.async.commit_group;" ::: "memory")
#define CP_WAIT(n)  asm volatile("cp.async.wait_group %0;" :: "n"(n) : "memory")
#define LDSM_X4(r0, r1, r2, r3, addr) \
    asm volatile("ldmatrix.sync.aligned.m8n8.x4.shared.b16 {%0,%1,%2,%3}, [%4];" \
        : "=r"(r0), "=r"(r1), "=r"(r2), "=r"(r3) : "r"(addr))
#define MMA_BF16(acc, a, b) \
    asm volatile("mma.sync.aligned.m16n8k16.row.col.f32.bf16.bf16.f32 " \
        "{%0,%1,%2,%3}, {%4,%5,%6,%7}, {%8,%9}, {%0,%1,%2,%3};" \
        : "+f"((acc)[0]), "+f"((acc)[1]), "+f"((acc)[2]), "+f"((acc)[3]) \
        : "r"((a)[0]), "r"((a)[1]), "r"((a)[2]), "r"((a)[3]), "r"((b)[0]), "r"((b)[1]))

// ---------------- helper device funcs ----------------
__device__ __forceinline__ void splitBt_elem(const float* __restrict__ B,
                                             __nv_bfloat16* th, __nv_bfloat16* tl,
                                             int t, int Nn) {
    int nrow = t >> 8, k = t & 255;
    float x = (nrow < Nn) ? B[(size_t)k * Nn + nrow] : 0.f;
    __nv_bfloat16 h = __float2bfloat16_rn(x);
    th[t] = h;
    tl[t] = __float2bfloat16_rn(x - __bfloat162float(h));
}

// ---------------- kernel 1: zero deg + el/er ----------------
__global__ void k_zero0(int n, int n6) {
    int i = blockIdx.x * blockDim.x + threadIdx.x;
    if (i < n) g_deg[i] = 0;
    if (i < n6) { g_el[i] = 0.f; g_er[i] = 0.f; }
}

// ---------------- kernel 2: splitA(feat) + splitBt(W0) + hist ----------------
__global__ void k_prep0(const float* __restrict__ feat, const float* __restrict__ W0,
                        const int* __restrict__ dst, int E) {
    int bx = blockIdx.x;
    if (bx < SPLITA_BLOCKS) {
        int i = bx * 256 + threadIdx.x;
        float4 v = reinterpret_cast<const float4*>(feat)[i];
        __nv_bfloat16 h0 = __float2bfloat16_rn(v.x);
        __nv_bfloat16 h1 = __float2bfloat16_rn(v.y);
        __nv_bfloat16 h2 = __float2bfloat16_rn(v.z);
        __nv_bfloat16 h3 = __float2bfloat16_rn(v.w);
        reinterpret_cast<ushort4*>(g_Ahi)[i] = make_ushort4(
            __bfloat16_as_ushort(h0), __bfloat16_as_ushort(h1),
            __bfloat16_as_ushort(h2), __bfloat16_as_ushort(h3));
        reinterpret_cast<ushort4*>(g_Alo)[i] = make_ushort4(
            __bfloat16_as_ushort(__float2bfloat16_rn(v.x - __bfloat162float(h0))),
            __bfloat16_as_ushort(__float2bfloat16_rn(v.y - __bfloat162float(h1))),
            __bfloat16_as_ushort(__float2bfloat16_rn(v.z - __bfloat162float(h2))),
            __bfloat16_as_ushort(__float2bfloat16_rn(v.w - __bfloat162float(h3))));
    } else if (bx < SPLITA_BLOCKS + 256) {
        int t = (bx - SPLITA_BLOCKS) * 256 + threadIdx.x;
        splitBt_elem(W0, g_Bth, g_Btl, t, 256);
    } else {
        int e = (bx - SPLITA_BLOCKS - 256) * 256 + threadIdx.x;
        if (e < E) atomicAdd(&g_deg[dst[e]], 1);
    }
}

// ---------------- kernel: scan ----------------
__global__ void k_scan(int n, int E) {
    __shared__ int wsum[32];
    __shared__ int carry;
    int lane = threadIdx.x & 31, w = threadIdx.x >> 5;
    if (threadIdx.x == 0) carry = 0;
    __syncthreads();
    for (int base = 0; base < n; base += 1024) {
        int i = base + threadIdx.x;
        int v = (i < n) ? g_deg[i] : 0;
        int x = v;
        #pragma unroll
        for (int off = 1; off < 32; off <<= 1) {
            int t = __shfl_up_sync(0xffffffffu, x, off);
            if (lane >= off) x += t;
        }
        if (lane == 31) wsum[w] = x;
        __syncthreads();
        if (w == 0) {
            int y = wsum[lane];
            #pragma unroll
            for (int off = 1; off < 32; off <<= 1) {
                int t = __shfl_up_sync(0xffffffffu, y, off);
                if (lane >= off) y += t;
            }
            wsum[lane] = y;
        }
        __syncthreads();
        int incl = x + (w ? wsum[w - 1] : 0) + carry;
        int excl = incl - v;
        if (i < n) { g_rowstart[i] = excl; g_cursor[i] = excl; }
        __syncthreads();
        if (threadIdx.x == 1023) carry = incl;
        __syncthreads();
    }
    if (threadIdx.x == 0) g_rowstart[n] = E;
}

// ---------------- prep1 / prep2 ----------------
__global__ void k_prep1(const float* __restrict__ W1, int n6) {
    int bx = blockIdx.x;
    if (bx < 256) {
        splitBt_elem(W1, g_Bth, g_Btl, bx * 256 + threadIdx.x, 256);
    } else {
        int i = (bx - 256) * 256 + threadIdx.x;
        if (i < n6) { g_el[i] = 0.f; g_er[i] = 0.f; }
    }
}
__global__ void k_prep2(const float* __restrict__ W2, const float* __restrict__ resW2, int n6) {
    int bx = blockIdx.x;
    if (bx < 256) {
        splitBt_elem(W2, g_Bth, g_Btl, bx * 256 + threadIdx.x, 240);
    } else if (bx < 512) {
        splitBt_elem(resW2, g_Bth2, g_Btl2, (bx - 512 + 256) * 256 + threadIdx.x, 240);
    } else {
        int i = (bx - 512) * 256 + threadIdx.x;
        if (i < n6) { g_el[i] = 0.f; g_er[i] = 0.f; }
    }
}

// ---------------- GEMM body (mma.sync split-bf16, 3-stage cp.async pipeline) ----------------
#define STAGE_BYTES 65536
#define GEMM_SMEM   (3 * STAGE_BYTES)

__device__ __forceinline__ void gemm_load_stage(
    uint32_t sb, const __nv_bfloat16* __restrict__ Ahi, const __nv_bfloat16* __restrict__ Alo,
    const __nv_bfloat16* __restrict__ Bth, const __nv_bfloat16* __restrict__ Btl,
    int m0, int n0, int M, int kb, int tid)
{
    #pragma unroll
    for (int it = 0; it < 4; ++it) {
        int idx = tid + it * 512;
        int prec = idx >> 10, rem = idx & 1023;
        int row = rem >> 3, ch = rem & 7;
        uint32_t dst = sb + prec * 16384 + row * 128 + (((uint32_t)(ch ^ (row & 7))) << 4);
        const __nv_bfloat16* srcb = prec ? Alo : Ahi;
        const __nv_bfloat16* src = srcb + (size_t)(m0 + row) * 256 + kb * 64 + ch * 8;
        cp16(dst, src, (m0 + row) < M ? 16u : 0u);
    }
    #pragma unroll
    for (int it = 0; it < 4; ++it) {
        int idx = tid + it * 512;
        int prec = idx >> 10, rem = idx & 1023;
        int row = rem >> 3, ch = rem & 7;
        uint32_t dst = sb + 32768 + prec * 16384 + row * 128 + (((uint32_t)(ch ^ (row & 7))) << 4);
        const __nv_bfloat16* srcb = prec ? Btl : Bth;
        const __nv_bfloat16* src = srcb + (size_t)(n0 + row) * 256 + kb * 64 + ch * 8;
        cp16(dst, src, 16u);
    }
}

template <bool ELR>
__device__ __forceinline__ void gemm_body(
    const __nv_bfloat16* __restrict__ Ahi, const __nv_bfloat16* __restrict__ Alo,
    const __nv_bfloat16* __restrict__ Bth, const __nv_bfloat16* __restrict__ Btl,
    __half* __restrict__ Ch, float* __restrict__ Cf,
    const float* __restrict__ al, const float* __restrict__ ar,
    float* __restrict__ el, float* __restrict__ er,
    int M, int Nn, int H, int D, int m0, int n0)
{
    extern __shared__ char smem[];
    const uint32_t sbase = smem_u32(smem);
    const int tid = threadIdx.x, wid = tid >> 5, lane = tid & 31;
    const int warp_m = wid & 3, warp_n = wid >> 2;

    float acc[2][4][4];
    #pragma unroll
    for (int mt = 0; mt < 2; ++mt)
        #pragma unroll
        for (int nt = 0; nt < 4; ++nt)
            #pragma unroll
            for (int q = 0; q < 4; ++q) acc[mt][nt][q] = 0.f;

    const int rowA = warp_m * 32 + (lane & 15);
    const int rowB = warp_n * 32 + (lane & 7) + ((lane >> 4) << 3);
    const uint32_t rowAswz = (uint32_t)(rowA & 7);
    const uint32_t rowBswz = (uint32_t)(rowB & 7);
    const int halfA = lane >> 4;
    const int halfB = (lane >> 3) & 1;

    // prologue: stages 0 and 1 in flight
    gemm_load_stage(sbase, Ahi, Alo, Bth, Btl, m0, n0, M, 0, tid);
    CP_COMMIT();
    gemm_load_stage(sbase + STAGE_BYTES, Ahi, Alo, Bth, Btl, m0, n0, M, 1, tid);
    CP_COMMIT();

    #pragma unroll 1
    for (int kb = 0; kb < 4; ++kb) {
        if (kb < 3) { CP_WAIT(1); } else { CP_WAIT(0); }
        __syncthreads();   // stage kb visible to all; all warps done with buf (kb+2)%3
        if (kb < 2) {
            gemm_load_stage(sbase + ((kb + 2) % 3) * STAGE_BYTES,
                            Ahi, Alo, Bth, Btl, m0, n0, M, kb + 2, tid);
            CP_COMMIT();
        }
        const uint32_t sb = sbase + (kb % 3) * STAGE_BYTES;
        #pragma unroll
        for (int s = 0; s < 4; ++s) {
            uint32_t a[2][2][4];
            uint32_t b[2][4][2];
            const uint32_t offA = (((uint32_t)(s * 2 + halfA) ^ rowAswz) << 4);
            const uint32_t offB = (((uint32_t)(s * 2 + halfB) ^ rowBswz) << 4);
            #pragma unroll
            for (int prec = 0; prec < 2; ++prec) {
                uint32_t baseA = sb + prec * 16384;
                #pragma unroll
                for (int mt = 0; mt < 2; ++mt) {
                    uint32_t addr = baseA + (uint32_t)(rowA + mt * 16) * 128 + offA;
                    LDSM_X4(a[prec][mt][0], a[prec][mt][1], a[prec][mt][2], a[prec][mt][3], addr);
                }
                uint32_t baseB = sb + 32768 + prec * 16384;
                #pragma unroll
                for (int ntp = 0; ntp < 2; ++ntp) {
                    uint32_t addr = baseB + (uint32_t)(rowB + ntp * 16) * 128 + offB;
                    LDSM_X4(b[prec][2 * ntp][0], b[prec][2 * ntp][1],
                            b[prec][2 * ntp + 1][0], b[prec][2 * ntp + 1][1], addr);
                }
            }
            #pragma unroll
            for (int mt = 0; mt < 2; ++mt)
                #pragma unroll
                for (int nt = 0; nt < 4; ++nt) {
                    MMA_BF16(acc[mt][nt], a[0][mt], b[0][nt]);
                    MMA_BF16(acc[mt][nt], a[0][mt], b[1][nt]);
                    MMA_BF16(acc[mt][nt], a[1][mt], b[0][nt]);
                }
        }
    }

    #pragma unroll
    for (int mt = 0; mt < 2; ++mt) {
        int row = m0 + warp_m * 32 + mt * 16 + (lane >> 2);
        #pragma unroll
        for (int nt = 0; nt < 4; ++nt) {
            int col = n0 + warp_n * 32 + nt * 8 + (lane & 3) * 2;
            if (col < Nn) {
                if (ELR) {
                    if (row < M)
                        *reinterpret_cast<__half2*>(Ch + (size_t)row * Nn + col) =
                            __floats2half2_rn(acc[mt][nt][0], acc[mt][nt][1]);
                    if (row + 8 < M)
                        *reinterpret_cast<__half2*>(Ch + (size_t)(row + 8) * Nn + col) =
                            __floats2half2_rn(acc[mt][nt][2], acc[mt][nt][3]);
                } else {
                    if (row < M)
                        *reinterpret_cast<float2*>(Cf + (size_t)row * Nn + col) =
                            make_float2(acc[mt][nt][0], acc[mt][nt][1]);
                    if (row + 8 < M)
                        *reinterpret_cast<float2*>(Cf + (size_t)(row + 8) * Nn + col) =
                            make_float2(acc[mt][nt][2], acc[mt][nt][3]);
                }
            }
        }
    }

    if (ELR) {
        const int colbase = n0 + warp_n * 32;
        const int h0 = colbase / D;
        int nt_split = ((h0 + 1) * D - colbase) >> 3;
        if (nt_split > 4) nt_split = 4;
        float sl[2][2][2] = {}, sr[2][2][2] = {};
        #pragma unroll
        for (int nt = 0; nt < 4; ++nt) {
            int colg = colbase + nt * 8;
            float2 av = make_float2(0.f, 0.f), rv = av;
            if (colg < Nn) {
                int h = (nt < nt_split) ? h0 : (h0 + 1);
                int d = colg - h * D + (lane & 3) * 2;
                av = __ldg(reinterpret_cast<const float2*>(al + h * D + d));
                rv = __ldg(reinterpret_cast<const float2*>(ar + h * D + d));
            }
            int slot = (nt >= nt_split);
            #pragma unroll
            for (int mt = 0; mt < 2; ++mt) {
                sl[mt][0][slot] += acc[mt][nt][0] * av.x + acc[mt][nt][1] * av.y;
                sr[mt][0][slot] += acc[mt][nt][0] * rv.x + acc[mt][nt][1] * rv.y;
                sl[mt][1][slot] += acc[mt][nt][2] * av.x + acc[mt][nt][3] * av.y;
                sr[mt][1][slot] += acc[mt][nt][2] * rv.x + acc[mt][nt][3] * rv.y;
            }
        }
        #pragma unroll
        for (int mt = 0; mt < 2; ++mt)
            #pragma unroll
            for (int rh = 0; rh < 2; ++rh)
                #pragma unroll
                for (int sidx = 0; sidx < 2; ++sidx) {
                    float vl = sl[mt][rh][sidx], vr = sr[mt][rh][sidx];
                    vl += __shfl_xor_sync(0xffffffffu, vl, 1);
                    vl += __shfl_xor_sync(0xffffffffu, vl, 2);
                    vr += __shfl_xor_sync(0xffffffffu, vr, 1);
                    vr += __shfl_xor_sync(0xffffffffu, vr, 2);
                    sl[mt][rh][sidx] = vl; sr[mt][rh][sidx] = vr;
                }
        if ((lane & 3) == 0) {
            bool slot1_valid = (nt_split < 4) && (colbase + nt_split * 8) < Nn;
            #pragma unroll
            for (int mt = 0; mt < 2; ++mt) {
                #pragma unroll
                for (int rh = 0; rh < 2; ++rh) {
                    int row = m0 + warp_m * 32 + mt * 16 + (lane >> 2) + rh * 8;
                    if (row < M) {
                        atomicAdd(&el[(size_t)row * H + h0], sl[mt][rh][0]);
                        atomicAdd(&er[(size_t)row * H + h0], sr[mt][rh][0]);
                        if (slot1_valid) {
                            atomicAdd(&el[(size_t)row * H + h0 + 1], sl[mt][rh][1]);
                            atomicAdd(&er[(size_t)row * H + h0 + 1], sr[mt][rh][1]);
                        }
                    }
                }
            }
        }
    }
}

// ---------------- GEMM launches ----------------
__global__ __launch_bounds__(512, 1) void k_gemm0(
    const __nv_bfloat16* __restrict__ Ahi, const __nv_bfloat16* __restrict__ Alo,
    __half* __restrict__ Ch, const float* __restrict__ al, const float* __restrict__ ar,
    float* __restrict__ el, float* __restrict__ er, int M, int nGemm,
    const int* __restrict__ src, const int* __restrict__ dst, int E)
{
    int bx = blockIdx.x;
    if (bx < nGemm) {
        gemm_body<true>(Ahi, Alo, g_Bth, g_Btl, Ch, nullptr, al, ar, el, er,
                        M, 256, 4, 64, (bx >> 1) * 128, (bx & 1) * 128);
    } else {
        int e = (bx - nGemm) * 512 + threadIdx.x;
        if (e < E) {
            int p = atomicAdd(&g_cursor[dst[e]], 1);
            g_srcs[p] = src[e];
        }
    }
}

__global__ __launch_bounds__(512, 1) void k_gemm1(
    const __nv_bfloat16* __restrict__ Ahi, const __nv_bfloat16* __restrict__ Alo,
    __half* __restrict__ Ch, const float* __restrict__ al, const float* __restrict__ ar,
    float* __restrict__ el, float* __restrict__ er, int M)
{
    int bx = blockIdx.x;
    gemm_body<true>(Ahi, Alo, g_Bth, g_Btl, Ch, nullptr, al, ar, el, er,
                    M, 256, 4, 64, (bx >> 1) * 128, (bx & 1) * 128);
}

__global__ __launch_bounds__(512, 1) void k_gemm2(
    const __nv_bfloat16* __restrict__ Ahi, const __nv_bfloat16* __restrict__ Alo,
    __half* __restrict__ Ch, float* __restrict__ Cf,
    const float* __restrict__ al, const float* __restrict__ ar,
    float* __restrict__ el, float* __restrict__ er, int M, int nGemm)
{
    int bx = blockIdx.x;
    if (bx < nGemm) {
        gemm_body<true>(Ahi, Alo, g_Bth, g_Btl, Ch, nullptr, al, ar, el, er,
                        M, 240, 6, 40, (bx >> 1) * 128, (bx & 1) * 128);
    } else {
        int b2 = bx - nGemm;
        gemm_body<false>(Ahi, Alo, g_Bth2, g_Btl2, nullptr, Cf, nullptr, nullptr,
                         nullptr, nullptr, M, 240, 1, 64, (b2 >> 1) * 128, (b2 & 1) * 128);
    }
}

// ---------------- aggregation helpers ----------------
__device__ __forceinline__ void fma_row(float4& a0, float4& a1, float wh, uint4 q) {
    float2 p0 = __half22float2(*reinterpret_cast<__half2*>(&q.x));
    float2 p1 = __half22float2(*reinterpret_cast<__half2*>(&q.y));
    float2 p2 = __half22float2(*reinterpret_cast<__half2*>(&q.z));
    float2 p3 = __half22float2(*reinterpret_cast<__half2*>(&q.w));
    a0.x = fmaf(wh, p0.x, a0.x); a0.y = fmaf(wh, p0.y, a0.y);
    a0.z = fmaf(wh, p1.x, a0.z); a0.w = fmaf(wh, p1.y, a0.w);
    a1.x = fmaf(wh, p2.x, a1.x); a1.y = fmaf(wh, p2.y, a1.y);
    a1.z = fmaf(wh, p3.x, a1.z); a1.w = fmaf(wh, p3.y, a1.w);
}

// ---------------- aggregation, layers 0/1 ----------------
template <bool RES>
__global__ __launch_bounds__(256) void k_agg256(
    const __half* __restrict__ zh, const float* __restrict__ el,
    const float* __restrict__ er, const float* __restrict__ bias,
    const float* __restrict__ xres, float* __restrict__ out,
    __nv_bfloat16* __restrict__ ohi, __nv_bfloat16* __restrict__ olo, int n)
{
    int gw = (blockIdx.x * blockDim.x + threadIdx.x) >> 5;
    if (gw >= n) return;
    int lane = threadIdx.x & 31;
    int beg = g_rowstart[gw], end = g_rowstart[gw + 1];
    float erh = (lane < 4) ? __ldg(&er[gw * 4 + lane]) : 0.f;
    int h = lane >> 3;
    int c0 = lane * 8;
    float4 acc0 = make_float4(0.f, 0.f, 0.f, 0.f), acc1 = acc0;
    float denom = 0.f;
    int i = beg;
    #pragma unroll 1
    for (; i + 2 <= end; i += 2) {
        int s0 = __ldg(&g_srcs[i]);
        int s1 = __ldg(&g_srcs[i + 1]);
        uint4 q0 = __ldg(reinterpret_cast<const uint4*>(zh + (size_t)s0 * 256 + c0));
        uint4 q1 = __ldg(reinterpret_cast<const uint4*>(zh + (size_t)s1 * 256 + c0));
        float w0 = 0.f, w1 = 0.f;
        if (lane < 4) {
            float e0 = __ldg(&el[s0 * 4 + lane]) + erh;
            float e1 = __ldg(&el[s1 * 4 + lane]) + erh;
            e0 = (e0 > 0.f) ? e0 : 0.2f * e0;
            e1 = (e1 > 0.f) ? e1 : 0.2f * e1;
            w0 = __expf(e0); w1 = __expf(e1);
            denom += w0 + w1;
        }
        float wh0 = __shfl_sync(0xffffffffu, w0, h);
        float wh1 = __shfl_sync(0xffffffffu, w1, h);
        fma_row(acc0, acc1, wh0, q0);
        fma_row(acc0, acc1, wh1, q1);
    }
    if (i < end) {
        int s0 = __ldg(&g_srcs[i]);
        uint4 q0 = __ldg(reinterpret_cast<const uint4*>(zh + (size_t)s0 * 256 + c0));
        float w0 = 0.f;
        if (lane < 4) {
            float e0 = __ldg(&el[s0 * 4 + lane]) + erh;
            e0 = (e0 > 0.f) ? e0 : 0.2f * e0;
            w0 = __expf(e0);
            denom += w0;
        }
        float wh0 = __shfl_sync(0xffffffffu, w0, h);
        fma_row(acc0, acc1, wh0, q0);
    }
    float dh = __shfl_sync(0xffffffffu, denom, h);
    float inv = 1.f / dh;
    const float4* bp = reinterpret_cast<const float4*>(bias + c0);
    float4 b0 = __ldg(bp), b1 = __ldg(bp + 1);
    float v[8];
    v[0] = fmaf(acc0.x, inv, b0.x); v[1] = fmaf(acc0.y, inv, b0.y);
    v[2] = fmaf(acc0.z, inv, b0.z); v[3] = fmaf(acc0.w, inv, b0.w);
    v[4] = fmaf(acc1.x, inv, b1.x); v[5] = fmaf(acc1.y, inv, b1.y);
    v[6] = fmaf(acc1.z, inv, b1.z); v[7] = fmaf(acc1.w, inv, b1.w);
    if (RES) {
        const float4* rp = reinterpret_cast<const float4*>(xres + (size_t)gw * 256 + c0);
        float4 r0 = __ldg(rp), r1 = __ldg(rp + 1);
        v[0] += r0.x; v[1] += r0.y; v[2] += r0.z; v[3] += r0.w;
        v[4] += r1.x; v[5] += r1.y; v[6] += r1.z; v[7] += r1.w;
    }
    #pragma unroll
    for (int j = 0; j < 8; ++j) v[j] = (v[j] > 0.f) ? v[j] : expm1f(v[j]);
    float4* op = reinterpret_cast<float4*>(out + (size_t)gw * 256 + c0);
    op[0] = make_float4(v[0], v[1], v[2], v[3]);
    op[1] = make_float4(v[4], v[5], v[6], v[7]);
    ushort hi[8], lo[8];
    #pragma unroll
    for (int j = 0; j < 8; ++j) {
        __nv_bfloat16 hh = __float2bfloat16_rn(v[j]);
        hi[j] = __bfloat16_as_ushort(hh);
        lo[j] = __bfloat16_as_ushort(__float2bfloat16_rn(v[j] - __bfloat162float(hh)));
    }
    ushort4* hp = reinterpret_cast<ushort4*>(ohi + (size_t)gw * 256 + c0);
    ushort4* lp = reinterpret_cast<ushort4*>(olo + (size_t)gw * 256 + c0);
    hp[0] = make_ushort4(hi[0], hi[1], hi[2], hi[3]);
    hp[1] = make_ushort4(hi[4], hi[5], hi[6], hi[7]);
    lp[0] = make_ushort4(lo[0], lo[1], lo[2], lo[3]);
    lp[1] = make_ushort4(lo[4], lo[5], lo[6], lo[7]);
}

// ---------------- aggregation, layer 2 ----------------
__global__ __launch_bounds__(256) void k_agg_l2(
    const __half* __restrict__ zh, const float* __restrict__ el,
    const float* __restrict__ er, const float* __restrict__ bias,
    const float* __restrict__ res, float* __restrict__ logits, int n)
{
    __shared__ float sout[8][240];
    int wInB = threadIdx.x >> 5;
    int gw = blockIdx.x * 8 + wInB;
    int lane = threadIdx.x & 31;
    bool act = (lane < 30);
    if (gw < n) {
        int beg = g_rowstart[gw], end = g_rowstart[gw + 1];
        float erh = (lane < 6) ? __ldg(&er[gw * 6 + lane]) : 0.f;
        int h = act ? (lane / 5) : 0;
        int c0 = lane * 8;
        float4 acc0 = make_float4(0.f, 0.f, 0.f, 0.f), acc1 = acc0;
        float denom = 0.f;
        int i = beg;
        #pragma unroll 1
        for (; i + 2 <= end; i += 2) {
            int s0 = __ldg(&g_srcs[i]);
            int s1 = __ldg(&g_srcs[i + 1]);
            uint4 q0 = make_uint4(0, 0, 0, 0), q1 = q0;
            if (act) {
                q0 = __ldg(reinterpret_cast<const uint4*>(zh + (size_t)s0 * 240 + c0));
                q1 = __ldg(reinterpret_cast<const uint4*>(zh + (size_t)s1 * 240 + c0));
            }
            float w0 = 0.f, w1 = 0.f;
            if (lane < 6) {
                float e0 = __ldg(&el[s0 * 6 + lane]) + erh;
                float e1 = __ldg(&el[s1 * 6 + lane]) + erh;
                e0 = (e0 > 0.f) ? e0 : 0.2f * e0;
                e1 = (e1 > 0.f) ? e1 : 0.2f * e1;
                w0 = __expf(e0); w1 = __expf(e1);
                denom += w0 + w1;
            }
            float wh0 = __shfl_sync(0xffffffffu, w0, h);
            float wh1 = __shfl_sync(0xffffffffu, w1, h);
            if (act) {
                fma_row(acc0, acc1, wh0, q0);
                fma_row(acc0, acc1, wh1, q1);
            }
        }
        if (i < end) {
            int s0 = __ldg(&g_srcs[i]);
            uint4 q0 = make_uint4(0, 0, 0, 0);
            if (act) q0 = __ldg(reinterpret_cast<const uint4*>(zh + (size_t)s0 * 240 + c0));
            float w0 = 0.f;
            if (lane < 6) {
                float e0 = __ldg(&el[s0 * 6 + lane]) + erh;
                e0 = (e0 > 0.f) ? e0 : 0.2f * e0;
                w0 = __expf(e0);
                denom += w0;
            }
            float wh0 = __shfl_sync(0xffffffffu, w0, h);
            if (act) fma_row(acc0, acc1, wh0, q0);
        }
        float dh = __shfl_sync(0xffffffffu, denom, h);
        if (act) {
            float inv = 1.f / dh;
            const float4* bp = reinterpret_cast<const float4*>(bias + c0);
            const float4* rp = reinterpret_cast<const float4*>(res + (size_t)gw * 240 + c0);
            float4 b0 = __ldg(bp), b1 = __ldg(bp + 1);
            float4 r0 = __ldg(rp), r1 = __ldg(rp + 1);
            sout[wInB][c0 + 0] = fmaf(acc0.x, inv, b0.x) + r0.x;
            sout[wInB][c0 + 1] = fmaf(acc0.y, inv, b0.y) + r0.y;
            sout[wInB][c0 + 2] = fmaf(acc0.z, inv, b0.z) + r0.z;
            sout[wInB][c0 + 3] = fmaf(acc0.w, inv, b0.w) + r0.w;
            sout[wInB][c0 + 4] = fmaf(acc1.x, inv, b1.x) + r1.x;
            sout[wInB][c0 + 5] = fmaf(acc1.y, inv, b1.y) + r1.y;
            sout[wInB][c0 + 6] = fmaf(acc1.z, inv, b1.z) + r1.z;
            sout[wInB][c0 + 7] = fmaf(acc1.w, inv, b1.w) + r1.w;
        }
    }
    __syncwarp();
    if (gw < n) {
        for (int d = lane; d < 40; d += 32) {
            float s_ = 0.f;
            #pragma unroll
            for (int hh = 0; hh < 6; ++hh) s_ += sout[wInB][hh * 40 + d];
            logits[(size_t)gw * 40 + d] = s_ * (1.0f / 6.0f);
        }
    }
}

// ---------------- host ----------------
extern "C" void kernel_launch(void* const* d_in, const int* in_sizes, int n_in,
                              void* d_out, int out_size)
{
    const float* feat  = (const float*)d_in[0];
    const int*   src   = (const int*)d_in[1];
    const int*   dst   = (const int*)d_in[2];
    const float* W0    = (const float*)d_in[3];
    const float* al0   = (const float*)d_in[4];
    const float* ar0   = (const float*)d_in[5];
    const float* b0    = (const float*)d_in[6];
    const float* W1    = (const float*)d_in[7];
    const float* al1   = (const float*)d_in[8];
    const float* ar1   = (const float*)d_in[9];
    const float* b1    = (const float*)d_in[10];
    const float* W2    = (const float*)d_in[11];
    const float* al2   = (const float*)d_in[12];
    const float* ar2   = (const float*)d_in[13];
    const float* b2    = (const float*)d_in[14];
    const float* resW2 = (const float*)d_in[15];

    const int n = NNODES;
    const int E = in_sizes[1];

    float* logits = (float*)d_out;
    float* h1     = (float*)d_out + n * 40;

    float *ph0, *pr2, *pel, *per;
    __half* pzh;
    __nv_bfloat16 *pAh, *pAl;
    cudaGetSymbolAddress((void**)&pzh, g_zh);
    cudaGetSymbolAddress((void**)&ph0, g_h0);
    cudaGetSymbolAddress((void**)&pr2, g_r2);
    cudaGetSymbolAddress((void**)&pel, g_el);
    cudaGetSymbolAddress((void**)&per, g_er);
    cudaGetSymbolAddress((void**)&pAh, g_Ahi);
    cudaGetSymbolAddress((void**)&pAl, g_Alo);

    cudaFuncSetAttribute(k_gemm0, cudaFuncAttributeMaxDynamicSharedMemorySize, GEMM_SMEM);
    cudaFuncSetAttribute(k_gemm1, cudaFuncAttributeMaxDynamicSharedMemorySize, GEMM_SMEM);
    cudaFuncSetAttribute(k_gemm2, cudaFuncAttributeMaxDynamicSharedMemorySize, GEMM_SMEM);

    const int nGemm = ((n + 127) / 128) * 2;          // 782
    const int histBlocks = (E + 255) / 256;
    const int scatBlocks = (E + 511) / 512;
    const int zeroBlocks = (n * 6 + 255) / 256;
    const int aggBlocks  = (n + 7) / 8;

    // 1. zero deg + el/er(L0)
    k_zero0<<<zeroBlocks, 256>>>(n, n * 6);
    // 2. splitA(feat) + splitBt(W0) + hist
    k_prep0<<<SPLITA_BLOCKS + 256 + histBlocks, 256>>>(feat, W0, dst, E);
    // 3. scan
    k_scan<<<1, 1024>>>(n, E);
    // 4. gemm L0 + scatter
    k_gemm0<<<nGemm + scatBlocks, 512, GEMM_SMEM>>>(pAh, pAl, pzh, al0, ar0, pel, per,
                                                    n, nGemm, src, dst, E);
    // 5. agg L0
    k_agg256<false><<<aggBlocks, 256>>>(pzh, pel, per, b0, nullptr, ph0, pAh, pAl, n);
    // 6. prep L1
    k_prep1<<<256 + zeroBlocks, 256>>>(W1, n * 6);
    // 7. gemm L1
    k_gemm1<<<nGemm, 512, GEMM_SMEM>>>(pAh, pAl, pzh, al1, ar1, pel, per, n);
    // 8. agg L1 -> h1 (in d_out)
    k_agg256<true><<<aggBlocks, 256>>>(pzh, pel, per, b1, ph0, h1, pAh, pAl, n);
    // 9. prep L2
    k_prep2<<<512 + zeroBlocks, 256>>>(W2, resW2, n * 6);
    // 10. gemm L2 dual (W2 + resW2)
    k_gemm2<<<2 * nGemm, 512, GEMM_SMEM>>>(pAh, pAl, pzh, pr2, al2, ar2, pel, per, n, nGemm);
    // 11. agg L2 -> logits
    k_agg_l2<<<aggBlocks, 256>>>(pzh, pel, per, b2, pr2, logits, n);
}

// round 8
// speedup vs baseline: 2.7314x; 1.0548x over previous
#include <cuda_runtime.h>
#include <cuda_bf16.h>
#include <cuda_fp16.h>
#include <math.h>
#include <cstdint>

// ---------------- problem constants ----------------
#define NNODES 50000
#define ECAP   1000000
#define SPLITA_BLOCKS 12500   // (NNODES*256/4)/256

// ---------------- device scratch ----------------
__device__ __align__(16) __half g_zh[NNODES * 256];
__device__ float g_h0[NNODES * 256];
__device__ float g_r2[NNODES * 40];
__device__ float g_el[NNODES * 6];
__device__ float g_er[NNODES * 6];
__device__ int   g_deg[NNODES];
__device__ int   g_rowstart[NNODES + 1];
__device__ int   g_cursor[NNODES];
__device__ int   g_srcs[ECAP];
__device__ __align__(16) __nv_bfloat16 g_Ahi[NNODES * 256];
__device__ __align__(16) __nv_bfloat16 g_Alo[NNODES * 256];
__device__ __align__(16) __nv_bfloat16 g_Bth[256 * 256];
__device__ __align__(16) __nv_bfloat16 g_Btl[256 * 256];
__device__ __align__(16) __nv_bfloat16 g_Bth2[64 * 256];   // resW2_mean, [64(d pad) x 256(k)]
__device__ __align__(16) __nv_bfloat16 g_Btl2[64 * 256];

// ================= PTX helpers =================
__device__ __forceinline__ uint32_t smem_u32(const void* p) {
    uint32_t a;
    asm("{ .reg .u64 t; cvta.to.shared.u64 t, %1; cvt.u32.u64 %0, t; }" : "=r"(a) : "l"(p));
    return a;
}
__device__ __forceinline__ void cp16(uint32_t dst, const void* src, uint32_t srcsize) {
    asm volatile("cp.async.cg.shared.global [%0], [%1], 16, %2;"
                 :: "r"(dst), "l"(src), "r"(srcsize));
}
#define CP_COMMIT() asm volatile("cp.async.commit_group;" ::: "memory")
#define CP_WAIT(n)  asm volatile("cp.async.wait_group %0;" :: "n"(n) : "memory")
#define LDSM_X4(r0, r1, r2, r3, addr) \
    asm volatile("ldmatrix.sync.aligned.m8n8.x4.shared.b16 {%0,%1,%2,%3}, [%4];" \
        : "=r"(r0), "=r"(r1), "=r"(r2), "=r"(r3) : "r"(addr))
#define MMA_BF16(acc, a, b) \
    asm volatile("mma.sync.aligned.m16n8k16.row.col.f32.bf16.bf16.f32 " \
        "{%0,%1,%2,%3}, {%4,%5,%6,%7}, {%8,%9}, {%0,%1,%2,%3};" \
        : "+f"((acc)[0]), "+f"((acc)[1]), "+f"((acc)[2]), "+f"((acc)[3]) \
        : "r"((a)[0]), "r"((a)[1]), "r"((a)[2]), "r"((a)[3]), "r"((b)[0]), "r"((b)[1]))

// ---------------- helper device funcs ----------------
__device__ __forceinline__ void splitBt_elem(const float* __restrict__ B,
                                             __nv_bfloat16* th, __nv_bfloat16* tl,
                                             int t, int Nn) {
    int nrow = t >> 8, k = t & 255;
    float x = (nrow < Nn) ? B[(size_t)k * Nn + nrow] : 0.f;
    __nv_bfloat16 h = __float2bfloat16_rn(x);
    th[t] = h;
    tl[t] = __float2bfloat16_rn(x - __bfloat162float(h));
}

// ---------------- kernel 1: zero deg + el/er ----------------
__global__ void k_zero0(int n, int n6) {
    int i = blockIdx.x * blockDim.x + threadIdx.x;
    if (i < n) g_deg[i] = 0;
    if (i < n6) { g_el[i] = 0.f; g_er[i] = 0.f; }
}

// ---------------- kernel 2: splitA(feat) + splitBt(W0) + hist ----------------
__global__ void k_prep0(const float* __restrict__ feat, const float* __restrict__ W0,
                        const int* __restrict__ dst, int E) {
    int bx = blockIdx.x;
    if (bx < SPLITA_BLOCKS) {
        int i = bx * 256 + threadIdx.x;
        float4 v = reinterpret_cast<const float4*>(feat)[i];
        __nv_bfloat16 h0 = __float2bfloat16_rn(v.x);
        __nv_bfloat16 h1 = __float2bfloat16_rn(v.y);
        __nv_bfloat16 h2 = __float2bfloat16_rn(v.z);
        __nv_bfloat16 h3 = __float2bfloat16_rn(v.w);
        reinterpret_cast<ushort4*>(g_Ahi)[i] = make_ushort4(
            __bfloat16_as_ushort(h0), __bfloat16_as_ushort(h1),
            __bfloat16_as_ushort(h2), __bfloat16_as_ushort(h3));
        reinterpret_cast<ushort4*>(g_Alo)[i] = make_ushort4(
            __bfloat16_as_ushort(__float2bfloat16_rn(v.x - __bfloat162float(h0))),
            __bfloat16_as_ushort(__float2bfloat16_rn(v.y - __bfloat162float(h1))),
            __bfloat16_as_ushort(__float2bfloat16_rn(v.z - __bfloat162float(h2))),
            __bfloat16_as_ushort(__float2bfloat16_rn(v.w - __bfloat162float(h3))));
    } else if (bx < SPLITA_BLOCKS + 256) {
        int t = (bx - SPLITA_BLOCKS) * 256 + threadIdx.x;
        splitBt_elem(W0, g_Bth, g_Btl, t, 256);
    } else {
        int e = (bx - SPLITA_BLOCKS - 256) * 256 + threadIdx.x;
        if (e < E) atomicAdd(&g_deg[dst[e]], 1);
    }
}

// ---------------- kernel: scan ----------------
__global__ void k_scan(int n, int E) {
    __shared__ int wsum[32];
    __shared__ int carry;
    int lane = threadIdx.x & 31, w = threadIdx.x >> 5;
    if (threadIdx.x == 0) carry = 0;
    __syncthreads();
    for (int base = 0; base < n; base += 1024) {
        int i = base + threadIdx.x;
        int v = (i < n) ? g_deg[i] : 0;
        int x = v;
        #pragma unroll
        for (int off = 1; off < 32; off <<= 1) {
            int t = __shfl_up_sync(0xffffffffu, x, off);
            if (lane >= off) x += t;
        }
        if (lane == 31) wsum[w] = x;
        __syncthreads();
        if (w == 0) {
            int y = wsum[lane];
            #pragma unroll
            for (int off = 1; off < 32; off <<= 1) {
                int t = __shfl_up_sync(0xffffffffu, y, off);
                if (lane >= off) y += t;
            }
            wsum[lane] = y;
        }
        __syncthreads();
        int incl = x + (w ? wsum[w - 1] : 0) + carry;
        int excl = incl - v;
        if (i < n) { g_rowstart[i] = excl; g_cursor[i] = excl; }
        __syncthreads();
        if (threadIdx.x == 1023) carry = incl;
        __syncthreads();
    }
    if (threadIdx.x == 0) g_rowstart[n] = E;
}

// ---------------- prep1 / prep2 ----------------
__global__ void k_prep1(const float* __restrict__ W1, int n6) {
    int bx = blockIdx.x;
    if (bx < 256) {
        splitBt_elem(W1, g_Bth, g_Btl, bx * 256 + threadIdx.x, 256);
    } else {
        int i = (bx - 256) * 256 + threadIdx.x;
        if (i < n6) { g_el[i] = 0.f; g_er[i] = 0.f; }
    }
}
// prep2: split W2 (240 cols) + head-averaged resW2_mean (64x256) + zero el/er
__global__ void k_prep2(const float* __restrict__ W2, const float* __restrict__ resW2, int n6) {
    int bx = blockIdx.x;
    if (bx < 256) {
        splitBt_elem(W2, g_Bth, g_Btl, bx * 256 + threadIdx.x, 240);
    } else if (bx < 256 + 64) {
        int t = (bx - 256) * 256 + threadIdx.x;    // t in [0, 64*256)
        int d = t >> 8, k = t & 255;
        float x = 0.f;
        if (d < 40) {
            float s_ = 0.f;
            #pragma unroll
            for (int h = 0; h < 6; ++h) s_ += resW2[(size_t)k * 240 + h * 40 + d];
            x = s_ * (1.0f / 6.0f);
        }
        __nv_bfloat16 hh = __float2bfloat16_rn(x);
        g_Bth2[t] = hh;
        g_Btl2[t] = __float2bfloat16_rn(x - __bfloat162float(hh));
    } else {
        int i = (bx - 256 - 64) * 256 + threadIdx.x;
        if (i < n6) { g_el[i] = 0.f; g_er[i] = 0.f; }
    }
}

// ---------------- GEMM body (mma.sync split-bf16, 3-stage pipeline, templated BN) ----------------
// BN=128: 512 threads, 16 warps (4x4). BN=64: 256 threads, 8 warps (4x2). Warp tile 32x32.
template <int BN>
__device__ __forceinline__ void gemm_load_stage(
    uint32_t sb, const __nv_bfloat16* __restrict__ Ahi, const __nv_bfloat16* __restrict__ Alo,
    const __nv_bfloat16* __restrict__ Bth, const __nv_bfloat16* __restrict__ Btl,
    int m0, int n0, int M, int kb, int tid)
{
    constexpr int THREADS = (BN == 128) ? 512 : 256;
    constexpr int BHALF = BN * 8;            // chunks per precision for B
    #pragma unroll
    for (int it = 0; it < 2048 / THREADS; ++it) {
        int idx = tid + it * THREADS;
        int prec = idx >> 10, rem = idx & 1023;
        int row = rem >> 3, ch = rem & 7;
        uint32_t dst = sb + prec * 16384 + row * 128 + (((uint32_t)(ch ^ (row & 7))) << 4);
        const __nv_bfloat16* srcb = prec ? Alo : Ahi;
        const __nv_bfloat16* src = srcb + (size_t)(m0 + row) * 256 + kb * 64 + ch * 8;
        cp16(dst, src, (m0 + row) < M ? 16u : 0u);
    }
    #pragma unroll
    for (int it = 0; it < (2 * BHALF) / THREADS; ++it) {
        int idx = tid + it * THREADS;
        int prec = idx / BHALF, rem = idx % BHALF;
        int row = rem >> 3, ch = rem & 7;
        uint32_t dst = sb + 32768 + prec * (BN * 128) + row * 128 + (((uint32_t)(ch ^ (row & 7))) << 4);
        const __nv_bfloat16* srcb = prec ? Btl : Bth;
        const __nv_bfloat16* src = srcb + (size_t)(n0 + row) * 256 + kb * 64 + ch * 8;
        cp16(dst, src, 16u);
    }
}

template <bool ELR, int BN>
__device__ __forceinline__ void gemm_body(
    const __nv_bfloat16* __restrict__ Ahi, const __nv_bfloat16* __restrict__ Alo,
    const __nv_bfloat16* __restrict__ Bth, const __nv_bfloat16* __restrict__ Btl,
    __half* __restrict__ Ch, float* __restrict__ Cf,
    const float* __restrict__ al, const float* __restrict__ ar,
    float* __restrict__ el, float* __restrict__ er,
    int M, int Nn, int H, int D, int m0, int n0)
{
    constexpr uint32_t STAGE = 32768u + (uint32_t)BN * 256u;
    extern __shared__ char smem[];
    const uint32_t sbase = smem_u32(smem);
    const int tid = threadIdx.x, wid = tid >> 5, lane = tid & 31;
    const int warp_m = wid & 3, warp_n = wid >> 2;

    float acc[2][4][4];
    #pragma unroll
    for (int mt = 0; mt < 2; ++mt)
        #pragma unroll
        for (int nt = 0; nt < 4; ++nt)
            #pragma unroll
            for (int q = 0; q < 4; ++q) acc[mt][nt][q] = 0.f;

    const int rowA = warp_m * 32 + (lane & 15);
    const int rowB = warp_n * 32 + (lane & 7) + ((lane >> 4) << 3);
    const uint32_t rowAswz = (uint32_t)(rowA & 7);
    const uint32_t rowBswz = (uint32_t)(rowB & 7);
    const int halfA = lane >> 4;
    const int halfB = (lane >> 3) & 1;

    gemm_load_stage<BN>(sbase, Ahi, Alo, Bth, Btl, m0, n0, M, 0, tid);
    CP_COMMIT();
    gemm_load_stage<BN>(sbase + STAGE, Ahi, Alo, Bth, Btl, m0, n0, M, 1, tid);
    CP_COMMIT();

    #pragma unroll 1
    for (int kb = 0; kb < 4; ++kb) {
        if (kb < 3) { CP_WAIT(1); } else { CP_WAIT(0); }
        __syncthreads();
        if (kb < 2) {
            gemm_load_stage<BN>(sbase + ((kb + 2) % 3) * STAGE,
                                Ahi, Alo, Bth, Btl, m0, n0, M, kb + 2, tid);
            CP_COMMIT();
        }
        const uint32_t sb = sbase + (kb % 3) * STAGE;
        #pragma unroll
        for (int s = 0; s < 4; ++s) {
            uint32_t a[2][2][4];
            uint32_t b[2][4][2];
            const uint32_t offA = (((uint32_t)(s * 2 + halfA) ^ rowAswz) << 4);
            const uint32_t offB = (((uint32_t)(s * 2 + halfB) ^ rowBswz) << 4);
            #pragma unroll
            for (int prec = 0; prec < 2; ++prec) {
                uint32_t baseA = sb + prec * 16384;
                #pragma unroll
                for (int mt = 0; mt < 2; ++mt) {
                    uint32_t addr = baseA + (uint32_t)(rowA + mt * 16) * 128 + offA;
                    LDSM_X4(a[prec][mt][0], a[prec][mt][1], a[prec][mt][2], a[prec][mt][3], addr);
                }
                uint32_t baseB = sb + 32768 + prec * (BN * 128);
                #pragma unroll
                for (int ntp = 0; ntp < 2; ++ntp) {
                    uint32_t addr = baseB + (uint32_t)(rowB + ntp * 16) * 128 + offB;
                    LDSM_X4(b[prec][2 * ntp][0], b[prec][2 * ntp][1],
                            b[prec][2 * ntp + 1][0], b[prec][2 * ntp + 1][1], addr);
                }
            }
            #pragma unroll
            for (int mt = 0; mt < 2; ++mt)
                #pragma unroll
                for (int nt = 0; nt < 4; ++nt) {
                    MMA_BF16(acc[mt][nt], a[0][mt], b[0][nt]);
                    MMA_BF16(acc[mt][nt], a[0][mt], b[1][nt]);
                    MMA_BF16(acc[mt][nt], a[1][mt], b[0][nt]);
                }
        }
    }

    #pragma unroll
    for (int mt = 0; mt < 2; ++mt) {
        int row = m0 + warp_m * 32 + mt * 16 + (lane >> 2);
        #pragma unroll
        for (int nt = 0; nt < 4; ++nt) {
            int col = n0 + warp_n * 32 + nt * 8 + (lane & 3) * 2;
            if (col < Nn) {
                if (ELR) {
                    if (row < M)
                        *reinterpret_cast<__half2*>(Ch + (size_t)row * Nn + col) =
                            __floats2half2_rn(acc[mt][nt][0], acc[mt][nt][1]);
                    if (row + 8 < M)
                        *reinterpret_cast<__half2*>(Ch + (size_t)(row + 8) * Nn + col) =
                            __floats2half2_rn(acc[mt][nt][2], acc[mt][nt][3]);
                } else {
                    if (row < M)
                        *reinterpret_cast<float2*>(Cf + (size_t)row * Nn + col) =
                            make_float2(acc[mt][nt][0], acc[mt][nt][1]);
                    if (row + 8 < M)
                        *reinterpret_cast<float2*>(Cf + (size_t)(row + 8) * Nn + col) =
                            make_float2(acc[mt][nt][2], acc[mt][nt][3]);
                }
            }
        }
    }

    if (ELR) {
        const int colbase = n0 + warp_n * 32;
        const int h0 = colbase / D;
        int nt_split = ((h0 + 1) * D - colbase) >> 3;
        if (nt_split > 4) nt_split = 4;
        float sl[2][2][2] = {}, sr[2][2][2] = {};
        #pragma unroll
        for (int nt = 0; nt < 4; ++nt) {
            int colg = colbase + nt * 8;
            float2 av = make_float2(0.f, 0.f), rv = av;
            if (colg < Nn) {
                int h = (nt < nt_split) ? h0 : (h0 + 1);
                int d = colg - h * D + (lane & 3) * 2;
                av = __ldg(reinterpret_cast<const float2*>(al + h * D + d));
                rv = __ldg(reinterpret_cast<const float2*>(ar + h * D + d));
            }
            int slot = (nt >= nt_split);
            #pragma unroll
            for (int mt = 0; mt < 2; ++mt) {
                sl[mt][0][slot] += acc[mt][nt][0] * av.x + acc[mt][nt][1] * av.y;
                sr[mt][0][slot] += acc[mt][nt][0] * rv.x + acc[mt][nt][1] * rv.y;
                sl[mt][1][slot] += acc[mt][nt][2] * av.x + acc[mt][nt][3] * av.y;
                sr[mt][1][slot] += acc[mt][nt][2] * rv.x + acc[mt][nt][3] * rv.y;
            }
        }
        #pragma unroll
        for (int mt = 0; mt < 2; ++mt)
            #pragma unroll
            for (int rh = 0; rh < 2; ++rh)
                #pragma unroll
                for (int sidx = 0; sidx < 2; ++sidx) {
                    float vl = sl[mt][rh][sidx], vr = sr[mt][rh][sidx];
                    vl += __shfl_xor_sync(0xffffffffu, vl, 1);
                    vl += __shfl_xor_sync(0xffffffffu, vl, 2);
                    vr += __shfl_xor_sync(0xffffffffu, vr, 1);
                    vr += __shfl_xor_sync(0xffffffffu, vr, 2);
                    sl[mt][rh][sidx] = vl; sr[mt][rh][sidx] = vr;
                }
        if ((lane & 3) == 0) {
            bool slot1_valid = (nt_split < 4) && (colbase + nt_split * 8) < Nn;
            #pragma unroll
            for (int mt = 0; mt < 2; ++mt) {
                #pragma unroll
                for (int rh = 0; rh < 2; ++rh) {
                    int row = m0 + warp_m * 32 + mt * 16 + (lane >> 2) + rh * 8;
                    if (row < M) {
                        atomicAdd(&el[(size_t)row * H + h0], sl[mt][rh][0]);
                        atomicAdd(&er[(size_t)row * H + h0], sr[mt][rh][0]);
                        if (slot1_valid) {
                            atomicAdd(&el[(size_t)row * H + h0 + 1], sl[mt][rh][1]);
                            atomicAdd(&er[(size_t)row * H + h0 + 1], sr[mt][rh][1]);
                        }
                    }
                }
            }
        }
    }
}

#define GEMM_SMEM128 (3 * (32768 + 128 * 256))
#define GEMM_SMEM64  (3 * (32768 + 64 * 256))

// ---------------- GEMM launches ----------------
__global__ __launch_bounds__(512, 1) void k_gemm0(
    const __nv_bfloat16* __restrict__ Ahi, const __nv_bfloat16* __restrict__ Alo,
    __half* __restrict__ Ch, const float* __restrict__ al, const float* __restrict__ ar,
    float* __restrict__ el, float* __restrict__ er, int M, int nGemm,
    const int* __restrict__ src, const int* __restrict__ dst, int E)
{
    int bx = blockIdx.x;
    if (bx < nGemm) {
        gemm_body<true, 128>(Ahi, Alo, g_Bth, g_Btl, Ch, nullptr, al, ar, el, er,
                             M, 256, 4, 64, (bx >> 1) * 128, (bx & 1) * 128);
    } else {
        int e = (bx - nGemm) * 512 + threadIdx.x;
        if (e < E) {
            int p = atomicAdd(&g_cursor[dst[e]], 1);
            g_srcs[p] = src[e];
        }
    }
}

__global__ __launch_bounds__(512, 1) void k_gemm1(
    const __nv_bfloat16* __restrict__ Ahi, const __nv_bfloat16* __restrict__ Alo,
    __half* __restrict__ Ch, const float* __restrict__ al, const float* __restrict__ ar,
    float* __restrict__ el, float* __restrict__ er, int M)
{
    int bx = blockIdx.x;
    gemm_body<true, 128>(Ahi, Alo, g_Bth, g_Btl, Ch, nullptr, al, ar, el, er,
                         M, 256, 4, 64, (bx >> 1) * 128, (bx & 1) * 128);
}

__global__ __launch_bounds__(512, 1) void k_gemm2(
    const __nv_bfloat16* __restrict__ Ahi, const __nv_bfloat16* __restrict__ Alo,
    __half* __restrict__ Ch, const float* __restrict__ al, const float* __restrict__ ar,
    float* __restrict__ el, float* __restrict__ er, int M)
{
    int bx = blockIdx.x;
    gemm_body<true, 128>(Ahi, Alo, g_Bth, g_Btl, Ch, nullptr, al, ar, el, er,
                         M, 240, 6, 40, (bx >> 1) * 128, (bx & 1) * 128);
}

// small GEMM: r2m[n,40] = h1 @ resW2_mean  (BN=64 tile, 256 threads)
__global__ __launch_bounds__(256, 1) void k_gemm_res(
    const __nv_bfloat16* __restrict__ Ahi, const __nv_bfloat16* __restrict__ Alo,
    float* __restrict__ Cf, int M)
{
    gemm_body<false, 64>(Ahi, Alo, g_Bth2, g_Btl2, nullptr, Cf, nullptr, nullptr,
                         nullptr, nullptr, M, 40, 1, 64, blockIdx.x * 128, 0);
}

// ---------------- aggregation helpers ----------------
__device__ __forceinline__ void fma_row(float4& a0, float4& a1, float wh, uint4 q) {
    float2 p0 = __half22float2(*reinterpret_cast<__half2*>(&q.x));
    float2 p1 = __half22float2(*reinterpret_cast<__half2*>(&q.y));
    float2 p2 = __half22float2(*reinterpret_cast<__half2*>(&q.z));
    float2 p3 = __half22float2(*reinterpret_cast<__half2*>(&q.w));
    a0.x = fmaf(wh, p0.x, a0.x); a0.y = fmaf(wh, p0.y, a0.y);
    a0.z = fmaf(wh, p1.x, a0.z); a0.w = fmaf(wh, p1.y, a0.w);
    a1.x = fmaf(wh, p2.x, a1.x); a1.y = fmaf(wh, p2.y, a1.y);
    a1.z = fmaf(wh, p3.x, a1.z); a1.w = fmaf(wh, p3.y, a1.w);
}

// ---------------- aggregation, layers 0/1 ----------------
template <bool RES>
__global__ __launch_bounds__(256) void k_agg256(
    const __half* __restrict__ zh, const float* __restrict__ el,
    const float* __restrict__ er, const float* __restrict__ bias,
    const float* __restrict__ xres, float* __restrict__ out,
    __nv_bfloat16* __restrict__ ohi, __nv_bfloat16* __restrict__ olo, int n)
{
    int gw = (blockIdx.x * blockDim.x + threadIdx.x) >> 5;
    if (gw >= n) return;
    int lane = threadIdx.x & 31;
    int beg = g_rowstart[gw], end = g_rowstart[gw + 1];
    float erh = (lane < 4) ? __ldg(&er[gw * 4 + lane]) : 0.f;
    int h = lane >> 3;
    int c0 = lane * 8;
    float4 acc0 = make_float4(0.f, 0.f, 0.f, 0.f), acc1 = acc0;
    float denom = 0.f;
    int i = beg;
    #pragma unroll 1
    for (; i + 2 <= end; i += 2) {
        int s0 = __ldg(&g_srcs[i]);
        int s1 = __ldg(&g_srcs[i + 1]);
        uint4 q0 = __ldg(reinterpret_cast<const uint4*>(zh + (size_t)s0 * 256 + c0));
        uint4 q1 = __ldg(reinterpret_cast<const uint4*>(zh + (size_t)s1 * 256 + c0));
        float w0 = 0.f, w1 = 0.f;
        if (lane < 4) {
            float e0 = __ldg(&el[s0 * 4 + lane]) + erh;
            float e1 = __ldg(&el[s1 * 4 + lane]) + erh;
            e0 = (e0 > 0.f) ? e0 : 0.2f * e0;
            e1 = (e1 > 0.f) ? e1 : 0.2f * e1;
            w0 = __expf(e0); w1 = __expf(e1);
            denom += w0 + w1;
        }
        float wh0 = __shfl_sync(0xffffffffu, w0, h);
        float wh1 = __shfl_sync(0xffffffffu, w1, h);
        fma_row(acc0, acc1, wh0, q0);
        fma_row(acc0, acc1, wh1, q1);
    }
    if (i < end) {
        int s0 = __ldg(&g_srcs[i]);
        uint4 q0 = __ldg(reinterpret_cast<const uint4*>(zh + (size_t)s0 * 256 + c0));
        float w0 = 0.f;
        if (lane < 4) {
            float e0 = __ldg(&el[s0 * 4 + lane]) + erh;
            e0 = (e0 > 0.f) ? e0 : 0.2f * e0;
            w0 = __expf(e0);
            denom += w0;
        }
        float wh0 = __shfl_sync(0xffffffffu, w0, h);
        fma_row(acc0, acc1, wh0, q0);
    }
    float dh = __shfl_sync(0xffffffffu, denom, h);
    float inv = 1.f / dh;
    const float4* bp = reinterpret_cast<const float4*>(bias + c0);
    float4 b0 = __ldg(bp), b1 = __ldg(bp + 1);
    float v[8];
    v[0] = fmaf(acc0.x, inv, b0.x); v[1] = fmaf(acc0.y, inv, b0.y);
    v[2] = fmaf(acc0.z, inv, b0.z); v[3] = fmaf(acc0.w, inv, b0.w);
    v[4] = fmaf(acc1.x, inv, b1.x); v[5] = fmaf(acc1.y, inv, b1.y);
    v[6] = fmaf(acc1.z, inv, b1.z); v[7] = fmaf(acc1.w, inv, b1.w);
    if (RES) {
        const float4* rp = reinterpret_cast<const float4*>(xres + (size_t)gw * 256 + c0);
        float4 r0 = __ldg(rp), r1 = __ldg(rp + 1);
        v[0] += r0.x; v[1] += r0.y; v[2] += r0.z; v[3] += r0.w;
        v[4] += r1.x; v[5] += r1.y; v[6] += r1.z; v[7] += r1.w;
    }
    #pragma unroll
    for (int j = 0; j < 8; ++j) v[j] = (v[j] > 0.f) ? v[j] : expm1f(v[j]);
    float4* op = reinterpret_cast<float4*>(out + (size_t)gw * 256 + c0);
    op[0] = make_float4(v[0], v[1], v[2], v[3]);
    op[1] = make_float4(v[4], v[5], v[6], v[7]);
    ushort hi[8], lo[8];
    #pragma unroll
    for (int j = 0; j < 8; ++j) {
        __nv_bfloat16 hh = __float2bfloat16_rn(v[j]);
        hi[j] = __bfloat16_as_ushort(hh);
        lo[j] = __bfloat16_as_ushort(__float2bfloat16_rn(v[j] - __bfloat162float(hh)));
    }
    ushort4* hp = reinterpret_cast<ushort4*>(ohi + (size_t)gw * 256 + c0);
    ushort4* lp = reinterpret_cast<ushort4*>(olo + (size_t)gw * 256 + c0);
    hp[0] = make_ushort4(hi[0], hi[1], hi[2], hi[3]);
    hp[1] = make_ushort4(hi[4], hi[5], hi[6], hi[7]);
    lp[0] = make_ushort4(lo[0], lo[1], lo[2], lo[3]);
    lp[1] = make_ushort4(lo[4], lo[5], lo[6], lo[7]);
}

// ---------------- aggregation, layer 2 (res via head-averaged r2m[n,40]) ----------------
__global__ __launch_bounds__(256) void k_agg_l2(
    const __half* __restrict__ zh, const float* __restrict__ el,
    const float* __restrict__ er, const float* __restrict__ bias,
    const float* __restrict__ r2m, float* __restrict__ logits, int n)
{
    __shared__ float sout[8][240];
    int wInB = threadIdx.x >> 5;
    int gw = blockIdx.x * 8 + wInB;
    int lane = threadIdx.x & 31;
    bool act = (lane < 30);
    if (gw < n) {
        int beg = g_rowstart[gw], end = g_rowstart[gw + 1];
        float erh = (lane < 6) ? __ldg(&er[gw * 6 + lane]) : 0.f;
        int h = act ? (lane / 5) : 0;
        int c0 = lane * 8;
        float4 acc0 = make_float4(0.f, 0.f, 0.f, 0.f), acc1 = acc0;
        float denom = 0.f;
        int i = beg;
        #pragma unroll 1
        for (; i + 2 <= end; i += 2) {
            int s0 = __ldg(&g_srcs[i]);
            int s1 = __ldg(&g_srcs[i + 1]);
            uint4 q0 = make_uint4(0, 0, 0, 0), q1 = q0;
            if (act) {
                q0 = __ldg(reinterpret_cast<const uint4*>(zh + (size_t)s0 * 240 + c0));
                q1 = __ldg(reinterpret_cast<const uint4*>(zh + (size_t)s1 * 240 + c0));
            }
            float w0 = 0.f, w1 = 0.f;
            if (lane < 6) {
                float e0 = __ldg(&el[s0 * 6 + lane]) + erh;
                float e1 = __ldg(&el[s1 * 6 + lane]) + erh;
                e0 = (e0 > 0.f) ? e0 : 0.2f * e0;
                e1 = (e1 > 0.f) ? e1 : 0.2f * e1;
                w0 = __expf(e0); w1 = __expf(e1);
                denom += w0 + w1;
            }
            float wh0 = __shfl_sync(0xffffffffu, w0, h);
            float wh1 = __shfl_sync(0xffffffffu, w1, h);
            if (act) {
                fma_row(acc0, acc1, wh0, q0);
                fma_row(acc0, acc1, wh1, q1);
            }
        }
        if (i < end) {
            int s0 = __ldg(&g_srcs[i]);
            uint4 q0 = make_uint4(0, 0, 0, 0);
            if (act) q0 = __ldg(reinterpret_cast<const uint4*>(zh + (size_t)s0 * 240 + c0));
            float w0 = 0.f;
            if (lane < 6) {
                float e0 = __ldg(&el[s0 * 6 + lane]) + erh;
                e0 = (e0 > 0.f) ? e0 : 0.2f * e0;
                w0 = __expf(e0);
                denom += w0;
            }
            float wh0 = __shfl_sync(0xffffffffu, w0, h);
            if (act) fma_row(acc0, acc1, wh0, q0);
        }
        float dh = __shfl_sync(0xffffffffu, denom, h);
        if (act) {
            float inv = 1.f / dh;
            const float4* bp = reinterpret_cast<const float4*>(bias + c0);
            float4 b0 = __ldg(bp), b1 = __ldg(bp + 1);
            sout[wInB][c0 + 0] = fmaf(acc0.x, inv, b0.x);
            sout[wInB][c0 + 1] = fmaf(acc0.y, inv, b0.y);
            sout[wInB][c0 + 2] = fmaf(acc0.z, inv, b0.z);
            sout[wInB][c0 + 3] = fmaf(acc0.w, inv, b0.w);
            sout[wInB][c0 + 4] = fmaf(acc1.x, inv, b1.x);
            sout[wInB][c0 + 5] = fmaf(acc1.y, inv, b1.y);
            sout[wInB][c0 + 6] = fmaf(acc1.z, inv, b1.z);
            sout[wInB][c0 + 7] = fmaf(acc1.w, inv, b1.w);
        }
    }
    __syncwarp();
    if (gw < n) {
        for (int d = lane; d < 40; d += 32) {
            float s_ = 0.f;
            #pragma unroll
            for (int hh = 0; hh < 6; ++hh) s_ += sout[wInB][hh * 40 + d];
            logits[(size_t)gw * 40 + d] = s_ * (1.0f / 6.0f) + __ldg(&r2m[(size_t)gw * 40 + d]);
        }
    }
}

// ---------------- host ----------------
extern "C" void kernel_launch(void* const* d_in, const int* in_sizes, int n_in,
                              void* d_out, int out_size)
{
    const float* feat  = (const float*)d_in[0];
    const int*   src   = (const int*)d_in[1];
    const int*   dst   = (const int*)d_in[2];
    const float* W0    = (const float*)d_in[3];
    const float* al0   = (const float*)d_in[4];
    const float* ar0   = (const float*)d_in[5];
    const float* b0    = (const float*)d_in[6];
    const float* W1    = (const float*)d_in[7];
    const float* al1   = (const float*)d_in[8];
    const float* ar1   = (const float*)d_in[9];
    const float* b1    = (const float*)d_in[10];
    const float* W2    = (const float*)d_in[11];
    const float* al2   = (const float*)d_in[12];
    const float* ar2   = (const float*)d_in[13];
    const float* b2    = (const float*)d_in[14];
    const float* resW2 = (const float*)d_in[15];

    const int n = NNODES;
    const int E = in_sizes[1];

    float* logits = (float*)d_out;
    float* h1     = (float*)d_out + n * 40;

    float *ph0, *pr2, *pel, *per;
    __half* pzh;
    __nv_bfloat16 *pAh, *pAl;
    cudaGetSymbolAddress((void**)&pzh, g_zh);
    cudaGetSymbolAddress((void**)&ph0, g_h0);
    cudaGetSymbolAddress((void**)&pr2, g_r2);
    cudaGetSymbolAddress((void**)&pel, g_el);
    cudaGetSymbolAddress((void**)&per, g_er);
    cudaGetSymbolAddress((void**)&pAh, g_Ahi);
    cudaGetSymbolAddress((void**)&pAl, g_Alo);

    cudaFuncSetAttribute(k_gemm0, cudaFuncAttributeMaxDynamicSharedMemorySize, GEMM_SMEM128);
    cudaFuncSetAttribute(k_gemm1, cudaFuncAttributeMaxDynamicSharedMemorySize, GEMM_SMEM128);
    cudaFuncSetAttribute(k_gemm2, cudaFuncAttributeMaxDynamicSharedMemorySize, GEMM_SMEM128);
    cudaFuncSetAttribute(k_gemm_res, cudaFuncAttributeMaxDynamicSharedMemorySize, GEMM_SMEM64);

    const int nGemm = ((n + 127) / 128) * 2;          // 782
    const int nGemmM = (n + 127) / 128;               // 391
    const int histBlocks = (E + 255) / 256;
    const int scatBlocks = (E + 511) / 512;
    const int zeroBlocks = (n * 6 + 255) / 256;
    const int aggBlocks  = (n + 7) / 8;

    // 1. zero deg + el/er(L0)
    k_zero0<<<zeroBlocks, 256>>>(n, n * 6);
    // 2. splitA(feat) + splitBt(W0) + hist
    k_prep0<<<SPLITA_BLOCKS + 256 + histBlocks, 256>>>(feat, W0, dst, E);
    // 3. scan
    k_scan<<<1, 1024>>>(n, E);
    // 4. gemm L0 + scatter
    k_gemm0<<<nGemm + scatBlocks, 512, GEMM_SMEM128>>>(pAh, pAl, pzh, al0, ar0, pel, per,
                                                       n, nGemm, src, dst, E);
    // 5. agg L0
    k_agg256<false><<<aggBlocks, 256>>>(pzh, pel, per, b0, nullptr, ph0, pAh, pAl, n);
    // 6. prep L1
    k_prep1<<<256 + zeroBlocks, 256>>>(W1, n * 6);
    // 7. gemm L1
    k_gemm1<<<nGemm, 512, GEMM_SMEM128>>>(pAh, pAl, pzh, al1, ar1, pel, per, n);
    // 8. agg L1 -> h1 (in d_out)
    k_agg256<true><<<aggBlocks, 256>>>(pzh, pel, per, b1, ph0, h1, pAh, pAl, n);
    // 9. prep L2 (W2 split + resW2_mean split + zero el/er)
    k_prep2<<<256 + 64 + zeroBlocks, 256>>>(W2, resW2, n * 6);
    // 10. gemm L2 (W2, ELR)
    k_gemm2<<<nGemm, 512, GEMM_SMEM128>>>(pAh, pAl, pzh, al2, ar2, pel, per, n);
    // 10b. small gemm: r2m = h1 @ resW2_mean
    k_gemm_res<<<nGemmM, 256, GEMM_SMEM64>>>(pAh, pAl, pr2, n);
    // 11. agg L2 -> logits
    k_agg_l2<<<aggBlocks, 256>>>(pzh, pel, per, b2, pr2, logits, n);
}

// round 9
// speedup vs baseline: 2.7429x; 1.0042x over previous
#include <cuda_runtime.h>
#include <cuda_bf16.h>
#include <cuda_fp16.h>
#include <math.h>
#include <cstdint>

// ---------------- problem constants ----------------
#define NNODES 50000
#define ECAP   1000000
#define SPLITA_BLOCKS 12500   // (NNODES*256/4)/256

// ---------------- device scratch ----------------
__device__ __align__(16) __half g_zh[NNODES * 256];
__device__ float g_h0[NNODES * 256];
__device__ float g_r2[NNODES * 40];
__device__ float g_el[NNODES * 6];
__device__ float g_er[NNODES * 6];
__device__ int   g_deg[NNODES];
__device__ int   g_rowstart[NNODES + 1];
__device__ int   g_cursor[NNODES];
__device__ int   g_srcs[ECAP];
__device__ __align__(16) __nv_bfloat16 g_Ahi[NNODES * 256];
__device__ __align__(16) __nv_bfloat16 g_Alo[NNODES * 256];
__device__ __align__(16) __nv_bfloat16 g_Bth[256 * 256];
__device__ __align__(16) __nv_bfloat16 g_Btl[256 * 256];
__device__ __align__(16) __nv_bfloat16 g_Bth2[64 * 256];   // resW2_mean, [64(d pad) x 256(k)]
__device__ __align__(16) __nv_bfloat16 g_Btl2[64 * 256];

// ================= PTX helpers =================
__device__ __forceinline__ uint32_t smem_u32(const void* p) {
    uint32_t a;
    asm("{ .reg .u64 t; cvta.to.shared.u64 t, %1; cvt.u32.u64 %0, t; }" : "=r"(a) : "l"(p));
    return a;
}
__device__ __forceinline__ void cp16(uint32_t dst, const void* src, uint32_t srcsize) {
    asm volatile("cp.async.cg.shared.global [%0], [%1], 16, %2;"
                 :: "r"(dst), "l"(src), "r"(srcsize));
}
#define CP_COMMIT() asm volatile("cp.async.commit_group;" ::: "memory")
#define CP_WAIT(n)  asm volatile("cp.async.wait_group %0;" :: "n"(n) : "memory")
#define LDSM_X4(r0, r1, r2, r3, addr) \
    asm volatile("ldmatrix.sync.aligned.m8n8.x4.shared.b16 {%0,%1,%2,%3}, [%4];" \
        : "=r"(r0), "=r"(r1), "=r"(r2), "=r"(r3) : "r"(addr))
#define MMA_BF16(acc, a, b) \
    asm volatile("mma.sync.aligned.m16n8k16.row.col.f32.bf16.bf16.f32 " \
        "{%0,%1,%2,%3}, {%4,%5,%6,%7}, {%8,%9}, {%0,%1,%2,%3};" \
        : "+f"((acc)[0]), "+f"((acc)[1]), "+f"((acc)[2]), "+f"((acc)[3]) \
        : "r"((a)[0]), "r"((a)[1]), "r"((a)[2]), "r"((a)[3]), "r"((b)[0]), "r"((b)[1]))

// ---------------- helper device funcs ----------------
__device__ __forceinline__ void splitBt_elem(const float* __restrict__ B,
                                             __nv_bfloat16* th, __nv_bfloat16* tl,
                                             int t, int Nn) {
    int nrow = t >> 8, k = t & 255;
    float x = (nrow < Nn) ? B[(size_t)k * Nn + nrow] : 0.f;
    __nv_bfloat16 h = __float2bfloat16_rn(x);
    th[t] = h;
    tl[t] = __float2bfloat16_rn(x - __bfloat162float(h));
}

// ---------------- kernel 1: zero deg + el/er ----------------
__global__ void k_zero0(int n, int n6) {
    int i = blockIdx.x * blockDim.x + threadIdx.x;
    if (i < n) g_deg[i] = 0;
    if (i < n6) { g_el[i] = 0.f; g_er[i] = 0.f; }
}

// ---------------- kernel 2: splitA(feat) + splitBt(W0) + hist ----------------
__global__ void k_prep0(const float* __restrict__ feat, const float* __restrict__ W0,
                        const int* __restrict__ dst, int E) {
    int bx = blockIdx.x;
    if (bx < SPLITA_BLOCKS) {
        int i = bx * 256 + threadIdx.x;
        float4 v = reinterpret_cast<const float4*>(feat)[i];
        __nv_bfloat16 h0 = __float2bfloat16_rn(v.x);
        __nv_bfloat16 h1 = __float2bfloat16_rn(v.y);
        __nv_bfloat16 h2 = __float2bfloat16_rn(v.z);
        __nv_bfloat16 h3 = __float2bfloat16_rn(v.w);
        reinterpret_cast<ushort4*>(g_Ahi)[i] = make_ushort4(
            __bfloat16_as_ushort(h0), __bfloat16_as_ushort(h1),
            __bfloat16_as_ushort(h2), __bfloat16_as_ushort(h3));
        reinterpret_cast<ushort4*>(g_Alo)[i] = make_ushort4(
            __bfloat16_as_ushort(__float2bfloat16_rn(v.x - __bfloat162float(h0))),
            __bfloat16_as_ushort(__float2bfloat16_rn(v.y - __bfloat162float(h1))),
            __bfloat16_as_ushort(__float2bfloat16_rn(v.z - __bfloat162float(h2))),
            __bfloat16_as_ushort(__float2bfloat16_rn(v.w - __bfloat162float(h3))));
    } else if (bx < SPLITA_BLOCKS + 256) {
        int t = (bx - SPLITA_BLOCKS) * 256 + threadIdx.x;
        splitBt_elem(W0, g_Bth, g_Btl, t, 256);
    } else {
        int e = (bx - SPLITA_BLOCKS - 256) * 256 + threadIdx.x;
        if (e < E) atomicAdd(&g_deg[dst[e]], 1);
    }
}

// ---------------- kernel: scan ----------------
__global__ void k_scan(int n, int E) {
    __shared__ int wsum[32];
    __shared__ int carry;
    int lane = threadIdx.x & 31, w = threadIdx.x >> 5;
    if (threadIdx.x == 0) carry = 0;
    __syncthreads();
    for (int base = 0; base < n; base += 1024) {
        int i = base + threadIdx.x;
        int v = (i < n) ? g_deg[i] : 0;
        int x = v;
        #pragma unroll
        for (int off = 1; off < 32; off <<= 1) {
            int t = __shfl_up_sync(0xffffffffu, x, off);
            if (lane >= off) x += t;
        }
        if (lane == 31) wsum[w] = x;
        __syncthreads();
        if (w == 0) {
            int y = wsum[lane];
            #pragma unroll
            for (int off = 1; off < 32; off <<= 1) {
                int t = __shfl_up_sync(0xffffffffu, y, off);
                if (lane >= off) y += t;
            }
            wsum[lane] = y;
        }
        __syncthreads();
        int incl = x + (w ? wsum[w - 1] : 0) + carry;
        int excl = incl - v;
        if (i < n) { g_rowstart[i] = excl; g_cursor[i] = excl; }
        __syncthreads();
        if (threadIdx.x == 1023) carry = incl;
        __syncthreads();
    }
    if (threadIdx.x == 0) g_rowstart[n] = E;
}

// ---------------- prep1 / prep2 ----------------
__global__ void k_prep1(const float* __restrict__ W1, int n6) {
    int bx = blockIdx.x;
    if (bx < 256) {
        splitBt_elem(W1, g_Bth, g_Btl, bx * 256 + threadIdx.x, 256);
    } else {
        int i = (bx - 256) * 256 + threadIdx.x;
        if (i < n6) { g_el[i] = 0.f; g_er[i] = 0.f; }
    }
}
// prep2: split W2 (240 cols) + head-averaged resW2_mean (64x256) + zero el/er
__global__ void k_prep2(const float* __restrict__ W2, const float* __restrict__ resW2, int n6) {
    int bx = blockIdx.x;
    if (bx < 256) {
        splitBt_elem(W2, g_Bth, g_Btl, bx * 256 + threadIdx.x, 240);
    } else if (bx < 256 + 64) {
        int t = (bx - 256) * 256 + threadIdx.x;    // t in [0, 64*256)
        int d = t >> 8, k = t & 255;
        float x = 0.f;
        if (d < 40) {
            float s_ = 0.f;
            #pragma unroll
            for (int h = 0; h < 6; ++h) s_ += resW2[(size_t)k * 240 + h * 40 + d];
            x = s_ * (1.0f / 6.0f);
        }
        __nv_bfloat16 hh = __float2bfloat16_rn(x);
        g_Bth2[t] = hh;
        g_Btl2[t] = __float2bfloat16_rn(x - __bfloat162float(hh));
    } else {
        int i = (bx - 256 - 64) * 256 + threadIdx.x;
        if (i < n6) { g_el[i] = 0.f; g_er[i] = 0.f; }
    }
}

// ---------------- GEMM body (mma.sync split-bf16, 3-stage pipeline, templated BN) ----------------
template <int BN>
__device__ __forceinline__ void gemm_load_stage(
    uint32_t sb, const __nv_bfloat16* __restrict__ Ahi, const __nv_bfloat16* __restrict__ Alo,
    const __nv_bfloat16* __restrict__ Bth, const __nv_bfloat16* __restrict__ Btl,
    int m0, int n0, int M, int kb, int tid)
{
    constexpr int THREADS = (BN == 128) ? 512 : 256;
    constexpr int BHALF = BN * 8;            // chunks per precision for B
    #pragma unroll
    for (int it = 0; it < 2048 / THREADS; ++it) {
        int idx = tid + it * THREADS;
        int prec = idx >> 10, rem = idx & 1023;
        int row = rem >> 3, ch = rem & 7;
        uint32_t dst = sb + prec * 16384 + row * 128 + (((uint32_t)(ch ^ (row & 7))) << 4);
        const __nv_bfloat16* srcb = prec ? Alo : Ahi;
        const __nv_bfloat16* src = srcb + (size_t)(m0 + row) * 256 + kb * 64 + ch * 8;
        cp16(dst, src, (m0 + row) < M ? 16u : 0u);
    }
    #pragma unroll
    for (int it = 0; it < (2 * BHALF) / THREADS; ++it) {
        int idx = tid + it * THREADS;
        int prec = idx / BHALF, rem = idx % BHALF;
        int row = rem >> 3, ch = rem & 7;
        uint32_t dst = sb + 32768 + prec * (BN * 128) + row * 128 + (((uint32_t)(ch ^ (row & 7))) << 4);
        const __nv_bfloat16* srcb = prec ? Btl : Bth;
        const __nv_bfloat16* src = srcb + (size_t)(n0 + row) * 256 + kb * 64 + ch * 8;
        cp16(dst, src, 16u);
    }
}

template <bool ELR, int BN>
__device__ __forceinline__ void gemm_body(
    const __nv_bfloat16* __restrict__ Ahi, const __nv_bfloat16* __restrict__ Alo,
    const __nv_bfloat16* __restrict__ Bth, const __nv_bfloat16* __restrict__ Btl,
    __half* __restrict__ Ch, float* __restrict__ Cf,
    const float* __restrict__ al, const float* __restrict__ ar,
    float* __restrict__ el, float* __restrict__ er,
    int M, int Nn, int H, int D, int m0, int n0)
{
    constexpr uint32_t STAGE = 32768u + (uint32_t)BN * 256u;
    extern __shared__ char smem[];
    const uint32_t sbase = smem_u32(smem);
    const int tid = threadIdx.x, wid = tid >> 5, lane = tid & 31;
    const int warp_m = wid & 3, warp_n = wid >> 2;

    float acc[2][4][4];
    #pragma unroll
    for (int mt = 0; mt < 2; ++mt)
        #pragma unroll
        for (int nt = 0; nt < 4; ++nt)
            #pragma unroll
            for (int q = 0; q < 4; ++q) acc[mt][nt][q] = 0.f;

    const int rowA = warp_m * 32 + (lane & 15);
    const int rowB = warp_n * 32 + (lane & 7) + ((lane >> 4) << 3);
    const uint32_t rowAswz = (uint32_t)(rowA & 7);
    const uint32_t rowBswz = (uint32_t)(rowB & 7);
    const int halfA = lane >> 4;
    const int halfB = (lane >> 3) & 1;

    gemm_load_stage<BN>(sbase, Ahi, Alo, Bth, Btl, m0, n0, M, 0, tid);
    CP_COMMIT();
    gemm_load_stage<BN>(sbase + STAGE, Ahi, Alo, Bth, Btl, m0, n0, M, 1, tid);
    CP_COMMIT();

    #pragma unroll 1
    for (int kb = 0; kb < 4; ++kb) {
        if (kb < 3) { CP_WAIT(1); } else { CP_WAIT(0); }
        __syncthreads();
        if (kb < 2) {
            gemm_load_stage<BN>(sbase + ((kb + 2) % 3) * STAGE,
                                Ahi, Alo, Bth, Btl, m0, n0, M, kb + 2, tid);
            CP_COMMIT();
        }
        const uint32_t sb = sbase + (kb % 3) * STAGE;
        #pragma unroll
        for (int s = 0; s < 4; ++s) {
            uint32_t a[2][2][4];
            uint32_t b[2][4][2];
            const uint32_t offA = (((uint32_t)(s * 2 + halfA) ^ rowAswz) << 4);
            const uint32_t offB = (((uint32_t)(s * 2 + halfB) ^ rowBswz) << 4);
            #pragma unroll
            for (int prec = 0; prec < 2; ++prec) {
                uint32_t baseA = sb + prec * 16384;
                #pragma unroll
                for (int mt = 0; mt < 2; ++mt) {
                    uint32_t addr = baseA + (uint32_t)(rowA + mt * 16) * 128 + offA;
                    LDSM_X4(a[prec][mt][0], a[prec][mt][1], a[prec][mt][2], a[prec][mt][3], addr);
                }
                uint32_t baseB = sb + 32768 + prec * (BN * 128);
                #pragma unroll
                for (int ntp = 0; ntp < 2; ++ntp) {
                    uint32_t addr = baseB + (uint32_t)(rowB + ntp * 16) * 128 + offB;
                    LDSM_X4(b[prec][2 * ntp][0], b[prec][2 * ntp][1],
                            b[prec][2 * ntp + 1][0], b[prec][2 * ntp + 1][1], addr);
                }
            }
            // combo OUTER, (mt,nt) inner: 8 independent MMAs between reuses of
            // the same accumulator -> HMMA latency fully pipelined.
            #pragma unroll
            for (int combo = 0; combo < 3; ++combo) {
                const int pa = (combo == 2) ? 1 : 0;
                const int pb = (combo == 1) ? 1 : 0;
                #pragma unroll
                for (int mt = 0; mt < 2; ++mt)
                    #pragma unroll
                    for (int nt = 0; nt < 4; ++nt)
                        MMA_BF16(acc[mt][nt], a[pa][mt], b[pb][nt]);
            }
        }
    }

    #pragma unroll
    for (int mt = 0; mt < 2; ++mt) {
        int row = m0 + warp_m * 32 + mt * 16 + (lane >> 2);
        #pragma unroll
        for (int nt = 0; nt < 4; ++nt) {
            int col = n0 + warp_n * 32 + nt * 8 + (lane & 3) * 2;
            if (col < Nn) {
                if (ELR) {
                    if (row < M)
                        *reinterpret_cast<__half2*>(Ch + (size_t)row * Nn + col) =
                            __floats2half2_rn(acc[mt][nt][0], acc[mt][nt][1]);
                    if (row + 8 < M)
                        *reinterpret_cast<__half2*>(Ch + (size_t)(row + 8) * Nn + col) =
                            __floats2half2_rn(acc[mt][nt][2], acc[mt][nt][3]);
                } else {
                    if (row < M)
                        *reinterpret_cast<float2*>(Cf + (size_t)row * Nn + col) =
                            make_float2(acc[mt][nt][0], acc[mt][nt][1]);
                    if (row + 8 < M)
                        *reinterpret_cast<float2*>(Cf + (size_t)(row + 8) * Nn + col) =
                            make_float2(acc[mt][nt][2], acc[mt][nt][3]);
                }
            }
        }
    }

    if (ELR) {
        const int colbase = n0 + warp_n * 32;
        const int h0 = colbase / D;
        int nt_split = ((h0 + 1) * D - colbase) >> 3;
        if (nt_split > 4) nt_split = 4;
        float sl[2][2][2] = {}, sr[2][2][2] = {};
        #pragma unroll
        for (int nt = 0; nt < 4; ++nt) {
            int colg = colbase + nt * 8;
            float2 av = make_float2(0.f, 0.f), rv = av;
            if (colg < Nn) {
                int h = (nt < nt_split) ? h0 : (h0 + 1);
                int d = colg - h * D + (lane & 3) * 2;
                av = __ldg(reinterpret_cast<const float2*>(al + h * D + d));
                rv = __ldg(reinterpret_cast<const float2*>(ar + h * D + d));
            }
            int slot = (nt >= nt_split);
            #pragma unroll
            for (int mt = 0; mt < 2; ++mt) {
                sl[mt][0][slot] += acc[mt][nt][0] * av.x + acc[mt][nt][1] * av.y;
                sr[mt][0][slot] += acc[mt][nt][0] * rv.x + acc[mt][nt][1] * rv.y;
                sl[mt][1][slot] += acc[mt][nt][2] * av.x + acc[mt][nt][3] * av.y;
                sr[mt][1][slot] += acc[mt][nt][2] * rv.x + acc[mt][nt][3] * rv.y;
            }
        }
        #pragma unroll
        for (int mt = 0; mt < 2; ++mt)
            #pragma unroll
            for (int rh = 0; rh < 2; ++rh)
                #pragma unroll
                for (int sidx = 0; sidx < 2; ++sidx) {
                    float vl = sl[mt][rh][sidx], vr = sr[mt][rh][sidx];
                    vl += __shfl_xor_sync(0xffffffffu, vl, 1);
                    vl += __shfl_xor_sync(0xffffffffu, vl, 2);
                    vr += __shfl_xor_sync(0xffffffffu, vr, 1);
                    vr += __shfl_xor_sync(0xffffffffu, vr, 2);
                    sl[mt][rh][sidx] = vl; sr[mt][rh][sidx] = vr;
                }
        if ((lane & 3) == 0) {
            bool slot1_valid = (nt_split < 4) && (colbase + nt_split * 8) < Nn;
            #pragma unroll
            for (int mt = 0; mt < 2; ++mt) {
                #pragma unroll
                for (int rh = 0; rh < 2; ++rh) {
                    int row = m0 + warp_m * 32 + mt * 16 + (lane >> 2) + rh * 8;
                    if (row < M) {
                        atomicAdd(&el[(size_t)row * H + h0], sl[mt][rh][0]);
                        atomicAdd(&er[(size_t)row * H + h0], sr[mt][rh][0]);
                        if (slot1_valid) {
                            atomicAdd(&el[(size_t)row * H + h0 + 1], sl[mt][rh][1]);
                            atomicAdd(&er[(size_t)row * H + h0 + 1], sr[mt][rh][1]);
                        }
                    }
                }
            }
        }
    }
}

#define GEMM_SMEM128 (3 * (32768 + 128 * 256))
#define GEMM_SMEM64  (3 * (32768 + 64 * 256))

// ---------------- GEMM launches ----------------
__global__ __launch_bounds__(512, 1) void k_gemm0(
    const __nv_bfloat16* __restrict__ Ahi, const __nv_bfloat16* __restrict__ Alo,
    __half* __restrict__ Ch, const float* __restrict__ al, const float* __restrict__ ar,
    float* __restrict__ el, float* __restrict__ er, int M, int nGemm,
    const int* __restrict__ src, const int* __restrict__ dst, int E)
{
    int bx = blockIdx.x;
    if (bx < nGemm) {
        gemm_body<true, 128>(Ahi, Alo, g_Bth, g_Btl, Ch, nullptr, al, ar, el, er,
                             M, 256, 4, 64, (bx >> 1) * 128, (bx & 1) * 128);
    } else {
        int e = (bx - nGemm) * 512 + threadIdx.x;
        if (e < E) {
            int p = atomicAdd(&g_cursor[dst[e]], 1);
            g_srcs[p] = src[e];
        }
    }
}

__global__ __launch_bounds__(512, 1) void k_gemm1(
    const __nv_bfloat16* __restrict__ Ahi, const __nv_bfloat16* __restrict__ Alo,
    __half* __restrict__ Ch, const float* __restrict__ al, const float* __restrict__ ar,
    float* __restrict__ el, float* __restrict__ er, int M)
{
    int bx = blockIdx.x;
    gemm_body<true, 128>(Ahi, Alo, g_Bth, g_Btl, Ch, nullptr, al, ar, el, er,
                         M, 256, 4, 64, (bx >> 1) * 128, (bx & 1) * 128);
}

__global__ __launch_bounds__(512, 1) void k_gemm2(
    const __nv_bfloat16* __restrict__ Ahi, const __nv_bfloat16* __restrict__ Alo,
    __half* __restrict__ Ch, const float* __restrict__ al, const float* __restrict__ ar,
    float* __restrict__ el, float* __restrict__ er, int M)
{
    int bx = blockIdx.x;
    gemm_body<true, 128>(Ahi, Alo, g_Bth, g_Btl, Ch, nullptr, al, ar, el, er,
                         M, 240, 6, 40, (bx >> 1) * 128, (bx & 1) * 128);
}

// small GEMM: r2m[n,40] = h1 @ resW2_mean  (BN=64 tile, 256 threads)
__global__ __launch_bounds__(256, 1) void k_gemm_res(
    const __nv_bfloat16* __restrict__ Ahi, const __nv_bfloat16* __restrict__ Alo,
    float* __restrict__ Cf, int M)
{
    gemm_body<false, 64>(Ahi, Alo, g_Bth2, g_Btl2, nullptr, Cf, nullptr, nullptr,
                         nullptr, nullptr, M, 40, 1, 64, blockIdx.x * 128, 0);
}

// ---------------- aggregation helpers ----------------
__device__ __forceinline__ void fma_row(float4& a0, float4& a1, float wh, uint4 q) {
    float2 p0 = __half22float2(*reinterpret_cast<__half2*>(&q.x));
    float2 p1 = __half22float2(*reinterpret_cast<__half2*>(&q.y));
    float2 p2 = __half22float2(*reinterpret_cast<__half2*>(&q.z));
    float2 p3 = __half22float2(*reinterpret_cast<__half2*>(&q.w));
    a0.x = fmaf(wh, p0.x, a0.x); a0.y = fmaf(wh, p0.y, a0.y);
    a0.z = fmaf(wh, p1.x, a0.z); a0.w = fmaf(wh, p1.y, a0.w);
    a1.x = fmaf(wh, p2.x, a1.x); a1.y = fmaf(wh, p2.y, a1.y);
    a1.z = fmaf(wh, p3.x, a1.z); a1.w = fmaf(wh, p3.y, a1.w);
}

// ---------------- aggregation, layers 0/1 ----------------
template <bool RES>
__global__ __launch_bounds__(256) void k_agg256(
    const __half* __restrict__ zh, const float* __restrict__ el,
    const float* __restrict__ er, const float* __restrict__ bias,
    const float* __restrict__ xres, float* __restrict__ out,
    __nv_bfloat16* __restrict__ ohi, __nv_bfloat16* __restrict__ olo, int n)
{
    int gw = (blockIdx.x * blockDim.x + threadIdx.x) >> 5;
    if (gw >= n) return;
    int lane = threadIdx.x & 31;
    int beg = g_rowstart[gw], end = g_rowstart[gw + 1];
    float erh = (lane < 4) ? __ldg(&er[gw * 4 + lane]) : 0.f;
    int h = lane >> 3;
    int c0 = lane * 8;
    float4 acc0 = make_float4(0.f, 0.f, 0.f, 0.f), acc1 = acc0;
    float denom = 0.f;
    int i = beg;
    #pragma unroll 1
    for (; i + 2 <= end; i += 2) {
        int s0 = __ldg(&g_srcs[i]);
        int s1 = __ldg(&g_srcs[i + 1]);
        uint4 q0 = __ldg(reinterpret_cast<const uint4*>(zh + (size_t)s0 * 256 + c0));
        uint4 q1 = __ldg(reinterpret_cast<const uint4*>(zh + (size_t)s1 * 256 + c0));
        float w0 = 0.f, w1 = 0.f;
        if (lane < 4) {
            float e0 = __ldg(&el[s0 * 4 + lane]) + erh;
            float e1 = __ldg(&el[s1 * 4 + lane]) + erh;
            e0 = (e0 > 0.f) ? e0 : 0.2f * e0;
            e1 = (e1 > 0.f) ? e1 : 0.2f * e1;
            w0 = __expf(e0); w1 = __expf(e1);
            denom += w0 + w1;
        }
        float wh0 = __shfl_sync(0xffffffffu, w0, h);
        float wh1 = __shfl_sync(0xffffffffu, w1, h);
        fma_row(acc0, acc1, wh0, q0);
        fma_row(acc0, acc1, wh1, q1);
    }
    if (i < end) {
        int s0 = __ldg(&g_srcs[i]);
        uint4 q0 = __ldg(reinterpret_cast<const uint4*>(zh + (size_t)s0 * 256 + c0));
        float w0 = 0.f;
        if (lane < 4) {
            float e0 = __ldg(&el[s0 * 4 + lane]) + erh;
            e0 = (e0 > 0.f) ? e0 : 0.2f * e0;
            w0 = __expf(e0);
            denom += w0;
        }
        float wh0 = __shfl_sync(0xffffffffu, w0, h);
        fma_row(acc0, acc1, wh0, q0);
    }
    float dh = __shfl_sync(0xffffffffu, denom, h);
    float inv = 1.f / dh;
    const float4* bp = reinterpret_cast<const float4*>(bias + c0);
    float4 b0 = __ldg(bp), b1 = __ldg(bp + 1);
    float v[8];
    v[0] = fmaf(acc0.x, inv, b0.x); v[1] = fmaf(acc0.y, inv, b0.y);
    v[2] = fmaf(acc0.z, inv, b0.z); v[3] = fmaf(acc0.w, inv, b0.w);
    v[4] = fmaf(acc1.x, inv, b1.x); v[5] = fmaf(acc1.y, inv, b1.y);
    v[6] = fmaf(acc1.z, inv, b1.z); v[7] = fmaf(acc1.w, inv, b1.w);
    if (RES) {
        const float4* rp = reinterpret_cast<const float4*>(xres + (size_t)gw * 256 + c0);
        float4 r0 = __ldg(rp), r1 = __ldg(rp + 1);
        v[0] += r0.x; v[1] += r0.y; v[2] += r0.z; v[3] += r0.w;
        v[4] += r1.x; v[5] += r1.y; v[6] += r1.z; v[7] += r1.w;
    }
    #pragma unroll
    for (int j = 0; j < 8; ++j) v[j] = (v[j] > 0.f) ? v[j] : expm1f(v[j]);
    float4* op = reinterpret_cast<float4*>(out + (size_t)gw * 256 + c0);
    op[0] = make_float4(v[0], v[1], v[2], v[3]);
    op[1] = make_float4(v[4], v[5], v[6], v[7]);
    ushort hi[8], lo[8];
    #pragma unroll
    for (int j = 0; j < 8; ++j) {
        __nv_bfloat16 hh = __float2bfloat16_rn(v[j]);
        hi[j] = __bfloat16_as_ushort(hh);
        lo[j] = __bfloat16_as_ushort(__float2bfloat16_rn(v[j] - __bfloat162float(hh)));
    }
    ushort4* hp = reinterpret_cast<ushort4*>(ohi + (size_t)gw * 256 + c0);
    ushort4* lp = reinterpret_cast<ushort4*>(olo + (size_t)gw * 256 + c0);
    hp[0] = make_ushort4(hi[0], hi[1], hi[2], hi[3]);
    hp[1] = make_ushort4(hi[4], hi[5], hi[6], hi[7]);
    lp[0] = make_ushort4(lo[0], lo[1], lo[2], lo[3]);
    lp[1] = make_ushort4(lo[4], lo[5], lo[6], lo[7]);
}

// ---------------- aggregation, layer 2 (res via head-averaged r2m[n,40]) ----------------
__global__ __launch_bounds__(256) void k_agg_l2(
    const __half* __restrict__ zh, const float* __restrict__ el,
    const float* __restrict__ er, const float* __restrict__ bias,
    const float* __restrict__ r2m, float* __restrict__ logits, int n)
{
    __shared__ float sout[8][240];
    int wInB = threadIdx.x >> 5;
    int gw = blockIdx.x * 8 + wInB;
    int lane = threadIdx.x & 31;
    bool act = (lane < 30);
    if (gw < n) {
        int beg = g_rowstart[gw], end = g_rowstart[gw + 1];
        float erh = (lane < 6) ? __ldg(&er[gw * 6 + lane]) : 0.f;
        int h = act ? (lane / 5) : 0;
        int c0 = lane * 8;
        float4 acc0 = make_float4(0.f, 0.f, 0.f, 0.f), acc1 = acc0;
        float denom = 0.f;
        int i = beg;
        #pragma unroll 1
        for (; i + 2 <= end; i += 2) {
            int s0 = __ldg(&g_srcs[i]);
            int s1 = __ldg(&g_srcs[i + 1]);
            uint4 q0 = make_uint4(0, 0, 0, 0), q1 = q0;
            if (act) {
                q0 = __ldg(reinterpret_cast<const uint4*>(zh + (size_t)s0 * 240 + c0));
                q1 = __ldg(reinterpret_cast<const uint4*>(zh + (size_t)s1 * 240 + c0));
            }
            float w0 = 0.f, w1 = 0.f;
            if (lane < 6) {
                float e0 = __ldg(&el[s0 * 6 + lane]) + erh;
                float e1 = __ldg(&el[s1 * 6 + lane]) + erh;
                e0 = (e0 > 0.f) ? e0 : 0.2f * e0;
                e1 = (e1 > 0.f) ? e1 : 0.2f * e1;
                w0 = __expf(e0); w1 = __expf(e1);
                denom += w0 + w1;
            }
            float wh0 = __shfl_sync(0xffffffffu, w0, h);
            float wh1 = __shfl_sync(0xffffffffu, w1, h);
            if (act) {
                fma_row(acc0, acc1, wh0, q0);
                fma_row(acc0, acc1, wh1, q1);
            }
        }
        if (i < end) {
            int s0 = __ldg(&g_srcs[i]);
            uint4 q0 = make_uint4(0, 0, 0, 0);
            if (act) q0 = __ldg(reinterpret_cast<const uint4*>(zh + (size_t)s0 * 240 + c0));
            float w0 = 0.f;
            if (lane < 6) {
                float e0 = __ldg(&el[s0 * 6 + lane]) + erh;
                e0 = (e0 > 0.f) ? e0 : 0.2f * e0;
                w0 = __expf(e0);
                denom += w0;
            }
            float wh0 = __shfl_sync(0xffffffffu, w0, h);
            if (act) fma_row(acc0, acc1, wh0, q0);
        }
        float dh = __shfl_sync(0xffffffffu, denom, h);
        if (act) {
            float inv = 1.f / dh;
            const float4* bp = reinterpret_cast<const float4*>(bias + c0);
            float4 b0 = __ldg(bp), b1 = __ldg(bp + 1);
            sout[wInB][c0 + 0] = fmaf(acc0.x, inv, b0.x);
            sout[wInB][c0 + 1] = fmaf(acc0.y, inv, b0.y);
            sout[wInB][c0 + 2] = fmaf(acc0.z, inv, b0.z);
            sout[wInB][c0 + 3] = fmaf(acc0.w, inv, b0.w);
            sout[wInB][c0 + 4] = fmaf(acc1.x, inv, b1.x);
            sout[wInB][c0 + 5] = fmaf(acc1.y, inv, b1.y);
            sout[wInB][c0 + 6] = fmaf(acc1.z, inv, b1.z);
            sout[wInB][c0 + 7] = fmaf(acc1.w, inv, b1.w);
        }
    }
    __syncwarp();
    if (gw < n) {
        for (int d = lane; d < 40; d += 32) {
            float s_ = 0.f;
            #pragma unroll
            for (int hh = 0; hh < 6; ++hh) s_ += sout[wInB][hh * 40 + d];
            logits[(size_t)gw * 40 + d] = s_ * (1.0f / 6.0f) + __ldg(&r2m[(size_t)gw * 40 + d]);
        }
    }
}

// ---------------- host ----------------
extern "C" void kernel_launch(void* const* d_in, const int* in_sizes, int n_in,
                              void* d_out, int out_size)
{
    const float* feat  = (const float*)d_in[0];
    const int*   src   = (const int*)d_in[1];
    const int*   dst   = (const int*)d_in[2];
    const float* W0    = (const float*)d_in[3];
    const float* al0   = (const float*)d_in[4];
    const float* ar0   = (const float*)d_in[5];
    const float* b0    = (const float*)d_in[6];
    const float* W1    = (const float*)d_in[7];
    const float* al1   = (const float*)d_in[8];
    const float* ar1   = (const float*)d_in[9];
    const float* b1    = (const float*)d_in[10];
    const float* W2    = (const float*)d_in[11];
    const float* al2   = (const float*)d_in[12];
    const float* ar2   = (const float*)d_in[13];
    const float* b2    = (const float*)d_in[14];
    const float* resW2 = (const float*)d_in[15];

    const int n = NNODES;
    const int E = in_sizes[1];

    float* logits = (float*)d_out;
    float* h1     = (float*)d_out + n * 40;

    float *ph0, *pr2, *pel, *per;
    __half* pzh;
    __nv_bfloat16 *pAh, *pAl;
    cudaGetSymbolAddress((void**)&pzh, g_zh);
    cudaGetSymbolAddress((void**)&ph0, g_h0);
    cudaGetSymbolAddress((void**)&pr2, g_r2);
    cudaGetSymbolAddress((void**)&pel, g_el);
    cudaGetSymbolAddress((void**)&per, g_er);
    cudaGetSymbolAddress((void**)&pAh, g_Ahi);
    cudaGetSymbolAddress((void**)&pAl, g_Alo);

    cudaFuncSetAttribute(k_gemm0, cudaFuncAttributeMaxDynamicSharedMemorySize, GEMM_SMEM128);
    cudaFuncSetAttribute(k_gemm1, cudaFuncAttributeMaxDynamicSharedMemorySize, GEMM_SMEM128);
    cudaFuncSetAttribute(k_gemm2, cudaFuncAttributeMaxDynamicSharedMemorySize, GEMM_SMEM128);
    cudaFuncSetAttribute(k_gemm_res, cudaFuncAttributeMaxDynamicSharedMemorySize, GEMM_SMEM64);

    const int nGemm = ((n + 127) / 128) * 2;          // 782
    const int nGemmM = (n + 127) / 128;               // 391
    const int histBlocks = (E + 255) / 256;
    const int scatBlocks = (E + 511) / 512;
    const int zeroBlocks = (n * 6 + 255) / 256;
    const int aggBlocks  = (n + 7) / 8;

    // 1. zero deg + el/er(L0)
    k_zero0<<<zeroBlocks, 256>>>(n, n * 6);
    // 2. splitA(feat) + splitBt(W0) + hist
    k_prep0<<<SPLITA_BLOCKS + 256 + histBlocks, 256>>>(feat, W0, dst, E);
    // 3. scan
    k_scan<<<1, 1024>>>(n, E);
    // 4. gemm L0 + scatter
    k_gemm0<<<nGemm + scatBlocks, 512, GEMM_SMEM128>>>(pAh, pAl, pzh, al0, ar0, pel, per,
                                                       n, nGemm, src, dst, E);
    // 5. agg L0
    k_agg256<false><<<aggBlocks, 256>>>(pzh, pel, per, b0, nullptr, ph0, pAh, pAl, n);
    // 6. prep L1
    k_prep1<<<256 + zeroBlocks, 256>>>(W1, n * 6);
    // 7. gemm L1
    k_gemm1<<<nGemm, 512, GEMM_SMEM128>>>(pAh, pAl, pzh, al1, ar1, pel, per, n);
    // 8. agg L1 -> h1 (in d_out)
    k_agg256<true><<<aggBlocks, 256>>>(pzh, pel, per, b1, ph0, h1, pAh, pAl, n);
    // 9. prep L2 (W2 split + resW2_mean split + zero el/er)
    k_prep2<<<256 + 64 + zeroBlocks, 256>>>(W2, resW2, n * 6);
    // 10. gemm L2 (W2, ELR)
    k_gemm2<<<nGemm, 512, GEMM_SMEM128>>>(pAh, pAl, pzh, al2, ar2, pel, per, n);
    // 10b. small gemm: r2m = h1 @ resW2_mean
    k_gemm_res<<<nGemmM, 256, GEMM_SMEM64>>>(pAh, pAl, pr2, n);
    // 11. agg L2 -> logits
    k_agg_l2<<<aggBlocks, 256>>>(pzh, pel, per, b2, pr2, logits, n);
}

// round 10
// speedup vs baseline: 3.4809x; 1.2691x over previous
#include <cuda_runtime.h>
#include <cuda_fp16.h>
#include <math.h>
#include <cstdint>

// ---------------- problem constants ----------------
#define NNODES 50000
#define ECAP   1000000
#define SPLITA_BLOCKS 12500   // (NNODES*256/4)/256

// ---------------- device scratch ----------------
__device__ __align__(16) __half g_zh[NNODES * 256];
__device__ float g_h0[NNODES * 256];
__device__ float g_r2[NNODES * 40];
__device__ float g_el[NNODES * 6];
__device__ float g_er[NNODES * 6];
__device__ int   g_deg[NNODES];
__device__ int   g_rowstart[NNODES + 1];
__device__ int   g_cursor[NNODES];
__device__ int   g_srcs[ECAP];
__device__ __align__(16) __half g_Ah[NNODES * 256];   // fp16 GEMM A
__device__ __align__(16) __half g_Bh[256 * 256];      // fp16 weight [N(pad256) x K=256]
__device__ __align__(16) __half g_Bh2[64 * 256];      // resW2_mean fp16 [64(d pad) x 256]

// ================= PTX helpers =================
__device__ __forceinline__ uint32_t smem_u32(const void* p) {
    uint32_t a;
    asm("{ .reg .u64 t; cvta.to.shared.u64 t, %1; cvt.u32.u64 %0, t; }" : "=r"(a) : "l"(p));
    return a;
}
__device__ __forceinline__ void cp16(uint32_t dst, const void* src, uint32_t srcsize) {
    asm volatile("cp.async.cg.shared.global [%0], [%1], 16, %2;"
                 :: "r"(dst), "l"(src), "r"(srcsize));
}
#define CP_COMMIT() asm volatile("cp.async.commit_group;" ::: "memory")
#define CP_WAIT(n)  asm volatile("cp.async.wait_group %0;" :: "n"(n) : "memory")
#define LDSM_X4(r0, r1, r2, r3, addr) \
    asm volatile("ldmatrix.sync.aligned.m8n8.x4.shared.b16 {%0,%1,%2,%3}, [%4];" \
        : "=r"(r0), "=r"(r1), "=r"(r2), "=r"(r3) : "r"(addr))
#define MMA_F16(acc, a, b) \
    asm volatile("mma.sync.aligned.m16n8k16.row.col.f32.f16.f16.f32 " \
        "{%0,%1,%2,%3}, {%4,%5,%6,%7}, {%8,%9}, {%0,%1,%2,%3};" \
        : "+f"((acc)[0]), "+f"((acc)[1]), "+f"((acc)[2]), "+f"((acc)[3]) \
        : "r"((a)[0]), "r"((a)[1]), "r"((a)[2]), "r"((a)[3]), "r"((b)[0]), "r"((b)[1]))

// ---------------- helpers ----------------
__device__ __forceinline__ void convBt_elem(const float* __restrict__ B,
                                            __half* __restrict__ out, int t, int Nn) {
    int nrow = t >> 8, k = t & 255;
    float x = (nrow < Nn) ? B[(size_t)k * Nn + nrow] : 0.f;
    out[t] = __float2half_rn(x);
}

// ---------------- kernel 1: zero deg + el/er ----------------
__global__ void k_zero0(int n, int n6) {
    int i = blockIdx.x * blockDim.x + threadIdx.x;
    if (i < n) g_deg[i] = 0;
    if (i < n6) { g_el[i] = 0.f; g_er[i] = 0.f; }
}

// ---------------- kernel 2: conv feat->fp16 + conv W0 + hist ----------------
__global__ void k_prep0(const float* __restrict__ feat, const float* __restrict__ W0,
                        const int* __restrict__ dst, int E) {
    int bx = blockIdx.x;
    if (bx < SPLITA_BLOCKS) {
        int i = bx * 256 + threadIdx.x;
        float4 v = reinterpret_cast<const float4*>(feat)[i];
        __half2 p0 = __floats2half2_rn(v.x, v.y);
        __half2 p1 = __floats2half2_rn(v.z, v.w);
        reinterpret_cast<uint2*>(g_Ah)[i] =
            make_uint2(*reinterpret_cast<uint32_t*>(&p0), *reinterpret_cast<uint32_t*>(&p1));
    } else if (bx < SPLITA_BLOCKS + 256) {
        int t = (bx - SPLITA_BLOCKS) * 256 + threadIdx.x;
        convBt_elem(W0, g_Bh, t, 256);
    } else {
        int e = (bx - SPLITA_BLOCKS - 256) * 256 + threadIdx.x;
        if (e < E) atomicAdd(&g_deg[dst[e]], 1);
    }
}

// ---------------- kernel: scan ----------------
__global__ void k_scan(int n, int E) {
    __shared__ int wsum[32];
    __shared__ int carry;
    int lane = threadIdx.x & 31, w = threadIdx.x >> 5;
    if (threadIdx.x == 0) carry = 0;
    __syncthreads();
    for (int base = 0; base < n; base += 1024) {
        int i = base + threadIdx.x;
        int v = (i < n) ? g_deg[i] : 0;
        int x = v;
        #pragma unroll
        for (int off = 1; off < 32; off <<= 1) {
            int t = __shfl_up_sync(0xffffffffu, x, off);
            if (lane >= off) x += t;
        }
        if (lane == 31) wsum[w] = x;
        __syncthreads();
        if (w == 0) {
            int y = wsum[lane];
            #pragma unroll
            for (int off = 1; off < 32; off <<= 1) {
                int t = __shfl_up_sync(0xffffffffu, y, off);
                if (lane >= off) y += t;
            }
            wsum[lane] = y;
        }
        __syncthreads();
        int incl = x + (w ? wsum[w - 1] : 0) + carry;
        int excl = incl - v;
        if (i < n) { g_rowstart[i] = excl; g_cursor[i] = excl; }
        __syncthreads();
        if (threadIdx.x == 1023) carry = incl;
        __syncthreads();
    }
    if (threadIdx.x == 0) g_rowstart[n] = E;
}

// ---------------- prep1 / prep2 ----------------
__global__ void k_prep1(const float* __restrict__ W1, int n6) {
    int bx = blockIdx.x;
    if (bx < 256) {
        convBt_elem(W1, g_Bh, bx * 256 + threadIdx.x, 256);
    } else {
        int i = (bx - 256) * 256 + threadIdx.x;
        if (i < n6) { g_el[i] = 0.f; g_er[i] = 0.f; }
    }
}
__global__ void k_prep2(const float* __restrict__ W2, const float* __restrict__ resW2, int n6) {
    int bx = blockIdx.x;
    if (bx < 256) {
        convBt_elem(W2, g_Bh, bx * 256 + threadIdx.x, 240);
    } else if (bx < 256 + 64) {
        int t = (bx - 256) * 256 + threadIdx.x;
        int d = t >> 8, k = t & 255;
        float x = 0.f;
        if (d < 40) {
            float s_ = 0.f;
            #pragma unroll
            for (int h = 0; h < 6; ++h) s_ += resW2[(size_t)k * 240 + h * 40 + d];
            x = s_ * (1.0f / 6.0f);
        }
        g_Bh2[t] = __float2half_rn(x);
    } else {
        int i = (bx - 256 - 64) * 256 + threadIdx.x;
        if (i < n6) { g_el[i] = 0.f; g_er[i] = 0.f; }
    }
}

// ---------------- GEMM body (fp16 mma.sync, 3-stage pipeline, templated BN) ----------------
// A stage: 128 rows x 64 fp16 = 16 KB. B stage: BN x 64 fp16 = BN*128 bytes.
template <int BN>
__device__ __forceinline__ void gemm_load_stage(
    uint32_t sb, const __half* __restrict__ Ah, const __half* __restrict__ Bh,
    int m0, int n0, int M, int kb, int tid)
{
    constexpr int THREADS = (BN == 128) ? 512 : 256;
    #pragma unroll
    for (int it = 0; it < 1024 / THREADS; ++it) {
        int idx = tid + it * THREADS;
        int row = idx >> 3, ch = idx & 7;
        uint32_t dst = sb + row * 128 + (((uint32_t)(ch ^ (row & 7))) << 4);
        const __half* src = Ah + (size_t)(m0 + row) * 256 + kb * 64 + ch * 8;
        cp16(dst, src, (m0 + row) < M ? 16u : 0u);
    }
    #pragma unroll
    for (int it = 0; it < (BN * 8) / THREADS; ++it) {
        int idx = tid + it * THREADS;
        int row = idx >> 3, ch = idx & 7;
        uint32_t dst = sb + 16384 + row * 128 + (((uint32_t)(ch ^ (row & 7))) << 4);
        const __half* src = Bh + (size_t)(n0 + row) * 256 + kb * 64 + ch * 8;
        cp16(dst, src, 16u);
    }
}

template <bool ELR, int BN>
__device__ __forceinline__ void gemm_body(
    const __half* __restrict__ Ah, const __half* __restrict__ Bh,
    __half* __restrict__ Ch, float* __restrict__ Cf,
    const float* __restrict__ al, const float* __restrict__ ar,
    float* __restrict__ el, float* __restrict__ er,
    int M, int Nn, int H, int D, int m0, int n0)
{
    constexpr uint32_t STAGE = 16384u + (uint32_t)BN * 128u;
    extern __shared__ char smem[];
    const uint32_t sbase = smem_u32(smem);
    const int tid = threadIdx.x, wid = tid >> 5, lane = tid & 31;
    const int warp_m = wid & 3, warp_n = wid >> 2;

    float acc[2][4][4];
    #pragma unroll
    for (int mt = 0; mt < 2; ++mt)
        #pragma unroll
        for (int nt = 0; nt < 4; ++nt)
            #pragma unroll
            for (int q = 0; q < 4; ++q) acc[mt][nt][q] = 0.f;

    const int rowA = warp_m * 32 + (lane & 15);
    const int rowB = warp_n * 32 + (lane & 7) + ((lane >> 4) << 3);
    const uint32_t rowAswz = (uint32_t)(rowA & 7);
    const uint32_t rowBswz = (uint32_t)(rowB & 7);
    const int halfA = lane >> 4;
    const int halfB = (lane >> 3) & 1;

    gemm_load_stage<BN>(sbase, Ah, Bh, m0, n0, M, 0, tid);
    CP_COMMIT();
    gemm_load_stage<BN>(sbase + STAGE, Ah, Bh, m0, n0, M, 1, tid);
    CP_COMMIT();

    #pragma unroll 1
    for (int kb = 0; kb < 4; ++kb) {
        if (kb < 3) { CP_WAIT(1); } else { CP_WAIT(0); }
        __syncthreads();
        if (kb < 2) {
            gemm_load_stage<BN>(sbase + ((kb + 2) % 3) * STAGE, Ah, Bh, m0, n0, M, kb + 2, tid);
            CP_COMMIT();
        }
        const uint32_t sb = sbase + (kb % 3) * STAGE;
        #pragma unroll
        for (int s = 0; s < 4; ++s) {
            uint32_t a[2][4];
            uint32_t b[4][2];
            const uint32_t offA = (((uint32_t)(s * 2 + halfA) ^ rowAswz) << 4);
            const uint32_t offB = (((uint32_t)(s * 2 + halfB) ^ rowBswz) << 4);
            #pragma unroll
            for (int mt = 0; mt < 2; ++mt) {
                uint32_t addr = sb + (uint32_t)(rowA + mt * 16) * 128 + offA;
                LDSM_X4(a[mt][0], a[mt][1], a[mt][2], a[mt][3], addr);
            }
            #pragma unroll
            for (int ntp = 0; ntp < 2; ++ntp) {
                uint32_t addr = sb + 16384 + (uint32_t)(rowB + ntp * 16) * 128 + offB;
                LDSM_X4(b[2 * ntp][0], b[2 * ntp][1], b[2 * ntp + 1][0], b[2 * ntp + 1][1], addr);
            }
            #pragma unroll
            for (int mt = 0; mt < 2; ++mt)
                #pragma unroll
                for (int nt = 0; nt < 4; ++nt)
                    MMA_F16(acc[mt][nt], a[mt], b[nt]);
        }
    }

    #pragma unroll
    for (int mt = 0; mt < 2; ++mt) {
        int row = m0 + warp_m * 32 + mt * 16 + (lane >> 2);
        #pragma unroll
        for (int nt = 0; nt < 4; ++nt) {
            int col = n0 + warp_n * 32 + nt * 8 + (lane & 3) * 2;
            if (col < Nn) {
                if (ELR) {
                    if (row < M)
                        *reinterpret_cast<__half2*>(Ch + (size_t)row * Nn + col) =
                            __floats2half2_rn(acc[mt][nt][0], acc[mt][nt][1]);
                    if (row + 8 < M)
                        *reinterpret_cast<__half2*>(Ch + (size_t)(row + 8) * Nn + col) =
                            __floats2half2_rn(acc[mt][nt][2], acc[mt][nt][3]);
                } else {
                    if (row < M)
                        *reinterpret_cast<float2*>(Cf + (size_t)row * Nn + col) =
                            make_float2(acc[mt][nt][0], acc[mt][nt][1]);
                    if (row + 8 < M)
                        *reinterpret_cast<float2*>(Cf + (size_t)(row + 8) * Nn + col) =
                            make_float2(acc[mt][nt][2], acc[mt][nt][3]);
                }
            }
        }
    }

    if (ELR) {
        const int colbase = n0 + warp_n * 32;
        const int h0 = colbase / D;
        int nt_split = ((h0 + 1) * D - colbase) >> 3;
        if (nt_split > 4) nt_split = 4;
        float sl[2][2][2] = {}, sr[2][2][2] = {};
        #pragma unroll
        for (int nt = 0; nt < 4; ++nt) {
            int colg = colbase + nt * 8;
            float2 av = make_float2(0.f, 0.f), rv = av;
            if (colg < Nn) {
                int h = (nt < nt_split) ? h0 : (h0 + 1);
                int d = colg - h * D + (lane & 3) * 2;
                av = __ldg(reinterpret_cast<const float2*>(al + h * D + d));
                rv = __ldg(reinterpret_cast<const float2*>(ar + h * D + d));
            }
            int slot = (nt >= nt_split);
            #pragma unroll
            for (int mt = 0; mt < 2; ++mt) {
                sl[mt][0][slot] += acc[mt][nt][0] * av.x + acc[mt][nt][1] * av.y;
                sr[mt][0][slot] += acc[mt][nt][0] * rv.x + acc[mt][nt][1] * rv.y;
                sl[mt][1][slot] += acc[mt][nt][2] * av.x + acc[mt][nt][3] * av.y;
                sr[mt][1][slot] += acc[mt][nt][2] * rv.x + acc[mt][nt][3] * rv.y;
            }
        }
        #pragma unroll
        for (int mt = 0; mt < 2; ++mt)
            #pragma unroll
            for (int rh = 0; rh < 2; ++rh)
                #pragma unroll
                for (int sidx = 0; sidx < 2; ++sidx) {
                    float vl = sl[mt][rh][sidx], vr = sr[mt][rh][sidx];
                    vl += __shfl_xor_sync(0xffffffffu, vl, 1);
                    vl += __shfl_xor_sync(0xffffffffu, vl, 2);
                    vr += __shfl_xor_sync(0xffffffffu, vr, 1);
                    vr += __shfl_xor_sync(0xffffffffu, vr, 2);
                    sl[mt][rh][sidx] = vl; sr[mt][rh][sidx] = vr;
                }
        if ((lane & 3) == 0) {
            bool slot1_valid = (nt_split < 4) && (colbase + nt_split * 8) < Nn;
            #pragma unroll
            for (int mt = 0; mt < 2; ++mt) {
                #pragma unroll
                for (int rh = 0; rh < 2; ++rh) {
                    int row = m0 + warp_m * 32 + mt * 16 + (lane >> 2) + rh * 8;
                    if (row < M) {
                        atomicAdd(&el[(size_t)row * H + h0], sl[mt][rh][0]);
                        atomicAdd(&er[(size_t)row * H + h0], sr[mt][rh][0]);
                        if (slot1_valid) {
                            atomicAdd(&el[(size_t)row * H + h0 + 1], sl[mt][rh][1]);
                            atomicAdd(&er[(size_t)row * H + h0 + 1], sr[mt][rh][1]);
                        }
                    }
                }
            }
        }
    }
}

#define GEMM_SMEM128 (3 * (16384 + 128 * 128))
#define GEMM_SMEM64  (3 * (16384 + 64 * 128))

// ---------------- GEMM launches ----------------
__global__ __launch_bounds__(512, 1) void k_gemm0(
    const __half* __restrict__ Ah, __half* __restrict__ Ch,
    const float* __restrict__ al, const float* __restrict__ ar,
    float* __restrict__ el, float* __restrict__ er, int M, int nGemm,
    const int* __restrict__ src, const int* __restrict__ dst, int E)
{
    int bx = blockIdx.x;
    if (bx < nGemm) {
        gemm_body<true, 128>(Ah, g_Bh, Ch, nullptr, al, ar, el, er,
                             M, 256, 4, 64, (bx >> 1) * 128, (bx & 1) * 128);
    } else {
        int e = (bx - nGemm) * 512 + threadIdx.x;
        if (e < E) {
            int p = atomicAdd(&g_cursor[dst[e]], 1);
            g_srcs[p] = src[e];
        }
    }
}

__global__ __launch_bounds__(512, 1) void k_gemm1(
    const __half* __restrict__ Ah, __half* __restrict__ Ch,
    const float* __restrict__ al, const float* __restrict__ ar,
    float* __restrict__ el, float* __restrict__ er, int M)
{
    int bx = blockIdx.x;
    gemm_body<true, 128>(Ah, g_Bh, Ch, nullptr, al, ar, el, er,
                         M, 256, 4, 64, (bx >> 1) * 128, (bx & 1) * 128);
}

__global__ __launch_bounds__(512, 1) void k_gemm2(
    const __half* __restrict__ Ah, __half* __restrict__ Ch,
    const float* __restrict__ al, const float* __restrict__ ar,
    float* __restrict__ el, float* __restrict__ er, int M)
{
    int bx = blockIdx.x;
    gemm_body<true, 128>(Ah, g_Bh, Ch, nullptr, al, ar, el, er,
                         M, 240, 6, 40, (bx >> 1) * 128, (bx & 1) * 128);
}

__global__ __launch_bounds__(256, 1) void k_gemm_res(
    const __half* __restrict__ Ah, float* __restrict__ Cf, int M)
{
    gemm_body<false, 64>(Ah, g_Bh2, nullptr, Cf, nullptr, nullptr,
                         nullptr, nullptr, M, 40, 1, 64, blockIdx.x * 128, 0);
}

// ---------------- aggregation helpers ----------------
__device__ __forceinline__ void fma_row(float4& a0, float4& a1, float wh, uint4 q) {
    float2 p0 = __half22float2(*reinterpret_cast<__half2*>(&q.x));
    float2 p1 = __half22float2(*reinterpret_cast<__half2*>(&q.y));
    float2 p2 = __half22float2(*reinterpret_cast<__half2*>(&q.z));
    float2 p3 = __half22float2(*reinterpret_cast<__half2*>(&q.w));
    a0.x = fmaf(wh, p0.x, a0.x); a0.y = fmaf(wh, p0.y, a0.y);
    a0.z = fmaf(wh, p1.x, a0.z); a0.w = fmaf(wh, p1.y, a0.w);
    a1.x = fmaf(wh, p2.x, a1.x); a1.y = fmaf(wh, p2.y, a1.y);
    a1.z = fmaf(wh, p3.x, a1.z); a1.w = fmaf(wh, p3.y, a1.w);
}

// ---------------- aggregation, layers 0/1 (fp16 z; fp16 A output for next GEMM) ----------------
template <bool RES>
__global__ __launch_bounds__(256) void k_agg256(
    const __half* __restrict__ zh, const float* __restrict__ el,
    const float* __restrict__ er, const float* __restrict__ bias,
    const float* __restrict__ xres, float* __restrict__ out,
    __half* __restrict__ oah, int n)
{
    int gw = (blockIdx.x * blockDim.x + threadIdx.x) >> 5;
    if (gw >= n) return;
    int lane = threadIdx.x & 31;
    int beg = g_rowstart[gw], end = g_rowstart[gw + 1];
    float erh = (lane < 4) ? __ldg(&er[gw * 4 + lane]) : 0.f;
    int h = lane >> 3;
    int c0 = lane * 8;
    float4 acc0 = make_float4(0.f, 0.f, 0.f, 0.f), acc1 = acc0;
    float denom = 0.f;
    int i = beg;
    #pragma unroll 1
    for (; i + 2 <= end; i += 2) {
        int s0 = __ldg(&g_srcs[i]);
        int s1 = __ldg(&g_srcs[i + 1]);
        uint4 q0 = __ldg(reinterpret_cast<const uint4*>(zh + (size_t)s0 * 256 + c0));
        uint4 q1 = __ldg(reinterpret_cast<const uint4*>(zh + (size_t)s1 * 256 + c0));
        float w0 = 0.f, w1 = 0.f;
        if (lane < 4) {
            float e0 = __ldg(&el[s0 * 4 + lane]) + erh;
            float e1 = __ldg(&el[s1 * 4 + lane]) + erh;
            e0 = (e0 > 0.f) ? e0 : 0.2f * e0;
            e1 = (e1 > 0.f) ? e1 : 0.2f * e1;
            w0 = __expf(e0); w1 = __expf(e1);
            denom += w0 + w1;
        }
        float wh0 = __shfl_sync(0xffffffffu, w0, h);
        float wh1 = __shfl_sync(0xffffffffu, w1, h);
        fma_row(acc0, acc1, wh0, q0);
        fma_row(acc0, acc1, wh1, q1);
    }
    if (i < end) {
        int s0 = __ldg(&g_srcs[i]);
        uint4 q0 = __ldg(reinterpret_cast<const uint4*>(zh + (size_t)s0 * 256 + c0));
        float w0 = 0.f;
        if (lane < 4) {
            float e0 = __ldg(&el[s0 * 4 + lane]) + erh;
            e0 = (e0 > 0.f) ? e0 : 0.2f * e0;
            w0 = __expf(e0);
            denom += w0;
        }
        float wh0 = __shfl_sync(0xffffffffu, w0, h);
        fma_row(acc0, acc1, wh0, q0);
    }
    float dh = __shfl_sync(0xffffffffu, denom, h);
    float inv = 1.f / dh;
    const float4* bp = reinterpret_cast<const float4*>(bias + c0);
    float4 b0 = __ldg(bp), b1 = __ldg(bp + 1);
    float v[8];
    v[0] = fmaf(acc0.x, inv, b0.x); v[1] = fmaf(acc0.y, inv, b0.y);
    v[2] = fmaf(acc0.z, inv, b0.z); v[3] = fmaf(acc0.w, inv, b0.w);
    v[4] = fmaf(acc1.x, inv, b1.x); v[5] = fmaf(acc1.y, inv, b1.y);
    v[6] = fmaf(acc1.z, inv, b1.z); v[7] = fmaf(acc1.w, inv, b1.w);
    if (RES) {
        const float4* rp = reinterpret_cast<const float4*>(xres + (size_t)gw * 256 + c0);
        float4 r0 = __ldg(rp), r1 = __ldg(rp + 1);
        v[0] += r0.x; v[1] += r0.y; v[2] += r0.z; v[3] += r0.w;
        v[4] += r1.x; v[5] += r1.y; v[6] += r1.z; v[7] += r1.w;
    }
    #pragma unroll
    for (int j = 0; j < 8; ++j) v[j] = (v[j] > 0.f) ? v[j] : expm1f(v[j]);
    float4* op = reinterpret_cast<float4*>(out + (size_t)gw * 256 + c0);
    op[0] = make_float4(v[0], v[1], v[2], v[3]);
    op[1] = make_float4(v[4], v[5], v[6], v[7]);
    // fp16 copy for next layer's GEMM A
    __half2 p0 = __floats2half2_rn(v[0], v[1]);
    __half2 p1 = __floats2half2_rn(v[2], v[3]);
    __half2 p2 = __floats2half2_rn(v[4], v[5]);
    __half2 p3 = __floats2half2_rn(v[6], v[7]);
    *reinterpret_cast<uint4*>(oah + (size_t)gw * 256 + c0) =
        make_uint4(*reinterpret_cast<uint32_t*>(&p0), *reinterpret_cast<uint32_t*>(&p1),
                   *reinterpret_cast<uint32_t*>(&p2), *reinterpret_cast<uint32_t*>(&p3));
}

// ---------------- aggregation, layer 2 (res via head-averaged r2m[n,40]) ----------------
__global__ __launch_bounds__(256) void k_agg_l2(
    const __half* __restrict__ zh, const float* __restrict__ el,
    const float* __restrict__ er, const float* __restrict__ bias,
    const float* __restrict__ r2m, float* __restrict__ logits, int n)
{
    __shared__ float sout[8][240];
    int wInB = threadIdx.x >> 5;
    int gw = blockIdx.x * 8 + wInB;
    int lane = threadIdx.x & 31;
    bool act = (lane < 30);
    if (gw < n) {
        int beg = g_rowstart[gw], end = g_rowstart[gw + 1];
        float erh = (lane < 6) ? __ldg(&er[gw * 6 + lane]) : 0.f;
        int h = act ? (lane / 5) : 0;
        int c0 = lane * 8;
        float4 acc0 = make_float4(0.f, 0.f, 0.f, 0.f), acc1 = acc0;
        float denom = 0.f;
        int i = beg;
        #pragma unroll 1
        for (; i + 2 <= end; i += 2) {
            int s0 = __ldg(&g_srcs[i]);
            int s1 = __ldg(&g_srcs[i + 1]);
            uint4 q0 = make_uint4(0, 0, 0, 0), q1 = q0;
            if (act) {
                q0 = __ldg(reinterpret_cast<const uint4*>(zh + (size_t)s0 * 240 + c0));
                q1 = __ldg(reinterpret_cast<const uint4*>(zh + (size_t)s1 * 240 + c0));
            }
            float w0 = 0.f, w1 = 0.f;
            if (lane < 6) {
                float e0 = __ldg(&el[s0 * 6 + lane]) + erh;
                float e1 = __ldg(&el[s1 * 6 + lane]) + erh;
                e0 = (e0 > 0.f) ? e0 : 0.2f * e0;
                e1 = (e1 > 0.f) ? e1 : 0.2f * e1;
                w0 = __expf(e0); w1 = __expf(e1);
                denom += w0 + w1;
            }
            float wh0 = __shfl_sync(0xffffffffu, w0, h);
            float wh1 = __shfl_sync(0xffffffffu, w1, h);
            if (act) {
                fma_row(acc0, acc1, wh0, q0);
                fma_row(acc0, acc1, wh1, q1);
            }
        }
        if (i < end) {
            int s0 = __ldg(&g_srcs[i]);
            uint4 q0 = make_uint4(0, 0, 0, 0);
            if (act) q0 = __ldg(reinterpret_cast<const uint4*>(zh + (size_t)s0 * 240 + c0));
            float w0 = 0.f;
            if (lane < 6) {
                float e0 = __ldg(&el[s0 * 6 + lane]) + erh;
                e0 = (e0 > 0.f) ? e0 : 0.2f * e0;
                w0 = __expf(e0);
                denom += w0;
            }
            float wh0 = __shfl_sync(0xffffffffu, w0, h);
            if (act) fma_row(acc0, acc1, wh0, q0);
        }
        float dh = __shfl_sync(0xffffffffu, denom, h);
        if (act) {
            float inv = 1.f / dh;
            const float4* bp = reinterpret_cast<const float4*>(bias + c0);
            float4 b0 = __ldg(bp), b1 = __ldg(bp + 1);
            sout[wInB][c0 + 0] = fmaf(acc0.x, inv, b0.x);
            sout[wInB][c0 + 1] = fmaf(acc0.y, inv, b0.y);
            sout[wInB][c0 + 2] = fmaf(acc0.z, inv, b0.z);
            sout[wInB][c0 + 3] = fmaf(acc0.w, inv, b0.w);
            sout[wInB][c0 + 4] = fmaf(acc1.x, inv, b1.x);
            sout[wInB][c0 + 5] = fmaf(acc1.y, inv, b1.y);
            sout[wInB][c0 + 6] = fmaf(acc1.z, inv, b1.z);
            sout[wInB][c0 + 7] = fmaf(acc1.w, inv, b1.w);
        }
    }
    __syncwarp();
    if (gw < n) {
        for (int d = lane; d < 40; d += 32) {
            float s_ = 0.f;
            #pragma unroll
            for (int hh = 0; hh < 6; ++hh) s_ += sout[wInB][hh * 40 + d];
            logits[(size_t)gw * 40 + d] = s_ * (1.0f / 6.0f) + __ldg(&r2m[(size_t)gw * 40 + d]);
        }
    }
}

// ---------------- host ----------------
extern "C" void kernel_launch(void* const* d_in, const int* in_sizes, int n_in,
                              void* d_out, int out_size)
{
    const float* feat  = (const float*)d_in[0];
    const int*   src   = (const int*)d_in[1];
    const int*   dst   = (const int*)d_in[2];
    const float* W0    = (const float*)d_in[3];
    const float* al0   = (const float*)d_in[4];
    const float* ar0   = (const float*)d_in[5];
    const float* b0    = (const float*)d_in[6];
    const float* W1    = (const float*)d_in[7];
    const float* al1   = (const float*)d_in[8];
    const float* ar1   = (const float*)d_in[9];
    const float* b1    = (const float*)d_in[10];
    const float* W2    = (const float*)d_in[11];
    const float* al2   = (const float*)d_in[12];
    const float* ar2   = (const float*)d_in[13];
    const float* b2    = (const float*)d_in[14];
    const float* resW2 = (const float*)d_in[15];

    const int n = NNODES;
    const int E = in_sizes[1];

    float* logits = (float*)d_out;
    float* h1     = (float*)d_out + n * 40;

    float *ph0, *pr2, *pel, *per;
    __half *pzh, *pAh;
    cudaGetSymbolAddress((void**)&pzh, g_zh);
    cudaGetSymbolAddress((void**)&ph0, g_h0);
    cudaGetSymbolAddress((void**)&pr2, g_r2);
    cudaGetSymbolAddress((void**)&pel, g_el);
    cudaGetSymbolAddress((void**)&per, g_er);
    cudaGetSymbolAddress((void**)&pAh, g_Ah);

    cudaFuncSetAttribute(k_gemm0, cudaFuncAttributeMaxDynamicSharedMemorySize, GEMM_SMEM128);
    cudaFuncSetAttribute(k_gemm1, cudaFuncAttributeMaxDynamicSharedMemorySize, GEMM_SMEM128);
    cudaFuncSetAttribute(k_gemm2, cudaFuncAttributeMaxDynamicSharedMemorySize, GEMM_SMEM128);
    cudaFuncSetAttribute(k_gemm_res, cudaFuncAttributeMaxDynamicSharedMemorySize, GEMM_SMEM64);

    const int nGemm = ((n + 127) / 128) * 2;          // 782
    const int nGemmM = (n + 127) / 128;               // 391
    const int histBlocks = (E + 255) / 256;
    const int scatBlocks = (E + 511) / 512;
    const int zeroBlocks = (n * 6 + 255) / 256;
    const int aggBlocks  = (n + 7) / 8;

    // 1. zero deg + el/er(L0)
    k_zero0<<<zeroBlocks, 256>>>(n, n * 6);
    // 2. conv feat + conv W0 + hist
    k_prep0<<<SPLITA_BLOCKS + 256 + histBlocks, 256>>>(feat, W0, dst, E);
    // 3. scan
    k_scan<<<1, 1024>>>(n, E);
    // 4. gemm L0 + scatter
    k_gemm0<<<nGemm + scatBlocks, 512, GEMM_SMEM128>>>(pAh, pzh, al0, ar0, pel, per,
                                                       n, nGemm, src, dst, E);
    // 5. agg L0
    k_agg256<false><<<aggBlocks, 256>>>(pzh, pel, per, b0, nullptr, ph0, pAh, n);
    // 6. prep L1
    k_prep1<<<256 + zeroBlocks, 256>>>(W1, n * 6);
    // 7. gemm L1
    k_gemm1<<<nGemm, 512, GEMM_SMEM128>>>(pAh, pzh, al1, ar1, pel, per, n);
    // 8. agg L1 -> h1 (in d_out)
    k_agg256<true><<<aggBlocks, 256>>>(pzh, pel, per, b1, ph0, h1, pAh, n);
    // 9. prep L2 (W2 conv + resW2_mean conv + zero el/er)
    k_prep2<<<256 + 64 + zeroBlocks, 256>>>(W2, resW2, n * 6);
    // 10. gemm L2 (W2, ELR)
    k_gemm2<<<nGemm, 512, GEMM_SMEM128>>>(pAh, pzh, al2, ar2, pel, per, n);
    // 10b. small gemm: r2m = h1 @ resW2_mean
    k_gemm_res<<<nGemmM, 256, GEMM_SMEM64>>>(pAh, pr2, n);
    // 11. agg L2 -> logits
    k_agg_l2<<<aggBlocks, 256>>>(pzh, pel, per, b2, pr2, logits, n);
}

// round 11
// speedup vs baseline: 3.6166x; 1.0390x over previous
#include <cuda_runtime.h>
#include <cuda_fp16.h>
#include <math.h>
#include <cstdint>

// ---------------- problem constants ----------------
#define NNODES 50000
#define ECAP   1000000
#define SPLITA_BLOCKS 12500   // (NNODES*256/4)/256

// ---------------- device scratch ----------------
__device__ __align__(16) __half g_zh[NNODES * 256];
__device__ float g_h0[NNODES * 256];
__device__ float g_r2[NNODES * 40];
__device__ float g_elA[NNODES * 6];
__device__ float g_erA[NNODES * 6];
__device__ float g_elB[NNODES * 6];
__device__ float g_erB[NNODES * 6];
__device__ int   g_deg[NNODES];
__device__ int   g_rowstart[NNODES + 1];
__device__ int   g_cursor[NNODES];
__device__ int   g_srcs[ECAP];
__device__ __align__(16) __half g_Ah[NNODES * 256];   // fp16 GEMM A
__device__ __align__(16) __half g_Bh[256 * 256];      // fp16 weight [N(pad256) x K=256]
__device__ __align__(16) __half g_Bh2[64 * 256];      // resW2_mean fp16 [64(d pad) x 256]

// ================= PTX helpers =================
__device__ __forceinline__ uint32_t smem_u32(const void* p) {
    uint32_t a;
    asm("{ .reg .u64 t; cvta.to.shared.u64 t, %1; cvt.u32.u64 %0, t; }" : "=r"(a) : "l"(p));
    return a;
}
__device__ __forceinline__ void cp16(uint32_t dst, const void* src, uint32_t srcsize) {
    asm volatile("cp.async.cg.shared.global [%0], [%1], 16, %2;"
                 :: "r"(dst), "l"(src), "r"(srcsize));
}
#define CP_COMMIT() asm volatile("cp.async.commit_group;" ::: "memory")
#define CP_WAIT(n)  asm volatile("cp.async.wait_group %0;" :: "n"(n) : "memory")
#define LDSM_X4(r0, r1, r2, r3, addr) \
    asm volatile("ldmatrix.sync.aligned.m8n8.x4.shared.b16 {%0,%1,%2,%3}, [%4];" \
        : "=r"(r0), "=r"(r1), "=r"(r2), "=r"(r3) : "r"(addr))
#define MMA_F16(acc, a, b) \
    asm volatile("mma.sync.aligned.m16n8k16.row.col.f32.f16.f16.f32 " \
        "{%0,%1,%2,%3}, {%4,%5,%6,%7}, {%8,%9}, {%0,%1,%2,%3};" \
        : "+f"((acc)[0]), "+f"((acc)[1]), "+f"((acc)[2]), "+f"((acc)[3]) \
        : "r"((a)[0]), "r"((a)[1]), "r"((a)[2]), "r"((a)[3]), "r"((b)[0]), "r"((b)[1]))

// ---------------- helpers ----------------
__device__ __forceinline__ void convBt_elem(const float* __restrict__ B,
                                            __half* __restrict__ out, int t, int Nn) {
    int nrow = t >> 8, k = t & 255;
    float x = (nrow < Nn) ? B[(size_t)k * Nn + nrow] : 0.f;
    out[t] = __float2half_rn(x);
}
__device__ __forceinline__ void resmean_elem(const float* __restrict__ resW2, int t) {
    int d = t >> 8, k = t & 255;
    float x = 0.f;
    if (d < 40) {
        float s_ = 0.f;
        #pragma unroll
        for (int h = 0; h < 6; ++h) s_ += resW2[(size_t)k * 240 + h * 40 + d];
        x = s_ * (1.0f / 6.0f);
    }
    g_Bh2[t] = __float2half_rn(x);
}

// ---------------- kernel 1: zero deg + elA/erA ----------------
__global__ void k_zero0(int n, int n6) {
    int i = blockIdx.x * blockDim.x + threadIdx.x;
    if (i < n) g_deg[i] = 0;
    if (i < n6) { g_elA[i] = 0.f; g_erA[i] = 0.f; }
}

// ---------------- kernel 2: conv feat->fp16 + conv W0 + hist ----------------
__global__ void k_prep0(const float* __restrict__ feat, const float* __restrict__ W0,
                        const int* __restrict__ dst, int E) {
    int bx = blockIdx.x;
    if (bx < SPLITA_BLOCKS) {
        int i = bx * 256 + threadIdx.x;
        float4 v = reinterpret_cast<const float4*>(feat)[i];
        __half2 p0 = __floats2half2_rn(v.x, v.y);
        __half2 p1 = __floats2half2_rn(v.z, v.w);
        reinterpret_cast<uint2*>(g_Ah)[i] =
            make_uint2(*reinterpret_cast<uint32_t*>(&p0), *reinterpret_cast<uint32_t*>(&p1));
    } else if (bx < SPLITA_BLOCKS + 256) {
        int t = (bx - SPLITA_BLOCKS) * 256 + threadIdx.x;
        convBt_elem(W0, g_Bh, t, 256);
    } else {
        int e = (bx - SPLITA_BLOCKS - 256) * 256 + threadIdx.x;
        if (e < E) atomicAdd(&g_deg[dst[e]], 1);
    }
}

// ---------------- kernel: scan ----------------
__global__ void k_scan(int n, int E) {
    __shared__ int wsum[32];
    __shared__ int carry;
    int lane = threadIdx.x & 31, w = threadIdx.x >> 5;
    if (threadIdx.x == 0) carry = 0;
    __syncthreads();
    for (int base = 0; base < n; base += 1024) {
        int i = base + threadIdx.x;
        int v = (i < n) ? g_deg[i] : 0;
        int x = v;
        #pragma unroll
        for (int off = 1; off < 32; off <<= 1) {
            int t = __shfl_up_sync(0xffffffffu, x, off);
            if (lane >= off) x += t;
        }
        if (lane == 31) wsum[w] = x;
        __syncthreads();
        if (w == 0) {
            int y = wsum[lane];
            #pragma unroll
            for (int off = 1; off < 32; off <<= 1) {
                int t = __shfl_up_sync(0xffffffffu, y, off);
                if (lane >= off) y += t;
            }
            wsum[lane] = y;
        }
        __syncthreads();
        int incl = x + (w ? wsum[w - 1] : 0) + carry;
        int excl = incl - v;
        if (i < n) { g_rowstart[i] = excl; g_cursor[i] = excl; }
        __syncthreads();
        if (threadIdx.x == 1023) carry = incl;
        __syncthreads();
    }
    if (threadIdx.x == 0) g_rowstart[n] = E;
}

// ---------------- GEMM body: fp16 mma.sync, 3-stage pipeline, 8 warps ----------------
// BN=128: warp grid 4x2, warp tile 32x64 (NT=8). BN=64: warp tile 32x32 (NT=4).
template <int BN>
__device__ __forceinline__ void gemm_load_stage(
    uint32_t sb, const __half* __restrict__ Ah, const __half* __restrict__ Bh,
    int m0, int n0, int M, int kb, int tid)
{
    #pragma unroll
    for (int it = 0; it < 4; ++it) {
        int idx = tid + it * 256;
        int row = idx >> 3, ch = idx & 7;
        uint32_t dst = sb + row * 128 + (((uint32_t)(ch ^ (row & 7))) << 4);
        const __half* src = Ah + (size_t)(m0 + row) * 256 + kb * 64 + ch * 8;
        cp16(dst, src, (m0 + row) < M ? 16u : 0u);
    }
    #pragma unroll
    for (int it = 0; it < (BN * 8) / 256; ++it) {
        int idx = tid + it * 256;
        int row = idx >> 3, ch = idx & 7;
        uint32_t dst = sb + 16384 + row * 128 + (((uint32_t)(ch ^ (row & 7))) << 4);
        const __half* src = Bh + (size_t)(n0 + row) * 256 + kb * 64 + ch * 8;
        cp16(dst, src, 16u);
    }
}

template <bool ELR, int BN>
__device__ __forceinline__ void gemm_body(
    const __half* __restrict__ Ah, const __half* __restrict__ Bh,
    __half* __restrict__ Ch, float* __restrict__ Cf,
    const float* __restrict__ al, const float* __restrict__ ar,
    float* __restrict__ el, float* __restrict__ er,
    int M, int Nn, int H, int D, int m0, int n0)
{
    constexpr int NT = BN / 16;
    constexpr uint32_t STAGE = 16384u + (uint32_t)BN * 128u;
    extern __shared__ char smem[];
    const uint32_t sbase = smem_u32(smem);
    const int tid = threadIdx.x, wid = tid >> 5, lane = tid & 31;
    const int warp_m = wid & 3, warp_n = wid >> 2;   // 4 x 2 warps

    float acc[2][NT][4];
    #pragma unroll
    for (int mt = 0; mt < 2; ++mt)
        #pragma unroll
        for (int nt = 0; nt < NT; ++nt)
            #pragma unroll
            for (int q = 0; q < 4; ++q) acc[mt][nt][q] = 0.f;

    const int rowA = warp_m * 32 + (lane & 15);
    const int rowB = warp_n * (BN / 2) + (lane & 7) + ((lane >> 4) << 3);
    const uint32_t rowAswz = (uint32_t)(rowA & 7);
    const uint32_t rowBswz = (uint32_t)(rowB & 7);
    const int halfA = lane >> 4;
    const int halfB = (lane >> 3) & 1;

    gemm_load_stage<BN>(sbase, Ah, Bh, m0, n0, M, 0, tid);
    CP_COMMIT();
    gemm_load_stage<BN>(sbase + STAGE, Ah, Bh, m0, n0, M, 1, tid);
    CP_COMMIT();

    #pragma unroll 1
    for (int kb = 0; kb < 4; ++kb) {
        if (kb < 3) { CP_WAIT(1); } else { CP_WAIT(0); }
        __syncthreads();
        if (kb < 2) {
            gemm_load_stage<BN>(sbase + ((kb + 2) % 3) * STAGE, Ah, Bh, m0, n0, M, kb + 2, tid);
            CP_COMMIT();
        }
        const uint32_t sb = sbase + (kb % 3) * STAGE;
        #pragma unroll
        for (int s = 0; s < 4; ++s) {
            uint32_t a[2][4];
            uint32_t b[NT][2];
            const uint32_t offA = (((uint32_t)(s * 2 + halfA) ^ rowAswz) << 4);
            const uint32_t offB = (((uint32_t)(s * 2 + halfB) ^ rowBswz) << 4);
            #pragma unroll
            for (int mt = 0; mt < 2; ++mt) {
                uint32_t addr = sb + (uint32_t)(rowA + mt * 16) * 128 + offA;
                LDSM_X4(a[mt][0], a[mt][1], a[mt][2], a[mt][3], addr);
            }
            #pragma unroll
            for (int ntp = 0; ntp < NT / 2; ++ntp) {
                uint32_t addr = sb + 16384 + (uint32_t)(rowB + ntp * 16) * 128 + offB;
                LDSM_X4(b[2 * ntp][0], b[2 * ntp][1], b[2 * ntp + 1][0], b[2 * ntp + 1][1], addr);
            }
            #pragma unroll
            for (int mt = 0; mt < 2; ++mt)
                #pragma unroll
                for (int nt = 0; nt < NT; ++nt)
                    MMA_F16(acc[mt][nt], a[mt], b[nt]);
        }
    }

    #pragma unroll
    for (int mt = 0; mt < 2; ++mt) {
        int row = m0 + warp_m * 32 + mt * 16 + (lane >> 2);
        #pragma unroll
        for (int nt = 0; nt < NT; ++nt) {
            int col = n0 + warp_n * (BN / 2) + nt * 8 + (lane & 3) * 2;
            if (col < Nn) {
                if (ELR) {
                    if (row < M)
                        *reinterpret_cast<__half2*>(Ch + (size_t)row * Nn + col) =
                            __floats2half2_rn(acc[mt][nt][0], acc[mt][nt][1]);
                    if (row + 8 < M)
                        *reinterpret_cast<__half2*>(Ch + (size_t)(row + 8) * Nn + col) =
                            __floats2half2_rn(acc[mt][nt][2], acc[mt][nt][3]);
                } else {
                    if (row < M)
                        *reinterpret_cast<float2*>(Cf + (size_t)row * Nn + col) =
                            make_float2(acc[mt][nt][0], acc[mt][nt][1]);
                    if (row + 8 < M)
                        *reinterpret_cast<float2*>(Cf + (size_t)(row + 8) * Nn + col) =
                            make_float2(acc[mt][nt][2], acc[mt][nt][3]);
                }
            }
        }
    }

    if (ELR) {
        const int colbase = n0 + warp_n * (BN / 2);
        if (colbase < Nn) {
            const int h0 = colbase / D;
            const int colend = (colbase + BN / 2 < Nn) ? (colbase + BN / 2) : Nn;
            const int hmax = (colend - 1) / D;           // heads h0..hmax touched (<= h0+2)
            float sl[2][2][3] = {}, sr[2][2][3] = {};
            #pragma unroll
            for (int nt = 0; nt < NT; ++nt) {
                int colg = colbase + nt * 8;
                if (colg < Nn) {
                    int h = colg / D;
                    int slot = h - h0;
                    if (slot > 2) slot = 2;
                    int d = colg - h * D + (lane & 3) * 2;
                    float2 av = __ldg(reinterpret_cast<const float2*>(al + h * D + d));
                    float2 rv = __ldg(reinterpret_cast<const float2*>(ar + h * D + d));
                    #pragma unroll
                    for (int mt = 0; mt < 2; ++mt) {
                        sl[mt][0][slot] += acc[mt][nt][0] * av.x + acc[mt][nt][1] * av.y;
                        sr[mt][0][slot] += acc[mt][nt][0] * rv.x + acc[mt][nt][1] * rv.y;
                        sl[mt][1][slot] += acc[mt][nt][2] * av.x + acc[mt][nt][3] * av.y;
                        sr[mt][1][slot] += acc[mt][nt][2] * rv.x + acc[mt][nt][3] * rv.y;
                    }
                }
            }
            #pragma unroll
            for (int mt = 0; mt < 2; ++mt)
                #pragma unroll
                for (int rh = 0; rh < 2; ++rh)
                    #pragma unroll
                    for (int sx = 0; sx < 3; ++sx) {
                        float vl = sl[mt][rh][sx], vr = sr[mt][rh][sx];
                        vl += __shfl_xor_sync(0xffffffffu, vl, 1);
                        vl += __shfl_xor_sync(0xffffffffu, vl, 2);
                        vr += __shfl_xor_sync(0xffffffffu, vr, 1);
                        vr += __shfl_xor_sync(0xffffffffu, vr, 2);
                        sl[mt][rh][sx] = vl; sr[mt][rh][sx] = vr;
                    }
            if ((lane & 3) == 0) {
                int nslots = hmax - h0 + 1;
                if (nslots > 3) nslots = 3;
                #pragma unroll
                for (int mt = 0; mt < 2; ++mt) {
                    #pragma unroll
                    for (int rh = 0; rh < 2; ++rh) {
                        int row = m0 + warp_m * 32 + mt * 16 + (lane >> 2) + rh * 8;
                        if (row < M) {
                            for (int sx = 0; sx < nslots; ++sx) {
                                atomicAdd(&el[(size_t)row * H + h0 + sx], sl[mt][rh][sx]);
                                atomicAdd(&er[(size_t)row * H + h0 + sx], sr[mt][rh][sx]);
                            }
                        }
                    }
                }
            }
        }
    }
}

#define GEMM_SMEM128 (3 * (16384 + 128 * 128))

// ---------------- GEMM launches ----------------
__global__ __launch_bounds__(256, 2) void k_gemm0(
    const __half* __restrict__ Ah, __half* __restrict__ Ch,
    const float* __restrict__ al, const float* __restrict__ ar,
    float* __restrict__ el, float* __restrict__ er, int M, int nGemm,
    const int* __restrict__ src, const int* __restrict__ dst, int E)
{
    int bx = blockIdx.x;
    if (bx < nGemm) {
        gemm_body<true, 128>(Ah, g_Bh, Ch, nullptr, al, ar, el, er,
                             M, 256, 4, 64, (bx >> 1) * 128, (bx & 1) * 128);
    } else {
        int e = (bx - nGemm) * 256 + threadIdx.x;
        if (e < E) {
            int p = atomicAdd(&g_cursor[dst[e]], 1);
            g_srcs[p] = src[e];
        }
    }
}

__global__ __launch_bounds__(256, 2) void k_gemm1(
    const __half* __restrict__ Ah, __half* __restrict__ Ch,
    const float* __restrict__ al, const float* __restrict__ ar,
    float* __restrict__ el, float* __restrict__ er, int M)
{
    int bx = blockIdx.x;
    gemm_body<true, 128>(Ah, g_Bh, Ch, nullptr, al, ar, el, er,
                         M, 256, 4, 64, (bx >> 1) * 128, (bx & 1) * 128);
}

// L2: W2 GEMM (ELR) + resW2_mean GEMM in one launch
__global__ __launch_bounds__(256, 2) void k_gemm2(
    const __half* __restrict__ Ah, __half* __restrict__ Ch, float* __restrict__ Cf,
    const float* __restrict__ al, const float* __restrict__ ar,
    float* __restrict__ el, float* __restrict__ er, int M, int nGemm)
{
    int bx = blockIdx.x;
    if (bx < nGemm) {
        gemm_body<true, 128>(Ah, g_Bh, Ch, nullptr, al, ar, el, er,
                             M, 240, 6, 40, (bx >> 1) * 128, (bx & 1) * 128);
    } else {
        gemm_body<false, 64>(Ah, g_Bh2, nullptr, Cf, nullptr, nullptr, nullptr, nullptr,
                             M, 40, 1, 64, (bx - nGemm) * 128, 0);
    }
}

// ---------------- aggregation helpers ----------------
__device__ __forceinline__ void fma_row(float4& a0, float4& a1, float wh, uint4 q) {
    float2 p0 = __half22float2(*reinterpret_cast<__half2*>(&q.x));
    float2 p1 = __half22float2(*reinterpret_cast<__half2*>(&q.y));
    float2 p2 = __half22float2(*reinterpret_cast<__half2*>(&q.z));
    float2 p3 = __half22float2(*reinterpret_cast<__half2*>(&q.w));
    a0.x = fmaf(wh, p0.x, a0.x); a0.y = fmaf(wh, p0.y, a0.y);
    a0.z = fmaf(wh, p1.x, a0.z); a0.w = fmaf(wh, p1.y, a0.w);
    a1.x = fmaf(wh, p2.x, a1.x); a1.y = fmaf(wh, p2.y, a1.y);
    a1.z = fmaf(wh, p3.x, a1.z); a1.w = fmaf(wh, p3.y, a1.w);
}

// ---------------- aggregation, layers 0/1, with fused next-layer prep tail ----------------
// Tail blocks (bx >= nAgg): conv Wnext (256 blocks), optional resW2 mean (64 blocks),
// zero next layer's el/er (zeroBlocks).
template <bool RES>
__global__ __launch_bounds__(256) void k_agg256(
    const __half* __restrict__ zh, const float* __restrict__ el,
    const float* __restrict__ er, const float* __restrict__ bias,
    const float* __restrict__ xres, float* __restrict__ out,
    __half* __restrict__ oah, int n, int nAgg,
    const float* __restrict__ Wnext, int convN,
    const float* __restrict__ resW2,
    float* __restrict__ zel, float* __restrict__ zer, int n6)
{
    int bx = blockIdx.x;
    if (bx >= nAgg) {
        int t = bx - nAgg;
        if (t < 256) {
            convBt_elem(Wnext, g_Bh, t * 256 + threadIdx.x, convN);
        } else if (resW2 != nullptr && t < 320) {
            resmean_elem(resW2, (t - 256) * 256 + threadIdx.x);
        } else {
            int zoff = (resW2 != nullptr) ? 320 : 256;
            int i = (t - zoff) * 256 + threadIdx.x;
            if (i < n6) { zel[i] = 0.f; zer[i] = 0.f; }
        }
        return;
    }
    int gw = (bx * 256 + threadIdx.x) >> 5;
    if (gw >= n) return;
    int lane = threadIdx.x & 31;
    int beg = g_rowstart[gw], end = g_rowstart[gw + 1];
    float erh = (lane < 4) ? __ldg(&er[gw * 4 + lane]) : 0.f;
    int h = lane >> 3;
    int c0 = lane * 8;
    float4 acc0 = make_float4(0.f, 0.f, 0.f, 0.f), acc1 = acc0;
    float denom = 0.f;
    int i = beg;
    #pragma unroll 1
    for (; i + 2 <= end; i += 2) {
        int s0 = __ldg(&g_srcs[i]);
        int s1 = __ldg(&g_srcs[i + 1]);
        uint4 q0 = __ldg(reinterpret_cast<const uint4*>(zh + (size_t)s0 * 256 + c0));
        uint4 q1 = __ldg(reinterpret_cast<const uint4*>(zh + (size_t)s1 * 256 + c0));
        float w0 = 0.f, w1 = 0.f;
        if (lane < 4) {
            float e0 = __ldg(&el[s0 * 4 + lane]) + erh;
            float e1 = __ldg(&el[s1 * 4 + lane]) + erh;
            e0 = (e0 > 0.f) ? e0 : 0.2f * e0;
            e1 = (e1 > 0.f) ? e1 : 0.2f * e1;
            w0 = __expf(e0); w1 = __expf(e1);
            denom += w0 + w1;
        }
        float wh0 = __shfl_sync(0xffffffffu, w0, h);
        float wh1 = __shfl_sync(0xffffffffu, w1, h);
        fma_row(acc0, acc1, wh0, q0);
        fma_row(acc0, acc1, wh1, q1);
    }
    if (i < end) {
        int s0 = __ldg(&g_srcs[i]);
        uint4 q0 = __ldg(reinterpret_cast<const uint4*>(zh + (size_t)s0 * 256 + c0));
        float w0 = 0.f;
        if (lane < 4) {
            float e0 = __ldg(&el[s0 * 4 + lane]) + erh;
            e0 = (e0 > 0.f) ? e0 : 0.2f * e0;
            w0 = __expf(e0);
            denom += w0;
        }
        float wh0 = __shfl_sync(0xffffffffu, w0, h);
        fma_row(acc0, acc1, wh0, q0);
    }
    float dh = __shfl_sync(0xffffffffu, denom, h);
    float inv = 1.f / dh;
    const float4* bp = reinterpret_cast<const float4*>(bias + c0);
    float4 b0 = __ldg(bp), b1 = __ldg(bp + 1);
    float v[8];
    v[0] = fmaf(acc0.x, inv, b0.x); v[1] = fmaf(acc0.y, inv, b0.y);
    v[2] = fmaf(acc0.z, inv, b0.z); v[3] = fmaf(acc0.w, inv, b0.w);
    v[4] = fmaf(acc1.x, inv, b1.x); v[5] = fmaf(acc1.y, inv, b1.y);
    v[6] = fmaf(acc1.z, inv, b1.z); v[7] = fmaf(acc1.w, inv, b1.w);
    if (RES) {
        const float4* rp = reinterpret_cast<const float4*>(xres + (size_t)gw * 256 + c0);
        float4 r0 = __ldg(rp), r1 = __ldg(rp + 1);
        v[0] += r0.x; v[1] += r0.y; v[2] += r0.z; v[3] += r0.w;
        v[4] += r1.x; v[5] += r1.y; v[6] += r1.z; v[7] += r1.w;
    }
    #pragma unroll
    for (int j = 0; j < 8; ++j) v[j] = (v[j] > 0.f) ? v[j] : expm1f(v[j]);
    float4* op = reinterpret_cast<float4*>(out + (size_t)gw * 256 + c0);
    op[0] = make_float4(v[0], v[1], v[2], v[3]);
    op[1] = make_float4(v[4], v[5], v[6], v[7]);
    __half2 p0 = __floats2half2_rn(v[0], v[1]);
    __half2 p1 = __floats2half2_rn(v[2], v[3]);
    __half2 p2 = __floats2half2_rn(v[4], v[5]);
    __half2 p3 = __floats2half2_rn(v[6], v[7]);
    *reinterpret_cast<uint4*>(oah + (size_t)gw * 256 + c0) =
        make_uint4(*reinterpret_cast<uint32_t*>(&p0), *reinterpret_cast<uint32_t*>(&p1),
                   *reinterpret_cast<uint32_t*>(&p2), *reinterpret_cast<uint32_t*>(&p3));
}

// ---------------- aggregation, layer 2 ----------------
__global__ __launch_bounds__(256) void k_agg_l2(
    const __half* __restrict__ zh, const float* __restrict__ el,
    const float* __restrict__ er, const float* __restrict__ bias,
    const float* __restrict__ r2m, float* __restrict__ logits, int n)
{
    __shared__ float sout[8][240];
    int wInB = threadIdx.x >> 5;
    int gw = blockIdx.x * 8 + wInB;
    int lane = threadIdx.x & 31;
    bool act = (lane < 30);
    if (gw < n) {
        int beg = g_rowstart[gw], end = g_rowstart[gw + 1];
        float erh = (lane < 6) ? __ldg(&er[gw * 6 + lane]) : 0.f;
        int h = act ? (lane / 5) : 0;
        int c0 = lane * 8;
        float4 acc0 = make_float4(0.f, 0.f, 0.f, 0.f), acc1 = acc0;
        float denom = 0.f;
        int i = beg;
        #pragma unroll 1
        for (; i + 2 <= end; i += 2) {
            int s0 = __ldg(&g_srcs[i]);
            int s1 = __ldg(&g_srcs[i + 1]);
            uint4 q0 = make_uint4(0, 0, 0, 0), q1 = q0;
            if (act) {
                q0 = __ldg(reinterpret_cast<const uint4*>(zh + (size_t)s0 * 240 + c0));
                q1 = __ldg(reinterpret_cast<const uint4*>(zh + (size_t)s1 * 240 + c0));
            }
            float w0 = 0.f, w1 = 0.f;
            if (lane < 6) {
                float e0 = __ldg(&el[s0 * 6 + lane]) + erh;
                float e1 = __ldg(&el[s1 * 6 + lane]) + erh;
                e0 = (e0 > 0.f) ? e0 : 0.2f * e0;
                e1 = (e1 > 0.f) ? e1 : 0.2f * e1;
                w0 = __expf(e0); w1 = __expf(e1);
                denom += w0 + w1;
            }
            float wh0 = __shfl_sync(0xffffffffu, w0, h);
            float wh1 = __shfl_sync(0xffffffffu, w1, h);
            if (act) {
                fma_row(acc0, acc1, wh0, q0);
                fma_row(acc0, acc1, wh1, q1);
            }
        }
        if (i < end) {
            int s0 = __ldg(&g_srcs[i]);
            uint4 q0 = make_uint4(0, 0, 0, 0);
            if (act) q0 = __ldg(reinterpret_cast<const uint4*>(zh + (size_t)s0 * 240 + c0));
            float w0 = 0.f;
            if (lane < 6) {
                float e0 = __ldg(&el[s0 * 6 + lane]) + erh;
                e0 = (e0 > 0.f) ? e0 : 0.2f * e0;
                w0 = __expf(e0);
                denom += w0;
            }
            float wh0 = __shfl_sync(0xffffffffu, w0, h);
            if (act) fma_row(acc0, acc1, wh0, q0);
        }
        float dh = __shfl_sync(0xffffffffu, denom, h);
        if (act) {
            float inv = 1.f / dh;
            const float4* bp = reinterpret_cast<const float4*>(bias + c0);
            float4 b0 = __ldg(bp), b1 = __ldg(bp + 1);
            sout[wInB][c0 + 0] = fmaf(acc0.x, inv, b0.x);
            sout[wInB][c0 + 1] = fmaf(acc0.y, inv, b0.y);
            sout[wInB][c0 + 2] = fmaf(acc0.z, inv, b0.z);
            sout[wInB][c0 + 3] = fmaf(acc0.w, inv, b0.w);
            sout[wInB][c0 + 4] = fmaf(acc1.x, inv, b1.x);
            sout[wInB][c0 + 5] = fmaf(acc1.y, inv, b1.y);
            sout[wInB][c0 + 6] = fmaf(acc1.z, inv, b1.z);
            sout[wInB][c0 + 7] = fmaf(acc1.w, inv, b1.w);
        }
    }
    __syncwarp();
    if (gw < n) {
        for (int d = lane; d < 40; d += 32) {
            float s_ = 0.f;
            #pragma unroll
            for (int hh = 0; hh < 6; ++hh) s_ += sout[wInB][hh * 40 + d];
            logits[(size_t)gw * 40 + d] = s_ * (1.0f / 6.0f) + __ldg(&r2m[(size_t)gw * 40 + d]);
        }
    }
}

// ---------------- host ----------------
extern "C" void kernel_launch(void* const* d_in, const int* in_sizes, int n_in,
                              void* d_out, int out_size)
{
    const float* feat  = (const float*)d_in[0];
    const int*   src   = (const int*)d_in[1];
    const int*   dst   = (const int*)d_in[2];
    const float* W0    = (const float*)d_in[3];
    const float* al0   = (const float*)d_in[4];
    const float* ar0   = (const float*)d_in[5];
    const float* b0    = (const float*)d_in[6];
    const float* W1    = (const float*)d_in[7];
    const float* al1   = (const float*)d_in[8];
    const float* ar1   = (const float*)d_in[9];
    const float* b1    = (const float*)d_in[10];
    const float* W2    = (const float*)d_in[11];
    const float* al2   = (const float*)d_in[12];
    const float* ar2   = (const float*)d_in[13];
    const float* b2    = (const float*)d_in[14];
    const float* resW2 = (const float*)d_in[15];

    const int n = NNODES;
    const int E = in_sizes[1];

    float* logits = (float*)d_out;
    float* h1     = (float*)d_out + n * 40;

    float *ph0, *pr2, *pelA, *perA, *pelB, *perB;
    __half *pzh, *pAh;
    cudaGetSymbolAddress((void**)&pzh,  g_zh);
    cudaGetSymbolAddress((void**)&ph0,  g_h0);
    cudaGetSymbolAddress((void**)&pr2,  g_r2);
    cudaGetSymbolAddress((void**)&pelA, g_elA);
    cudaGetSymbolAddress((void**)&perA, g_erA);
    cudaGetSymbolAddress((void**)&pelB, g_elB);
    cudaGetSymbolAddress((void**)&perB, g_erB);
    cudaGetSymbolAddress((void**)&pAh,  g_Ah);

    cudaFuncSetAttribute(k_gemm0, cudaFuncAttributeMaxDynamicSharedMemorySize, GEMM_SMEM128);
    cudaFuncSetAttribute(k_gemm1, cudaFuncAttributeMaxDynamicSharedMemorySize, GEMM_SMEM128);
    cudaFuncSetAttribute(k_gemm2, cudaFuncAttributeMaxDynamicSharedMemorySize, GEMM_SMEM128);

    const int nGemm = ((n + 127) / 128) * 2;          // 782
    const int nGemmM = (n + 127) / 128;               // 391
    const int histBlocks = (E + 255) / 256;
    const int scatBlocks = (E + 255) / 256;
    const int zeroBlocks = (n * 6 + 255) / 256;       // 1172
    const int aggBlocks  = (n + 7) / 8;               // 6250

    // 1. zero deg + elA/erA
    k_zero0<<<zeroBlocks, 256>>>(n, n * 6);
    // 2. conv feat + conv W0 + hist
    k_prep0<<<SPLITA_BLOCKS + 256 + histBlocks, 256>>>(feat, W0, dst, E);
    // 3. scan
    k_scan<<<1, 1024>>>(n, E);
    // 4. gemm L0 (elA) + scatter
    k_gemm0<<<nGemm + scatBlocks, 256, GEMM_SMEM128>>>(pAh, pzh, al0, ar0, pelA, perA,
                                                       n, nGemm, src, dst, E);
    // 5. agg L0 (reads elA) + tail: conv W1, zero elB
    k_agg256<false><<<aggBlocks + 256 + zeroBlocks, 256>>>(
        pzh, pelA, perA, b0, nullptr, ph0, pAh, n, aggBlocks,
        W1, 256, nullptr, pelB, perB, n * 6);
    // 6. gemm L1 (elB)
    k_gemm1<<<nGemm, 256, GEMM_SMEM128>>>(pAh, pzh, al1, ar1, pelB, perB, n);
    // 7. agg L1 (reads elB) + tail: conv W2, resW2 mean, zero elA
    k_agg256<true><<<aggBlocks + 256 + 64 + zeroBlocks, 256>>>(
        pzh, pelB, perB, b1, ph0, h1, pAh, n, aggBlocks,
        W2, 240, resW2, pelA, perA, n * 6);
    // 8. gemm L2 (elA) + res gemm
    k_gemm2<<<nGemm + nGemmM, 256, GEMM_SMEM128>>>(pAh, pzh, pr2, al2, ar2, pelA, perA,
                                                   n, nGemm);
    // 9. agg L2 -> logits
    k_agg_l2<<<aggBlocks, 256>>>(pzh, pelA, perA, b2, pr2, logits, n);
}

// round 12
// speedup vs baseline: 3.7408x; 1.0344x over previous
#include <cuda_runtime.h>
#include <cuda_fp16.h>
#include <math.h>
#include <cstdint>

// ---------------- problem constants ----------------
#define NNODES 50000
#define ECAP   1000000
#define SPLITA_BLOCKS 12500   // (NNODES*256/4)/256

// ---------------- device scratch ----------------
__device__ __align__(16) __half g_zh[NNODES * 256];
__device__ float g_r2[NNODES * 40];
__device__ float g_elA[NNODES * 6];
__device__ float g_erA[NNODES * 6];
__device__ float g_elB[NNODES * 6];
__device__ float g_erB[NNODES * 6];
__device__ int   g_deg[NNODES];
__device__ int   g_rowstart[NNODES + 1];
__device__ int   g_cursor[NNODES];
__device__ int   g_srcs[ECAP];
__device__ __align__(16) __half g_Ah[NNODES * 256];   // fp16 GEMM A / residual carrier
__device__ __align__(16) __half g_Bh[256 * 256];      // fp16 weight [N(pad256) x K=256]
__device__ __align__(16) __half g_Bh2[64 * 256];      // resW2_mean fp16 [64(d pad) x 256]

// ================= PTX helpers =================
__device__ __forceinline__ uint32_t smem_u32(const void* p) {
    uint32_t a;
    asm("{ .reg .u64 t; cvta.to.shared.u64 t, %1; cvt.u32.u64 %0, t; }" : "=r"(a) : "l"(p));
    return a;
}
__device__ __forceinline__ void cp16(uint32_t dst, const void* src, uint32_t srcsize) {
    asm volatile("cp.async.cg.shared.global [%0], [%1], 16, %2;"
                 :: "r"(dst), "l"(src), "r"(srcsize));
}
#define CP_COMMIT() asm volatile("cp.async.commit_group;" ::: "memory")
#define CP_WAIT(n)  asm volatile("cp.async.wait_group %0;" :: "n"(n) : "memory")
#define LDSM_X4(r0, r1, r2, r3, addr) \
    asm volatile("ldmatrix.sync.aligned.m8n8.x4.shared.b16 {%0,%1,%2,%3}, [%4];" \
        : "=r"(r0), "=r"(r1), "=r"(r2), "=r"(r3) : "r"(addr))
#define MMA_F16(acc, a, b) \
    asm volatile("mma.sync.aligned.m16n8k16.row.col.f32.f16.f16.f32 " \
        "{%0,%1,%2,%3}, {%4,%5,%6,%7}, {%8,%9}, {%0,%1,%2,%3};" \
        : "+f"((acc)[0]), "+f"((acc)[1]), "+f"((acc)[2]), "+f"((acc)[3]) \
        : "r"((a)[0]), "r"((a)[1]), "r"((a)[2]), "r"((a)[3]), "r"((b)[0]), "r"((b)[1]))

// ---------------- helpers ----------------
__device__ __forceinline__ void convBt_elem(const float* __restrict__ B,
                                            __half* __restrict__ out, int t, int Nn) {
    int nrow = t >> 8, k = t & 255;
    float x = (nrow < Nn) ? B[(size_t)k * Nn + nrow] : 0.f;
    out[t] = __float2half_rn(x);
}
__device__ __forceinline__ void resmean_elem(const float* __restrict__ resW2, int t) {
    int d = t >> 8, k = t & 255;
    float x = 0.f;
    if (d < 40) {
        float s_ = 0.f;
        #pragma unroll
        for (int h = 0; h < 6; ++h) s_ += resW2[(size_t)k * 240 + h * 40 + d];
        x = s_ * (1.0f / 6.0f);
    }
    g_Bh2[t] = __float2half_rn(x);
}

// ---------------- kernel 1: zero deg + elA/erA ----------------
__global__ void k_zero0(int n, int n6) {
    int i = blockIdx.x * blockDim.x + threadIdx.x;
    if (i < n) g_deg[i] = 0;
    if (i < n6) { g_elA[i] = 0.f; g_erA[i] = 0.f; }
}

// ---------------- kernel 2: conv feat->fp16 + conv W0 + hist ----------------
__global__ void k_prep0(const float* __restrict__ feat, const float* __restrict__ W0,
                        const int* __restrict__ dst, int E) {
    int bx = blockIdx.x;
    if (bx < SPLITA_BLOCKS) {
        int i = bx * 256 + threadIdx.x;
        float4 v = reinterpret_cast<const float4*>(feat)[i];
        __half2 p0 = __floats2half2_rn(v.x, v.y);
        __half2 p1 = __floats2half2_rn(v.z, v.w);
        reinterpret_cast<uint2*>(g_Ah)[i] =
            make_uint2(*reinterpret_cast<uint32_t*>(&p0), *reinterpret_cast<uint32_t*>(&p1));
    } else if (bx < SPLITA_BLOCKS + 256) {
        int t = (bx - SPLITA_BLOCKS) * 256 + threadIdx.x;
        convBt_elem(W0, g_Bh, t, 256);
    } else {
        int e = (bx - SPLITA_BLOCKS - 256) * 256 + threadIdx.x;
        if (e < E) atomicAdd(&g_deg[dst[e]], 1);
    }
}

// ---------------- kernel: scan ----------------
__global__ void k_scan(int n, int E) {
    __shared__ int wsum[32];
    __shared__ int carry;
    int lane = threadIdx.x & 31, w = threadIdx.x >> 5;
    if (threadIdx.x == 0) carry = 0;
    __syncthreads();
    for (int base = 0; base < n; base += 1024) {
        int i = base + threadIdx.x;
        int v = (i < n) ? g_deg[i] : 0;
        int x = v;
        #pragma unroll
        for (int off = 1; off < 32; off <<= 1) {
            int t = __shfl_up_sync(0xffffffffu, x, off);
            if (lane >= off) x += t;
        }
        if (lane == 31) wsum[w] = x;
        __syncthreads();
        if (w == 0) {
            int y = wsum[lane];
            #pragma unroll
            for (int off = 1; off < 32; off <<= 1) {
                int t = __shfl_up_sync(0xffffffffu, y, off);
                if (lane >= off) y += t;
            }
            wsum[lane] = y;
        }
        __syncthreads();
        int incl = x + (w ? wsum[w - 1] : 0) + carry;
        int excl = incl - v;
        if (i < n) { g_rowstart[i] = excl; g_cursor[i] = excl; }
        __syncthreads();
        if (threadIdx.x == 1023) carry = incl;
        __syncthreads();
    }
    if (threadIdx.x == 0) g_rowstart[n] = E;
}

// ---------------- GEMM body (fp16 mma.sync, 3-stage, 8 warps, warp tile 32xBN/2) ----------------
template <int BN>
__device__ __forceinline__ void gemm_load_stage(
    uint32_t sb, const __half* __restrict__ Ah, const __half* __restrict__ Bh,
    int m0, int n0, int M, int kb, int tid)
{
    #pragma unroll
    for (int it = 0; it < 4; ++it) {
        int idx = tid + it * 256;
        int row = idx >> 3, ch = idx & 7;
        uint32_t dst = sb + row * 128 + (((uint32_t)(ch ^ (row & 7))) << 4);
        const __half* src = Ah + (size_t)(m0 + row) * 256 + kb * 64 + ch * 8;
        cp16(dst, src, (m0 + row) < M ? 16u : 0u);
    }
    #pragma unroll
    for (int it = 0; it < (BN * 8) / 256; ++it) {
        int idx = tid + it * 256;
        int row = idx >> 3, ch = idx & 7;
        uint32_t dst = sb + 16384 + row * 128 + (((uint32_t)(ch ^ (row & 7))) << 4);
        const __half* src = Bh + (size_t)(n0 + row) * 256 + kb * 64 + ch * 8;
        cp16(dst, src, 16u);
    }
}

template <bool ELR, int BN>
__device__ __forceinline__ void gemm_body(
    const __half* __restrict__ Ah, const __half* __restrict__ Bh,
    __half* __restrict__ Ch, float* __restrict__ Cf,
    const float* __restrict__ al, const float* __restrict__ ar,
    float* __restrict__ el, float* __restrict__ er,
    int M, int Nn, int H, int D, int m0, int n0)
{
    constexpr int NT = BN / 16;
    constexpr uint32_t STAGE = 16384u + (uint32_t)BN * 128u;
    extern __shared__ char smem[];
    const uint32_t sbase = smem_u32(smem);
    const int tid = threadIdx.x, wid = tid >> 5, lane = tid & 31;
    const int warp_m = wid & 3, warp_n = wid >> 2;

    float acc[2][NT][4];
    #pragma unroll
    for (int mt = 0; mt < 2; ++mt)
        #pragma unroll
        for (int nt = 0; nt < NT; ++nt)
            #pragma unroll
            for (int q = 0; q < 4; ++q) acc[mt][nt][q] = 0.f;

    const int rowA = warp_m * 32 + (lane & 15);
    const int rowB = warp_n * (BN / 2) + (lane & 7) + ((lane >> 4) << 3);
    const uint32_t rowAswz = (uint32_t)(rowA & 7);
    const uint32_t rowBswz = (uint32_t)(rowB & 7);
    const int halfA = lane >> 4;
    const int halfB = (lane >> 3) & 1;

    gemm_load_stage<BN>(sbase, Ah, Bh, m0, n0, M, 0, tid);
    CP_COMMIT();
    gemm_load_stage<BN>(sbase + STAGE, Ah, Bh, m0, n0, M, 1, tid);
    CP_COMMIT();

    #pragma unroll 1
    for (int kb = 0; kb < 4; ++kb) {
        if (kb < 3) { CP_WAIT(1); } else { CP_WAIT(0); }
        __syncthreads();
        if (kb < 2) {
            gemm_load_stage<BN>(sbase + ((kb + 2) % 3) * STAGE, Ah, Bh, m0, n0, M, kb + 2, tid);
            CP_COMMIT();
        }
        const uint32_t sb = sbase + (kb % 3) * STAGE;
        #pragma unroll
        for (int s = 0; s < 4; ++s) {
            uint32_t a[2][4];
            uint32_t b[NT][2];
            const uint32_t offA = (((uint32_t)(s * 2 + halfA) ^ rowAswz) << 4);
            const uint32_t offB = (((uint32_t)(s * 2 + halfB) ^ rowBswz) << 4);
            #pragma unroll
            for (int mt = 0; mt < 2; ++mt) {
                uint32_t addr = sb + (uint32_t)(rowA + mt * 16) * 128 + offA;
                LDSM_X4(a[mt][0], a[mt][1], a[mt][2], a[mt][3], addr);
            }
            #pragma unroll
            for (int ntp = 0; ntp < NT / 2; ++ntp) {
                uint32_t addr = sb + 16384 + (uint32_t)(rowB + ntp * 16) * 128 + offB;
                LDSM_X4(b[2 * ntp][0], b[2 * ntp][1], b[2 * ntp + 1][0], b[2 * ntp + 1][1], addr);
            }
            #pragma unroll
            for (int mt = 0; mt < 2; ++mt)
                #pragma unroll
                for (int nt = 0; nt < NT; ++nt)
                    MMA_F16(acc[mt][nt], a[mt], b[nt]);
        }
    }

    #pragma unroll
    for (int mt = 0; mt < 2; ++mt) {
        int row = m0 + warp_m * 32 + mt * 16 + (lane >> 2);
        #pragma unroll
        for (int nt = 0; nt < NT; ++nt) {
            int col = n0 + warp_n * (BN / 2) + nt * 8 + (lane & 3) * 2;
            if (col < Nn) {
                if (ELR) {
                    if (row < M)
                        *reinterpret_cast<__half2*>(Ch + (size_t)row * Nn + col) =
                            __floats2half2_rn(acc[mt][nt][0], acc[mt][nt][1]);
                    if (row + 8 < M)
                        *reinterpret_cast<__half2*>(Ch + (size_t)(row + 8) * Nn + col) =
                            __floats2half2_rn(acc[mt][nt][2], acc[mt][nt][3]);
                } else {
                    if (row < M)
                        *reinterpret_cast<float2*>(Cf + (size_t)row * Nn + col) =
                            make_float2(acc[mt][nt][0], acc[mt][nt][1]);
                    if (row + 8 < M)
                        *reinterpret_cast<float2*>(Cf + (size_t)(row + 8) * Nn + col) =
                            make_float2(acc[mt][nt][2], acc[mt][nt][3]);
                }
            }
        }
    }

    if (ELR) {
        const int colbase = n0 + warp_n * (BN / 2);
        if (colbase < Nn) {
            const int h0 = colbase / D;
            const int colend = (colbase + BN / 2 < Nn) ? (colbase + BN / 2) : Nn;
            const int hmax = (colend - 1) / D;
            float sl[2][2][3] = {}, sr[2][2][3] = {};
            #pragma unroll
            for (int nt = 0; nt < NT; ++nt) {
                int colg = colbase + nt * 8;
                if (colg < Nn) {
                    int h = colg / D;
                    int slot = h - h0;
                    if (slot > 2) slot = 2;
                    int d = colg - h * D + (lane & 3) * 2;
                    float2 av = __ldg(reinterpret_cast<const float2*>(al + h * D + d));
                    float2 rv = __ldg(reinterpret_cast<const float2*>(ar + h * D + d));
                    #pragma unroll
                    for (int mt = 0; mt < 2; ++mt) {
                        sl[mt][0][slot] += acc[mt][nt][0] * av.x + acc[mt][nt][1] * av.y;
                        sr[mt][0][slot] += acc[mt][nt][0] * rv.x + acc[mt][nt][1] * rv.y;
                        sl[mt][1][slot] += acc[mt][nt][2] * av.x + acc[mt][nt][3] * av.y;
                        sr[mt][1][slot] += acc[mt][nt][2] * rv.x + acc[mt][nt][3] * rv.y;
                    }
                }
            }
            #pragma unroll
            for (int mt = 0; mt < 2; ++mt)
                #pragma unroll
                for (int rh = 0; rh < 2; ++rh)
                    #pragma unroll
                    for (int sx = 0; sx < 3; ++sx) {
                        float vl = sl[mt][rh][sx], vr = sr[mt][rh][sx];
                        vl += __shfl_xor_sync(0xffffffffu, vl, 1);
                        vl += __shfl_xor_sync(0xffffffffu, vl, 2);
                        vr += __shfl_xor_sync(0xffffffffu, vr, 1);
                        vr += __shfl_xor_sync(0xffffffffu, vr, 2);
                        sl[mt][rh][sx] = vl; sr[mt][rh][sx] = vr;
                    }
            if ((lane & 3) == 0) {
                int nslots = hmax - h0 + 1;
                if (nslots > 3) nslots = 3;
                #pragma unroll
                for (int mt = 0; mt < 2; ++mt) {
                    #pragma unroll
                    for (int rh = 0; rh < 2; ++rh) {
                        int row = m0 + warp_m * 32 + mt * 16 + (lane >> 2) + rh * 8;
                        if (row < M) {
                            for (int sx = 0; sx < nslots; ++sx) {
                                atomicAdd(&el[(size_t)row * H + h0 + sx], sl[mt][rh][sx]);
                                atomicAdd(&er[(size_t)row * H + h0 + sx], sr[mt][rh][sx]);
                            }
                        }
                    }
                }
            }
        }
    }
}

#define GEMM_SMEM128 (3 * (16384 + 128 * 128))

// ---------------- GEMM launches ----------------
__global__ __launch_bounds__(256, 2) void k_gemm0(
    const __half* __restrict__ Ah, __half* __restrict__ Ch,
    const float* __restrict__ al, const float* __restrict__ ar,
    float* __restrict__ el, float* __restrict__ er, int M, int nGemm,
    const int* __restrict__ src, const int* __restrict__ dst, int E)
{
    int bx = blockIdx.x;
    if (bx < nGemm) {
        gemm_body<true, 128>(Ah, g_Bh, Ch, nullptr, al, ar, el, er,
                             M, 256, 4, 64, (bx >> 1) * 128, (bx & 1) * 128);
    } else {
        int e = (bx - nGemm) * 256 + threadIdx.x;
        if (e < E) {
            int p = atomicAdd(&g_cursor[dst[e]], 1);
            g_srcs[p] = src[e];
        }
    }
}

__global__ __launch_bounds__(256, 2) void k_gemm1(
    const __half* __restrict__ Ah, __half* __restrict__ Ch,
    const float* __restrict__ al, const float* __restrict__ ar,
    float* __restrict__ el, float* __restrict__ er, int M)
{
    int bx = blockIdx.x;
    gemm_body<true, 128>(Ah, g_Bh, Ch, nullptr, al, ar, el, er,
                         M, 256, 4, 64, (bx >> 1) * 128, (bx & 1) * 128);
}

__global__ __launch_bounds__(256, 2) void k_gemm2(
    const __half* __restrict__ Ah, __half* __restrict__ Ch, float* __restrict__ Cf,
    const float* __restrict__ al, const float* __restrict__ ar,
    float* __restrict__ el, float* __restrict__ er, int M, int nGemm)
{
    int bx = blockIdx.x;
    if (bx < nGemm) {
        gemm_body<true, 128>(Ah, g_Bh, Ch, nullptr, al, ar, el, er,
                             M, 240, 6, 40, (bx >> 1) * 128, (bx & 1) * 128);
    } else {
        gemm_body<false, 64>(Ah, g_Bh2, nullptr, Cf, nullptr, nullptr, nullptr, nullptr,
                             M, 40, 1, 64, (bx - nGemm) * 128, 0);
    }
}

// ---------------- aggregation helpers ----------------
__device__ __forceinline__ void fma_row(float4& a0, float4& a1, float wh, uint4 q) {
    float2 p0 = __half22float2(*reinterpret_cast<__half2*>(&q.x));
    float2 p1 = __half22float2(*reinterpret_cast<__half2*>(&q.y));
    float2 p2 = __half22float2(*reinterpret_cast<__half2*>(&q.z));
    float2 p3 = __half22float2(*reinterpret_cast<__half2*>(&q.w));
    a0.x = fmaf(wh, p0.x, a0.x); a0.y = fmaf(wh, p0.y, a0.y);
    a0.z = fmaf(wh, p1.x, a0.z); a0.w = fmaf(wh, p1.y, a0.w);
    a1.x = fmaf(wh, p2.x, a1.x); a1.y = fmaf(wh, p2.y, a1.y);
    a1.z = fmaf(wh, p3.x, a1.z); a1.w = fmaf(wh, p3.y, a1.w);
}

// ---------------- aggregation, layers 0/1 (4x unrolled; fp16 residual from oah) ----------------
template <bool RES>
__global__ __launch_bounds__(256) void k_agg256(
    const __half* __restrict__ zh, const float* __restrict__ el,
    const float* __restrict__ er, const float* __restrict__ bias,
    float* __restrict__ out, __half* __restrict__ oah, int n, int nAgg,
    const float* __restrict__ Wnext, int convN,
    const float* __restrict__ resW2,
    float* __restrict__ zel, float* __restrict__ zer, int n6)
{
    int bx = blockIdx.x;
    if (bx >= nAgg) {
        int t = bx - nAgg;
        if (t < 256) {
            convBt_elem(Wnext, g_Bh, t * 256 + threadIdx.x, convN);
        } else if (resW2 != nullptr && t < 320) {
            resmean_elem(resW2, (t - 256) * 256 + threadIdx.x);
        } else {
            int zoff = (resW2 != nullptr) ? 320 : 256;
            int i = (t - zoff) * 256 + threadIdx.x;
            if (i < n6) { zel[i] = 0.f; zer[i] = 0.f; }
        }
        return;
    }
    int gw = (bx * 256 + threadIdx.x) >> 5;
    if (gw >= n) return;
    int lane = threadIdx.x & 31;
    int beg = g_rowstart[gw], end = g_rowstart[gw + 1];
    float erh = (lane < 4) ? __ldg(&er[gw * 4 + lane]) : 0.f;
    int h = lane >> 3;
    int c0 = lane * 8;
    float4 acc0 = make_float4(0.f, 0.f, 0.f, 0.f), acc1 = acc0;
    float denom = 0.f;
    int i = beg;
    #pragma unroll 1
    for (; i + 4 <= end; i += 4) {
        int s0 = __ldg(&g_srcs[i]);
        int s1 = __ldg(&g_srcs[i + 1]);
        int s2 = __ldg(&g_srcs[i + 2]);
        int s3 = __ldg(&g_srcs[i + 3]);
        uint4 q0 = __ldg(reinterpret_cast<const uint4*>(zh + (size_t)s0 * 256 + c0));
        uint4 q1 = __ldg(reinterpret_cast<const uint4*>(zh + (size_t)s1 * 256 + c0));
        uint4 q2 = __ldg(reinterpret_cast<const uint4*>(zh + (size_t)s2 * 256 + c0));
        uint4 q3 = __ldg(reinterpret_cast<const uint4*>(zh + (size_t)s3 * 256 + c0));
        float w0 = 0.f, w1 = 0.f, w2 = 0.f, w3 = 0.f;
        if (lane < 4) {
            float e0 = __ldg(&el[s0 * 4 + lane]) + erh;
            float e1 = __ldg(&el[s1 * 4 + lane]) + erh;
            float e2 = __ldg(&el[s2 * 4 + lane]) + erh;
            float e3 = __ldg(&el[s3 * 4 + lane]) + erh;
            e0 = (e0 > 0.f) ? e0 : 0.2f * e0;
            e1 = (e1 > 0.f) ? e1 : 0.2f * e1;
            e2 = (e2 > 0.f) ? e2 : 0.2f * e2;
            e3 = (e3 > 0.f) ? e3 : 0.2f * e3;
            w0 = __expf(e0); w1 = __expf(e1); w2 = __expf(e2); w3 = __expf(e3);
            denom += (w0 + w1) + (w2 + w3);
        }
        float wh0 = __shfl_sync(0xffffffffu, w0, h);
        float wh1 = __shfl_sync(0xffffffffu, w1, h);
        float wh2 = __shfl_sync(0xffffffffu, w2, h);
        float wh3 = __shfl_sync(0xffffffffu, w3, h);
        fma_row(acc0, acc1, wh0, q0);
        fma_row(acc0, acc1, wh1, q1);
        fma_row(acc0, acc1, wh2, q2);
        fma_row(acc0, acc1, wh3, q3);
    }
    #pragma unroll 1
    for (; i < end; ++i) {
        int s0 = __ldg(&g_srcs[i]);
        uint4 q0 = __ldg(reinterpret_cast<const uint4*>(zh + (size_t)s0 * 256 + c0));
        float w0 = 0.f;
        if (lane < 4) {
            float e0 = __ldg(&el[s0 * 4 + lane]) + erh;
            e0 = (e0 > 0.f) ? e0 : 0.2f * e0;
            w0 = __expf(e0);
            denom += w0;
        }
        float wh0 = __shfl_sync(0xffffffffu, w0, h);
        fma_row(acc0, acc1, wh0, q0);
    }
    float dh = __shfl_sync(0xffffffffu, denom, h);
    float inv = 1.f / dh;
    const float4* bp = reinterpret_cast<const float4*>(bias + c0);
    float4 b0 = __ldg(bp), b1 = __ldg(bp + 1);
    float v[8];
    v[0] = fmaf(acc0.x, inv, b0.x); v[1] = fmaf(acc0.y, inv, b0.y);
    v[2] = fmaf(acc0.z, inv, b0.z); v[3] = fmaf(acc0.w, inv, b0.w);
    v[4] = fmaf(acc1.x, inv, b1.x); v[5] = fmaf(acc1.y, inv, b1.y);
    v[6] = fmaf(acc1.z, inv, b1.z); v[7] = fmaf(acc1.w, inv, b1.w);
    if (RES) {
        // residual = previous layer's output, fp16, stored in oah (read before overwrite)
        uint4 rq = *reinterpret_cast<const uint4*>(oah + (size_t)gw * 256 + c0);
        float2 r0 = __half22float2(*reinterpret_cast<__half2*>(&rq.x));
        float2 r1 = __half22float2(*reinterpret_cast<__half2*>(&rq.y));
        float2 r2 = __half22float2(*reinterpret_cast<__half2*>(&rq.z));
        float2 r3 = __half22float2(*reinterpret_cast<__half2*>(&rq.w));
        v[0] += r0.x; v[1] += r0.y; v[2] += r1.x; v[3] += r1.y;
        v[4] += r2.x; v[5] += r2.y; v[6] += r3.x; v[7] += r3.y;
    }
    #pragma unroll
    for (int j = 0; j < 8; ++j) v[j] = (v[j] > 0.f) ? v[j] : expm1f(v[j]);
    if (out != nullptr) {
        float4* op = reinterpret_cast<float4*>(out + (size_t)gw * 256 + c0);
        op[0] = make_float4(v[0], v[1], v[2], v[3]);
        op[1] = make_float4(v[4], v[5], v[6], v[7]);
    }
    __half2 p0 = __floats2half2_rn(v[0], v[1]);
    __half2 p1 = __floats2half2_rn(v[2], v[3]);
    __half2 p2 = __floats2half2_rn(v[4], v[5]);
    __half2 p3 = __floats2half2_rn(v[6], v[7]);
    *reinterpret_cast<uint4*>(oah + (size_t)gw * 256 + c0) =
        make_uint4(*reinterpret_cast<uint32_t*>(&p0), *reinterpret_cast<uint32_t*>(&p1),
                   *reinterpret_cast<uint32_t*>(&p2), *reinterpret_cast<uint32_t*>(&p3));
}

// ---------------- aggregation, layer 2 (4x unrolled) ----------------
__global__ __launch_bounds__(256) void k_agg_l2(
    const __half* __restrict__ zh, const float* __restrict__ el,
    const float* __restrict__ er, const float* __restrict__ bias,
    const float* __restrict__ r2m, float* __restrict__ logits, int n)
{
    __shared__ float sout[8][240];
    int wInB = threadIdx.x >> 5;
    int gw = blockIdx.x * 8 + wInB;
    int lane = threadIdx.x & 31;
    bool act = (lane < 30);
    if (gw < n) {
        int beg = g_rowstart[gw], end = g_rowstart[gw + 1];
        float erh = (lane < 6) ? __ldg(&er[gw * 6 + lane]) : 0.f;
        int h = act ? (lane / 5) : 0;
        int c0 = lane * 8;
        float4 acc0 = make_float4(0.f, 0.f, 0.f, 0.f), acc1 = acc0;
        float denom = 0.f;
        int i = beg;
        #pragma unroll 1
        for (; i + 4 <= end; i += 4) {
            int s0 = __ldg(&g_srcs[i]);
            int s1 = __ldg(&g_srcs[i + 1]);
            int s2 = __ldg(&g_srcs[i + 2]);
            int s3 = __ldg(&g_srcs[i + 3]);
            uint4 q0 = make_uint4(0, 0, 0, 0), q1 = q0, q2 = q0, q3 = q0;
            if (act) {
                q0 = __ldg(reinterpret_cast<const uint4*>(zh + (size_t)s0 * 240 + c0));
                q1 = __ldg(reinterpret_cast<const uint4*>(zh + (size_t)s1 * 240 + c0));
                q2 = __ldg(reinterpret_cast<const uint4*>(zh + (size_t)s2 * 240 + c0));
                q3 = __ldg(reinterpret_cast<const uint4*>(zh + (size_t)s3 * 240 + c0));
            }
            float w0 = 0.f, w1 = 0.f, w2 = 0.f, w3 = 0.f;
            if (lane < 6) {
                float e0 = __ldg(&el[s0 * 6 + lane]) + erh;
                float e1 = __ldg(&el[s1 * 6 + lane]) + erh;
                float e2 = __ldg(&el[s2 * 6 + lane]) + erh;
                float e3 = __ldg(&el[s3 * 6 + lane]) + erh;
                e0 = (e0 > 0.f) ? e0 : 0.2f * e0;
                e1 = (e1 > 0.f) ? e1 : 0.2f * e1;
                e2 = (e2 > 0.f) ? e2 : 0.2f * e2;
                e3 = (e3 > 0.f) ? e3 : 0.2f * e3;
                w0 = __expf(e0); w1 = __expf(e1); w2 = __expf(e2); w3 = __expf(e3);
                denom += (w0 + w1) + (w2 + w3);
            }
            float wh0 = __shfl_sync(0xffffffffu, w0, h);
            float wh1 = __shfl_sync(0xffffffffu, w1, h);
            float wh2 = __shfl_sync(0xffffffffu, w2, h);
            float wh3 = __shfl_sync(0xffffffffu, w3, h);
            if (act) {
                fma_row(acc0, acc1, wh0, q0);
                fma_row(acc0, acc1, wh1, q1);
                fma_row(acc0, acc1, wh2, q2);
                fma_row(acc0, acc1, wh3, q3);
            }
        }
        #pragma unroll 1
        for (; i < end; ++i) {
            int s0 = __ldg(&g_srcs[i]);
            uint4 q0 = make_uint4(0, 0, 0, 0);
            if (act) q0 = __ldg(reinterpret_cast<const uint4*>(zh + (size_t)s0 * 240 + c0));
            float w0 = 0.f;
            if (lane < 6) {
                float e0 = __ldg(&el[s0 * 6 + lane]) + erh;
                e0 = (e0 > 0.f) ? e0 : 0.2f * e0;
                w0 = __expf(e0);
                denom += w0;
            }
            float wh0 = __shfl_sync(0xffffffffu, w0, h);
            if (act) fma_row(acc0, acc1, wh0, q0);
        }
        float dh = __shfl_sync(0xffffffffu, denom, h);
        if (act) {
            float inv = 1.f / dh;
            const float4* bp = reinterpret_cast<const float4*>(bias + c0);
            float4 b0 = __ldg(bp), b1 = __ldg(bp + 1);
            sout[wInB][c0 + 0] = fmaf(acc0.x, inv, b0.x);
            sout[wInB][c0 + 1] = fmaf(acc0.y, inv, b0.y);
            sout[wInB][c0 + 2] = fmaf(acc0.z, inv, b0.z);
            sout[wInB][c0 + 3] = fmaf(acc0.w, inv, b0.w);
            sout[wInB][c0 + 4] = fmaf(acc1.x, inv, b1.x);
            sout[wInB][c0 + 5] = fmaf(acc1.y, inv, b1.y);
            sout[wInB][c0 + 6] = fmaf(acc1.z, inv, b1.z);
            sout[wInB][c0 + 7] = fmaf(acc1.w, inv, b1.w);
        }
    }
    __syncwarp();
    if (gw < n) {
        for (int d = lane; d < 40; d += 32) {
            float s_ = 0.f;
            #pragma unroll
            for (int hh = 0; hh < 6; ++hh) s_ += sout[wInB][hh * 40 + d];
            logits[(size_t)gw * 40 + d] = s_ * (1.0f / 6.0f) + __ldg(&r2m[(size_t)gw * 40 + d]);
        }
    }
}

// ---------------- host ----------------
extern "C" void kernel_launch(void* const* d_in, const int* in_sizes, int n_in,
                              void* d_out, int out_size)
{
    const float* feat  = (const float*)d_in[0];
    const int*   src   = (const int*)d_in[1];
    const int*   dst   = (const int*)d_in[2];
    const float* W0    = (const float*)d_in[3];
    const float* al0   = (const float*)d_in[4];
    const float* ar0   = (const float*)d_in[5];
    const float* b0    = (const float*)d_in[6];
    const float* W1    = (const float*)d_in[7];
    const float* al1   = (const float*)d_in[8];
    const float* ar1   = (const float*)d_in[9];
    const float* b1    = (const float*)d_in[10];
    const float* W2    = (const float*)d_in[11];
    const float* al2   = (const float*)d_in[12];
    const float* ar2   = (const float*)d_in[13];
    const float* b2    = (const float*)d_in[14];
    const float* resW2 = (const float*)d_in[15];

    const int n = NNODES;
    const int E = in_sizes[1];

    float* logits = (float*)d_out;
    float* h1     = (float*)d_out + n * 40;

    float *pr2, *pelA, *perA, *pelB, *perB;
    __half *pzh, *pAh;
    cudaGetSymbolAddress((void**)&pzh,  g_zh);
    cudaGetSymbolAddress((void**)&pr2,  g_r2);
    cudaGetSymbolAddress((void**)&pelA, g_elA);
    cudaGetSymbolAddress((void**)&perA, g_erA);
    cudaGetSymbolAddress((void**)&pelB, g_elB);
    cudaGetSymbolAddress((void**)&perB, g_erB);
    cudaGetSymbolAddress((void**)&pAh,  g_Ah);

    cudaFuncSetAttribute(k_gemm0, cudaFuncAttributeMaxDynamicSharedMemorySize, GEMM_SMEM128);
    cudaFuncSetAttribute(k_gemm1, cudaFuncAttributeMaxDynamicSharedMemorySize, GEMM_SMEM128);
    cudaFuncSetAttribute(k_gemm2, cudaFuncAttributeMaxDynamicSharedMemorySize, GEMM_SMEM128);

    const int nGemm = ((n + 127) / 128) * 2;          // 782
    const int nGemmM = (n + 127) / 128;               // 391
    const int histBlocks = (E + 255) / 256;
    const int scatBlocks = (E + 255) / 256;
    const int zeroBlocks = (n * 6 + 255) / 256;       // 1172
    const int aggBlocks  = (n + 7) / 8;               // 6250

    // 1. zero deg + elA/erA
    k_zero0<<<zeroBlocks, 256>>>(n, n * 6);
    // 2. conv feat + conv W0 + hist
    k_prep0<<<SPLITA_BLOCKS + 256 + histBlocks, 256>>>(feat, W0, dst, E);
    // 3. scan
    k_scan<<<1, 1024>>>(n, E);
    // 4. gemm L0 (elA) + scatter
    k_gemm0<<<nGemm + scatBlocks, 256, GEMM_SMEM128>>>(pAh, pzh, al0, ar0, pelA, perA,
                                                       n, nGemm, src, dst, E);
    // 5. agg L0 (elA) -> oah only; tail: conv W1, zero elB
    k_agg256<false><<<aggBlocks + 256 + zeroBlocks, 256>>>(
        pzh, pelA, perA, b0, nullptr, pAh, n, aggBlocks,
        W1, 256, nullptr, pelB, perB, n * 6);
    // 6. gemm L1 (elB)
    k_gemm1<<<nGemm, 256, GEMM_SMEM128>>>(pAh, pzh, al1, ar1, pelB, perB, n);
    // 7. agg L1 (elB) -> h1 fp32 + oah; residual read from oah; tail: conv W2, resW2 mean, zero elA
    k_agg256<true><<<aggBlocks + 256 + 64 + zeroBlocks, 256>>>(
        pzh, pelB, perB, b1, h1, pAh, n, aggBlocks,
        W2, 240, resW2, pelA, perA, n * 6);
    // 8. gemm L2 (elA) + res gemm
    k_gemm2<<<nGemm + nGemmM, 256, GEMM_SMEM128>>>(pAh, pzh, pr2, al2, ar2, pelA, perA,
                                                   n, nGemm);
    // 9. agg L2 -> logits
    k_agg_l2<<<aggBlocks, 256>>>(pzh, pelA, perA, b2, pr2, logits, n);
}

// round 13
// speedup vs baseline: 4.0599x; 1.0853x over previous
#include <cuda_runtime.h>
#include <cuda_fp16.h>
#include <math.h>
#include <cstdint>

// ---------------- problem constants ----------------
#define NNODES 50000
#define ECAP   1000000
#define SPLITA_BLOCKS 12500   // (NNODES*256/4)/256

// ---------------- device scratch ----------------
__device__ __align__(16) __half g_zh[NNODES * 256];
__device__ float g_r2[NNODES * 40];
__device__ float g_elA[NNODES * 6];
__device__ float g_erA[NNODES * 6];
__device__ float g_elB[NNODES * 6];
__device__ float g_erB[NNODES * 6];
__device__ int   g_deg[NNODES];
__device__ int   g_rowstart[NNODES + 1];
__device__ int   g_cursor[NNODES];
__device__ int   g_srcs[ECAP];
__device__ __align__(16) __half g_Ah[NNODES * 256];
__device__ __align__(16) __half g_Bh[256 * 256];
__device__ __align__(16) __half g_Bh2[64 * 256];

// ================= PTX helpers =================
__device__ __forceinline__ uint32_t smem_u32(const void* p) {
    uint32_t a;
    asm("{ .reg .u64 t; cvta.to.shared.u64 t, %1; cvt.u32.u64 %0, t; }" : "=r"(a) : "l"(p));
    return a;
}
__device__ __forceinline__ void cp16(uint32_t dst, const void* src, uint32_t srcsize) {
    asm volatile("cp.async.cg.shared.global [%0], [%1], 16, %2;"
                 :: "r"(dst), "l"(src), "r"(srcsize));
}
#define CP_COMMIT() asm volatile("cp.async.commit_group;" ::: "memory")
#define CP_WAIT(n)  asm volatile("cp.async.wait_group %0;" :: "n"(n) : "memory")
#define LDSM_X4(r0, r1, r2, r3, addr) \
    asm volatile("ldmatrix.sync.aligned.m8n8.x4.shared.b16 {%0,%1,%2,%3}, [%4];" \
        : "=r"(r0), "=r"(r1), "=r"(r2), "=r"(r3) : "r"(addr))
#define MMA_F16(acc, a, b) \
    asm volatile("mma.sync.aligned.m16n8k16.row.col.f32.f16.f16.f32 " \
        "{%0,%1,%2,%3}, {%4,%5,%6,%7}, {%8,%9}, {%0,%1,%2,%3};" \
        : "+f"((acc)[0]), "+f"((acc)[1]), "+f"((acc)[2]), "+f"((acc)[3]) \
        : "r"((a)[0]), "r"((a)[1]), "r"((a)[2]), "r"((a)[3]), "r"((b)[0]), "r"((b)[1]))

// ---------------- helpers ----------------
__device__ __forceinline__ void convBt_elem(const float* __restrict__ B,
                                            __half* __restrict__ out, int t, int Nn) {
    int nrow = t >> 8, k = t & 255;
    float x = (nrow < Nn) ? B[(size_t)k * Nn + nrow] : 0.f;
    out[t] = __float2half_rn(x);
}
__device__ __forceinline__ void resmean_elem(const float* __restrict__ resW2, int t) {
    int d = t >> 8, k = t & 255;
    float x = 0.f;
    if (d < 40) {
        float s_ = 0.f;
        #pragma unroll
        for (int h = 0; h < 6; ++h) s_ += resW2[(size_t)k * 240 + h * 40 + d];
        x = s_ * (1.0f / 6.0f);
    }
    g_Bh2[t] = __float2half_rn(x);
}

// ---------------- prep0: conv feat->fp16 + conv W0 + hist ----------------
__global__ void k_prep0(const float* __restrict__ feat, const float* __restrict__ W0,
                        const int* __restrict__ dst, int E) {
    int bx = blockIdx.x;
    if (bx < SPLITA_BLOCKS) {
        int i = bx * 256 + threadIdx.x;
        float4 v = reinterpret_cast<const float4*>(feat)[i];
        __half2 p0 = __floats2half2_rn(v.x, v.y);
        __half2 p1 = __floats2half2_rn(v.z, v.w);
        reinterpret_cast<uint2*>(g_Ah)[i] =
            make_uint2(*reinterpret_cast<uint32_t*>(&p0), *reinterpret_cast<uint32_t*>(&p1));
    } else if (bx < SPLITA_BLOCKS + 256) {
        int t = (bx - SPLITA_BLOCKS) * 256 + threadIdx.x;
        convBt_elem(W0, g_Bh, t, 256);
    } else {
        int e = (bx - SPLITA_BLOCKS - 256) * 256 + threadIdx.x;
        if (e < E) atomicAdd(&g_deg[dst[e]], 1);
    }
}

// ---------------- scan ----------------
__global__ void k_scan(int n, int E) {
    __shared__ int wsum[32];
    __shared__ int carry;
    int lane = threadIdx.x & 31, w = threadIdx.x >> 5;
    if (threadIdx.x == 0) carry = 0;
    __syncthreads();
    for (int base = 0; base < n; base += 1024) {
        int i = base + threadIdx.x;
        int v = (i < n) ? g_deg[i] : 0;
        int x = v;
        #pragma unroll
        for (int off = 1; off < 32; off <<= 1) {
            int t = __shfl_up_sync(0xffffffffu, x, off);
            if (lane >= off) x += t;
        }
        if (lane == 31) wsum[w] = x;
        __syncthreads();
        if (w == 0) {
            int y = wsum[lane];
            #pragma unroll
            for (int off = 1; off < 32; off <<= 1) {
                int t = __shfl_up_sync(0xffffffffu, y, off);
                if (lane >= off) y += t;
            }
            wsum[lane] = y;
        }
        __syncthreads();
        int incl = x + (w ? wsum[w - 1] : 0) + carry;
        int excl = incl - v;
        if (i < n) { g_rowstart[i] = excl; g_cursor[i] = excl; }
        __syncthreads();
        if (threadIdx.x == 1023) carry = incl;
        __syncthreads();
    }
    if (threadIdx.x == 0) g_rowstart[n] = E;
}

// ---------------- GEMM body: fp16 mma.sync, BM=64, 128 threads (2x2 warps), 2-stage ----------------
// MODE: 0 = plain fp32 C, 1 = fp16 C + el/er direct store (D==64), 2 = fp16 C + el/er atomic.
template <int BN>
__device__ __forceinline__ void gemm_load_stage(
    uint32_t sb, const __half* __restrict__ Ah, const __half* __restrict__ Bh,
    int m0, int n0, int M, int kb, int tid)
{
    #pragma unroll
    for (int it = 0; it < 4; ++it) {                 // A: 64 rows x 8 chunks = 512
        int idx = tid + it * 128;
        int row = idx >> 3, ch = idx & 7;
        uint32_t dst = sb + row * 128 + (((uint32_t)(ch ^ (row & 7))) << 4);
        const __half* src = Ah + (size_t)(m0 + row) * 256 + kb * 64 + ch * 8;
        cp16(dst, src, (m0 + row) < M ? 16u : 0u);
    }
    #pragma unroll
    for (int it = 0; it < (BN * 8) / 128; ++it) {    // B: BN rows x 8 chunks
        int idx = tid + it * 128;
        int row = idx >> 3, ch = idx & 7;
        uint32_t dst = sb + 8192 + row * 128 + (((uint32_t)(ch ^ (row & 7))) << 4);
        const __half* src = Bh + (size_t)(n0 + row) * 256 + kb * 64 + ch * 8;
        cp16(dst, src, 16u);
    }
}

template <int MODE, int BN>
__device__ __forceinline__ void gemm_body(
    const __half* __restrict__ Ah, const __half* __restrict__ Bh,
    __half* __restrict__ Ch, float* __restrict__ Cf,
    const float* __restrict__ al, const float* __restrict__ ar,
    float* __restrict__ el, float* __restrict__ er,
    int M, int Nn, int H, int D, int m0, int n0)
{
    constexpr int NT = BN / 16;                      // warp covers BN/2 cols
    constexpr uint32_t STAGE = 8192u + (uint32_t)BN * 128u;
    extern __shared__ char smem[];
    const uint32_t sbase = smem_u32(smem);
    const int tid = threadIdx.x, wid = tid >> 5, lane = tid & 31;
    const int warp_m = wid & 1, warp_n = wid >> 1;   // 2 x 2 warps

    float acc[2][NT][4];
    #pragma unroll
    for (int mt = 0; mt < 2; ++mt)
        #pragma unroll
        for (int nt = 0; nt < NT; ++nt)
            #pragma unroll
            for (int q = 0; q < 4; ++q) acc[mt][nt][q] = 0.f;

    const int rowA = warp_m * 32 + (lane & 15);
    const int rowB = warp_n * (BN / 2) + (lane & 7) + ((lane >> 4) << 3);
    const uint32_t rowAswz = (uint32_t)(rowA & 7);
    const uint32_t rowBswz = (uint32_t)(rowB & 7);
    const int halfA = lane >> 4;
    const int halfB = (lane >> 3) & 1;

    gemm_load_stage<BN>(sbase, Ah, Bh, m0, n0, M, 0, tid);
    CP_COMMIT();
    gemm_load_stage<BN>(sbase + STAGE, Ah, Bh, m0, n0, M, 1, tid);
    CP_COMMIT();

    #pragma unroll 1
    for (int kb = 0; kb < 4; ++kb) {
        if (kb < 3) { CP_WAIT(1); } else { CP_WAIT(0); }
        __syncthreads();
        const uint32_t sb = sbase + (kb & 1) * STAGE;
        #pragma unroll
        for (int s = 0; s < 4; ++s) {
            uint32_t a[2][4];
            uint32_t b[NT][2];
            const uint32_t offA = (((uint32_t)(s * 2 + halfA) ^ rowAswz) << 4);
            const uint32_t offB = (((uint32_t)(s * 2 + halfB) ^ rowBswz) << 4);
            #pragma unroll
            for (int mt = 0; mt < 2; ++mt) {
                uint32_t addr = sb + (uint32_t)(rowA + mt * 16) * 128 + offA;
                LDSM_X4(a[mt][0], a[mt][1], a[mt][2], a[mt][3], addr);
            }
            #pragma unroll
            for (int ntp = 0; ntp < NT / 2; ++ntp) {
                uint32_t addr = sb + 8192 + (uint32_t)(rowB + ntp * 16) * 128 + offB;
                LDSM_X4(b[2 * ntp][0], b[2 * ntp][1], b[2 * ntp + 1][0], b[2 * ntp + 1][1], addr);
            }
            #pragma unroll
            for (int mt = 0; mt < 2; ++mt)
                #pragma unroll
                for (int nt = 0; nt < NT; ++nt)
                    MMA_F16(acc[mt][nt], a[mt], b[nt]);
        }
        __syncthreads();
        if (kb < 2) {
            gemm_load_stage<BN>(sbase + (kb & 1) * STAGE, Ah, Bh, m0, n0, M, kb + 2, tid);
            CP_COMMIT();
        }
    }

    #pragma unroll
    for (int mt = 0; mt < 2; ++mt) {
        int row = m0 + warp_m * 32 + mt * 16 + (lane >> 2);
        #pragma unroll
        for (int nt = 0; nt < NT; ++nt) {
            int col = n0 + warp_n * (BN / 2) + nt * 8 + (lane & 3) * 2;
            if (col < Nn) {
                if (MODE != 0) {
                    if (row < M)
                        *reinterpret_cast<__half2*>(Ch + (size_t)row * Nn + col) =
                            __floats2half2_rn(acc[mt][nt][0], acc[mt][nt][1]);
                    if (row + 8 < M)
                        *reinterpret_cast<__half2*>(Ch + (size_t)(row + 8) * Nn + col) =
                            __floats2half2_rn(acc[mt][nt][2], acc[mt][nt][3]);
                } else {
                    if (row < M)
                        *reinterpret_cast<float2*>(Cf + (size_t)row * Nn + col) =
                            make_float2(acc[mt][nt][0], acc[mt][nt][1]);
                    if (row + 8 < M)
                        *reinterpret_cast<float2*>(Cf + (size_t)(row + 8) * Nn + col) =
                            make_float2(acc[mt][nt][2], acc[mt][nt][3]);
                }
            }
        }
    }

    if (MODE == 1) {
        // D == 64, BN == 128: warp's 64 cols == exactly one head -> unique writer, plain store.
        const int h = (n0 + warp_n * 64) >> 6;
        float sl[2][2] = {}, sr[2][2] = {};
        #pragma unroll
        for (int nt = 0; nt < NT; ++nt) {
            int dloc = nt * 8 + (lane & 3) * 2;
            float2 av = __ldg(reinterpret_cast<const float2*>(al + h * 64 + dloc));
            float2 rv = __ldg(reinterpret_cast<const float2*>(ar + h * 64 + dloc));
            #pragma unroll
            for (int mt = 0; mt < 2; ++mt) {
                sl[mt][0] += acc[mt][nt][0] * av.x + acc[mt][nt][1] * av.y;
                sr[mt][0] += acc[mt][nt][0] * rv.x + acc[mt][nt][1] * rv.y;
                sl[mt][1] += acc[mt][nt][2] * av.x + acc[mt][nt][3] * av.y;
                sr[mt][1] += acc[mt][nt][2] * rv.x + acc[mt][nt][3] * rv.y;
            }
        }
        #pragma unroll
        for (int mt = 0; mt < 2; ++mt)
            #pragma unroll
            for (int rh = 0; rh < 2; ++rh) {
                float vl = sl[mt][rh], vr = sr[mt][rh];
                vl += __shfl_xor_sync(0xffffffffu, vl, 1);
                vl += __shfl_xor_sync(0xffffffffu, vl, 2);
                vr += __shfl_xor_sync(0xffffffffu, vr, 1);
                vr += __shfl_xor_sync(0xffffffffu, vr, 2);
                sl[mt][rh] = vl; sr[mt][rh] = vr;
            }
        if ((lane & 3) == 0) {
            #pragma unroll
            for (int mt = 0; mt < 2; ++mt)
                #pragma unroll
                for (int rh = 0; rh < 2; ++rh) {
                    int row = m0 + warp_m * 32 + mt * 16 + (lane >> 2) + rh * 8;
                    if (row < M) {
                        el[(size_t)row * H + h] = sl[mt][rh];
                        er[(size_t)row * H + h] = sr[mt][rh];
                    }
                }
        }
    } else if (MODE == 2) {
        const int colbase = n0 + warp_n * (BN / 2);
        if (colbase < Nn) {
            const int h0 = colbase / D;
            const int colend = (colbase + BN / 2 < Nn) ? (colbase + BN / 2) : Nn;
            const int hmax = (colend - 1) / D;
            float sl[2][2][3] = {}, sr[2][2][3] = {};
            #pragma unroll
            for (int nt = 0; nt < NT; ++nt) {
                int colg = colbase + nt * 8;
                if (colg < Nn) {
                    int h = colg / D;
                    int slot = h - h0;
                    if (slot > 2) slot = 2;
                    int d = colg - h * D + (lane & 3) * 2;
                    float2 av = __ldg(reinterpret_cast<const float2*>(al + h * D + d));
                    float2 rv = __ldg(reinterpret_cast<const float2*>(ar + h * D + d));
                    #pragma unroll
                    for (int mt = 0; mt < 2; ++mt) {
                        sl[mt][0][slot] += acc[mt][nt][0] * av.x + acc[mt][nt][1] * av.y;
                        sr[mt][0][slot] += acc[mt][nt][0] * rv.x + acc[mt][nt][1] * rv.y;
                        sl[mt][1][slot] += acc[mt][nt][2] * av.x + acc[mt][nt][3] * av.y;
                        sr[mt][1][slot] += acc[mt][nt][2] * rv.x + acc[mt][nt][3] * rv.y;
                    }
                }
            }
            #pragma unroll
            for (int mt = 0; mt < 2; ++mt)
                #pragma unroll
                for (int rh = 0; rh < 2; ++rh)
                    #pragma unroll
                    for (int sx = 0; sx < 3; ++sx) {
                        float vl = sl[mt][rh][sx], vr = sr[mt][rh][sx];
                        vl += __shfl_xor_sync(0xffffffffu, vl, 1);
                        vl += __shfl_xor_sync(0xffffffffu, vl, 2);
                        vr += __shfl_xor_sync(0xffffffffu, vr, 1);
                        vr += __shfl_xor_sync(0xffffffffu, vr, 2);
                        sl[mt][rh][sx] = vl; sr[mt][rh][sx] = vr;
                    }
            if ((lane & 3) == 0) {
                int nslots = hmax - h0 + 1;
                if (nslots > 3) nslots = 3;
                #pragma unroll
                for (int mt = 0; mt < 2; ++mt)
                    #pragma unroll
                    for (int rh = 0; rh < 2; ++rh) {
                        int row = m0 + warp_m * 32 + mt * 16 + (lane >> 2) + rh * 8;
                        if (row < M) {
                            for (int sx = 0; sx < nslots; ++sx) {
                                atomicAdd(&el[(size_t)row * H + h0 + sx], sl[mt][rh][sx]);
                                atomicAdd(&er[(size_t)row * H + h0 + sx], sr[mt][rh][sx]);
                            }
                        }
                    }
            }
        }
    }
}

#define GEMM_SMEM128 (2 * (8192 + 128 * 128))
#define GEMM_SMEM64  (2 * (8192 + 64 * 128))

// ---------------- GEMM launches (128 threads, BM=64) ----------------
__global__ __launch_bounds__(128, 4) void k_gemm0(
    const __half* __restrict__ Ah, __half* __restrict__ Ch,
    const float* __restrict__ al, const float* __restrict__ ar,
    float* __restrict__ el, float* __restrict__ er, int M, int nGemm,
    const int* __restrict__ src, const int* __restrict__ dst, int E)
{
    int bx = blockIdx.x;
    if (bx < nGemm) {
        gemm_body<1, 128>(Ah, g_Bh, Ch, nullptr, al, ar, el, er,
                          M, 256, 4, 64, (bx >> 1) * 64, (bx & 1) * 128);
    } else {
        int e = (bx - nGemm) * 128 + threadIdx.x;
        if (e < E) {
            int p = atomicAdd(&g_cursor[dst[e]], 1);
            g_srcs[p] = src[e];
        }
    }
}

__global__ __launch_bounds__(128, 4) void k_gemm1(
    const __half* __restrict__ Ah, __half* __restrict__ Ch,
    const float* __restrict__ al, const float* __restrict__ ar,
    float* __restrict__ el, float* __restrict__ er, int M)
{
    int bx = blockIdx.x;
    gemm_body<1, 128>(Ah, g_Bh, Ch, nullptr, al, ar, el, er,
                      M, 256, 4, 64, (bx >> 1) * 64, (bx & 1) * 128);
}

__global__ __launch_bounds__(128, 4) void k_gemm2(
    const __half* __restrict__ Ah, __half* __restrict__ Ch, float* __restrict__ Cf,
    const float* __restrict__ al, const float* __restrict__ ar,
    float* __restrict__ el, float* __restrict__ er, int M, int nGemm)
{
    int bx = blockIdx.x;
    if (bx < nGemm) {
        gemm_body<2, 128>(Ah, g_Bh, Ch, nullptr, al, ar, el, er,
                          M, 240, 6, 40, (bx >> 1) * 64, (bx & 1) * 128);
    } else {
        gemm_body<0, 64>(Ah, g_Bh2, nullptr, Cf, nullptr, nullptr, nullptr, nullptr,
                         M, 40, 1, 64, (bx - nGemm) * 64, 0);
    }
}

// ---------------- aggregation helpers ----------------
__device__ __forceinline__ void fma_row(float4& a0, float4& a1, float wh, uint4 q) {
    float2 p0 = __half22float2(*reinterpret_cast<__half2*>(&q.x));
    float2 p1 = __half22float2(*reinterpret_cast<__half2*>(&q.y));
    float2 p2 = __half22float2(*reinterpret_cast<__half2*>(&q.z));
    float2 p3 = __half22float2(*reinterpret_cast<__half2*>(&q.w));
    a0.x = fmaf(wh, p0.x, a0.x); a0.y = fmaf(wh, p0.y, a0.y);
    a0.z = fmaf(wh, p1.x, a0.z); a0.w = fmaf(wh, p1.y, a0.w);
    a1.x = fmaf(wh, p2.x, a1.x); a1.y = fmaf(wh, p2.y, a1.y);
    a1.z = fmaf(wh, p3.x, a1.z); a1.w = fmaf(wh, p3.y, a1.w);
}

// ---------------- aggregation, layers 0/1 ----------------
template <bool RES>
__global__ __launch_bounds__(256) void k_agg256(
    const __half* __restrict__ zh, const float* __restrict__ el,
    const float* __restrict__ er, const float* __restrict__ bias,
    float* __restrict__ out, __half* __restrict__ oah, int n, int nAgg,
    const float* __restrict__ Wnext, int convN,
    const float* __restrict__ resW2,
    float* __restrict__ zel, float* __restrict__ zer, int n6)
{
    int bx = blockIdx.x;
    if (bx >= nAgg) {
        int t = bx - nAgg;
        if (t < 256) {
            convBt_elem(Wnext, g_Bh, t * 256 + threadIdx.x, convN);
        } else if (resW2 != nullptr && t < 320) {
            resmean_elem(resW2, (t - 256) * 256 + threadIdx.x);
        } else if (zel != nullptr) {
            int zoff = (resW2 != nullptr) ? 320 : 256;
            int i = (t - zoff) * 256 + threadIdx.x;
            if (i < n6) { zel[i] = 0.f; zer[i] = 0.f; }
        }
        return;
    }
    int gw = (bx * 256 + threadIdx.x) >> 5;
    if (gw >= n) return;
    int lane = threadIdx.x & 31;
    int beg = g_rowstart[gw], end = g_rowstart[gw + 1];
    float erh = (lane < 4) ? __ldg(&er[gw * 4 + lane]) : 0.f;
    int h = lane >> 3;
    int c0 = lane * 8;
    float4 acc0 = make_float4(0.f, 0.f, 0.f, 0.f), acc1 = acc0;
    float denom = 0.f;
    int i = beg;
    #pragma unroll 1
    for (; i + 4 <= end; i += 4) {
        int s0 = __ldg(&g_srcs[i]);
        int s1 = __ldg(&g_srcs[i + 1]);
        int s2 = __ldg(&g_srcs[i + 2]);
        int s3 = __ldg(&g_srcs[i + 3]);
        uint4 q0 = __ldg(reinterpret_cast<const uint4*>(zh + (size_t)s0 * 256 + c0));
        uint4 q1 = __ldg(reinterpret_cast<const uint4*>(zh + (size_t)s1 * 256 + c0));
        uint4 q2 = __ldg(reinterpret_cast<const uint4*>(zh + (size_t)s2 * 256 + c0));
        uint4 q3 = __ldg(reinterpret_cast<const uint4*>(zh + (size_t)s3 * 256 + c0));
        float w0 = 0.f, w1 = 0.f, w2 = 0.f, w3 = 0.f;
        if (lane < 4) {
            float e0 = __ldg(&el[s0 * 4 + lane]) + erh;
            float e1 = __ldg(&el[s1 * 4 + lane]) + erh;
            float e2 = __ldg(&el[s2 * 4 + lane]) + erh;
            float e3 = __ldg(&el[s3 * 4 + lane]) + erh;
            e0 = (e0 > 0.f) ? e0 : 0.2f * e0;
            e1 = (e1 > 0.f) ? e1 : 0.2f * e1;
            e2 = (e2 > 0.f) ? e2 : 0.2f * e2;
            e3 = (e3 > 0.f) ? e3 : 0.2f * e3;
            w0 = __expf(e0); w1 = __expf(e1); w2 = __expf(e2); w3 = __expf(e3);
            denom += (w0 + w1) + (w2 + w3);
        }
        float wh0 = __shfl_sync(0xffffffffu, w0, h);
        float wh1 = __shfl_sync(0xffffffffu, w1, h);
        float wh2 = __shfl_sync(0xffffffffu, w2, h);
        float wh3 = __shfl_sync(0xffffffffu, w3, h);
        fma_row(acc0, acc1, wh0, q0);
        fma_row(acc0, acc1, wh1, q1);
        fma_row(acc0, acc1, wh2, q2);
        fma_row(acc0, acc1, wh3, q3);
    }
    #pragma unroll 1
    for (; i < end; ++i) {
        int s0 = __ldg(&g_srcs[i]);
        uint4 q0 = __ldg(reinterpret_cast<const uint4*>(zh + (size_t)s0 * 256 + c0));
        float w0 = 0.f;
        if (lane < 4) {
            float e0 = __ldg(&el[s0 * 4 + lane]) + erh;
            e0 = (e0 > 0.f) ? e0 : 0.2f * e0;
            w0 = __expf(e0);
            denom += w0;
        }
        float wh0 = __shfl_sync(0xffffffffu, w0, h);
        fma_row(acc0, acc1, wh0, q0);
    }
    float dh = __shfl_sync(0xffffffffu, denom, h);
    float inv = 1.f / dh;
    const float4* bp = reinterpret_cast<const float4*>(bias + c0);
    float4 b0 = __ldg(bp), b1 = __ldg(bp + 1);
    float v[8];
    v[0] = fmaf(acc0.x, inv, b0.x); v[1] = fmaf(acc0.y, inv, b0.y);
    v[2] = fmaf(acc0.z, inv, b0.z); v[3] = fmaf(acc0.w, inv, b0.w);
    v[4] = fmaf(acc1.x, inv, b1.x); v[5] = fmaf(acc1.y, inv, b1.y);
    v[6] = fmaf(acc1.z, inv, b1.z); v[7] = fmaf(acc1.w, inv, b1.w);
    if (RES) {
        uint4 rq = *reinterpret_cast<const uint4*>(oah + (size_t)gw * 256 + c0);
        float2 r0 = __half22float2(*reinterpret_cast<__half2*>(&rq.x));
        float2 r1 = __half22float2(*reinterpret_cast<__half2*>(&rq.y));
        float2 r2 = __half22float2(*reinterpret_cast<__half2*>(&rq.z));
        float2 r3 = __half22float2(*reinterpret_cast<__half2*>(&rq.w));
        v[0] += r0.x; v[1] += r0.y; v[2] += r1.x; v[3] += r1.y;
        v[4] += r2.x; v[5] += r2.y; v[6] += r3.x; v[7] += r3.y;
    }
    #pragma unroll
    for (int j = 0; j < 8; ++j) v[j] = (v[j] > 0.f) ? v[j] : expm1f(v[j]);
    if (out != nullptr) {
        float4* op = reinterpret_cast<float4*>(out + (size_t)gw * 256 + c0);
        op[0] = make_float4(v[0], v[1], v[2], v[3]);
        op[1] = make_float4(v[4], v[5], v[6], v[7]);
    }
    __half2 p0 = __floats2half2_rn(v[0], v[1]);
    __half2 p1 = __floats2half2_rn(v[2], v[3]);
    __half2 p2 = __floats2half2_rn(v[4], v[5]);
    __half2 p3 = __floats2half2_rn(v[6], v[7]);
    *reinterpret_cast<uint4*>(oah + (size_t)gw * 256 + c0) =
        make_uint4(*reinterpret_cast<uint32_t*>(&p0), *reinterpret_cast<uint32_t*>(&p1),
                   *reinterpret_cast<uint32_t*>(&p2), *reinterpret_cast<uint32_t*>(&p3));
}

// ---------------- aggregation, layer 2 ----------------
__global__ __launch_bounds__(256) void k_agg_l2(
    const __half* __restrict__ zh, const float* __restrict__ el,
    const float* __restrict__ er, const float* __restrict__ bias,
    const float* __restrict__ r2m, float* __restrict__ logits, int n)
{
    __shared__ float sout[8][240];
    int wInB = threadIdx.x >> 5;
    int gw = blockIdx.x * 8 + wInB;
    int lane = threadIdx.x & 31;
    bool act = (lane < 30);
    if (gw < n) {
        int beg = g_rowstart[gw], end = g_rowstart[gw + 1];
        float erh = (lane < 6) ? __ldg(&er[gw * 6 + lane]) : 0.f;
        int h = act ? (lane / 5) : 0;
        int c0 = lane * 8;
        float4 acc0 = make_float4(0.f, 0.f, 0.f, 0.f), acc1 = acc0;
        float denom = 0.f;
        int i = beg;
        #pragma unroll 1
        for (; i + 4 <= end; i += 4) {
            int s0 = __ldg(&g_srcs[i]);
            int s1 = __ldg(&g_srcs[i + 1]);
            int s2 = __ldg(&g_srcs[i + 2]);
            int s3 = __ldg(&g_srcs[i + 3]);
            uint4 q0 = make_uint4(0, 0, 0, 0), q1 = q0, q2 = q0, q3 = q0;
            if (act) {
                q0 = __ldg(reinterpret_cast<const uint4*>(zh + (size_t)s0 * 240 + c0));
                q1 = __ldg(reinterpret_cast<const uint4*>(zh + (size_t)s1 * 240 + c0));
                q2 = __ldg(reinterpret_cast<const uint4*>(zh + (size_t)s2 * 240 + c0));
                q3 = __ldg(reinterpret_cast<const uint4*>(zh + (size_t)s3 * 240 + c0));
            }
            float w0 = 0.f, w1 = 0.f, w2 = 0.f, w3 = 0.f;
            if (lane < 6) {
                float e0 = __ldg(&el[s0 * 6 + lane]) + erh;
                float e1 = __ldg(&el[s1 * 6 + lane]) + erh;
                float e2 = __ldg(&el[s2 * 6 + lane]) + erh;
                float e3 = __ldg(&el[s3 * 6 + lane]) + erh;
                e0 = (e0 > 0.f) ? e0 : 0.2f * e0;
                e1 = (e1 > 0.f) ? e1 : 0.2f * e1;
                e2 = (e2 > 0.f) ? e2 : 0.2f * e2;
                e3 = (e3 > 0.f) ? e3 : 0.2f * e3;
                w0 = __expf(e0); w1 = __expf(e1); w2 = __expf(e2); w3 = __expf(e3);
                denom += (w0 + w1) + (w2 + w3);
            }
            float wh0 = __shfl_sync(0xffffffffu, w0, h);
            float wh1 = __shfl_sync(0xffffffffu, w1, h);
            float wh2 = __shfl_sync(0xffffffffu, w2, h);
            float wh3 = __shfl_sync(0xffffffffu, w3, h);
            if (act) {
                fma_row(acc0, acc1, wh0, q0);
                fma_row(acc0, acc1, wh1, q1);
                fma_row(acc0, acc1, wh2, q2);
                fma_row(acc0, acc1, wh3, q3);
            }
        }
        #pragma unroll 1
        for (; i < end; ++i) {
            int s0 = __ldg(&g_srcs[i]);
            uint4 q0 = make_uint4(0, 0, 0, 0);
            if (act) q0 = __ldg(reinterpret_cast<const uint4*>(zh + (size_t)s0 * 240 + c0));
            float w0 = 0.f;
            if (lane < 6) {
                float e0 = __ldg(&el[s0 * 6 + lane]) + erh;
                e0 = (e0 > 0.f) ? e0 : 0.2f * e0;
                w0 = __expf(e0);
                denom += w0;
            }
            float wh0 = __shfl_sync(0xffffffffu, w0, h);
            if (act) fma_row(acc0, acc1, wh0, q0);
        }
        float dh = __shfl_sync(0xffffffffu, denom, h);
        if (act) {
            float inv = 1.f / dh;
            const float4* bp = reinterpret_cast<const float4*>(bias + c0);
            float4 b0 = __ldg(bp), b1 = __ldg(bp + 1);
            sout[wInB][c0 + 0] = fmaf(acc0.x, inv, b0.x);
            sout[wInB][c0 + 1] = fmaf(acc0.y, inv, b0.y);
            sout[wInB][c0 + 2] = fmaf(acc0.z, inv, b0.z);
            sout[wInB][c0 + 3] = fmaf(acc0.w, inv, b0.w);
            sout[wInB][c0 + 4] = fmaf(acc1.x, inv, b1.x);
            sout[wInB][c0 + 5] = fmaf(acc1.y, inv, b1.y);
            sout[wInB][c0 + 6] = fmaf(acc1.z, inv, b1.z);
            sout[wInB][c0 + 7] = fmaf(acc1.w, inv, b1.w);
        }
    }
    __syncwarp();
    if (gw < n) {
        for (int d = lane; d < 40; d += 32) {
            float s_ = 0.f;
            #pragma unroll
            for (int hh = 0; hh < 6; ++hh) s_ += sout[wInB][hh * 40 + d];
            logits[(size_t)gw * 40 + d] = s_ * (1.0f / 6.0f) + __ldg(&r2m[(size_t)gw * 40 + d]);
        }
    }
}

// ---------------- host ----------------
extern "C" void kernel_launch(void* const* d_in, const int* in_sizes, int n_in,
                              void* d_out, int out_size)
{
    const float* feat  = (const float*)d_in[0];
    const int*   src   = (const int*)d_in[1];
    const int*   dst   = (const int*)d_in[2];
    const float* W0    = (const float*)d_in[3];
    const float* al0   = (const float*)d_in[4];
    const float* ar0   = (const float*)d_in[5];
    const float* b0    = (const float*)d_in[6];
    const float* W1    = (const float*)d_in[7];
    const float* al1   = (const float*)d_in[8];
    const float* ar1   = (const float*)d_in[9];
    const float* b1    = (const float*)d_in[10];
    const float* W2    = (const float*)d_in[11];
    const float* al2   = (const float*)d_in[12];
    const float* ar2   = (const float*)d_in[13];
    const float* b2    = (const float*)d_in[14];
    const float* resW2 = (const float*)d_in[15];

    const int n = NNODES;
    const int E = in_sizes[1];

    float* logits = (float*)d_out;
    float* h1     = (float*)d_out + n * 40;

    float *pr2, *pelA, *perA, *pelB, *perB;
    __half *pzh, *pAh;
    int* pdeg;
    cudaGetSymbolAddress((void**)&pzh,  g_zh);
    cudaGetSymbolAddress((void**)&pr2,  g_r2);
    cudaGetSymbolAddress((void**)&pelA, g_elA);
    cudaGetSymbolAddress((void**)&perA, g_erA);
    cudaGetSymbolAddress((void**)&pelB, g_elB);
    cudaGetSymbolAddress((void**)&perB, g_erB);
    cudaGetSymbolAddress((void**)&pAh,  g_Ah);
    cudaGetSymbolAddress((void**)&pdeg, g_deg);

    cudaFuncSetAttribute(k_gemm0, cudaFuncAttributeMaxDynamicSharedMemorySize, GEMM_SMEM128);
    cudaFuncSetAttribute(k_gemm1, cudaFuncAttributeMaxDynamicSharedMemorySize, GEMM_SMEM128);
    cudaFuncSetAttribute(k_gemm2, cudaFuncAttributeMaxDynamicSharedMemorySize, GEMM_SMEM128);

    const int nGemm = ((n + 63) / 64) * 2;            // 1564
    const int nGemmM = (n + 63) / 64;                 // 782
    const int histBlocks = (E + 255) / 256;
    const int scatBlocks = (E + 127) / 128;
    const int zeroBlocks = (n * 6 + 255) / 256;
    const int aggBlocks  = (n + 7) / 8;

    // 1. zero deg (memset)
    cudaMemsetAsync(pdeg, 0, n * sizeof(int));
    // 2. conv feat + conv W0 + hist
    k_prep0<<<SPLITA_BLOCKS + 256 + histBlocks, 256>>>(feat, W0, dst, E);
    // 3. scan
    k_scan<<<1, 1024>>>(n, E);
    // 4. gemm L0 (el store -> elA) + scatter
    k_gemm0<<<nGemm + scatBlocks, 128, GEMM_SMEM128>>>(pAh, pzh, al0, ar0, pelA, perA,
                                                       n, nGemm, src, dst, E);
    // 5. agg L0 (elA) -> oah; tail: conv W1 (no zero needed)
    k_agg256<false><<<aggBlocks + 256, 256>>>(
        pzh, pelA, perA, b0, nullptr, pAh, n, aggBlocks,
        W1, 256, nullptr, nullptr, nullptr, 0);
    // 6. gemm L1 (el store -> elB)
    k_gemm1<<<nGemm, 128, GEMM_SMEM128>>>(pAh, pzh, al1, ar1, pelB, perB, n);
    // 7. agg L1 (elB) -> h1 + oah; tail: conv W2, resW2 mean, zero elA (for L2 atomics)
    k_agg256<true><<<aggBlocks + 256 + 64 + zeroBlocks, 256>>>(
        pzh, pelB, perB, b1, h1, pAh, n, aggBlocks,
        W2, 240, resW2, pelA, perA, n * 6);
    // 8. gemm L2 (atomic -> elA) + res gemm
    k_gemm2<<<nGemm + nGemmM, 128, GEMM_SMEM128>>>(pAh, pzh, pr2, al2, ar2, pelA, perA,
                                                   n, nGemm);
    // 9. agg L2 -> logits
    k_agg_l2<<<aggBlocks, 256>>>(pzh, pelA, perA, b2, pr2, logits, n);
}

// round 14
// speedup vs baseline: 4.1056x; 1.0112x over previous
#include <cuda_runtime.h>
#include <cuda_fp16.h>
#include <math.h>
#include <cstdint>

// ---------------- problem constants ----------------
#define NNODES 50000
#define ECAP   1000000
#define SPLITA_BLOCKS 12500   // (NNODES*256/4)/256
#define WSCALE 3.4657359028f  // ln(32): w' = exp(e - ln32); cancels in softmax

// ---------------- device scratch ----------------
__device__ __align__(16) __half g_zh[NNODES * 256];
__device__ float g_r2[NNODES * 40];
__device__ float g_elA[NNODES * 6];
__device__ float g_erA[NNODES * 6];
__device__ float g_elB[NNODES * 6];
__device__ float g_erB[NNODES * 6];
__device__ int   g_deg[NNODES];
__device__ int   g_rowstart[NNODES + 1];
__device__ int   g_cursor[NNODES];
__device__ int   g_srcs[ECAP];
__device__ __align__(16) __half g_Ah[NNODES * 256];
__device__ __align__(16) __half g_Bh[256 * 256];
__device__ __align__(16) __half g_Bh2[64 * 256];

// ================= PTX helpers =================
__device__ __forceinline__ uint32_t smem_u32(const void* p) {
    uint32_t a;
    asm("{ .reg .u64 t; cvta.to.shared.u64 t, %1; cvt.u32.u64 %0, t; }" : "=r"(a) : "l"(p));
    return a;
}
__device__ __forceinline__ void cp16(uint32_t dst, const void* src, uint32_t srcsize) {
    asm volatile("cp.async.cg.shared.global [%0], [%1], 16, %2;"
                 :: "r"(dst), "l"(src), "r"(srcsize));
}
#define CP_COMMIT() asm volatile("cp.async.commit_group;" ::: "memory")
#define CP_WAIT(n)  asm volatile("cp.async.wait_group %0;" :: "n"(n) : "memory")
#define LDSM_X4(r0, r1, r2, r3, addr) \
    asm volatile("ldmatrix.sync.aligned.m8n8.x4.shared.b16 {%0,%1,%2,%3}, [%4];" \
        : "=r"(r0), "=r"(r1), "=r"(r2), "=r"(r3) : "r"(addr))
#define MMA_F16(acc, a, b) \
    asm volatile("mma.sync.aligned.m16n8k16.row.col.f32.f16.f16.f32 " \
        "{%0,%1,%2,%3}, {%4,%5,%6,%7}, {%8,%9}, {%0,%1,%2,%3};" \
        : "+f"((acc)[0]), "+f"((acc)[1]), "+f"((acc)[2]), "+f"((acc)[3]) \
        : "r"((a)[0]), "r"((a)[1]), "r"((a)[2]), "r"((a)[3]), "r"((b)[0]), "r"((b)[1]))

// ---------------- helpers ----------------
__device__ __forceinline__ void convBt_elem(const float* __restrict__ B,
                                            __half* __restrict__ out, int t, int Nn) {
    int nrow = t >> 8, k = t & 255;
    float x = (nrow < Nn) ? B[(size_t)k * Nn + nrow] : 0.f;
    out[t] = __float2half_rn(x);
}
__device__ __forceinline__ void resmean_elem(const float* __restrict__ resW2, int t) {
    int d = t >> 8, k = t & 255;
    float x = 0.f;
    if (d < 40) {
        float s_ = 0.f;
        #pragma unroll
        for (int h = 0; h < 6; ++h) s_ += resW2[(size_t)k * 240 + h * 40 + d];
        x = s_ * (1.0f / 6.0f);
    }
    g_Bh2[t] = __float2half_rn(x);
}

// ---------------- prep0 ----------------
__global__ void k_prep0(const float* __restrict__ feat, const float* __restrict__ W0,
                        const int* __restrict__ dst, int E) {
    int bx = blockIdx.x;
    if (bx < SPLITA_BLOCKS) {
        int i = bx * 256 + threadIdx.x;
        float4 v = reinterpret_cast<const float4*>(feat)[i];
        __half2 p0 = __floats2half2_rn(v.x, v.y);
        __half2 p1 = __floats2half2_rn(v.z, v.w);
        reinterpret_cast<uint2*>(g_Ah)[i] =
            make_uint2(*reinterpret_cast<uint32_t*>(&p0), *reinterpret_cast<uint32_t*>(&p1));
    } else if (bx < SPLITA_BLOCKS + 256) {
        int t = (bx - SPLITA_BLOCKS) * 256 + threadIdx.x;
        convBt_elem(W0, g_Bh, t, 256);
    } else {
        int e = (bx - SPLITA_BLOCKS - 256) * 256 + threadIdx.x;
        if (e < E) atomicAdd(&g_deg[dst[e]], 1);
    }
}

// ---------------- scan ----------------
__global__ void k_scan(int n, int E) {
    __shared__ int wsum[32];
    __shared__ int carry;
    int lane = threadIdx.x & 31, w = threadIdx.x >> 5;
    if (threadIdx.x == 0) carry = 0;
    __syncthreads();
    for (int base = 0; base < n; base += 1024) {
        int i = base + threadIdx.x;
        int v = (i < n) ? g_deg[i] : 0;
        int x = v;
        #pragma unroll
        for (int off = 1; off < 32; off <<= 1) {
            int t = __shfl_up_sync(0xffffffffu, x, off);
            if (lane >= off) x += t;
        }
        if (lane == 31) wsum[w] = x;
        __syncthreads();
        if (w == 0) {
            int y = wsum[lane];
            #pragma unroll
            for (int off = 1; off < 32; off <<= 1) {
                int t = __shfl_up_sync(0xffffffffu, y, off);
                if (lane >= off) y += t;
            }
            wsum[lane] = y;
        }
        __syncthreads();
        int incl = x + (w ? wsum[w - 1] : 0) + carry;
        int excl = incl - v;
        if (i < n) { g_rowstart[i] = excl; g_cursor[i] = excl; }
        __syncthreads();
        if (threadIdx.x == 1023) carry = incl;
        __syncthreads();
    }
    if (threadIdx.x == 0) g_rowstart[n] = E;
}

// ---------------- GEMM body (fp16 mma.sync, BM=64, 128 threads, 2-stage) ----------------
template <int BN>
__device__ __forceinline__ void gemm_load_stage(
    uint32_t sb, const __half* __restrict__ Ah, const __half* __restrict__ Bh,
    int m0, int n0, int M, int kb, int tid)
{
    #pragma unroll
    for (int it = 0; it < 4; ++it) {
        int idx = tid + it * 128;
        int row = idx >> 3, ch = idx & 7;
        uint32_t dst = sb + row * 128 + (((uint32_t)(ch ^ (row & 7))) << 4);
        const __half* src = Ah + (size_t)(m0 + row) * 256 + kb * 64 + ch * 8;
        cp16(dst, src, (m0 + row) < M ? 16u : 0u);
    }
    #pragma unroll
    for (int it = 0; it < (BN * 8) / 128; ++it) {
        int idx = tid + it * 128;
        int row = idx >> 3, ch = idx & 7;
        uint32_t dst = sb + 8192 + row * 128 + (((uint32_t)(ch ^ (row & 7))) << 4);
        const __half* src = Bh + (size_t)(n0 + row) * 256 + kb * 64 + ch * 8;
        cp16(dst, src, 16u);
    }
}

template <int MODE, int BN>
__device__ __forceinline__ void gemm_body(
    const __half* __restrict__ Ah, const __half* __restrict__ Bh,
    __half* __restrict__ Ch, float* __restrict__ Cf,
    const float* __restrict__ al, const float* __restrict__ ar,
    float* __restrict__ el, float* __restrict__ er,
    int M, int Nn, int H, int D, int m0, int n0)
{
    constexpr int NT = BN / 16;
    constexpr uint32_t STAGE = 8192u + (uint32_t)BN * 128u;
    extern __shared__ char smem[];
    const uint32_t sbase = smem_u32(smem);
    const int tid = threadIdx.x, wid = tid >> 5, lane = tid & 31;
    const int warp_m = wid & 1, warp_n = wid >> 1;

    float acc[2][NT][4];
    #pragma unroll
    for (int mt = 0; mt < 2; ++mt)
        #pragma unroll
        for (int nt = 0; nt < NT; ++nt)
            #pragma unroll
            for (int q = 0; q < 4; ++q) acc[mt][nt][q] = 0.f;

    const int rowA = warp_m * 32 + (lane & 15);
    const int rowB = warp_n * (BN / 2) + (lane & 7) + ((lane >> 4) << 3);
    const uint32_t rowAswz = (uint32_t)(rowA & 7);
    const uint32_t rowBswz = (uint32_t)(rowB & 7);
    const int halfA = lane >> 4;
    const int halfB = (lane >> 3) & 1;

    gemm_load_stage<BN>(sbase, Ah, Bh, m0, n0, M, 0, tid);
    CP_COMMIT();
    gemm_load_stage<BN>(sbase + STAGE, Ah, Bh, m0, n0, M, 1, tid);
    CP_COMMIT();

    #pragma unroll 1
    for (int kb = 0; kb < 4; ++kb) {
        if (kb < 3) { CP_WAIT(1); } else { CP_WAIT(0); }
        __syncthreads();
        const uint32_t sb = sbase + (kb & 1) * STAGE;
        #pragma unroll
        for (int s = 0; s < 4; ++s) {
            uint32_t a[2][4];
            uint32_t b[NT][2];
            const uint32_t offA = (((uint32_t)(s * 2 + halfA) ^ rowAswz) << 4);
            const uint32_t offB = (((uint32_t)(s * 2 + halfB) ^ rowBswz) << 4);
            #pragma unroll
            for (int mt = 0; mt < 2; ++mt) {
                uint32_t addr = sb + (uint32_t)(rowA + mt * 16) * 128 + offA;
                LDSM_X4(a[mt][0], a[mt][1], a[mt][2], a[mt][3], addr);
            }
            #pragma unroll
            for (int ntp = 0; ntp < NT / 2; ++ntp) {
                uint32_t addr = sb + 8192 + (uint32_t)(rowB + ntp * 16) * 128 + offB;
                LDSM_X4(b[2 * ntp][0], b[2 * ntp][1], b[2 * ntp + 1][0], b[2 * ntp + 1][1], addr);
            }
            #pragma unroll
            for (int mt = 0; mt < 2; ++mt)
                #pragma unroll
                for (int nt = 0; nt < NT; ++nt)
                    MMA_F16(acc[mt][nt], a[mt], b[nt]);
        }
        __syncthreads();
        if (kb < 2) {
            gemm_load_stage<BN>(sbase + (kb & 1) * STAGE, Ah, Bh, m0, n0, M, kb + 2, tid);
            CP_COMMIT();
        }
    }

    #pragma unroll
    for (int mt = 0; mt < 2; ++mt) {
        int row = m0 + warp_m * 32 + mt * 16 + (lane >> 2);
        #pragma unroll
        for (int nt = 0; nt < NT; ++nt) {
            int col = n0 + warp_n * (BN / 2) + nt * 8 + (lane & 3) * 2;
            if (col < Nn) {
                if (MODE != 0) {
                    if (row < M)
                        *reinterpret_cast<__half2*>(Ch + (size_t)row * Nn + col) =
                            __floats2half2_rn(acc[mt][nt][0], acc[mt][nt][1]);
                    if (row + 8 < M)
                        *reinterpret_cast<__half2*>(Ch + (size_t)(row + 8) * Nn + col) =
                            __floats2half2_rn(acc[mt][nt][2], acc[mt][nt][3]);
                } else {
                    if (row < M)
                        *reinterpret_cast<float2*>(Cf + (size_t)row * Nn + col) =
                            make_float2(acc[mt][nt][0], acc[mt][nt][1]);
                    if (row + 8 < M)
                        *reinterpret_cast<float2*>(Cf + (size_t)(row + 8) * Nn + col) =
                            make_float2(acc[mt][nt][2], acc[mt][nt][3]);
                }
            }
        }
    }

    if (MODE == 1) {
        const int h = (n0 + warp_n * 64) >> 6;
        float sl[2][2] = {}, sr[2][2] = {};
        #pragma unroll
        for (int nt = 0; nt < NT; ++nt) {
            int dloc = nt * 8 + (lane & 3) * 2;
            float2 av = __ldg(reinterpret_cast<const float2*>(al + h * 64 + dloc));
            float2 rv = __ldg(reinterpret_cast<const float2*>(ar + h * 64 + dloc));
            #pragma unroll
            for (int mt = 0; mt < 2; ++mt) {
                sl[mt][0] += acc[mt][nt][0] * av.x + acc[mt][nt][1] * av.y;
                sr[mt][0] += acc[mt][nt][0] * rv.x + acc[mt][nt][1] * rv.y;
                sl[mt][1] += acc[mt][nt][2] * av.x + acc[mt][nt][3] * av.y;
                sr[mt][1] += acc[mt][nt][2] * rv.x + acc[mt][nt][3] * rv.y;
            }
        }
        #pragma unroll
        for (int mt = 0; mt < 2; ++mt)
            #pragma unroll
            for (int rh = 0; rh < 2; ++rh) {
                float vl = sl[mt][rh], vr = sr[mt][rh];
                vl += __shfl_xor_sync(0xffffffffu, vl, 1);
                vl += __shfl_xor_sync(0xffffffffu, vl, 2);
                vr += __shfl_xor_sync(0xffffffffu, vr, 1);
                vr += __shfl_xor_sync(0xffffffffu, vr, 2);
                sl[mt][rh] = vl; sr[mt][rh] = vr;
            }
        if ((lane & 3) == 0) {
            #pragma unroll
            for (int mt = 0; mt < 2; ++mt)
                #pragma unroll
                for (int rh = 0; rh < 2; ++rh) {
                    int row = m0 + warp_m * 32 + mt * 16 + (lane >> 2) + rh * 8;
                    if (row < M) {
                        el[(size_t)row * H + h] = sl[mt][rh];
                        er[(size_t)row * H + h] = sr[mt][rh];
                    }
                }
        }
    } else if (MODE == 2) {
        const int colbase = n0 + warp_n * (BN / 2);
        if (colbase < Nn) {
            const int h0 = colbase / D;
            const int colend = (colbase + BN / 2 < Nn) ? (colbase + BN / 2) : Nn;
            const int hmax = (colend - 1) / D;
            float sl[2][2][3] = {}, sr[2][2][3] = {};
            #pragma unroll
            for (int nt = 0; nt < NT; ++nt) {
                int colg = colbase + nt * 8;
                if (colg < Nn) {
                    int h = colg / D;
                    int slot = h - h0;
                    if (slot > 2) slot = 2;
                    int d = colg - h * D + (lane & 3) * 2;
                    float2 av = __ldg(reinterpret_cast<const float2*>(al + h * D + d));
                    float2 rv = __ldg(reinterpret_cast<const float2*>(ar + h * D + d));
                    #pragma unroll
                    for (int mt = 0; mt < 2; ++mt) {
                        sl[mt][0][slot] += acc[mt][nt][0] * av.x + acc[mt][nt][1] * av.y;
                        sr[mt][0][slot] += acc[mt][nt][0] * rv.x + acc[mt][nt][1] * rv.y;
                        sl[mt][1][slot] += acc[mt][nt][2] * av.x + acc[mt][nt][3] * av.y;
                        sr[mt][1][slot] += acc[mt][nt][2] * rv.x + acc[mt][nt][3] * rv.y;
                    }
                }
            }
            #pragma unroll
            for (int mt = 0; mt < 2; ++mt)
                #pragma unroll
                for (int rh = 0; rh < 2; ++rh)
                    #pragma unroll
                    for (int sx = 0; sx < 3; ++sx) {
                        float vl = sl[mt][rh][sx], vr = sr[mt][rh][sx];
                        vl += __shfl_xor_sync(0xffffffffu, vl, 1);
                        vl += __shfl_xor_sync(0xffffffffu, vl, 2);
                        vr += __shfl_xor_sync(0xffffffffu, vr, 1);
                        vr += __shfl_xor_sync(0xffffffffu, vr, 2);
                        sl[mt][rh][sx] = vl; sr[mt][rh][sx] = vr;
                    }
            if ((lane & 3) == 0) {
                int nslots = hmax - h0 + 1;
                if (nslots > 3) nslots = 3;
                #pragma unroll
                for (int mt = 0; mt < 2; ++mt)
                    #pragma unroll
                    for (int rh = 0; rh < 2; ++rh) {
                        int row = m0 + warp_m * 32 + mt * 16 + (lane >> 2) + rh * 8;
                        if (row < M) {
                            for (int sx = 0; sx < nslots; ++sx) {
                                atomicAdd(&el[(size_t)row * H + h0 + sx], sl[mt][rh][sx]);
                                atomicAdd(&er[(size_t)row * H + h0 + sx], sr[mt][rh][sx]);
                            }
                        }
                    }
            }
        }
    }
}

#define GEMM_SMEM128 (2 * (8192 + 128 * 128))

// ---------------- GEMM launches ----------------
__global__ __launch_bounds__(128, 4) void k_gemm0(
    const __half* __restrict__ Ah, __half* __restrict__ Ch,
    const float* __restrict__ al, const float* __restrict__ ar,
    float* __restrict__ el, float* __restrict__ er, int M, int nGemm,
    const int* __restrict__ src, const int* __restrict__ dst, int E)
{
    int bx = blockIdx.x;
    if (bx < nGemm) {
        gemm_body<1, 128>(Ah, g_Bh, Ch, nullptr, al, ar, el, er,
                          M, 256, 4, 64, (bx >> 1) * 64, (bx & 1) * 128);
    } else {
        int e = (bx - nGemm) * 128 + threadIdx.x;
        if (e < E) {
            int p = atomicAdd(&g_cursor[dst[e]], 1);
            g_srcs[p] = src[e];
        }
    }
}

__global__ __launch_bounds__(128, 4) void k_gemm1(
    const __half* __restrict__ Ah, __half* __restrict__ Ch,
    const float* __restrict__ al, const float* __restrict__ ar,
    float* __restrict__ el, float* __restrict__ er, int M)
{
    int bx = blockIdx.x;
    gemm_body<1, 128>(Ah, g_Bh, Ch, nullptr, al, ar, el, er,
                      M, 256, 4, 64, (bx >> 1) * 64, (bx & 1) * 128);
}

__global__ __launch_bounds__(128, 4) void k_gemm2(
    const __half* __restrict__ Ah, __half* __restrict__ Ch, float* __restrict__ Cf,
    const float* __restrict__ al, const float* __restrict__ ar,
    float* __restrict__ el, float* __restrict__ er, int M, int nGemm)
{
    int bx = blockIdx.x;
    if (bx < nGemm) {
        gemm_body<2, 128>(Ah, g_Bh, Ch, nullptr, al, ar, el, er,
                          M, 240, 6, 40, (bx >> 1) * 64, (bx & 1) * 128);
    } else {
        gemm_body<0, 64>(Ah, g_Bh2, nullptr, Cf, nullptr, nullptr, nullptr, nullptr,
                         M, 40, 1, 64, (bx - nGemm) * 64, 0);
    }
}

// ---------------- fp16 quad-tree accumulate ----------------
// acc[j] (float2) += sum over 4 edges of w_k * z_k, products+tree in half2.
__device__ __forceinline__ void quad_acc(
    float2* accf, const uint4& q0, const uint4& q1, const uint4& q2, const uint4& q3,
    __half2 w0, __half2 w1, __half2 w2, __half2 w3)
{
    const __half2* z0 = reinterpret_cast<const __half2*>(&q0);
    const __half2* z1 = reinterpret_cast<const __half2*>(&q1);
    const __half2* z2 = reinterpret_cast<const __half2*>(&q2);
    const __half2* z3 = reinterpret_cast<const __half2*>(&q3);
    #pragma unroll
    for (int j = 0; j < 4; ++j) {
        __half2 t = __hadd2(__hadd2(__hmul2(w0, z0[j]), __hmul2(w1, z1[j])),
                            __hadd2(__hmul2(w2, z2[j]), __hmul2(w3, z3[j])));
        float2 tf = __half22float2(t);
        accf[j].x += tf.x;
        accf[j].y += tf.y;
    }
}
__device__ __forceinline__ void one_acc(float2* accf, const uint4& q, __half2 w)
{
    const __half2* z = reinterpret_cast<const __half2*>(&q);
    #pragma unroll
    for (int j = 0; j < 4; ++j) {
        float2 tf = __half22float2(__hmul2(w, z[j]));
        accf[j].x += tf.x;
        accf[j].y += tf.y;
    }
}

// ---------------- aggregation, layers 0/1 ----------------
template <bool RES>
__global__ __launch_bounds__(256) void k_agg256(
    const __half* __restrict__ zh, const float* __restrict__ el,
    const float* __restrict__ er, const float* __restrict__ bias,
    float* __restrict__ out, __half* __restrict__ oah, int n, int nAgg,
    const float* __restrict__ Wnext, int convN,
    const float* __restrict__ resW2,
    float* __restrict__ zel, float* __restrict__ zer, int n6)
{
    int bx = blockIdx.x;
    if (bx >= nAgg) {
        int t = bx - nAgg;
        if (t < 256) {
            convBt_elem(Wnext, g_Bh, t * 256 + threadIdx.x, convN);
        } else if (resW2 != nullptr && t < 320) {
            resmean_elem(resW2, (t - 256) * 256 + threadIdx.x);
        } else if (zel != nullptr) {
            int zoff = (resW2 != nullptr) ? 320 : 256;
            int i = (t - zoff) * 256 + threadIdx.x;
            if (i < n6) { zel[i] = 0.f; zer[i] = 0.f; }
        }
        return;
    }
    int gw = (bx * 256 + threadIdx.x) >> 5;
    if (gw >= n) return;
    int lane = threadIdx.x & 31;
    int beg = g_rowstart[gw], end = g_rowstart[gw + 1];
    float erh = (lane < 4) ? __ldg(&er[gw * 4 + lane]) : 0.f;
    int h = lane >> 3;
    int c0 = lane * 8;
    float2 accf[4] = {{0.f,0.f},{0.f,0.f},{0.f,0.f},{0.f,0.f}};
    float denom = 0.f;
    int i = beg;
    #pragma unroll 1
    for (; i + 4 <= end; i += 4) {
        int s0 = __ldg(&g_srcs[i]);
        int s1 = __ldg(&g_srcs[i + 1]);
        int s2 = __ldg(&g_srcs[i + 2]);
        int s3 = __ldg(&g_srcs[i + 3]);
        uint4 q0 = __ldg(reinterpret_cast<const uint4*>(zh + (size_t)s0 * 256 + c0));
        uint4 q1 = __ldg(reinterpret_cast<const uint4*>(zh + (size_t)s1 * 256 + c0));
        uint4 q2 = __ldg(reinterpret_cast<const uint4*>(zh + (size_t)s2 * 256 + c0));
        uint4 q3 = __ldg(reinterpret_cast<const uint4*>(zh + (size_t)s3 * 256 + c0));
        float w0 = 0.f, w1 = 0.f, w2 = 0.f, w3 = 0.f;
        if (lane < 4) {
            float e0 = __ldg(&el[s0 * 4 + lane]) + erh;
            float e1 = __ldg(&el[s1 * 4 + lane]) + erh;
            float e2 = __ldg(&el[s2 * 4 + lane]) + erh;
            float e3 = __ldg(&el[s3 * 4 + lane]) + erh;
            e0 = (e0 > 0.f) ? e0 : 0.2f * e0;
            e1 = (e1 > 0.f) ? e1 : 0.2f * e1;
            e2 = (e2 > 0.f) ? e2 : 0.2f * e2;
            e3 = (e3 > 0.f) ? e3 : 0.2f * e3;
            w0 = __expf(e0 - WSCALE); w1 = __expf(e1 - WSCALE);
            w2 = __expf(e2 - WSCALE); w3 = __expf(e3 - WSCALE);
            denom += (w0 + w1) + (w2 + w3);
        }
        __half2 wh0 = __float2half2_rn(__shfl_sync(0xffffffffu, w0, h));
        __half2 wh1 = __float2half2_rn(__shfl_sync(0xffffffffu, w1, h));
        __half2 wh2 = __float2half2_rn(__shfl_sync(0xffffffffu, w2, h));
        __half2 wh3 = __float2half2_rn(__shfl_sync(0xffffffffu, w3, h));
        quad_acc(accf, q0, q1, q2, q3, wh0, wh1, wh2, wh3);
    }
    #pragma unroll 1
    for (; i < end; ++i) {
        int s0 = __ldg(&g_srcs[i]);
        uint4 q0 = __ldg(reinterpret_cast<const uint4*>(zh + (size_t)s0 * 256 + c0));
        float w0 = 0.f;
        if (lane < 4) {
            float e0 = __ldg(&el[s0 * 4 + lane]) + erh;
            e0 = (e0 > 0.f) ? e0 : 0.2f * e0;
            w0 = __expf(e0 - WSCALE);
            denom += w0;
        }
        __half2 wh0 = __float2half2_rn(__shfl_sync(0xffffffffu, w0, h));
        one_acc(accf, q0, wh0);
    }
    float dh = __shfl_sync(0xffffffffu, denom, h);
    float inv = 1.f / dh;
    const float4* bp = reinterpret_cast<const float4*>(bias + c0);
    float4 b0 = __ldg(bp), b1 = __ldg(bp + 1);
    float v[8];
    v[0] = fmaf(accf[0].x, inv, b0.x); v[1] = fmaf(accf[0].y, inv, b0.y);
    v[2] = fmaf(accf[1].x, inv, b0.z); v[3] = fmaf(accf[1].y, inv, b0.w);
    v[4] = fmaf(accf[2].x, inv, b1.x); v[5] = fmaf(accf[2].y, inv, b1.y);
    v[6] = fmaf(accf[3].x, inv, b1.z); v[7] = fmaf(accf[3].y, inv, b1.w);
    if (RES) {
        uint4 rq = *reinterpret_cast<const uint4*>(oah + (size_t)gw * 256 + c0);
        float2 r0 = __half22float2(*reinterpret_cast<__half2*>(&rq.x));
        float2 r1 = __half22float2(*reinterpret_cast<__half2*>(&rq.y));
        float2 r2 = __half22float2(*reinterpret_cast<__half2*>(&rq.z));
        float2 r3 = __half22float2(*reinterpret_cast<__half2*>(&rq.w));
        v[0] += r0.x; v[1] += r0.y; v[2] += r1.x; v[3] += r1.y;
        v[4] += r2.x; v[5] += r2.y; v[6] += r3.x; v[7] += r3.y;
    }
    #pragma unroll
    for (int j = 0; j < 8; ++j) v[j] = (v[j] > 0.f) ? v[j] : expm1f(v[j]);
    if (out != nullptr) {
        float4* op = reinterpret_cast<float4*>(out + (size_t)gw * 256 + c0);
        op[0] = make_float4(v[0], v[1], v[2], v[3]);
        op[1] = make_float4(v[4], v[5], v[6], v[7]);
    }
    __half2 p0 = __floats2half2_rn(v[0], v[1]);
    __half2 p1 = __floats2half2_rn(v[2], v[3]);
    __half2 p2 = __floats2half2_rn(v[4], v[5]);
    __half2 p3 = __floats2half2_rn(v[6], v[7]);
    *reinterpret_cast<uint4*>(oah + (size_t)gw * 256 + c0) =
        make_uint4(*reinterpret_cast<uint32_t*>(&p0), *reinterpret_cast<uint32_t*>(&p1),
                   *reinterpret_cast<uint32_t*>(&p2), *reinterpret_cast<uint32_t*>(&p3));
}

// ---------------- aggregation, layer 2 ----------------
__global__ __launch_bounds__(256) void k_agg_l2(
    const __half* __restrict__ zh, const float* __restrict__ el,
    const float* __restrict__ er, const float* __restrict__ bias,
    const float* __restrict__ r2m, float* __restrict__ logits, int n)
{
    __shared__ float sout[8][240];
    int wInB = threadIdx.x >> 5;
    int gw = blockIdx.x * 8 + wInB;
    int lane = threadIdx.x & 31;
    bool act = (lane < 30);
    if (gw < n) {
        int beg = g_rowstart[gw], end = g_rowstart[gw + 1];
        float erh = (lane < 6) ? __ldg(&er[gw * 6 + lane]) : 0.f;
        int h = act ? (lane / 5) : 0;
        int c0 = lane * 8;
        float2 accf[4] = {{0.f,0.f},{0.f,0.f},{0.f,0.f},{0.f,0.f}};
        float denom = 0.f;
        int i = beg;
        #pragma unroll 1
        for (; i + 4 <= end; i += 4) {
            int s0 = __ldg(&g_srcs[i]);
            int s1 = __ldg(&g_srcs[i + 1]);
            int s2 = __ldg(&g_srcs[i + 2]);
            int s3 = __ldg(&g_srcs[i + 3]);
            uint4 q0 = make_uint4(0, 0, 0, 0), q1 = q0, q2 = q0, q3 = q0;
            if (act) {
                q0 = __ldg(reinterpret_cast<const uint4*>(zh + (size_t)s0 * 240 + c0));
                q1 = __ldg(reinterpret_cast<const uint4*>(zh + (size_t)s1 * 240 + c0));
                q2 = __ldg(reinterpret_cast<const uint4*>(zh + (size_t)s2 * 240 + c0));
                q3 = __ldg(reinterpret_cast<const uint4*>(zh + (size_t)s3 * 240 + c0));
            }
            float w0 = 0.f, w1 = 0.f, w2 = 0.f, w3 = 0.f;
            if (lane < 6) {
                float e0 = __ldg(&el[s0 * 6 + lane]) + erh;
                float e1 = __ldg(&el[s1 * 6 + lane]) + erh;
                float e2 = __ldg(&el[s2 * 6 + lane]) + erh;
                float e3 = __ldg(&el[s3 * 6 + lane]) + erh;
                e0 = (e0 > 0.f) ? e0 : 0.2f * e0;
                e1 = (e1 > 0.f) ? e1 : 0.2f * e1;
                e2 = (e2 > 0.f) ? e2 : 0.2f * e2;
                e3 = (e3 > 0.f) ? e3 : 0.2f * e3;
                w0 = __expf(e0 - WSCALE); w1 = __expf(e1 - WSCALE);
                w2 = __expf(e2 - WSCALE); w3 = __expf(e3 - WSCALE);
                denom += (w0 + w1) + (w2 + w3);
            }
            __half2 wh0 = __float2half2_rn(__shfl_sync(0xffffffffu, w0, h));
            __half2 wh1 = __float2half2_rn(__shfl_sync(0xffffffffu, w1, h));
            __half2 wh2 = __float2half2_rn(__shfl_sync(0xffffffffu, w2, h));
            __half2 wh3 = __float2half2_rn(__shfl_sync(0xffffffffu, w3, h));
            if (act) quad_acc(accf, q0, q1, q2, q3, wh0, wh1, wh2, wh3);
        }
        #pragma unroll 1
        for (; i < end; ++i) {
            int s0 = __ldg(&g_srcs[i]);
            uint4 q0 = make_uint4(0, 0, 0, 0);
            if (act) q0 = __ldg(reinterpret_cast<const uint4*>(zh + (size_t)s0 * 240 + c0));
            float w0 = 0.f;
            if (lane < 6) {
                float e0 = __ldg(&el[s0 * 6 + lane]) + erh;
                e0 = (e0 > 0.f) ? e0 : 0.2f * e0;
                w0 = __expf(e0 - WSCALE);
                denom += w0;
            }
            __half2 wh0 = __float2half2_rn(__shfl_sync(0xffffffffu, w0, h));
            if (act) one_acc(accf, q0, wh0);
        }
        float dh = __shfl_sync(0xffffffffu, denom, h);
        if (act) {
            float inv = 1.f / dh;
            const float4* bp = reinterpret_cast<const float4*>(bias + c0);
            float4 b0 = __ldg(bp), b1 = __ldg(bp + 1);
            sout[wInB][c0 + 0] = fmaf(accf[0].x, inv, b0.x);
            sout[wInB][c0 + 1] = fmaf(accf[0].y, inv, b0.y);
            sout[wInB][c0 + 2] = fmaf(accf[1].x, inv, b0.z);
            sout[wInB][c0 + 3] = fmaf(accf[1].y, inv, b0.w);
            sout[wInB][c0 + 4] = fmaf(accf[2].x, inv, b1.x);
            sout[wInB][c0 + 5] = fmaf(accf[2].y, inv, b1.y);
            sout[wInB][c0 + 6] = fmaf(accf[3].x, inv, b1.z);
            sout[wInB][c0 + 7] = fmaf(accf[3].y, inv, b1.w);
        }
    }
    __syncwarp();
    if (gw < n) {
        for (int d = lane; d < 40; d += 32) {
            float s_ = 0.f;
            #pragma unroll
            for (int hh = 0; hh < 6; ++hh) s_ += sout[wInB][hh * 40 + d];
            logits[(size_t)gw * 40 + d] = s_ * (1.0f / 6.0f) + __ldg(&r2m[(size_t)gw * 40 + d]);
        }
    }
}

// ---------------- host ----------------
extern "C" void kernel_launch(void* const* d_in, const int* in_sizes, int n_in,
                              void* d_out, int out_size)
{
    const float* feat  = (const float*)d_in[0];
    const int*   src   = (const int*)d_in[1];
    const int*   dst   = (const int*)d_in[2];
    const float* W0    = (const float*)d_in[3];
    const float* al0   = (const float*)d_in[4];
    const float* ar0   = (const float*)d_in[5];
    const float* b0    = (const float*)d_in[6];
    const float* W1    = (const float*)d_in[7];
    const float* al1   = (const float*)d_in[8];
    const float* ar1   = (const float*)d_in[9];
    const float* b1    = (const float*)d_in[10];
    const float* W2    = (const float*)d_in[11];
    const float* al2   = (const float*)d_in[12];
    const float* ar2   = (const float*)d_in[13];
    const float* b2    = (const float*)d_in[14];
    const float* resW2 = (const float*)d_in[15];

    const int n = NNODES;
    const int E = in_sizes[1];

    float* logits = (float*)d_out;
    float* h1     = (float*)d_out + n * 40;

    float *pr2, *pelA, *perA, *pelB, *perB;
    __half *pzh, *pAh;
    int* pdeg;
    cudaGetSymbolAddress((void**)&pzh,  g_zh);
    cudaGetSymbolAddress((void**)&pr2,  g_r2);
    cudaGetSymbolAddress((void**)&pelA, g_elA);
    cudaGetSymbolAddress((void**)&perA, g_erA);
    cudaGetSymbolAddress((void**)&pelB, g_elB);
    cudaGetSymbolAddress((void**)&perB, g_erB);
    cudaGetSymbolAddress((void**)&pAh,  g_Ah);
    cudaGetSymbolAddress((void**)&pdeg, g_deg);

    cudaFuncSetAttribute(k_gemm0, cudaFuncAttributeMaxDynamicSharedMemorySize, GEMM_SMEM128);
    cudaFuncSetAttribute(k_gemm1, cudaFuncAttributeMaxDynamicSharedMemorySize, GEMM_SMEM128);
    cudaFuncSetAttribute(k_gemm2, cudaFuncAttributeMaxDynamicSharedMemorySize, GEMM_SMEM128);

    const int nGemm = ((n + 63) / 64) * 2;
    const int nGemmM = (n + 63) / 64;
    const int histBlocks = (E + 255) / 256;
    const int scatBlocks = (E + 127) / 128;
    const int zeroBlocks = (n * 6 + 255) / 256;
    const int aggBlocks  = (n + 7) / 8;

    cudaMemsetAsync(pdeg, 0, n * sizeof(int));
    k_prep0<<<SPLITA_BLOCKS + 256 + histBlocks, 256>>>(feat, W0, dst, E);
    k_scan<<<1, 1024>>>(n, E);
    k_gemm0<<<nGemm + scatBlocks, 128, GEMM_SMEM128>>>(pAh, pzh, al0, ar0, pelA, perA,
                                                       n, nGemm, src, dst, E);
    k_agg256<false><<<aggBlocks + 256, 256>>>(
        pzh, pelA, perA, b0, nullptr, pAh, n, aggBlocks,
        W1, 256, nullptr, nullptr, nullptr, 0);
    k_gemm1<<<nGemm, 128, GEMM_SMEM128>>>(pAh, pzh, al1, ar1, pelB, perB, n);
    k_agg256<true><<<aggBlocks + 256 + 64 + zeroBlocks, 256>>>(
        pzh, pelB, perB, b1, h1, pAh, n, aggBlocks,
        W2, 240, resW2, pelA, perA, n * 6);
    k_gemm2<<<nGemm + nGemmM, 128, GEMM_SMEM128>>>(pAh, pzh, pr2, al2, ar2, pelA, perA,
                                                   n, nGemm);
    k_agg_l2<<<aggBlocks, 256>>>(pzh, pelA, perA, b2, pr2, logits, n);
}